// round 1
// baseline (speedup 1.0000x reference)
#include <cuda_runtime.h>
#include <math.h>

#define NN 65535          // number of tree nodes (2^16 - 1)
#define BIGF 1e30f

// ---------------- scratch (static device globals; no cudaMalloc) -------------
__device__ float g_x[(size_t)NN * 288];      // features  [N,288]
__device__ float g_xg[(size_t)NN * 1024];    // gates pre-activation [N,1024]
__device__ float g_H[(size_t)NN * 256];      // LSTM hidden
__device__ float g_C[(size_t)NN * 256];      // LSTM cell
__device__ int   g_mask_is_byte;             // bool-dtype detection flag

__device__ __forceinline__ float sigf(float x) { return 1.0f / (1.0f + expf(-x)); }

__device__ __forceinline__ int read_bool(const void* p, int idx) {
    return g_mask_is_byte ? (int)(((const unsigned char*)p)[idx])
                          : (((const int*)p)[idx] != 0);
}

// ---------------- bool dtype detection --------------------------------------
// If masks are int32 {0,1}, every 32-bit word is <= 1. If they are packed
// 1-byte bools, words formed from 4 random bits exceed 1 with overwhelming
// probability within 256 words.
__global__ void k_detect(const unsigned int* __restrict__ m) {
    __shared__ int found;
    if (threadIdx.x == 0) found = 0;
    __syncthreads();
    unsigned int v = m[threadIdx.x];   // 256 words = 1KB, in-bounds either way
    if (v > 1u) found = 1;
    __syncthreads();
    if (threadIdx.x == 0) g_mask_is_byte = found;
}

// ---------------- op projection: x[:, 0:32] ----------------------------------
__global__ void k_op(const float* __restrict__ op_vec,
                     const float* __restrict__ W_op,
                     const float* __restrict__ b_op) {
    int idx = blockIdx.x * 256 + threadIdx.x;
    if (idx >= NN * 32) return;
    int n = idx >> 5, o = idx & 31;
    float acc = b_op[o];
    const float* v = op_vec + n * 32;
    const float* w = W_op + o * 32;
#pragma unroll
    for (int p = 0; p < 32; p++) acc += w[p] * v[p];
    g_x[(size_t)n * 288 + o] = acc;
}

// ---------------- pooled predicate features: x[:, 32:160] --------------------
// GEMM over rows=(node,k) pairs (M = N*8, K=64, Ncols=64) with the masked
// min/max pooling fused into the epilogue (each thread owns all 8 k of a node).
// Block: 16 nodes (128 rows) x 64 cols, 128 threads, 8x8 per thread.
__global__ void k_pool(const float* __restrict__ preds1, const void* mask1, const void* and1,
                       const float* __restrict__ preds2, const void* mask2, const void* and2,
                       const float* __restrict__ W_pred, const float* __restrict__ b_pred) {
    int cond = blockIdx.y;
    const float* preds = cond ? preds2 : preds1;
    const void*  maskp = cond ? mask2 : mask1;
    const void*  andp  = cond ? and2  : and1;

    __shared__ float As[128][36];   // preds rows (p-major)
    __shared__ float Bs[64][36];    // W_pred rows (p-major)

    int tid = threadIdx.x;
    int trow = tid >> 3;            // 16 node groups (8 rows each)
    int tcol = tid & 7;             // 8 col groups (8 cols each)
    int nodeBase = blockIdx.x * 16;

    float acc[8][8];
#pragma unroll
    for (int i = 0; i < 8; i++)
#pragma unroll
        for (int j = 0; j < 8; j++) acc[i][j] = 0.0f;

    const float* src = preds + (size_t)nodeBase * 512;   // 16 nodes * 8k * 64p contiguous
    int maxr = (NN - nodeBase) * 8;
    if (maxr > 128) maxr = 128;

    for (int k0 = 0; k0 < 64; k0 += 32) {
        for (int idx = tid; idx < 128 * 32; idx += 128) {
            int r = idx >> 5, kk = idx & 31;
            As[r][kk] = (r < maxr) ? src[r * 64 + k0 + kk] : 0.0f;
        }
        for (int idx = tid; idx < 64 * 32; idx += 128) {
            int c = idx >> 5, kk = idx & 31;
            Bs[c][kk] = W_pred[c * 64 + k0 + kk];
        }
        __syncthreads();
#pragma unroll
        for (int kk4 = 0; kk4 < 8; kk4++) {
            float4 a4[8], b4[8];
#pragma unroll
            for (int i = 0; i < 8; i++)
                a4[i] = *reinterpret_cast<const float4*>(&As[trow * 8 + i][kk4 * 4]);
#pragma unroll
            for (int j = 0; j < 8; j++)
                b4[j] = *reinterpret_cast<const float4*>(&Bs[tcol * 8 + j][kk4 * 4]);
#pragma unroll
            for (int i = 0; i < 8; i++)
#pragma unroll
                for (int j = 0; j < 8; j++)
                    acc[i][j] += a4[i].x * b4[j].x + a4[i].y * b4[j].y +
                                 a4[i].z * b4[j].z + a4[i].w * b4[j].w;
        }
        __syncthreads();
    }

    int node = nodeBase + trow;
    if (node < NN) {
        int mk[8], anyb = 0;
#pragma unroll
        for (int i = 0; i < 8; i++) { mk[i] = read_bool(maskp, node * 8 + i); anyb |= mk[i]; }
        int ia = read_bool(andp, node);
#pragma unroll
        for (int j = 0; j < 8; j++) {
            int q = tcol * 8 + j;
            float bq = b_pred[q];
            float mn = BIGF, mx = -BIGF;
#pragma unroll
            for (int i = 0; i < 8; i++) {
                float v = acc[i][j] + bq;
                if (mk[i]) { mn = fminf(mn, v); mx = fmaxf(mx, v); }
            }
            float pooled = anyb ? (ia ? mn : mx) : 0.0f;
            g_x[(size_t)node * 288 + 32 + cond * 64 + q] = pooled;
        }
    }
}

// ---------------- bitmap projection: x[:, 160:288] ---------------------------
// GEMM M=N, Ncols=128, K=1000. Block 128x128, 256 threads, 8x8 per thread.
__global__ void k_bm(const float* __restrict__ bitmap,
                     const float* __restrict__ W_bm,
                     const float* __restrict__ b_bm) {
    __shared__ float As[128][12];
    __shared__ float Bs[128][12];
    int tid = threadIdx.x;
    int rowBase = blockIdx.x * 128;
    int trow = tid >> 4, tcol = tid & 15;
    float acc[8][8];
#pragma unroll
    for (int i = 0; i < 8; i++)
#pragma unroll
        for (int j = 0; j < 8; j++) acc[i][j] = 0.0f;
    int maxr = NN - rowBase;
    if (maxr > 128) maxr = 128;

    for (int k0 = 0; k0 < 1000; k0 += 8) {
        for (int idx = tid; idx < 1024; idx += 256) {
            int r = idx >> 3, kk = idx & 7;
            As[r][kk] = (r < maxr) ? bitmap[(size_t)(rowBase + r) * 1000 + k0 + kk] : 0.0f;
        }
        for (int idx = tid; idx < 1024; idx += 256) {
            int c = idx >> 3, kk = idx & 7;
            Bs[c][kk] = W_bm[c * 1000 + k0 + kk];
        }
        __syncthreads();
#pragma unroll
        for (int kk4 = 0; kk4 < 2; kk4++) {
            float4 a4[8], b4[8];
#pragma unroll
            for (int i = 0; i < 8; i++)
                a4[i] = *reinterpret_cast<const float4*>(&As[trow * 8 + i][kk4 * 4]);
#pragma unroll
            for (int j = 0; j < 8; j++)
                b4[j] = *reinterpret_cast<const float4*>(&Bs[tcol * 8 + j][kk4 * 4]);
#pragma unroll
            for (int i = 0; i < 8; i++)
#pragma unroll
                for (int j = 0; j < 8; j++)
                    acc[i][j] += a4[i].x * b4[j].x + a4[i].y * b4[j].y +
                                 a4[i].z * b4[j].z + a4[i].w * b4[j].w;
        }
        __syncthreads();
    }
#pragma unroll
    for (int i = 0; i < 8; i++) {
        int row = rowBase + trow * 8 + i;
        if (row < NN) {
#pragma unroll
            for (int j = 0; j < 8; j++) {
                int c = tcol * 8 + j;
                g_x[(size_t)row * 288 + 160 + c] = acc[i][j] + b_bm[c];
            }
        }
    }
}

// ---------------- xg = x @ W_ih^T + (b_ih + b_hh) ----------------------------
// GEMM M=N, Ncols=1024 (tiled 128 per block.y), K=288.
__global__ void k_xg(const float* __restrict__ W_ih,
                     const float* __restrict__ b_ih,
                     const float* __restrict__ b_hh) {
    __shared__ float As[128][12];
    __shared__ float Bs[128][12];
    int tid = threadIdx.x;
    int rowBase = blockIdx.x * 128;
    int colBase = blockIdx.y * 128;
    int trow = tid >> 4, tcol = tid & 15;
    float acc[8][8];
#pragma unroll
    for (int i = 0; i < 8; i++)
#pragma unroll
        for (int j = 0; j < 8; j++) acc[i][j] = 0.0f;
    int maxr = NN - rowBase;
    if (maxr > 128) maxr = 128;

    for (int k0 = 0; k0 < 288; k0 += 8) {
        for (int idx = tid; idx < 1024; idx += 256) {
            int r = idx >> 3, kk = idx & 7;
            As[r][kk] = (r < maxr) ? g_x[(size_t)(rowBase + r) * 288 + k0 + kk] : 0.0f;
        }
        for (int idx = tid; idx < 1024; idx += 256) {
            int c = idx >> 3, kk = idx & 7;
            Bs[c][kk] = W_ih[(size_t)(colBase + c) * 288 + k0 + kk];
        }
        __syncthreads();
#pragma unroll
        for (int kk4 = 0; kk4 < 2; kk4++) {
            float4 a4[8], b4[8];
#pragma unroll
            for (int i = 0; i < 8; i++)
                a4[i] = *reinterpret_cast<const float4*>(&As[trow * 8 + i][kk4 * 4]);
#pragma unroll
            for (int j = 0; j < 8; j++)
                b4[j] = *reinterpret_cast<const float4*>(&Bs[tcol * 8 + j][kk4 * 4]);
#pragma unroll
            for (int i = 0; i < 8; i++)
#pragma unroll
                for (int j = 0; j < 8; j++)
                    acc[i][j] += a4[i].x * b4[j].x + a4[i].y * b4[j].y +
                                 a4[i].z * b4[j].z + a4[i].w * b4[j].w;
        }
        __syncthreads();
    }
#pragma unroll
    for (int i = 0; i < 8; i++) {
        int row = rowBase + trow * 8 + i;
        if (row < NN) {
#pragma unroll
            for (int j = 0; j < 8; j++) {
                int o = colBase + tcol * 8 + j;
                g_xg[(size_t)row * 1024 + o] = acc[i][j] + b_ih[o] + b_hh[o];
            }
        }
    }
}

// ---------------- leaves (d = D): c0 = 0 -------------------------------------
__global__ void k_leaf() {
    int n = blockIdx.x;          // 0..32767
    int j = threadIdx.x;         // 0..255
    const float* xr = g_xg + (size_t)n * 1024;
    float gi = xr[j];
    float gg = xr[512 + j];
    float go = xr[768 + j];
    float c = sigf(gi) * tanhf(gg);
    float h = sigf(go) * tanhf(c);
    g_H[(size_t)n * 256 + j] = h;
    g_C[(size_t)n * 256 + j] = c;
}

// ---------------- interior level: h0 avg + GEMM(W_hh) + LSTM pointwise -------
// Block: 32 nodes x 64 j-cols x 4 gates; 256 threads; each thread: 8 rows x 4 gates.
__global__ void k_level(int start, int nd, const float* __restrict__ W_hh) {
    __shared__ float h0s[32][36];
    __shared__ float Ws[256][36];
    int tid = threadIdx.x;
    int jx = tid & 63, ry = tid >> 6;
    int rowBase = blockIdx.x * 32;
    int jbase = blockIdx.y * 64;

    float acc[8][4];
#pragma unroll
    for (int i = 0; i < 8; i++)
#pragma unroll
        for (int g = 0; g < 4; g++) acc[i][g] = 0.0f;

    for (int k0 = 0; k0 < 256; k0 += 32) {
        for (int idx = tid; idx < 32 * 32; idx += 256) {
            int r = idx >> 5, kk = idx & 31;
            float v = 0.0f;
            int rr = rowBase + r;
            if (rr < nd) {
                int node = start + rr;
                int ci = 2 * node - NN;
                v = 0.5f * (g_H[(size_t)ci * 256 + k0 + kk] +
                            g_H[(size_t)(ci - 1) * 256 + k0 + kk]);
            }
            h0s[r][kk] = v;
        }
        {
            int wrow = ((tid >> 6) * 256) + jbase + (tid & 63);  // gate*256 + j
#pragma unroll
            for (int kk = 0; kk < 32; kk++) Ws[tid][kk] = W_hh[(size_t)wrow * 256 + k0 + kk];
        }
        __syncthreads();
#pragma unroll
        for (int kk4 = 0; kk4 < 8; kk4++) {
            float4 w4[4];
#pragma unroll
            for (int g = 0; g < 4; g++)
                w4[g] = *reinterpret_cast<const float4*>(&Ws[g * 64 + jx][kk4 * 4]);
#pragma unroll
            for (int i = 0; i < 8; i++) {
                float4 a4 = *reinterpret_cast<const float4*>(&h0s[ry * 8 + i][kk4 * 4]);
#pragma unroll
                for (int g = 0; g < 4; g++)
                    acc[i][g] += a4.x * w4[g].x + a4.y * w4[g].y +
                                 a4.z * w4[g].z + a4.w * w4[g].w;
            }
        }
        __syncthreads();
    }

    int j = jbase + jx;
#pragma unroll
    for (int i = 0; i < 8; i++) {
        int rr = rowBase + ry * 8 + i;
        if (rr < nd) {
            int node = start + rr;
            const float* xr = g_xg + (size_t)node * 1024;
            float gi = acc[i][0] + xr[j];
            float gf = acc[i][1] + xr[256 + j];
            float gg = acc[i][2] + xr[512 + j];
            float go = acc[i][3] + xr[768 + j];
            int ci = 2 * node - NN;
            float c0 = 0.5f * (g_C[(size_t)ci * 256 + j] + g_C[(size_t)(ci - 1) * 256 + j]);
            float cn = sigf(gf) * c0 + sigf(gi) * tanhf(gg);
            float hn = sigf(go) * tanhf(cn);
            g_H[(size_t)node * 256 + j] = hn;
            g_C[(size_t)node * 256 + j] = cn;
        }
    }
}

// ---------------- output heads ----------------------------------------------
__global__ void k_heads(const float* __restrict__ W2a, const float* __restrict__ b2a,
                        const float* __restrict__ W3a, const float* __restrict__ b3a,
                        const float* __restrict__ Woa, const float* __restrict__ boa,
                        const float* __restrict__ W2b, const float* __restrict__ b2b,
                        const float* __restrict__ W3b, const float* __restrict__ b3b,
                        const float* __restrict__ Wob, const float* __restrict__ bob,
                        float* __restrict__ out) {
    __shared__ float hv[256];
    __shared__ float t1[2][128];
    __shared__ float t2[2][128];
    __shared__ float red[256];
    int tid = threadIdx.x;
    hv[tid] = g_H[(size_t)(NN - 1) * 256 + tid];
    __syncthreads();
    int head = tid >> 7, j = tid & 127;
    const float* W2 = head ? W2b : W2a; const float* b2 = head ? b2b : b2a;
    const float* W3 = head ? W3b : W3a; const float* b3 = head ? b3b : b3a;
    const float* Wo = head ? Wob : Woa; const float* bo = head ? bob : boa;

    float t = b2[j];
    for (int k = 0; k < 256; k++) t += W2[j * 256 + k] * hv[k];
    t1[head][j] = fmaxf(t, 0.0f);
    __syncthreads();
    t = b3[j];
    for (int k = 0; k < 128; k++) t += W3[j * 128 + k] * t1[head][k];
    t2[head][j] = fmaxf(t, 0.0f);
    __syncthreads();
    red[tid] = Wo[j] * t2[head][j];
    __syncthreads();
    for (int s = 64; s > 0; s >>= 1) {
        if (j < s) red[tid] += red[tid + s];
        __syncthreads();
    }
    if (j == 0) out[head] = 1.0f / (1.0f + expf(-(red[tid] + bo[0])));
}

// ---------------- launch ------------------------------------------------------
extern "C" void kernel_launch(void* const* d_in, const int* in_sizes, int n_in,
                              void* d_out, int out_size) {
    const float* op_vec   = (const float*)d_in[0];
    const float* c1_preds = (const float*)d_in[1];
    const void*  c1_mask  = d_in[2];
    const void*  c1_and   = d_in[3];
    const float* c2_preds = (const float*)d_in[4];
    const void*  c2_mask  = d_in[5];
    const void*  c2_and   = d_in[6];
    const float* bitmap   = (const float*)d_in[7];
    const float* W_op     = (const float*)d_in[8];
    const float* b_op     = (const float*)d_in[9];
    const float* W_pred   = (const float*)d_in[10];
    const float* b_pred   = (const float*)d_in[11];
    const float* W_bm     = (const float*)d_in[12];
    const float* b_bm     = (const float*)d_in[13];
    const float* W_ih     = (const float*)d_in[14];
    const float* b_ih     = (const float*)d_in[15];
    const float* W_hh     = (const float*)d_in[16];
    const float* b_hh     = (const float*)d_in[17];
    const float* W_h2t1   = (const float*)d_in[18];
    const float* b_h2t1   = (const float*)d_in[19];
    const float* W_h3t1   = (const float*)d_in[20];
    const float* b_h3t1   = (const float*)d_in[21];
    const float* W_o1     = (const float*)d_in[22];
    const float* b_o1     = (const float*)d_in[23];
    const float* W_h2t2   = (const float*)d_in[24];
    const float* b_h2t2   = (const float*)d_in[25];
    const float* W_h3t2   = (const float*)d_in[26];
    const float* b_h3t2   = (const float*)d_in[27];
    const float* W_o2     = (const float*)d_in[28];
    const float* b_o2     = (const float*)d_in[29];
    float* out = (float*)d_out;

    k_detect<<<1, 256>>>((const unsigned int*)c1_mask);

    k_op<<<(NN * 32 + 255) / 256, 256>>>(op_vec, W_op, b_op);

    {
        dim3 grid((NN + 15) / 16, 2);
        k_pool<<<grid, 128>>>(c1_preds, c1_mask, c1_and,
                              c2_preds, c2_mask, c2_and,
                              W_pred, b_pred);
    }

    k_bm<<<(NN + 127) / 128, 256>>>(bitmap, W_bm, b_bm);

    {
        dim3 grid((NN + 127) / 128, 8);
        k_xg<<<grid, 256>>>(W_ih, b_ih, b_hh);
    }

    k_leaf<<<32768, 256>>>();

    for (int d = 14; d >= 0; d--) {
        int nd = 1 << d;
        int start = NN - (1 << (d + 1)) + 1;
        dim3 grid((nd + 31) / 32, 4);
        k_level<<<grid, 256>>>(start, nd, W_hh);
    }

    k_heads<<<1, 256>>>(W_h2t1, b_h2t1, W_h3t1, b_h3t1, W_o1, b_o1,
                        W_h2t2, b_h2t2, W_h3t2, b_h3t2, W_o2, b_o2,
                        out);
}

// round 2
// speedup vs baseline: 3.4731x; 3.4731x over previous
#include <cuda_runtime.h>
#include <math.h>

#define NN 65535          // number of tree nodes (2^16 - 1)
#define BIGF 1e30f

// ---------------- scratch (static device globals; no cudaMalloc) -------------
__device__ float g_x[(size_t)NN * 288];      // features  [N,288]
__device__ float g_xg[(size_t)NN * 1024];    // gates pre-activation [N,1024]
__device__ float g_H[(size_t)NN * 256];      // LSTM hidden
__device__ float g_C[(size_t)NN * 256];      // LSTM cell
__device__ int   g_mask_is_byte;             // bool-dtype detection flag

__device__ __forceinline__ float sigf(float x) { return 1.0f / (1.0f + expf(-x)); }

__device__ __forceinline__ int read_bool(const void* p, int idx) {
    return g_mask_is_byte ? (int)(((const unsigned char*)p)[idx])
                          : (((const int*)p)[idx] != 0);
}

__device__ __forceinline__ unsigned smem_u32(const void* p) {
    return (unsigned)__cvta_generic_to_shared(p);
}
__device__ __forceinline__ void cpa16(unsigned dst, const float* src, int srcBytes) {
    asm volatile("cp.async.cg.shared.global [%0], [%1], 16, %2;\n"
                 :: "r"(dst), "l"(src), "r"(srcBytes));
}
__device__ __forceinline__ void cpa_commit() { asm volatile("cp.async.commit_group;\n"); }
__device__ __forceinline__ void cpa_wait0()  { asm volatile("cp.async.wait_group 0;\n"); }

// ---------------- bool dtype detection --------------------------------------
__global__ void k_detect(const unsigned int* __restrict__ m) {
    __shared__ int found;
    if (threadIdx.x == 0) found = 0;
    __syncthreads();
    unsigned int v = m[threadIdx.x];
    if (v > 1u) found = 1;
    __syncthreads();
    if (threadIdx.x == 0) g_mask_is_byte = found;
}

// ---------------- op projection: x[:, 0:32] ----------------------------------
// 8 nodes per block; warp per node; W_op cached in smem (conflict-free pad).
__global__ void k_op(const float* __restrict__ op_vec,
                     const float* __restrict__ W_op,
                     const float* __restrict__ b_op) {
    __shared__ float Ws[32][33];
    __shared__ float bs[32];
    int tid = threadIdx.x;
    if (tid < 32) bs[tid] = b_op[tid];
    for (int i = tid; i < 1024; i += 256) Ws[i >> 5][i & 31] = W_op[i];
    __syncthreads();
    int node = blockIdx.x * 8 + (tid >> 5);
    int o = tid & 31;
    if (node >= NN) return;
    float vl = op_vec[node * 32 + o];
    float acc = bs[o];
#pragma unroll
    for (int p = 0; p < 32; p++)
        acc += Ws[o][p] * __shfl_sync(0xffffffffu, vl, p);
    g_x[(size_t)node * 288 + o] = acc;
}

// ---------------- pooled predicate features: x[:, 32:160] --------------------
// Rows = (node,k) pairs: 256 rows (32 nodes) x 64 cols per block; K=64.
// cp.async double-buffered; pooling fused in epilogue (thread owns all 8 k).
__global__ __launch_bounds__(256, 2)
void k_pool(const float* __restrict__ preds1, const void* mask1, const void* and1,
            const float* __restrict__ preds2, const void* mask2, const void* and2,
            const float* __restrict__ W_pred, const float* __restrict__ b_pred) {
    const int K = 64, NT = 4;
    __shared__ float As[2][256 * 16];
    __shared__ float Bs[2][64 * 16];

    int cond = blockIdx.y;
    const float* preds = cond ? preds2 : preds1;
    const void*  maskp = cond ? mask2 : mask1;
    const void*  andp  = cond ? and2  : and1;

    int tid = threadIdx.x;
    int trow = tid >> 3;            // node within block (0..31)
    int tcol = tid & 7;             // col group (8 cols each)
    int nodeBase = blockIdx.x * 32;
    int rowGlobalBase = nodeBase * 8;
    const int MR = NN * 8;

    float acc[8][8];
#pragma unroll
    for (int i = 0; i < 8; i++)
#pragma unroll
        for (int j = 0; j < 8; j++) acc[i][j] = 0.0f;

    float bregs[4];

    // --- prologue: tile 0 ---
    {
        int k0 = 0;
#pragma unroll
        for (int i = 0; i < 4; i++) {
            int c = tid + 256 * i; int r = c >> 2, ch = c & 3;
            int row = rowGlobalBase + r;
            int srcB = (row < MR) ? 16 : 0;
            const float* s = preds + (size_t)(row < MR ? row : MR - 1) * 64 + k0 + ch * 4;
            cpa16(smem_u32(&As[0][r * 16 + ch * 4]), s, srcB);
        }
        cpa_commit();
#pragma unroll
        for (int q = 0; q < 4; q++) {
            int idx = tid + 256 * q; int c = idx >> 4, kk = idx & 15;
            bregs[q] = W_pred[c * 64 + k0 + kk];
        }
        cpa_wait0(); __syncthreads();
#pragma unroll
        for (int q = 0; q < 4; q++) {
            int idx = tid + 256 * q; int c = idx >> 4, kk = idx & 15;
            int chunk = (kk >> 2) ^ ((c >> 3) & 3);
            Bs[0][c * 16 + chunk * 4 + (kk & 3)] = bregs[q];
        }
        __syncthreads();
    }

    for (int t = 0; t < NT; t++) {
        int cur = t & 1, nxt = cur ^ 1;
        if (t + 1 < NT) {
            int k0 = (t + 1) * 16;
#pragma unroll
            for (int i = 0; i < 4; i++) {
                int c = tid + 256 * i; int r = c >> 2, ch = c & 3;
                int row = rowGlobalBase + r;
                int srcB = (row < MR) ? 16 : 0;
                const float* s = preds + (size_t)(row < MR ? row : MR - 1) * 64 + k0 + ch * 4;
                cpa16(smem_u32(&As[nxt][r * 16 + ch * 4]), s, srcB);
            }
            cpa_commit();
#pragma unroll
            for (int q = 0; q < 4; q++) {
                int idx = tid + 256 * q; int c = idx >> 4, kk = idx & 15;
                bregs[q] = W_pred[c * 64 + k0 + kk];
            }
        }
#pragma unroll
        for (int kk4 = 0; kk4 < 4; kk4++) {
            float4 a4[8];
#pragma unroll
            for (int i = 0; i < 8; i++)
                a4[i] = *(const float4*)&As[cur][(trow * 8 + i) * 16 + kk4 * 4];
            int sw = ((kk4 ^ (tcol & 3)) << 2);
#pragma unroll
            for (int j = 0; j < 8; j++) {
                float4 b4 = *(const float4*)&Bs[cur][(tcol * 8 + j) * 16 + sw];
#pragma unroll
                for (int i = 0; i < 8; i++)
                    acc[i][j] += a4[i].x * b4.x + a4[i].y * b4.y +
                                 a4[i].z * b4.z + a4[i].w * b4.w;
            }
        }
        __syncthreads();
        if (t + 1 < NT) {
            cpa_wait0();
#pragma unroll
            for (int q = 0; q < 4; q++) {
                int idx = tid + 256 * q; int c = idx >> 4, kk = idx & 15;
                int chunk = (kk >> 2) ^ ((c >> 3) & 3);
                Bs[nxt][c * 16 + chunk * 4 + (kk & 3)] = bregs[q];
            }
            __syncthreads();
        }
    }

    int node = nodeBase + trow;
    if (node < NN) {
        int mk[8], anyb = 0;
#pragma unroll
        for (int i = 0; i < 8; i++) { mk[i] = read_bool(maskp, node * 8 + i); anyb |= mk[i]; }
        int ia = read_bool(andp, node);
        float res[8];
#pragma unroll
        for (int j = 0; j < 8; j++) {
            int q = tcol * 8 + j;
            float bq = b_pred[q];
            float mn = BIGF, mx = -BIGF;
#pragma unroll
            for (int i = 0; i < 8; i++) {
                float v = acc[i][j] + bq;
                if (mk[i]) { mn = fminf(mn, v); mx = fmaxf(mx, v); }
            }
            res[j] = anyb ? (ia ? mn : mx) : 0.0f;
        }
        float* dst = &g_x[(size_t)node * 288 + 32 + cond * 64 + tcol * 8];
        *(float4*)dst       = make_float4(res[0], res[1], res[2], res[3]);
        *(float4*)(dst + 4) = make_float4(res[4], res[5], res[6], res[7]);
    }
}

// ---------------- generic 128x128 GEMM body (bm / xg share this) -------------
// C[row, colBase+c] = sum_k A[row,k]*B[colBase+c,k]  with per-kernel epilogue.
// As row-major [128][16] (cp.async), Bs row-major [128][16] chunk-swizzled.

// k_bm: A=bitmap [NN,1000], B=W_bm [128,1000] -> g_x cols 160..288
__global__ __launch_bounds__(256, 2)
void k_bm(const float* __restrict__ Ag, const float* __restrict__ Bg,
          const float* __restrict__ bias) {
    const int K = 1000, NT = (K + 15) / 16;   // 63
    __shared__ float As[2][128 * 16];
    __shared__ float Bs[2][128 * 16];
    int tid = threadIdx.x;
    int trow = tid >> 4, tcol = tid & 15;
    int rowBase = blockIdx.x * 128;
    float acc[8][8];
#pragma unroll
    for (int i = 0; i < 8; i++)
#pragma unroll
        for (int j = 0; j < 8; j++) acc[i][j] = 0.0f;
    float bregs[8];

    // prologue tile 0
    {
        int k0 = 0;
#pragma unroll
        for (int i = 0; i < 2; i++) {
            int c = tid + 256 * i; int r = c >> 2, ch = c & 3;
            int row = rowBase + r; int k = k0 + ch * 4;
            int valid = K - k;
            int srcB = valid >= 4 ? 16 : (valid > 0 ? valid * 4 : 0);
            if (row >= NN) srcB = 0;
            const float* s = Ag + (size_t)(row < NN ? row : NN - 1) * K + (k < K ? k : K - 4);
            cpa16(smem_u32(&As[0][r * 16 + ch * 4]), s, srcB);
        }
        cpa_commit();
#pragma unroll
        for (int q = 0; q < 8; q++) {
            int idx = tid + 256 * q; int c = idx >> 4, kk = idx & 15; int k = k0 + kk;
            bregs[q] = (k < K) ? Bg[(size_t)c * K + k] : 0.0f;
        }
        cpa_wait0(); __syncthreads();
#pragma unroll
        for (int q = 0; q < 8; q++) {
            int idx = tid + 256 * q; int c = idx >> 4, kk = idx & 15;
            int chunk = (kk >> 2) ^ ((c >> 3) & 3);
            Bs[0][c * 16 + chunk * 4 + (kk & 3)] = bregs[q];
        }
        __syncthreads();
    }

    for (int t = 0; t < NT; t++) {
        int cur = t & 1, nxt = cur ^ 1;
        if (t + 1 < NT) {
            int k0 = (t + 1) * 16;
#pragma unroll
            for (int i = 0; i < 2; i++) {
                int c = tid + 256 * i; int r = c >> 2, ch = c & 3;
                int row = rowBase + r; int k = k0 + ch * 4;
                int valid = K - k;
                int srcB = valid >= 4 ? 16 : (valid > 0 ? valid * 4 : 0);
                if (row >= NN) srcB = 0;
                const float* s = Ag + (size_t)(row < NN ? row : NN - 1) * K + (k < K ? k : K - 4);
                cpa16(smem_u32(&As[nxt][r * 16 + ch * 4]), s, srcB);
            }
            cpa_commit();
#pragma unroll
            for (int q = 0; q < 8; q++) {
                int idx = tid + 256 * q; int c = idx >> 4, kk = idx & 15; int k = k0 + kk;
                bregs[q] = (k < K) ? Bg[(size_t)c * K + k] : 0.0f;
            }
        }
#pragma unroll
        for (int kk4 = 0; kk4 < 4; kk4++) {
            float4 a4[8];
#pragma unroll
            for (int i = 0; i < 8; i++)
                a4[i] = *(const float4*)&As[cur][(trow * 8 + i) * 16 + kk4 * 4];
            int sw = ((kk4 ^ (tcol & 3)) << 2);
#pragma unroll
            for (int j = 0; j < 8; j++) {
                float4 b4 = *(const float4*)&Bs[cur][(tcol * 8 + j) * 16 + sw];
#pragma unroll
                for (int i = 0; i < 8; i++)
                    acc[i][j] += a4[i].x * b4.x + a4[i].y * b4.y +
                                 a4[i].z * b4.z + a4[i].w * b4.w;
            }
        }
        __syncthreads();
        if (t + 1 < NT) {
            cpa_wait0();
#pragma unroll
            for (int q = 0; q < 8; q++) {
                int idx = tid + 256 * q; int c = idx >> 4, kk = idx & 15;
                int chunk = (kk >> 2) ^ ((c >> 3) & 3);
                Bs[nxt][c * 16 + chunk * 4 + (kk & 3)] = bregs[q];
            }
            __syncthreads();
        }
    }

#pragma unroll
    for (int i = 0; i < 8; i++) {
        int row = rowBase + trow * 8 + i;
        if (row < NN) {
            float* dst = &g_x[(size_t)row * 288 + 160 + tcol * 8];
            float4 o0, o1;
            o0.x = acc[i][0] + bias[tcol * 8 + 0]; o0.y = acc[i][1] + bias[tcol * 8 + 1];
            o0.z = acc[i][2] + bias[tcol * 8 + 2]; o0.w = acc[i][3] + bias[tcol * 8 + 3];
            o1.x = acc[i][4] + bias[tcol * 8 + 4]; o1.y = acc[i][5] + bias[tcol * 8 + 5];
            o1.z = acc[i][6] + bias[tcol * 8 + 6]; o1.w = acc[i][7] + bias[tcol * 8 + 7];
            *(float4*)dst = o0; *(float4*)(dst + 4) = o1;
        }
    }
}

// k_xg: A=g_x [NN,288], B=W_ih [1024,288] -> g_xg. grid (colBlocks=8, rowBlocks=512)
__global__ __launch_bounds__(256, 2)
void k_xg(const float* __restrict__ Bg, const float* __restrict__ b_ih,
          const float* __restrict__ b_hh) {
    const int K = 288, NT = K / 16;   // 18
    __shared__ float As[2][128 * 16];
    __shared__ float Bs[2][128 * 16];
    int tid = threadIdx.x;
    int trow = tid >> 4, tcol = tid & 15;
    int rowBase = blockIdx.y * 128;
    int colBase = blockIdx.x * 128;
    const float* Ag = g_x;
    float acc[8][8];
#pragma unroll
    for (int i = 0; i < 8; i++)
#pragma unroll
        for (int j = 0; j < 8; j++) acc[i][j] = 0.0f;
    float bregs[8];

    {
        int k0 = 0;
#pragma unroll
        for (int i = 0; i < 2; i++) {
            int c = tid + 256 * i; int r = c >> 2, ch = c & 3;
            int row = rowBase + r;
            int srcB = (row < NN) ? 16 : 0;
            const float* s = Ag + (size_t)(row < NN ? row : NN - 1) * K + k0 + ch * 4;
            cpa16(smem_u32(&As[0][r * 16 + ch * 4]), s, srcB);
        }
        cpa_commit();
#pragma unroll
        for (int q = 0; q < 8; q++) {
            int idx = tid + 256 * q; int c = idx >> 4, kk = idx & 15;
            bregs[q] = Bg[(size_t)(colBase + c) * K + k0 + kk];
        }
        cpa_wait0(); __syncthreads();
#pragma unroll
        for (int q = 0; q < 8; q++) {
            int idx = tid + 256 * q; int c = idx >> 4, kk = idx & 15;
            int chunk = (kk >> 2) ^ ((c >> 3) & 3);
            Bs[0][c * 16 + chunk * 4 + (kk & 3)] = bregs[q];
        }
        __syncthreads();
    }

    for (int t = 0; t < NT; t++) {
        int cur = t & 1, nxt = cur ^ 1;
        if (t + 1 < NT) {
            int k0 = (t + 1) * 16;
#pragma unroll
            for (int i = 0; i < 2; i++) {
                int c = tid + 256 * i; int r = c >> 2, ch = c & 3;
                int row = rowBase + r;
                int srcB = (row < NN) ? 16 : 0;
                const float* s = Ag + (size_t)(row < NN ? row : NN - 1) * K + k0 + ch * 4;
                cpa16(smem_u32(&As[nxt][r * 16 + ch * 4]), s, srcB);
            }
            cpa_commit();
#pragma unroll
            for (int q = 0; q < 8; q++) {
                int idx = tid + 256 * q; int c = idx >> 4, kk = idx & 15;
                bregs[q] = Bg[(size_t)(colBase + c) * K + k0 + kk];
            }
        }
#pragma unroll
        for (int kk4 = 0; kk4 < 4; kk4++) {
            float4 a4[8];
#pragma unroll
            for (int i = 0; i < 8; i++)
                a4[i] = *(const float4*)&As[cur][(trow * 8 + i) * 16 + kk4 * 4];
            int sw = ((kk4 ^ (tcol & 3)) << 2);
#pragma unroll
            for (int j = 0; j < 8; j++) {
                float4 b4 = *(const float4*)&Bs[cur][(tcol * 8 + j) * 16 + sw];
#pragma unroll
                for (int i = 0; i < 8; i++)
                    acc[i][j] += a4[i].x * b4.x + a4[i].y * b4.y +
                                 a4[i].z * b4.z + a4[i].w * b4.w;
            }
        }
        __syncthreads();
        if (t + 1 < NT) {
            cpa_wait0();
#pragma unroll
            for (int q = 0; q < 8; q++) {
                int idx = tid + 256 * q; int c = idx >> 4, kk = idx & 15;
                int chunk = (kk >> 2) ^ ((c >> 3) & 3);
                Bs[nxt][c * 16 + chunk * 4 + (kk & 3)] = bregs[q];
            }
            __syncthreads();
        }
    }

#pragma unroll
    for (int i = 0; i < 8; i++) {
        int row = rowBase + trow * 8 + i;
        if (row < NN) {
            int o = colBase + tcol * 8;
            float* dst = &g_xg[(size_t)row * 1024 + o];
            float4 o0, o1;
            o0.x = acc[i][0] + b_ih[o + 0] + b_hh[o + 0];
            o0.y = acc[i][1] + b_ih[o + 1] + b_hh[o + 1];
            o0.z = acc[i][2] + b_ih[o + 2] + b_hh[o + 2];
            o0.w = acc[i][3] + b_ih[o + 3] + b_hh[o + 3];
            o1.x = acc[i][4] + b_ih[o + 4] + b_hh[o + 4];
            o1.y = acc[i][5] + b_ih[o + 5] + b_hh[o + 5];
            o1.z = acc[i][6] + b_ih[o + 6] + b_hh[o + 6];
            o1.w = acc[i][7] + b_ih[o + 7] + b_hh[o + 7];
            *(float4*)dst = o0; *(float4*)(dst + 4) = o1;
        }
    }
}

// ---------------- leaves (d = D): c0 = 0 -------------------------------------
__global__ void k_leaf() {
    int n = blockIdx.x;
    int j = threadIdx.x;
    const float* xr = g_xg + (size_t)n * 1024;
    float gi = xr[j];
    float gg = xr[512 + j];
    float go = xr[768 + j];
    float c = sigf(gi) * tanhf(gg);
    float h = sigf(go) * tanhf(c);
    g_H[(size_t)n * 256 + j] = h;
    g_C[(size_t)n * 256 + j] = c;
}

// ---------------- interior level: h0 avg + GEMM(W_hh) + LSTM pointwise -------
__global__ __launch_bounds__(256)
void k_level(int start, int nd, const float* __restrict__ W_hh) {
    __shared__ float h0s[32][36];
    __shared__ float Ws[256][36];
    int tid = threadIdx.x;
    int jx = tid & 63, ry = tid >> 6;
    int rowBase = blockIdx.x * 32;
    int jbase = blockIdx.y * 64;

    float acc[8][4];
#pragma unroll
    for (int i = 0; i < 8; i++)
#pragma unroll
        for (int g = 0; g < 4; g++) acc[i][g] = 0.0f;

    for (int k0 = 0; k0 < 256; k0 += 32) {
        {
            int r = tid >> 3, c4 = tid & 7;
            float4 v = make_float4(0.f, 0.f, 0.f, 0.f);
            int rr = rowBase + r;
            if (rr < nd) {
                int node = start + rr;
                int ci = 2 * node - NN;
                float4 a = *(const float4*)&g_H[(size_t)ci * 256 + k0 + c4 * 4];
                float4 b = *(const float4*)&g_H[(size_t)(ci - 1) * 256 + k0 + c4 * 4];
                v = make_float4(0.5f * (a.x + b.x), 0.5f * (a.y + b.y),
                                0.5f * (a.z + b.z), 0.5f * (a.w + b.w));
            }
            *(float4*)&h0s[r][c4 * 4] = v;
        }
        {
            int wrow = ry * 256 + jbase + jx;   // gate*256 + j
            const float* src = &W_hh[(size_t)wrow * 256 + k0];
#pragma unroll
            for (int c = 0; c < 8; c++)
                *(float4*)&Ws[tid][c * 4] = *(const float4*)&src[c * 4];
        }
        __syncthreads();
#pragma unroll
        for (int kk4 = 0; kk4 < 8; kk4++) {
            float4 w4[4];
#pragma unroll
            for (int g = 0; g < 4; g++)
                w4[g] = *(const float4*)&Ws[g * 64 + jx][kk4 * 4];
#pragma unroll
            for (int i = 0; i < 8; i++) {
                float4 a4 = *(const float4*)&h0s[ry * 8 + i][kk4 * 4];
#pragma unroll
                for (int g = 0; g < 4; g++)
                    acc[i][g] += a4.x * w4[g].x + a4.y * w4[g].y +
                                 a4.z * w4[g].z + a4.w * w4[g].w;
            }
        }
        __syncthreads();
    }

    int j = jbase + jx;
#pragma unroll
    for (int i = 0; i < 8; i++) {
        int rr = rowBase + ry * 8 + i;
        if (rr < nd) {
            int node = start + rr;
            const float* xr = g_xg + (size_t)node * 1024;
            float gi = acc[i][0] + xr[j];
            float gf = acc[i][1] + xr[256 + j];
            float gg = acc[i][2] + xr[512 + j];
            float go = acc[i][3] + xr[768 + j];
            int ci = 2 * node - NN;
            float c0 = 0.5f * (g_C[(size_t)ci * 256 + j] + g_C[(size_t)(ci - 1) * 256 + j]);
            float cn = sigf(gf) * c0 + sigf(gi) * tanhf(gg);
            float hn = sigf(go) * tanhf(cn);
            g_H[(size_t)node * 256 + j] = hn;
            g_C[(size_t)node * 256 + j] = cn;
        }
    }
}

// ---------------- output heads ----------------------------------------------
__global__ void k_heads(const float* __restrict__ W2a, const float* __restrict__ b2a,
                        const float* __restrict__ W3a, const float* __restrict__ b3a,
                        const float* __restrict__ Woa, const float* __restrict__ boa,
                        const float* __restrict__ W2b, const float* __restrict__ b2b,
                        const float* __restrict__ W3b, const float* __restrict__ b3b,
                        const float* __restrict__ Wob, const float* __restrict__ bob,
                        float* __restrict__ out) {
    __shared__ float hv[256];
    __shared__ float t1[2][128];
    __shared__ float t2[2][128];
    __shared__ float red[256];
    int tid = threadIdx.x;
    hv[tid] = g_H[(size_t)(NN - 1) * 256 + tid];
    __syncthreads();
    int head = tid >> 7, j = tid & 127;
    const float* W2 = head ? W2b : W2a; const float* b2 = head ? b2b : b2a;
    const float* W3 = head ? W3b : W3a; const float* b3 = head ? b3b : b3a;
    const float* Wo = head ? Wob : Woa; const float* bo = head ? bob : boa;

    float t = b2[j];
    for (int k = 0; k < 256; k++) t += W2[j * 256 + k] * hv[k];
    t1[head][j] = fmaxf(t, 0.0f);
    __syncthreads();
    t = b3[j];
    for (int k = 0; k < 128; k++) t += W3[j * 128 + k] * t1[head][k];
    t2[head][j] = fmaxf(t, 0.0f);
    __syncthreads();
    red[tid] = Wo[j] * t2[head][j];
    __syncthreads();
    for (int s = 64; s > 0; s >>= 1) {
        if (j < s) red[tid] += red[tid + s];
        __syncthreads();
    }
    if (j == 0) out[head] = 1.0f / (1.0f + expf(-(red[tid] + bo[0])));
}

// ---------------- launch ------------------------------------------------------
extern "C" void kernel_launch(void* const* d_in, const int* in_sizes, int n_in,
                              void* d_out, int out_size) {
    const float* op_vec   = (const float*)d_in[0];
    const float* c1_preds = (const float*)d_in[1];
    const void*  c1_mask  = d_in[2];
    const void*  c1_and   = d_in[3];
    const float* c2_preds = (const float*)d_in[4];
    const void*  c2_mask  = d_in[5];
    const void*  c2_and   = d_in[6];
    const float* bitmap   = (const float*)d_in[7];
    const float* W_op     = (const float*)d_in[8];
    const float* b_op     = (const float*)d_in[9];
    const float* W_pred   = (const float*)d_in[10];
    const float* b_pred   = (const float*)d_in[11];
    const float* W_bm     = (const float*)d_in[12];
    const float* b_bm     = (const float*)d_in[13];
    const float* W_ih     = (const float*)d_in[14];
    const float* b_ih     = (const float*)d_in[15];
    const float* W_hh     = (const float*)d_in[16];
    const float* b_hh     = (const float*)d_in[17];
    const float* W_h2t1   = (const float*)d_in[18];
    const float* b_h2t1   = (const float*)d_in[19];
    const float* W_h3t1   = (const float*)d_in[20];
    const float* b_h3t1   = (const float*)d_in[21];
    const float* W_o1     = (const float*)d_in[22];
    const float* b_o1     = (const float*)d_in[23];
    const float* W_h2t2   = (const float*)d_in[24];
    const float* b_h2t2   = (const float*)d_in[25];
    const float* W_h3t2   = (const float*)d_in[26];
    const float* b_h3t2   = (const float*)d_in[27];
    const float* W_o2     = (const float*)d_in[28];
    const float* b_o2     = (const float*)d_in[29];
    float* out = (float*)d_out;

    k_detect<<<1, 256>>>((const unsigned int*)c1_mask);

    k_op<<<(NN + 7) / 8, 256>>>(op_vec, W_op, b_op);

    {
        dim3 grid((NN + 31) / 32, 2);
        k_pool<<<grid, 256>>>(c1_preds, c1_mask, c1_and,
                              c2_preds, c2_mask, c2_and,
                              W_pred, b_pred);
    }

    k_bm<<<(NN + 127) / 128, 256>>>(bitmap, W_bm, b_bm);

    {
        dim3 grid(8, (NN + 127) / 128);   // col-blocks fast -> A-tile L2 reuse
        k_xg<<<grid, 256>>>(W_ih, b_ih, b_hh);
    }

    k_leaf<<<32768, 256>>>();

    for (int d = 14; d >= 0; d--) {
        int nd = 1 << d;
        int start = NN - (1 << (d + 1)) + 1;
        dim3 grid((nd + 31) / 32, 4);
        k_level<<<grid, 256>>>(start, nd, W_hh);
    }

    k_heads<<<1, 256>>>(W_h2t1, b_h2t1, W_h3t1, b_h3t1, W_o1, b_o1,
                        W_h2t2, b_h2t2, W_h3t2, b_h3t2, W_o2, b_o2,
                        out);
}

// round 5
// speedup vs baseline: 5.3229x; 1.5326x over previous
#include <cuda_runtime.h>
#include <cuda_bf16.h>
#include <math.h>
#include <cstdint>
#include <stdint.h>

#define NN 65535          // number of tree nodes (2^16 - 1)
#define MRPOOL (NN * 8)   // pool GEMM rows
#define BIGF 1e30f
#define STR 72            // smem row stride in bf16 elems (144 B, conflict-free)

// ---------------- scratch (static device globals; no cudaMalloc) -------------
__device__ __nv_bfloat16 g_xh[(size_t)NN * 288];   // features hi
__device__ __nv_bfloat16 g_xl[(size_t)NN * 288];   // features lo
__device__ float g_xg[(size_t)NN * 1024];          // gates pre-activation
__device__ float g_H[(size_t)NN * 256];            // LSTM hidden
__device__ float g_C[(size_t)NN * 256];            // LSTM cell
__device__ int   g_mask_is_byte;

// pre-split weights (bf16 hi/lo)
__device__ __nv_bfloat16 g_Wih_h[1024 * 288], g_Wih_l[1024 * 288];
__device__ __nv_bfloat16 g_Whh_h[1024 * 256], g_Whh_l[1024 * 256];
__device__ __nv_bfloat16 g_Wbm_h[128 * 1000], g_Wbm_l[128 * 1000];
__device__ __nv_bfloat16 g_Wp_h[64 * 64],     g_Wp_l[64 * 64];

__device__ __forceinline__ float sigf(float x) { return 1.0f / (1.0f + expf(-x)); }

__device__ __forceinline__ int read_bool(const void* p, int idx) {
    return g_mask_is_byte ? (int)(((const unsigned char*)p)[idx])
                          : (((const int*)p)[idx] != 0);
}

// ---------------- bf16 split helpers -----------------------------------------
__device__ __forceinline__ void split2(float x, float y, uint32_t& h, uint32_t& l) {
    __nv_bfloat16 hx = __float2bfloat16(x), hy = __float2bfloat16(y);
    __nv_bfloat16 lx = __float2bfloat16(x - __bfloat162float(hx));
    __nv_bfloat16 ly = __float2bfloat16(y - __bfloat162float(hy));
    h = ((uint32_t)__bfloat16_as_ushort(hy) << 16) | __bfloat16_as_ushort(hx);
    l = ((uint32_t)__bfloat16_as_ushort(ly) << 16) | __bfloat16_as_ushort(lx);
}

// ---------------- mma.sync m16n8k16 bf16 -------------------------------------
__device__ __forceinline__ void mma_bf16(float d[4], const uint32_t a[4], const uint32_t b[2]) {
    asm volatile(
        "mma.sync.aligned.m16n8k16.row.col.f32.bf16.bf16.f32 "
        "{%0,%1,%2,%3}, {%4,%5,%6,%7}, {%8,%9}, {%0,%1,%2,%3};\n"
        : "+f"(d[0]), "+f"(d[1]), "+f"(d[2]), "+f"(d[3])
        : "r"(a[0]), "r"(a[1]), "r"(a[2]), "r"(a[3]), "r"(b[0]), "r"(b[1]));
}

// One K-chunk (32 fp32 = hi[0:32) + lo[32:64) bf16) for a 32x64 warp tile.
// 3 split passes: Ah*Bh, Ah*Bl, Al*Bh.
__device__ __forceinline__ void mma_chunk(const __nv_bfloat16* As, const __nv_bfloat16* Bs,
                                          int wm, int wn, int lane, float acc[2][8][4]) {
#pragma unroll
    for (int pass = 0; pass < 3; pass++) {
        int ka = (pass == 2) ? 32 : 0;
        int kb = (pass == 1) ? 32 : 0;
#pragma unroll
        for (int ks = 0; ks < 2; ks++) {
            int kA = ka + ks * 16 + (lane & 3) * 2;
            int kB = kb + ks * 16 + (lane & 3) * 2;
            uint32_t af[2][4];
#pragma unroll
            for (int mt = 0; mt < 2; mt++) {
                const __nv_bfloat16* p = As + (wm * 32 + mt * 16 + (lane >> 2)) * STR + kA;
                af[mt][0] = *(const uint32_t*)p;
                af[mt][1] = *(const uint32_t*)(p + 8 * STR);
                af[mt][2] = *(const uint32_t*)(p + 8);
                af[mt][3] = *(const uint32_t*)(p + 8 * STR + 8);
            }
#pragma unroll
            for (int nt = 0; nt < 8; nt++) {
                const __nv_bfloat16* p = Bs + (wn * 64 + nt * 8 + (lane >> 2)) * STR + kB;
                uint32_t bq[2] = { *(const uint32_t*)p, *(const uint32_t*)(p + 8) };
#pragma unroll
                for (int mt = 0; mt < 2; mt++)
                    mma_bf16(acc[mt][nt], af[mt], bq);
            }
        }
    }
}

// ---------------- tile loaders (ldg phase -> regs, sts phase -> smem) --------
// slots: SLOTS*256 = ROWS*4; each slot handles 8 K-elements of one row.
template <int SLOTS>
__device__ __forceinline__ void ldg_f32(const float* __restrict__ src, int ld, int rowBase,
                                        int maxRow, int k0, int Ktot, int tid, float4 (*v)[2]) {
#pragma unroll
    for (int s = 0; s < SLOTS; s++) {
        int idx = tid + 256 * s;
        int r = idx >> 2, g = idx & 3;
        int row = rowBase + r, k = k0 + g * 8;
        float4 a = make_float4(0.f, 0.f, 0.f, 0.f), b = a;
        if (row < maxRow && k + 8 <= Ktot) {
            const float* p = src + (size_t)row * ld + k;
            a = *(const float4*)p;
            b = *(const float4*)(p + 4);
        }
        v[s][0] = a; v[s][1] = b;
    }
}

template <int SLOTS>
__device__ __forceinline__ void sts_split(__nv_bfloat16* As, int tid, float4 (*v)[2]) {
#pragma unroll
    for (int s = 0; s < SLOTS; s++) {
        int idx = tid + 256 * s;
        int r = idx >> 2, g = idx & 3;
        uint32_t h0, l0, h1, l1, h2, l2, h3, l3;
        split2(v[s][0].x, v[s][0].y, h0, l0);
        split2(v[s][0].z, v[s][0].w, h1, l1);
        split2(v[s][1].x, v[s][1].y, h2, l2);
        split2(v[s][1].z, v[s][1].w, h3, l3);
        __nv_bfloat16* p = As + r * STR + g * 8;
        *(uint4*)p        = make_uint4(h0, h1, h2, h3);
        *(uint4*)(p + 32) = make_uint4(l0, l1, l2, l3);
    }
}

template <int SLOTS>
__device__ __forceinline__ void ldg_bf16(const __nv_bfloat16* __restrict__ sh,
                                         const __nv_bfloat16* __restrict__ sl,
                                         int ld, int rowBase, int maxRow, int k0, int Ktot,
                                         int tid, uint4 (*v)[2]) {
#pragma unroll
    for (int s = 0; s < SLOTS; s++) {
        int idx = tid + 256 * s;
        int r = idx >> 2, g = idx & 3;
        int row = rowBase + r, k = k0 + g * 8;
        uint4 a = make_uint4(0, 0, 0, 0), b = a;
        if (row < maxRow && k + 8 <= Ktot) {
            size_t off = (size_t)row * ld + k;
            a = *(const uint4*)(sh + off);
            b = *(const uint4*)(sl + off);
        }
        v[s][0] = a; v[s][1] = b;
    }
}

template <int SLOTS>
__device__ __forceinline__ void sts_bf16(__nv_bfloat16* As, int tid, uint4 (*v)[2]) {
#pragma unroll
    for (int s = 0; s < SLOTS; s++) {
        int idx = tid + 256 * s;
        int r = idx >> 2, g = idx & 3;
        __nv_bfloat16* p = As + r * STR + g * 8;
        *(uint4*)p        = v[s][0];
        *(uint4*)(p + 32) = v[s][1];
    }
}

// level-specific loaders
__device__ __forceinline__ void ldg_avgH(int start, int nd, int rowBase, int k0, int tid,
                                         float4 (*v)[2]) {
#pragma unroll
    for (int s = 0; s < 2; s++) {
        int idx = tid + 256 * s;
        int r = idx >> 2, g = idx & 3;
        int rr = rowBase + r;
        float4 a = make_float4(0.f, 0.f, 0.f, 0.f), b = a;
        if (rr < nd) {
            int node = start + rr;
            int ci = 2 * node - NN;
            const float* p0 = g_H + (size_t)ci * 256 + k0 + g * 8;
            const float* p1 = g_H + (size_t)(ci - 1) * 256 + k0 + g * 8;
            float4 x0 = *(const float4*)p0, x1 = *(const float4*)(p0 + 4);
            float4 y0 = *(const float4*)p1, y1 = *(const float4*)(p1 + 4);
            a = make_float4(0.5f * (x0.x + y0.x), 0.5f * (x0.y + y0.y),
                            0.5f * (x0.z + y0.z), 0.5f * (x0.w + y0.w));
            b = make_float4(0.5f * (x1.x + y1.x), 0.5f * (x1.y + y1.y),
                            0.5f * (x1.z + y1.z), 0.5f * (x1.w + y1.w));
        }
        v[s][0] = a; v[s][1] = b;
    }
}

__device__ __forceinline__ void ldg_Whh(int jbase, int k0, int tid, uint4 (*v)[2]) {
#pragma unroll
    for (int s = 0; s < 2; s++) {
        int idx = tid + 256 * s;
        int r = idx >> 2, g = idx & 3;              // r = block col 0..127
        int wrow = (r >> 5) * 256 + jbase + (r & 31);
        size_t off = (size_t)wrow * 256 + k0 + g * 8;
        v[s][0] = *(const uint4*)(g_Whh_h + off);
        v[s][1] = *(const uint4*)(g_Whh_l + off);
    }
}

// ---------------- small kernels ----------------------------------------------
__global__ void k_detect(const unsigned int* __restrict__ m) {
    __shared__ int found;
    if (threadIdx.x == 0) found = 0;
    __syncthreads();
    unsigned int v = m[threadIdx.x];
    if (v > 1u) found = 1;
    __syncthreads();
    if (threadIdx.x == 0) g_mask_is_byte = found;
}

__global__ void k_wsplit(const float* __restrict__ Wih, const float* __restrict__ Whh,
                         const float* __restrict__ Wbm, const float* __restrict__ Wp) {
    int i = blockIdx.x * 256 + threadIdx.x;
    const int S1 = 1024 * 288, S2 = 1024 * 256, S3 = 128 * 1000, S4 = 64 * 64;
    float w; __nv_bfloat16 h;
    if (i < S1) {
        w = Wih[i]; h = __float2bfloat16(w);
        g_Wih_h[i] = h; g_Wih_l[i] = __float2bfloat16(w - __bfloat162float(h));
    } else if (i < S1 + S2) {
        int j = i - S1; w = Whh[j]; h = __float2bfloat16(w);
        g_Whh_h[j] = h; g_Whh_l[j] = __float2bfloat16(w - __bfloat162float(h));
    } else if (i < S1 + S2 + S3) {
        int j = i - S1 - S2; w = Wbm[j]; h = __float2bfloat16(w);
        g_Wbm_h[j] = h; g_Wbm_l[j] = __float2bfloat16(w - __bfloat162float(h));
    } else if (i < S1 + S2 + S3 + S4) {
        int j = i - S1 - S2 - S3; w = Wp[j]; h = __float2bfloat16(w);
        g_Wp_h[j] = h; g_Wp_l[j] = __float2bfloat16(w - __bfloat162float(h));
    }
}

__global__ void k_op(const float* __restrict__ op_vec,
                     const float* __restrict__ W_op,
                     const float* __restrict__ b_op) {
    __shared__ float Ws[32][33];
    __shared__ float bs[32];
    int tid = threadIdx.x;
    if (tid < 32) bs[tid] = b_op[tid];
    for (int i = tid; i < 1024; i += 256) Ws[i >> 5][i & 31] = W_op[i];
    __syncthreads();
    int node = blockIdx.x * 8 + (tid >> 5);
    int o = tid & 31;
    if (node >= NN) return;
    float vl = op_vec[node * 32 + o];
    float acc = bs[o];
#pragma unroll
    for (int p = 0; p < 32; p++)
        acc += Ws[o][p] * __shfl_sync(0xffffffffu, vl, p);
    __nv_bfloat16 h = __float2bfloat16(acc);
    g_xh[(size_t)node * 288 + o] = h;
    g_xl[(size_t)node * 288 + o] = __float2bfloat16(acc - __bfloat162float(h));
}

// ============ mma GEMM 1: pool (256Mx64N block, K=64) ========================
__global__ __launch_bounds__(256)
void k_pool_mma(const float* __restrict__ preds1, const void* mask1, const void* and1,
                const float* __restrict__ preds2, const void* mask2, const void* and2,
                const float* __restrict__ b_pred) {
    extern __shared__ __nv_bfloat16 sm[];
    __nv_bfloat16* As[2] = { sm, sm + 256 * STR };
    __nv_bfloat16* Bs[2] = { sm + 512 * STR, sm + 512 * STR + 64 * STR };
    float* stage = (float*)sm;   // reused after GEMM: [256][68]

    int tid = threadIdx.x, lane = tid & 31, warp = tid >> 5;
    int cond = blockIdx.y;
    const float* preds = cond ? preds2 : preds1;
    const void*  maskp = cond ? mask2 : mask1;
    const void*  andp  = cond ? and2  : and1;
    int rowBase = blockIdx.x * 256;

    float acc[2][8][4];
#pragma unroll
    for (int a = 0; a < 2; a++)
#pragma unroll
        for (int b = 0; b < 8; b++)
#pragma unroll
            for (int c = 0; c < 4; c++) acc[a][b][c] = 0.f;

    float4 va[4][2]; uint4 vb[1][2];
    ldg_f32<4>(preds, 64, rowBase, MRPOOL, 0, 64, tid, va);
    ldg_bf16<1>(g_Wp_h, g_Wp_l, 64, 0, 64, 0, 64, tid, vb);
    sts_split<4>(As[0], tid, va);
    sts_bf16<1>(Bs[0], tid, vb);
    __syncthreads();

    const int NC = 2;
    for (int t = 0; t < NC; t++) {
        bool more = (t + 1 < NC);
        if (more) {
            ldg_f32<4>(preds, 64, rowBase, MRPOOL, (t + 1) * 32, 64, tid, va);
            ldg_bf16<1>(g_Wp_h, g_Wp_l, 64, 0, 64, (t + 1) * 32, 64, tid, vb);
        }
        mma_chunk(As[t & 1], Bs[t & 1], warp, 0, lane, acc);
        if (more) {
            sts_split<4>(As[(t + 1) & 1], tid, va);
            sts_bf16<1>(Bs[(t + 1) & 1], tid, vb);
        }
        __syncthreads();
    }

    // stage accs: rows block-local [0,256), cols [0,64)
#pragma unroll
    for (int mt = 0; mt < 2; mt++) {
#pragma unroll
        for (int nt = 0; nt < 8; nt++) {
            int r = warp * 32 + mt * 16 + (lane >> 2);
            int c = nt * 8 + (lane & 3) * 2;
            stage[r * 68 + c] = acc[mt][nt][0];
            stage[r * 68 + c + 1] = acc[mt][nt][1];
            stage[(r + 8) * 68 + c] = acc[mt][nt][2];
            stage[(r + 8) * 68 + c + 1] = acc[mt][nt][3];
        }
    }
    __syncthreads();

    // pooling epilogue: 32 nodes per block, thread handles 1 node x 8 cols
    int node = blockIdx.x * 32 + (tid >> 3);
    int cg = (tid & 7) * 8;
    if (node < NN) {
        float bb[8];
        *(float4*)bb       = *(const float4*)(b_pred + cg);
        *(float4*)(bb + 4) = *(const float4*)(b_pred + cg + 4);
        int mk[8], anyb = 0;
#pragma unroll
        for (int i = 0; i < 8; i++) { mk[i] = read_bool(maskp, node * 8 + i); anyb |= mk[i]; }
        int ia = read_bool(andp, node);
        int rb = (tid >> 3) * 8;
        float out[8];
#pragma unroll
        for (int j = 0; j < 8; j++) {
            float mn = BIGF, mx = -BIGF;
#pragma unroll
            for (int i = 0; i < 8; i++) {
                float v = stage[(rb + i) * 68 + cg + j] + bb[j];
                if (mk[i]) { mn = fminf(mn, v); mx = fmaxf(mx, v); }
            }
            out[j] = anyb ? (ia ? mn : mx) : 0.0f;
        }
        size_t base = (size_t)node * 288 + 32 + cond * 64 + cg;
#pragma unroll
        for (int j = 0; j < 8; j += 2) {
            uint32_t h, l;
            split2(out[j], out[j + 1], h, l);
            *(uint32_t*)(g_xh + base + j) = h;
            *(uint32_t*)(g_xl + base + j) = l;
        }
    }
}

// ============ mma GEMM 2: bm (128Mx128N block, K=1000) =======================
__global__ __launch_bounds__(256)
void k_bm_mma(const float* __restrict__ bitmap, const float* __restrict__ b_bm) {
    extern __shared__ __nv_bfloat16 sm[];
    __nv_bfloat16* As[2] = { sm, sm + 128 * STR };
    __nv_bfloat16* Bs[2] = { sm + 256 * STR, sm + 384 * STR };
    int tid = threadIdx.x, lane = tid & 31, warp = tid >> 5;
    int wm = warp >> 1, wn = warp & 1;
    int rowBase = blockIdx.x * 128;

    float acc[2][8][4];
#pragma unroll
    for (int a = 0; a < 2; a++)
#pragma unroll
        for (int b = 0; b < 8; b++)
#pragma unroll
            for (int c = 0; c < 4; c++) acc[a][b][c] = 0.f;

    float4 va[2][2]; uint4 vb[2][2];
    ldg_f32<2>(bitmap, 1000, rowBase, NN, 0, 1000, tid, va);
    ldg_bf16<2>(g_Wbm_h, g_Wbm_l, 1000, 0, 128, 0, 1000, tid, vb);
    sts_split<2>(As[0], tid, va);
    sts_bf16<2>(Bs[0], tid, vb);
    __syncthreads();

    const int NC = 32;   // 1000 -> 31.25, padded with zero-guards
    for (int t = 0; t < NC; t++) {
        bool more = (t + 1 < NC);
        if (more) {
            ldg_f32<2>(bitmap, 1000, rowBase, NN, (t + 1) * 32, 1000, tid, va);
            ldg_bf16<2>(g_Wbm_h, g_Wbm_l, 1000, 0, 128, (t + 1) * 32, 1000, tid, vb);
        }
        mma_chunk(As[t & 1], Bs[t & 1], wm, wn, lane, acc);
        if (more) {
            sts_split<2>(As[(t + 1) & 1], tid, va);
            sts_bf16<2>(Bs[(t + 1) & 1], tid, vb);
        }
        __syncthreads();
    }

    // epilogue: + bias, split, store to g_xh/g_xl cols 160..288
#pragma unroll
    for (int nt = 0; nt < 8; nt++) {
        int c = wn * 64 + nt * 8 + (lane & 3) * 2;
        float bx = b_bm[c], by = b_bm[c + 1];
#pragma unroll
        for (int mt = 0; mt < 2; mt++) {
            int r0 = rowBase + wm * 32 + mt * 16 + (lane >> 2);
            if (r0 < NN) {
                uint32_t h, l;
                split2(acc[mt][nt][0] + bx, acc[mt][nt][1] + by, h, l);
                *(uint32_t*)(g_xh + (size_t)r0 * 288 + 160 + c) = h;
                *(uint32_t*)(g_xl + (size_t)r0 * 288 + 160 + c) = l;
            }
            if (r0 + 8 < NN) {
                uint32_t h, l;
                split2(acc[mt][nt][2] + bx, acc[mt][nt][3] + by, h, l);
                *(uint32_t*)(g_xh + (size_t)(r0 + 8) * 288 + 160 + c) = h;
                *(uint32_t*)(g_xl + (size_t)(r0 + 8) * 288 + 160 + c) = l;
            }
        }
    }
}

// ============ mma GEMM 3: xg (128Mx128N block, K=288) ========================
__global__ __launch_bounds__(256)
void k_xg_mma(const float* __restrict__ b_ih, const float* __restrict__ b_hh) {
    extern __shared__ __nv_bfloat16 sm[];
    __nv_bfloat16* As[2] = { sm, sm + 128 * STR };
    __nv_bfloat16* Bs[2] = { sm + 256 * STR, sm + 384 * STR };
    int tid = threadIdx.x, lane = tid & 31, warp = tid >> 5;
    int wm = warp >> 1, wn = warp & 1;
    int colBase = blockIdx.x * 128;
    int rowBase = blockIdx.y * 128;

    float acc[2][8][4];
#pragma unroll
    for (int a = 0; a < 2; a++)
#pragma unroll
        for (int b = 0; b < 8; b++)
#pragma unroll
            for (int c = 0; c < 4; c++) acc[a][b][c] = 0.f;

    uint4 va[2][2]; uint4 vb[2][2];
    ldg_bf16<2>(g_xh, g_xl, 288, rowBase, NN, 0, 288, tid, va);
    ldg_bf16<2>(g_Wih_h, g_Wih_l, 288, colBase, 1024, 0, 288, tid, vb);
    sts_bf16<2>(As[0], tid, va);
    sts_bf16<2>(Bs[0], tid, vb);
    __syncthreads();

    const int NC = 9;
    for (int t = 0; t < NC; t++) {
        bool more = (t + 1 < NC);
        if (more) {
            ldg_bf16<2>(g_xh, g_xl, 288, rowBase, NN, (t + 1) * 32, 288, tid, va);
            ldg_bf16<2>(g_Wih_h, g_Wih_l, 288, colBase, 1024, (t + 1) * 32, 288, tid, vb);
        }
        mma_chunk(As[t & 1], Bs[t & 1], wm, wn, lane, acc);
        if (more) {
            sts_bf16<2>(As[(t + 1) & 1], tid, va);
            sts_bf16<2>(Bs[(t + 1) & 1], tid, vb);
        }
        __syncthreads();
    }

#pragma unroll
    for (int nt = 0; nt < 8; nt++) {
        int c = colBase + wn * 64 + nt * 8 + (lane & 3) * 2;
        float bx = b_ih[c] + b_hh[c], by = b_ih[c + 1] + b_hh[c + 1];
#pragma unroll
        for (int mt = 0; mt < 2; mt++) {
            int r0 = rowBase + wm * 32 + mt * 16 + (lane >> 2);
            if (r0 < NN)
                *(float2*)(g_xg + (size_t)r0 * 1024 + c) =
                    make_float2(acc[mt][nt][0] + bx, acc[mt][nt][1] + by);
            if (r0 + 8 < NN)
                *(float2*)(g_xg + (size_t)(r0 + 8) * 1024 + c) =
                    make_float2(acc[mt][nt][2] + bx, acc[mt][nt][3] + by);
        }
    }
}

// ============ mma level kernel (nd >= 128): fused GEMM + LSTM pointwise ======
// block: 128 nodes x (4 gates x 32 j); grid (ceil(nd/128), 8)
__global__ __launch_bounds__(256)
void k_level_mma(int start, int nd) {
    extern __shared__ __nv_bfloat16 sm[];
    __nv_bfloat16* As[2] = { sm, sm + 128 * STR };
    __nv_bfloat16* Bs[2] = { sm + 256 * STR, sm + 384 * STR };
    float* stage = (float*)sm;   // [128][132] after GEMM

    int tid = threadIdx.x, lane = tid & 31, warp = tid >> 5;
    int wm = warp >> 1, wn = warp & 1;
    int rowBase = blockIdx.x * 128;
    int jbase = blockIdx.y * 32;

    float acc[2][8][4];
#pragma unroll
    for (int a = 0; a < 2; a++)
#pragma unroll
        for (int b = 0; b < 8; b++)
#pragma unroll
            for (int c = 0; c < 4; c++) acc[a][b][c] = 0.f;

    float4 va[2][2]; uint4 vb[2][2];
    ldg_avgH(start, nd, rowBase, 0, tid, va);
    ldg_Whh(jbase, 0, tid, vb);
    sts_split<2>(As[0], tid, va);
    sts_bf16<2>(Bs[0], tid, vb);
    __syncthreads();

    const int NC = 8;
    for (int t = 0; t < NC; t++) {
        bool more = (t + 1 < NC);
        if (more) {
            ldg_avgH(start, nd, rowBase, (t + 1) * 32, tid, va);
            ldg_Whh(jbase, (t + 1) * 32, tid, vb);
        }
        mma_chunk(As[t & 1], Bs[t & 1], wm, wn, lane, acc);
        if (more) {
            sts_split<2>(As[(t + 1) & 1], tid, va);
            sts_bf16<2>(Bs[(t + 1) & 1], tid, vb);
        }
        __syncthreads();
    }

    // stage: rows local [0,128), cols [0,128) = gate*32 + jj
#pragma unroll
    for (int mt = 0; mt < 2; mt++) {
#pragma unroll
        for (int nt = 0; nt < 8; nt++) {
            int r = wm * 32 + mt * 16 + (lane >> 2);
            int c = wn * 64 + nt * 8 + (lane & 3) * 2;
            stage[r * 132 + c] = acc[mt][nt][0];
            stage[r * 132 + c + 1] = acc[mt][nt][1];
            stage[(r + 8) * 132 + c] = acc[mt][nt][2];
            stage[(r + 8) * 132 + c + 1] = acc[mt][nt][3];
        }
    }
    __syncthreads();

    // pointwise: 128 nodes x 32 j = 4096 pairs / 256 threads = 16 each
#pragma unroll
    for (int i = 0; i < 16; i++) {
        int idx = tid + 256 * i;
        int r = idx >> 5, jj = idx & 31;
        int rr = rowBase + r;
        if (rr < nd) {
            int node = start + rr;
            int j = jbase + jj;
            const float* xr = g_xg + (size_t)node * 1024;
            float gi = stage[r * 132 + jj]       + xr[j];
            float gf = stage[r * 132 + 32 + jj]  + xr[256 + j];
            float gg = stage[r * 132 + 64 + jj]  + xr[512 + j];
            float go = stage[r * 132 + 96 + jj]  + xr[768 + j];
            int ci = 2 * node - NN;
            float c0 = 0.5f * (g_C[(size_t)ci * 256 + j] + g_C[(size_t)(ci - 1) * 256 + j]);
            float cn = sigf(gf) * c0 + sigf(gi) * tanhf(gg);
            float hn = sigf(go) * tanhf(cn);
            g_H[(size_t)node * 256 + j] = hn;
            g_C[(size_t)node * 256 + j] = cn;
        }
    }
}

// ---------------- leaves (d = D): c0 = 0 -------------------------------------
__global__ void k_leaf() {
    int n = blockIdx.x;
    int j = threadIdx.x;
    const float* xr = g_xg + (size_t)n * 1024;
    float gi = xr[j];
    float gg = xr[512 + j];
    float go = xr[768 + j];
    float c = sigf(gi) * tanhf(gg);
    float h = sigf(go) * tanhf(c);
    g_H[(size_t)n * 256 + j] = h;
    g_C[(size_t)n * 256 + j] = c;
}

// ---------------- SIMT level kernel for small levels -------------------------
__global__ __launch_bounds__(256)
void k_level(int start, int nd, const float* __restrict__ W_hh) {
    __shared__ float h0s[32][36];
    __shared__ float Ws[256][36];
    int tid = threadIdx.x;
    int jx = tid & 63, ry = tid >> 6;
    int rowBase = blockIdx.x * 32;
    int jbase = blockIdx.y * 64;

    float acc[8][4];
#pragma unroll
    for (int i = 0; i < 8; i++)
#pragma unroll
        for (int g = 0; g < 4; g++) acc[i][g] = 0.0f;

    for (int k0 = 0; k0 < 256; k0 += 32) {
        {
            int r = tid >> 3, c4 = tid & 7;
            float4 v = make_float4(0.f, 0.f, 0.f, 0.f);
            int rr = rowBase + r;
            if (rr < nd) {
                int node = start + rr;
                int ci = 2 * node - NN;
                float4 a = *(const float4*)&g_H[(size_t)ci * 256 + k0 + c4 * 4];
                float4 b = *(const float4*)&g_H[(size_t)(ci - 1) * 256 + k0 + c4 * 4];
                v = make_float4(0.5f * (a.x + b.x), 0.5f * (a.y + b.y),
                                0.5f * (a.z + b.z), 0.5f * (a.w + b.w));
            }
            *(float4*)&h0s[r][c4 * 4] = v;
        }
        {
            int wrow = ry * 256 + jbase + jx;
            const float* src = &W_hh[(size_t)wrow * 256 + k0];
#pragma unroll
            for (int c = 0; c < 8; c++)
                *(float4*)&Ws[tid][c * 4] = *(const float4*)&src[c * 4];
        }
        __syncthreads();
#pragma unroll
        for (int kk4 = 0; kk4 < 8; kk4++) {
            float4 w4[4];
#pragma unroll
            for (int g = 0; g < 4; g++)
                w4[g] = *(const float4*)&Ws[g * 64 + jx][kk4 * 4];
#pragma unroll
            for (int i = 0; i < 8; i++) {
                float4 a4 = *(const float4*)&h0s[ry * 8 + i][kk4 * 4];
#pragma unroll
                for (int g = 0; g < 4; g++)
                    acc[i][g] += a4.x * w4[g].x + a4.y * w4[g].y +
                                 a4.z * w4[g].z + a4.w * w4[g].w;
            }
        }
        __syncthreads();
    }

    int j = jbase + jx;
#pragma unroll
    for (int i = 0; i < 8; i++) {
        int rr = rowBase + ry * 8 + i;
        if (rr < nd) {
            int node = start + rr;
            const float* xr = g_xg + (size_t)node * 1024;
            float gi = acc[i][0] + xr[j];
            float gf = acc[i][1] + xr[256 + j];
            float gg = acc[i][2] + xr[512 + j];
            float go = acc[i][3] + xr[768 + j];
            int ci = 2 * node - NN;
            float c0 = 0.5f * (g_C[(size_t)ci * 256 + j] + g_C[(size_t)(ci - 1) * 256 + j]);
            float cn = sigf(gf) * c0 + sigf(gi) * tanhf(gg);
            float hn = sigf(go) * tanhf(cn);
            g_H[(size_t)node * 256 + j] = hn;
            g_C[(size_t)node * 256 + j] = cn;
        }
    }
}

// ---------------- output heads ----------------------------------------------
__global__ void k_heads(const float* __restrict__ W2a, const float* __restrict__ b2a,
                        const float* __restrict__ W3a, const float* __restrict__ b3a,
                        const float* __restrict__ Woa, const float* __restrict__ boa,
                        const float* __restrict__ W2b, const float* __restrict__ b2b,
                        const float* __restrict__ W3b, const float* __restrict__ b3b,
                        const float* __restrict__ Wob, const float* __restrict__ bob,
                        float* __restrict__ out) {
    __shared__ float hv[256];
    __shared__ float t1[2][128];
    __shared__ float t2[2][128];
    __shared__ float red[256];
    int tid = threadIdx.x;
    hv[tid] = g_H[(size_t)(NN - 1) * 256 + tid];
    __syncthreads();
    int head = tid >> 7, j = tid & 127;
    const float* W2 = head ? W2b : W2a; const float* b2 = head ? b2b : b2a;
    const float* W3 = head ? W3b : W3a; const float* b3 = head ? b3b : b3a;
    const float* Wo = head ? Wob : Woa; const float* bo = head ? bob : boa;

    float t = b2[j];
    for (int k = 0; k < 256; k++) t += W2[j * 256 + k] * hv[k];
    t1[head][j] = fmaxf(t, 0.0f);
    __syncthreads();
    t = b3[j];
    for (int k = 0; k < 128; k++) t += W3[j * 128 + k] * t1[head][k];
    t2[head][j] = fmaxf(t, 0.0f);
    __syncthreads();
    red[tid] = Wo[j] * t2[head][j];
    __syncthreads();
    for (int s = 64; s > 0; s >>= 1) {
        if (j < s) red[tid] += red[tid + s];
        __syncthreads();
    }
    if (j == 0) out[head] = 1.0f / (1.0f + expf(-(red[tid] + bo[0])));
}

// ---------------- launch ------------------------------------------------------
extern "C" void kernel_launch(void* const* d_in, const int* in_sizes, int n_in,
                              void* d_out, int out_size) {
    const float* op_vec   = (const float*)d_in[0];
    const float* c1_preds = (const float*)d_in[1];
    const void*  c1_mask  = d_in[2];
    const void*  c1_and   = d_in[3];
    const float* c2_preds = (const float*)d_in[4];
    const void*  c2_mask  = d_in[5];
    const void*  c2_and   = d_in[6];
    const float* bitmap   = (const float*)d_in[7];
    const float* W_op     = (const float*)d_in[8];
    const float* b_op     = (const float*)d_in[9];
    const float* W_pred   = (const float*)d_in[10];
    const float* b_pred   = (const float*)d_in[11];
    const float* W_bm     = (const float*)d_in[12];
    const float* b_bm     = (const float*)d_in[13];
    const float* W_ih     = (const float*)d_in[14];
    const float* b_ih     = (const float*)d_in[15];
    const float* W_hh     = (const float*)d_in[16];
    const float* b_hh     = (const float*)d_in[17];
    const float* W_h2t1   = (const float*)d_in[18];
    const float* b_h2t1   = (const float*)d_in[19];
    const float* W_h3t1   = (const float*)d_in[20];
    const float* b_h3t1   = (const float*)d_in[21];
    const float* W_o1     = (const float*)d_in[22];
    const float* b_o1     = (const float*)d_in[23];
    const float* W_h2t2   = (const float*)d_in[24];
    const float* b_h2t2   = (const float*)d_in[25];
    const float* W_h3t2   = (const float*)d_in[26];
    const float* b_h3t2   = (const float*)d_in[27];
    const float* W_o2     = (const float*)d_in[28];
    const float* b_o2     = (const float*)d_in[29];
    float* out = (float*)d_out;

    // dynamic smem sizes (bytes)
    const int SM_GEMM = 4 * 128 * STR * 2;               // 73728
    const int SM_POOL = (2 * 256 + 2 * 64) * STR * 2;    // 92160
    static int configured = 0;
    if (!configured) {
        cudaFuncSetAttribute(k_pool_mma, cudaFuncAttributeMaxDynamicSharedMemorySize, SM_POOL);
        cudaFuncSetAttribute(k_bm_mma,   cudaFuncAttributeMaxDynamicSharedMemorySize, SM_GEMM);
        cudaFuncSetAttribute(k_xg_mma,   cudaFuncAttributeMaxDynamicSharedMemorySize, SM_GEMM);
        cudaFuncSetAttribute(k_level_mma,cudaFuncAttributeMaxDynamicSharedMemorySize, SM_GEMM);
        configured = 1;
    }

    k_detect<<<1, 256>>>((const unsigned int*)c1_mask);
    k_wsplit<<<(1024 * 288 + 1024 * 256 + 128 * 1000 + 64 * 64 + 255) / 256, 256>>>(
        W_ih, W_hh, W_bm, W_pred);

    k_op<<<(NN + 7) / 8, 256>>>(op_vec, W_op, b_op);

    {
        dim3 grid((MRPOOL + 255) / 256, 2);
        k_pool_mma<<<grid, 256, SM_POOL>>>(c1_preds, c1_mask, c1_and,
                                           c2_preds, c2_mask, c2_and, b_pred);
    }

    k_bm_mma<<<(NN + 127) / 128, 256, SM_GEMM>>>(bitmap, b_bm);

    {
        dim3 grid(8, (NN + 127) / 128);
        k_xg_mma<<<grid, 256, SM_GEMM>>>(b_ih, b_hh);
    }

    k_leaf<<<32768, 256>>>();

    for (int d = 14; d >= 0; d--) {
        int nd = 1 << d;
        int start = NN - (1 << (d + 1)) + 1;
        if (nd >= 128) {
            dim3 grid((nd + 127) / 128, 8);
            k_level_mma<<<grid, 256, SM_GEMM>>>(start, nd);
        } else {
            dim3 grid((nd + 31) / 32, 4);
            k_level<<<grid, 256>>>(start, nd, W_hh);
        }
    }

    k_heads<<<1, 256>>>(W_h2t1, b_h2t1, W_h3t1, b_h3t1, W_o1, b_o1,
                        W_h2t2, b_h2t2, W_h3t2, b_h3t2, W_o2, b_o2,
                        out);
}

// round 6
// speedup vs baseline: 6.4731x; 1.2161x over previous
#include <cuda_runtime.h>
#include <cuda_bf16.h>
#include <math.h>
#include <cstdint>
#include <stdint.h>

#define NN 65535          // number of tree nodes (2^16 - 1)
#define MRPOOL (NN * 8)   // pool GEMM rows
#define BIGF 1e30f
#define STR 72            // smem row stride in bf16 elems (144 B)

// ---------------- scratch (static device globals; no cudaMalloc) -------------
__device__ __nv_bfloat16 g_xh[(size_t)NN * 288];   // features hi
__device__ __nv_bfloat16 g_xl[(size_t)NN * 288];   // features lo
__device__ float g_xg[(size_t)NN * 1024];          // gates pre-activation
__device__ float g_H[(size_t)NN * 256];            // LSTM hidden
__device__ float g_C[(size_t)NN * 256];            // LSTM cell
__device__ int   g_mask_is_byte;

// pre-split weights (bf16 hi/lo)
__device__ __nv_bfloat16 g_Wih_h[1024 * 288], g_Wih_l[1024 * 288];
__device__ __nv_bfloat16 g_Whh_h[1024 * 256], g_Whh_l[1024 * 256];
__device__ __nv_bfloat16 g_Wbm_h[128 * 1000], g_Wbm_l[128 * 1000];
__device__ __nv_bfloat16 g_Wp_h[64 * 64],     g_Wp_l[64 * 64];

__device__ __forceinline__ float sigf(float x) { return 1.0f / (1.0f + expf(-x)); }

__device__ __forceinline__ int read_bool(const void* p, int idx) {
    return g_mask_is_byte ? (int)(((const unsigned char*)p)[idx])
                          : (((const int*)p)[idx] != 0);
}

__device__ __forceinline__ unsigned smem_u32(const void* p) {
    return (unsigned)__cvta_generic_to_shared(p);
}
__device__ __forceinline__ void cpa16(unsigned dst, const void* src, int nbytes) {
    asm volatile("cp.async.cg.shared.global [%0], [%1], 16, %2;\n"
                 :: "r"(dst), "l"(src), "r"(nbytes));
}
#define CPA_COMMIT() asm volatile("cp.async.commit_group;\n")
#define CPA_WAIT0()  asm volatile("cp.async.wait_group 0;\n")

// ---------------- bf16 split helpers -----------------------------------------
__device__ __forceinline__ void split2(float x, float y, uint32_t& h, uint32_t& l) {
    __nv_bfloat16 hx = __float2bfloat16(x), hy = __float2bfloat16(y);
    __nv_bfloat16 lx = __float2bfloat16(x - __bfloat162float(hx));
    __nv_bfloat16 ly = __float2bfloat16(y - __bfloat162float(hy));
    h = ((uint32_t)__bfloat16_as_ushort(hy) << 16) | __bfloat16_as_ushort(hx);
    l = ((uint32_t)__bfloat16_as_ushort(ly) << 16) | __bfloat16_as_ushort(lx);
}

// ---------------- mma.sync m16n8k16 bf16 -------------------------------------
__device__ __forceinline__ void mma_bf16(float d[4], const uint32_t a[4], const uint32_t b[2]) {
    asm volatile(
        "mma.sync.aligned.m16n8k16.row.col.f32.bf16.bf16.f32 "
        "{%0,%1,%2,%3}, {%4,%5,%6,%7}, {%8,%9}, {%0,%1,%2,%3};\n"
        : "+f"(d[0]), "+f"(d[1]), "+f"(d[2]), "+f"(d[3])
        : "r"(a[0]), "r"(a[1]), "r"(a[2]), "r"(a[3]), "r"(b[0]), "r"(b[1]));
}

// One K-chunk (32 fp32 = hi[0:32) + lo[32:64) bf16) for a 32x64 warp tile.
__device__ __forceinline__ void mma_chunk(const __nv_bfloat16* As, const __nv_bfloat16* Bs,
                                          int wm, int wn, int lane, float acc[2][8][4]) {
#pragma unroll
    for (int pass = 0; pass < 3; pass++) {
        int ka = (pass == 2) ? 32 : 0;
        int kb = (pass == 1) ? 32 : 0;
#pragma unroll
        for (int ks = 0; ks < 2; ks++) {
            int kA = ka + ks * 16 + (lane & 3) * 2;
            int kB = kb + ks * 16 + (lane & 3) * 2;
            uint32_t af[2][4];
#pragma unroll
            for (int mt = 0; mt < 2; mt++) {
                const __nv_bfloat16* p = As + (wm * 32 + mt * 16 + (lane >> 2)) * STR + kA;
                af[mt][0] = *(const uint32_t*)p;
                af[mt][1] = *(const uint32_t*)(p + 8 * STR);
                af[mt][2] = *(const uint32_t*)(p + 8);
                af[mt][3] = *(const uint32_t*)(p + 8 * STR + 8);
            }
#pragma unroll
            for (int nt = 0; nt < 8; nt++) {
                const __nv_bfloat16* p = Bs + (wn * 64 + nt * 8 + (lane >> 2)) * STR + kB;
                uint32_t bq[2] = { *(const uint32_t*)p, *(const uint32_t*)(p + 8) };
#pragma unroll
                for (int mt = 0; mt < 2; mt++)
                    mma_bf16(acc[mt][nt], af[mt], bq);
            }
        }
    }
}

// 32x32 warp-tile variant (pool)
__device__ __forceinline__ void mma_chunk32(const __nv_bfloat16* As, const __nv_bfloat16* Bs,
                                            int wm, int wn, int lane, float acc[2][4][4]) {
#pragma unroll
    for (int pass = 0; pass < 3; pass++) {
        int ka = (pass == 2) ? 32 : 0;
        int kb = (pass == 1) ? 32 : 0;
#pragma unroll
        for (int ks = 0; ks < 2; ks++) {
            int kA = ka + ks * 16 + (lane & 3) * 2;
            int kB = kb + ks * 16 + (lane & 3) * 2;
            uint32_t af[2][4];
#pragma unroll
            for (int mt = 0; mt < 2; mt++) {
                const __nv_bfloat16* p = As + (wm * 32 + mt * 16 + (lane >> 2)) * STR + kA;
                af[mt][0] = *(const uint32_t*)p;
                af[mt][1] = *(const uint32_t*)(p + 8 * STR);
                af[mt][2] = *(const uint32_t*)(p + 8);
                af[mt][3] = *(const uint32_t*)(p + 8 * STR + 8);
            }
#pragma unroll
            for (int nt = 0; nt < 4; nt++) {
                const __nv_bfloat16* p = Bs + (wn * 32 + nt * 8 + (lane >> 2)) * STR + kB;
                uint32_t bq[2] = { *(const uint32_t*)p, *(const uint32_t*)(p + 8) };
#pragma unroll
                for (int mt = 0; mt < 2; mt++)
                    mma_bf16(acc[mt][nt], af[mt], bq);
            }
        }
    }
}

// ---------------- loaders ----------------------------------------------------
// fp32 -> regs (later split+STS). SLOTS*256 = ROWS*4.
template <int SLOTS>
__device__ __forceinline__ void ldg_f32(const float* __restrict__ src, int ld, int rowBase,
                                        int maxRow, int k0, int Ktot, int tid, float4 (*v)[2]) {
#pragma unroll
    for (int s = 0; s < SLOTS; s++) {
        int idx = tid + 256 * s;
        int r = idx >> 2, g = idx & 3;
        int row = rowBase + r, k = k0 + g * 8;
        float4 a = make_float4(0.f, 0.f, 0.f, 0.f), b = a;
        if (row < maxRow && k + 8 <= Ktot) {
            const float* p = src + (size_t)row * ld + k;
            a = *(const float4*)p;
            b = *(const float4*)(p + 4);
        }
        v[s][0] = a; v[s][1] = b;
    }
}

template <int SLOTS>
__device__ __forceinline__ void sts_split(__nv_bfloat16* As, int tid, float4 (*v)[2]) {
#pragma unroll
    for (int s = 0; s < SLOTS; s++) {
        int idx = tid + 256 * s;
        int r = idx >> 2, g = idx & 3;
        uint32_t h0, l0, h1, l1, h2, l2, h3, l3;
        split2(v[s][0].x, v[s][0].y, h0, l0);
        split2(v[s][0].z, v[s][0].w, h1, l1);
        split2(v[s][1].x, v[s][1].y, h2, l2);
        split2(v[s][1].z, v[s][1].w, h3, l3);
        __nv_bfloat16* p = As + r * STR + g * 8;
        *(uint4*)p        = make_uint4(h0, h1, h2, h3);
        *(uint4*)(p + 32) = make_uint4(l0, l1, l2, l3);
    }
}

// bf16 hi/lo operand -> smem tile via cp.async. ROWS/32 slots.
template <int ROWS>
__device__ __forceinline__ void cpa_bf16(__nv_bfloat16* Bs,
        const __nv_bfloat16* __restrict__ sh, const __nv_bfloat16* __restrict__ sl,
        int ld, int rowBase, int maxRow, int k0, int Ktot, int tid) {
#pragma unroll
    for (int s = 0; s < ROWS / 32; s++) {
        int idx = tid + 256 * s;
        int r = idx >> 3, part = idx & 7;
        int row = rowBase + r;
        int k = k0 + (part & 3) * 8;
        int ok = (row < maxRow && k + 8 <= Ktot) ? 16 : 0;
        int rowc = (row < maxRow) ? row : (maxRow - 1);
        int kc = (k + 8 <= Ktot) ? k : 0;
        const __nv_bfloat16* src = ((part < 4) ? sh : sl) + (size_t)rowc * ld + kc;
        unsigned dst = smem_u32(Bs + r * STR + ((part < 4) ? 0 : 32) + (part & 3) * 8);
        cpa16(dst, src, ok);
    }
}

// W_hh tile loader (row mapping gate*256 + jbase + j)
__device__ __forceinline__ void cpa_Whh(__nv_bfloat16* Bs, int jbase, int k0, int tid) {
#pragma unroll
    for (int s = 0; s < 4; s++) {
        int idx = tid + 256 * s;
        int r = idx >> 3, part = idx & 7;
        int wrow = (r >> 5) * 256 + jbase + (r & 31);
        int k = k0 + (part & 3) * 8;
        const __nv_bfloat16* src = ((part < 4) ? g_Whh_h : g_Whh_l) + (size_t)wrow * 256 + k;
        unsigned dst = smem_u32(Bs + r * STR + ((part < 4) ? 0 : 32) + (part & 3) * 8);
        cpa16(dst, src, 16);
    }
}

// averaged child H -> regs
__device__ __forceinline__ void ldg_avgH(int start, int nd, int rowBase, int k0, int tid,
                                         float4 (*v)[2]) {
#pragma unroll
    for (int s = 0; s < 2; s++) {
        int idx = tid + 256 * s;
        int r = idx >> 2, g = idx & 3;
        int rr = rowBase + r;
        float4 a = make_float4(0.f, 0.f, 0.f, 0.f), b = a;
        if (rr < nd) {
            int node = start + rr;
            int ci = 2 * node - NN;
            const float* p0 = g_H + (size_t)ci * 256 + k0 + g * 8;
            const float* p1 = g_H + (size_t)(ci - 1) * 256 + k0 + g * 8;
            float4 x0 = *(const float4*)p0, x1 = *(const float4*)(p0 + 4);
            float4 y0 = *(const float4*)p1, y1 = *(const float4*)(p1 + 4);
            a = make_float4(0.5f * (x0.x + y0.x), 0.5f * (x0.y + y0.y),
                            0.5f * (x0.z + y0.z), 0.5f * (x0.w + y0.w));
            b = make_float4(0.5f * (x1.x + y1.x), 0.5f * (x1.y + y1.y),
                            0.5f * (x1.z + y1.z), 0.5f * (x1.w + y1.w));
        }
        v[s][0] = a; v[s][1] = b;
    }
}

// ---------------- small kernels ----------------------------------------------
__global__ void k_detect(const unsigned int* __restrict__ m) {
    __shared__ int found;
    if (threadIdx.x == 0) found = 0;
    __syncthreads();
    unsigned int v = m[threadIdx.x];
    if (v > 1u) found = 1;
    __syncthreads();
    if (threadIdx.x == 0) g_mask_is_byte = found;
}

__global__ void k_wsplit(const float* __restrict__ Wih, const float* __restrict__ Whh,
                         const float* __restrict__ Wbm, const float* __restrict__ Wp) {
    int i = blockIdx.x * 256 + threadIdx.x;
    const int S1 = 1024 * 288, S2 = 1024 * 256, S3 = 128 * 1000, S4 = 64 * 64;
    float w; __nv_bfloat16 h;
    if (i < S1) {
        w = Wih[i]; h = __float2bfloat16(w);
        g_Wih_h[i] = h; g_Wih_l[i] = __float2bfloat16(w - __bfloat162float(h));
    } else if (i < S1 + S2) {
        int j = i - S1; w = Whh[j]; h = __float2bfloat16(w);
        g_Whh_h[j] = h; g_Whh_l[j] = __float2bfloat16(w - __bfloat162float(h));
    } else if (i < S1 + S2 + S3) {
        int j = i - S1 - S2; w = Wbm[j]; h = __float2bfloat16(w);
        g_Wbm_h[j] = h; g_Wbm_l[j] = __float2bfloat16(w - __bfloat162float(h));
    } else if (i < S1 + S2 + S3 + S4) {
        int j = i - S1 - S2 - S3; w = Wp[j]; h = __float2bfloat16(w);
        g_Wp_h[j] = h; g_Wp_l[j] = __float2bfloat16(w - __bfloat162float(h));
    }
}

__global__ void k_op(const float* __restrict__ op_vec,
                     const float* __restrict__ W_op,
                     const float* __restrict__ b_op) {
    __shared__ float Ws[32][33];
    __shared__ float bs[32];
    int tid = threadIdx.x;
    if (tid < 32) bs[tid] = b_op[tid];
    for (int i = tid; i < 1024; i += 256) Ws[i >> 5][i & 31] = W_op[i];
    __syncthreads();
    int node = blockIdx.x * 8 + (tid >> 5);
    int o = tid & 31;
    if (node >= NN) return;
    float vl = op_vec[node * 32 + o];
    float acc = bs[o];
#pragma unroll
    for (int p = 0; p < 32; p++)
        acc += Ws[o][p] * __shfl_sync(0xffffffffu, vl, p);
    __nv_bfloat16 h = __float2bfloat16(acc);
    g_xh[(size_t)node * 288 + o] = h;
    g_xl[(size_t)node * 288 + o] = __float2bfloat16(acc - __bfloat162float(h));
}

// ============ mma GEMM 1: pool (128Mx64N block, warp 32x32, K=64) ============
__global__ __launch_bounds__(256, 2)
void k_pool_mma(const float* __restrict__ preds1, const void* mask1, const void* and1,
                const float* __restrict__ preds2, const void* mask2, const void* and2,
                const float* __restrict__ b_pred) {
    extern __shared__ __nv_bfloat16 sm[];
    __nv_bfloat16* As[2] = { sm, sm + 128 * STR };
    __nv_bfloat16* Bs[2] = { sm + 256 * STR, sm + 256 * STR + 64 * STR };
    float* stage = (float*)sm;   // reused after GEMM: [128][68]

    int tid = threadIdx.x, lane = tid & 31, warp = tid >> 5;
    int wm = warp >> 1, wn = warp & 1;
    int cond = blockIdx.y;
    const float* preds = cond ? preds2 : preds1;
    const void*  maskp = cond ? mask2 : mask1;
    const void*  andp  = cond ? and2  : and1;
    int rowBase = blockIdx.x * 128;

    float acc[2][4][4];
#pragma unroll
    for (int a = 0; a < 2; a++)
#pragma unroll
        for (int b = 0; b < 4; b++)
#pragma unroll
            for (int c = 0; c < 4; c++) acc[a][b][c] = 0.f;

    float4 va[2][2];
    // prologue: both B chunks (whole K=64 of W_pred) + A chunk 0
    cpa_bf16<64>(Bs[0], g_Wp_h, g_Wp_l, 64, 0, 64, 0, 64, tid);
    cpa_bf16<64>(Bs[1], g_Wp_h, g_Wp_l, 64, 0, 64, 32, 64, tid);
    CPA_COMMIT();
    ldg_f32<2>(preds, 64, rowBase, MRPOOL, 0, 64, tid, va);
    sts_split<2>(As[0], tid, va);
    CPA_WAIT0();
    __syncthreads();

    for (int t = 0; t < 2; t++) {
        bool more = (t == 0);
        if (more) ldg_f32<2>(preds, 64, rowBase, MRPOOL, 32, 64, tid, va);
        mma_chunk32(As[t], Bs[t], wm, wn, lane, acc);
        if (more) sts_split<2>(As[1], tid, va);
        __syncthreads();
    }

    // stage accs: rows [0,128), cols [0,64)
#pragma unroll
    for (int mt = 0; mt < 2; mt++) {
#pragma unroll
        for (int nt = 0; nt < 4; nt++) {
            int r = wm * 32 + mt * 16 + (lane >> 2);
            int c = wn * 32 + nt * 8 + (lane & 3) * 2;
            stage[r * 68 + c] = acc[mt][nt][0];
            stage[r * 68 + c + 1] = acc[mt][nt][1];
            stage[(r + 8) * 68 + c] = acc[mt][nt][2];
            stage[(r + 8) * 68 + c + 1] = acc[mt][nt][3];
        }
    }
    __syncthreads();

    // pooling epilogue: 16 nodes per block; 16 threads/node x 4 cols
    int node = blockIdx.x * 16 + (tid >> 4);
    int cg = (tid & 15) * 4;
    if (node < NN) {
        float bb[4];
        *(float4*)bb = *(const float4*)(b_pred + cg);
        int mk[8], anyb = 0;
#pragma unroll
        for (int i = 0; i < 8; i++) { mk[i] = read_bool(maskp, node * 8 + i); anyb |= mk[i]; }
        int ia = read_bool(andp, node);
        int rb = (tid >> 4) * 8;
        float out[4];
#pragma unroll
        for (int j = 0; j < 4; j++) {
            float mn = BIGF, mx = -BIGF;
#pragma unroll
            for (int i = 0; i < 8; i++) {
                float v = stage[(rb + i) * 68 + cg + j] + bb[j];
                if (mk[i]) { mn = fminf(mn, v); mx = fmaxf(mx, v); }
            }
            out[j] = anyb ? (ia ? mn : mx) : 0.0f;
        }
        size_t base = (size_t)node * 288 + 32 + cond * 64 + cg;
        uint32_t h0, l0, h1, l1;
        split2(out[0], out[1], h0, l0);
        split2(out[2], out[3], h1, l1);
        *(uint32_t*)(g_xh + base) = h0;     *(uint32_t*)(g_xh + base + 2) = h1;
        *(uint32_t*)(g_xl + base) = l0;     *(uint32_t*)(g_xl + base + 2) = l1;
    }
}

// ============ mma GEMM 2: bm (128Mx128N block, K=1000) =======================
__global__ __launch_bounds__(256, 2)
void k_bm_mma(const float* __restrict__ bitmap, const float* __restrict__ b_bm) {
    extern __shared__ __nv_bfloat16 sm[];
    __nv_bfloat16* As[2] = { sm, sm + 128 * STR };
    __nv_bfloat16* Bs[2] = { sm + 256 * STR, sm + 384 * STR };
    int tid = threadIdx.x, lane = tid & 31, warp = tid >> 5;
    int wm = warp >> 1, wn = warp & 1;
    int rowBase = blockIdx.x * 128;

    float acc[2][8][4];
#pragma unroll
    for (int a = 0; a < 2; a++)
#pragma unroll
        for (int b = 0; b < 8; b++)
#pragma unroll
            for (int c = 0; c < 4; c++) acc[a][b][c] = 0.f;

    float4 va[2][2];
    cpa_bf16<128>(Bs[0], g_Wbm_h, g_Wbm_l, 1000, 0, 128, 0, 1000, tid);
    CPA_COMMIT();
    ldg_f32<2>(bitmap, 1000, rowBase, NN, 0, 1000, tid, va);
    sts_split<2>(As[0], tid, va);
    CPA_WAIT0();
    __syncthreads();

    const int NC = 32;
    for (int t = 0; t < NC; t++) {
        bool more = (t + 1 < NC);
        if (more) {
            cpa_bf16<128>(Bs[(t + 1) & 1], g_Wbm_h, g_Wbm_l, 1000, 0, 128, (t + 1) * 32, 1000, tid);
            CPA_COMMIT();
            ldg_f32<2>(bitmap, 1000, rowBase, NN, (t + 1) * 32, 1000, tid, va);
        }
        mma_chunk(As[t & 1], Bs[t & 1], wm, wn, lane, acc);
        if (more) {
            sts_split<2>(As[(t + 1) & 1], tid, va);
            CPA_WAIT0();
        }
        __syncthreads();
    }

#pragma unroll
    for (int nt = 0; nt < 8; nt++) {
        int c = wn * 64 + nt * 8 + (lane & 3) * 2;
        float bx = b_bm[c], by = b_bm[c + 1];
#pragma unroll
        for (int mt = 0; mt < 2; mt++) {
            int r0 = rowBase + wm * 32 + mt * 16 + (lane >> 2);
            if (r0 < NN) {
                uint32_t h, l;
                split2(acc[mt][nt][0] + bx, acc[mt][nt][1] + by, h, l);
                *(uint32_t*)(g_xh + (size_t)r0 * 288 + 160 + c) = h;
                *(uint32_t*)(g_xl + (size_t)r0 * 288 + 160 + c) = l;
            }
            if (r0 + 8 < NN) {
                uint32_t h, l;
                split2(acc[mt][nt][2] + bx, acc[mt][nt][3] + by, h, l);
                *(uint32_t*)(g_xh + (size_t)(r0 + 8) * 288 + 160 + c) = h;
                *(uint32_t*)(g_xl + (size_t)(r0 + 8) * 288 + 160 + c) = l;
            }
        }
    }
}

// ============ mma GEMM 3: xg (128Mx128N block, K=288, all cp.async) ==========
__global__ __launch_bounds__(256, 2)
void k_xg_mma(const float* __restrict__ b_ih, const float* __restrict__ b_hh) {
    extern __shared__ __nv_bfloat16 sm[];
    __nv_bfloat16* As[2] = { sm, sm + 128 * STR };
    __nv_bfloat16* Bs[2] = { sm + 256 * STR, sm + 384 * STR };
    int tid = threadIdx.x, lane = tid & 31, warp = tid >> 5;
    int wm = warp >> 1, wn = warp & 1;
    int colBase = blockIdx.x * 128;
    int rowBase = blockIdx.y * 128;

    float acc[2][8][4];
#pragma unroll
    for (int a = 0; a < 2; a++)
#pragma unroll
        for (int b = 0; b < 8; b++)
#pragma unroll
            for (int c = 0; c < 4; c++) acc[a][b][c] = 0.f;

    cpa_bf16<128>(As[0], g_xh, g_xl, 288, rowBase, NN, 0, 288, tid);
    cpa_bf16<128>(Bs[0], g_Wih_h, g_Wih_l, 288, colBase, 1024, 0, 288, tid);
    CPA_COMMIT();
    CPA_WAIT0();
    __syncthreads();

    const int NC = 9;
    for (int t = 0; t < NC; t++) {
        bool more = (t + 1 < NC);
        if (more) {
            cpa_bf16<128>(As[(t + 1) & 1], g_xh, g_xl, 288, rowBase, NN, (t + 1) * 32, 288, tid);
            cpa_bf16<128>(Bs[(t + 1) & 1], g_Wih_h, g_Wih_l, 288, colBase, 1024, (t + 1) * 32, 288, tid);
            CPA_COMMIT();
        }
        mma_chunk(As[t & 1], Bs[t & 1], wm, wn, lane, acc);
        if (more) CPA_WAIT0();
        __syncthreads();
    }

#pragma unroll
    for (int nt = 0; nt < 8; nt++) {
        int c = colBase + wn * 64 + nt * 8 + (lane & 3) * 2;
        float bx = b_ih[c] + b_hh[c], by = b_ih[c + 1] + b_hh[c + 1];
#pragma unroll
        for (int mt = 0; mt < 2; mt++) {
            int r0 = rowBase + wm * 32 + mt * 16 + (lane >> 2);
            if (r0 < NN)
                *(float2*)(g_xg + (size_t)r0 * 1024 + c) =
                    make_float2(acc[mt][nt][0] + bx, acc[mt][nt][1] + by);
            if (r0 + 8 < NN)
                *(float2*)(g_xg + (size_t)(r0 + 8) * 1024 + c) =
                    make_float2(acc[mt][nt][2] + bx, acc[mt][nt][3] + by);
        }
    }
}

// ============ mma level kernel (nd >= 128): fused GEMM + LSTM pointwise ======
__global__ __launch_bounds__(256, 2)
void k_level_mma(int start, int nd) {
    extern __shared__ __nv_bfloat16 sm[];
    __nv_bfloat16* As[2] = { sm, sm + 128 * STR };
    __nv_bfloat16* Bs[2] = { sm + 256 * STR, sm + 384 * STR };
    float* stage = (float*)sm;   // [128][132] after GEMM

    int tid = threadIdx.x, lane = tid & 31, warp = tid >> 5;
    int wm = warp >> 1, wn = warp & 1;
    int rowBase = blockIdx.x * 128;
    int jbase = blockIdx.y * 32;

    float acc[2][8][4];
#pragma unroll
    for (int a = 0; a < 2; a++)
#pragma unroll
        for (int b = 0; b < 8; b++)
#pragma unroll
            for (int c = 0; c < 4; c++) acc[a][b][c] = 0.f;

    float4 va[2][2];
    cpa_Whh(Bs[0], jbase, 0, tid);
    CPA_COMMIT();
    ldg_avgH(start, nd, rowBase, 0, tid, va);
    sts_split<2>(As[0], tid, va);
    CPA_WAIT0();
    __syncthreads();

    const int NC = 8;
    for (int t = 0; t < NC; t++) {
        bool more = (t + 1 < NC);
        if (more) {
            cpa_Whh(Bs[(t + 1) & 1], jbase, (t + 1) * 32, tid);
            CPA_COMMIT();
            ldg_avgH(start, nd, rowBase, (t + 1) * 32, tid, va);
        }
        mma_chunk(As[t & 1], Bs[t & 1], wm, wn, lane, acc);
        if (more) {
            sts_split<2>(As[(t + 1) & 1], tid, va);
            CPA_WAIT0();
        }
        __syncthreads();
    }

    // stage: rows local [0,128), cols [0,128) = gate*32 + jj
#pragma unroll
    for (int mt = 0; mt < 2; mt++) {
#pragma unroll
        for (int nt = 0; nt < 8; nt++) {
            int r = wm * 32 + mt * 16 + (lane >> 2);
            int c = wn * 64 + nt * 8 + (lane & 3) * 2;
            stage[r * 132 + c] = acc[mt][nt][0];
            stage[r * 132 + c + 1] = acc[mt][nt][1];
            stage[(r + 8) * 132 + c] = acc[mt][nt][2];
            stage[(r + 8) * 132 + c + 1] = acc[mt][nt][3];
        }
    }
    __syncthreads();

#pragma unroll
    for (int i = 0; i < 16; i++) {
        int idx = tid + 256 * i;
        int r = idx >> 5, jj = idx & 31;
        int rr = rowBase + r;
        if (rr < nd) {
            int node = start + rr;
            int j = jbase + jj;
            const float* xr = g_xg + (size_t)node * 1024;
            float gi = stage[r * 132 + jj]       + xr[j];
            float gf = stage[r * 132 + 32 + jj]  + xr[256 + j];
            float gg = stage[r * 132 + 64 + jj]  + xr[512 + j];
            float go = stage[r * 132 + 96 + jj]  + xr[768 + j];
            int ci = 2 * node - NN;
            float c0 = 0.5f * (g_C[(size_t)ci * 256 + j] + g_C[(size_t)(ci - 1) * 256 + j]);
            float cn = sigf(gf) * c0 + sigf(gi) * tanhf(gg);
            float hn = sigf(go) * tanhf(cn);
            g_H[(size_t)node * 256 + j] = hn;
            g_C[(size_t)node * 256 + j] = cn;
        }
    }
}

// ---------------- leaves (d = D): c0 = 0 -------------------------------------
__global__ void k_leaf() {
    int n = blockIdx.x;
    int j = threadIdx.x;
    const float* xr = g_xg + (size_t)n * 1024;
    float gi = xr[j];
    float gg = xr[512 + j];
    float go = xr[768 + j];
    float c = sigf(gi) * tanhf(gg);
    float h = sigf(go) * tanhf(c);
    g_H[(size_t)n * 256 + j] = h;
    g_C[(size_t)n * 256 + j] = c;
}

// ---------------- SIMT level kernel for small levels -------------------------
__global__ __launch_bounds__(256)
void k_level(int start, int nd, const float* __restrict__ W_hh) {
    __shared__ float h0s[32][36];
    __shared__ float Ws[256][36];
    int tid = threadIdx.x;
    int jx = tid & 63, ry = tid >> 6;
    int rowBase = blockIdx.x * 32;
    int jbase = blockIdx.y * 64;

    float acc[8][4];
#pragma unroll
    for (int i = 0; i < 8; i++)
#pragma unroll
        for (int g = 0; g < 4; g++) acc[i][g] = 0.0f;

    for (int k0 = 0; k0 < 256; k0 += 32) {
        {
            int r = tid >> 3, c4 = tid & 7;
            float4 v = make_float4(0.f, 0.f, 0.f, 0.f);
            int rr = rowBase + r;
            if (rr < nd) {
                int node = start + rr;
                int ci = 2 * node - NN;
                float4 a = *(const float4*)&g_H[(size_t)ci * 256 + k0 + c4 * 4];
                float4 b = *(const float4*)&g_H[(size_t)(ci - 1) * 256 + k0 + c4 * 4];
                v = make_float4(0.5f * (a.x + b.x), 0.5f * (a.y + b.y),
                                0.5f * (a.z + b.z), 0.5f * (a.w + b.w));
            }
            *(float4*)&h0s[r][c4 * 4] = v;
        }
        {
            int wrow = ry * 256 + jbase + jx;
            const float* src = &W_hh[(size_t)wrow * 256 + k0];
#pragma unroll
            for (int c = 0; c < 8; c++)
                *(float4*)&Ws[tid][c * 4] = *(const float4*)&src[c * 4];
        }
        __syncthreads();
#pragma unroll
        for (int kk4 = 0; kk4 < 8; kk4++) {
            float4 w4[4];
#pragma unroll
            for (int g = 0; g < 4; g++)
                w4[g] = *(const float4*)&Ws[g * 64 + jx][kk4 * 4];
#pragma unroll
            for (int i = 0; i < 8; i++) {
                float4 a4 = *(const float4*)&h0s[ry * 8 + i][kk4 * 4];
#pragma unroll
                for (int g = 0; g < 4; g++)
                    acc[i][g] += a4.x * w4[g].x + a4.y * w4[g].y +
                                 a4.z * w4[g].z + a4.w * w4[g].w;
            }
        }
        __syncthreads();
    }

    int j = jbase + jx;
#pragma unroll
    for (int i = 0; i < 8; i++) {
        int rr = rowBase + ry * 8 + i;
        if (rr < nd) {
            int node = start + rr;
            const float* xr = g_xg + (size_t)node * 1024;
            float gi = acc[i][0] + xr[j];
            float gf = acc[i][1] + xr[256 + j];
            float gg = acc[i][2] + xr[512 + j];
            float go = acc[i][3] + xr[768 + j];
            int ci = 2 * node - NN;
            float c0 = 0.5f * (g_C[(size_t)ci * 256 + j] + g_C[(size_t)(ci - 1) * 256 + j]);
            float cn = sigf(gf) * c0 + sigf(gi) * tanhf(gg);
            float hn = sigf(go) * tanhf(cn);
            g_H[(size_t)node * 256 + j] = hn;
            g_C[(size_t)node * 256 + j] = cn;
        }
    }
}

// ---------------- output heads ----------------------------------------------
__global__ void k_heads(const float* __restrict__ W2a, const float* __restrict__ b2a,
                        const float* __restrict__ W3a, const float* __restrict__ b3a,
                        const float* __restrict__ Woa, const float* __restrict__ boa,
                        const float* __restrict__ W2b, const float* __restrict__ b2b,
                        const float* __restrict__ W3b, const float* __restrict__ b3b,
                        const float* __restrict__ Wob, const float* __restrict__ bob,
                        float* __restrict__ out) {
    __shared__ float hv[256];
    __shared__ float t1[2][128];
    __shared__ float t2[2][128];
    __shared__ float red[256];
    int tid = threadIdx.x;
    hv[tid] = g_H[(size_t)(NN - 1) * 256 + tid];
    __syncthreads();
    int head = tid >> 7, j = tid & 127;
    const float* W2 = head ? W2b : W2a; const float* b2 = head ? b2b : b2a;
    const float* W3 = head ? W3b : W3a; const float* b3 = head ? b3b : b3a;
    const float* Wo = head ? Wob : Woa; const float* bo = head ? bob : boa;

    float t = b2[j];
    for (int k = 0; k < 256; k++) t += W2[j * 256 + k] * hv[k];
    t1[head][j] = fmaxf(t, 0.0f);
    __syncthreads();
    t = b3[j];
    for (int k = 0; k < 128; k++) t += W3[j * 128 + k] * t1[head][k];
    t2[head][j] = fmaxf(t, 0.0f);
    __syncthreads();
    red[tid] = Wo[j] * t2[head][j];
    __syncthreads();
    for (int s = 64; s > 0; s >>= 1) {
        if (j < s) red[tid] += red[tid + s];
        __syncthreads();
    }
    if (j == 0) out[head] = 1.0f / (1.0f + expf(-(red[tid] + bo[0])));
}

// ---------------- launch ------------------------------------------------------
extern "C" void kernel_launch(void* const* d_in, const int* in_sizes, int n_in,
                              void* d_out, int out_size) {
    const float* op_vec   = (const float*)d_in[0];
    const float* c1_preds = (const float*)d_in[1];
    const void*  c1_mask  = d_in[2];
    const void*  c1_and   = d_in[3];
    const float* c2_preds = (const float*)d_in[4];
    const void*  c2_mask  = d_in[5];
    const void*  c2_and   = d_in[6];
    const float* bitmap   = (const float*)d_in[7];
    const float* W_op     = (const float*)d_in[8];
    const float* b_op     = (const float*)d_in[9];
    const float* W_pred   = (const float*)d_in[10];
    const float* b_pred   = (const float*)d_in[11];
    const float* W_bm     = (const float*)d_in[12];
    const float* b_bm     = (const float*)d_in[13];
    const float* W_ih     = (const float*)d_in[14];
    const float* b_ih     = (const float*)d_in[15];
    const float* W_hh     = (const float*)d_in[16];
    const float* b_hh     = (const float*)d_in[17];
    const float* W_h2t1   = (const float*)d_in[18];
    const float* b_h2t1   = (const float*)d_in[19];
    const float* W_h3t1   = (const float*)d_in[20];
    const float* b_h3t1   = (const float*)d_in[21];
    const float* W_o1     = (const float*)d_in[22];
    const float* b_o1     = (const float*)d_in[23];
    const float* W_h2t2   = (const float*)d_in[24];
    const float* b_h2t2   = (const float*)d_in[25];
    const float* W_h3t2   = (const float*)d_in[26];
    const float* b_h3t2   = (const float*)d_in[27];
    const float* W_o2     = (const float*)d_in[28];
    const float* b_o2     = (const float*)d_in[29];
    float* out = (float*)d_out;

    const int SM_GEMM = 4 * 128 * STR * 2;                       // 73728
    const int SM_POOL = (2 * 128 + 2 * 64) * STR * 2;            // 55296
    static int configured = 0;
    if (!configured) {
        cudaFuncSetAttribute(k_pool_mma, cudaFuncAttributeMaxDynamicSharedMemorySize, SM_POOL);
        cudaFuncSetAttribute(k_bm_mma,   cudaFuncAttributeMaxDynamicSharedMemorySize, SM_GEMM);
        cudaFuncSetAttribute(k_xg_mma,   cudaFuncAttributeMaxDynamicSharedMemorySize, SM_GEMM);
        cudaFuncSetAttribute(k_level_mma,cudaFuncAttributeMaxDynamicSharedMemorySize, SM_GEMM);
        configured = 1;
    }

    k_detect<<<1, 256>>>((const unsigned int*)c1_mask);
    k_wsplit<<<(1024 * 288 + 1024 * 256 + 128 * 1000 + 64 * 64 + 255) / 256, 256>>>(
        W_ih, W_hh, W_bm, W_pred);

    k_op<<<(NN + 7) / 8, 256>>>(op_vec, W_op, b_op);

    {
        dim3 grid((MRPOOL + 127) / 128, 2);
        k_pool_mma<<<grid, 256, SM_POOL>>>(c1_preds, c1_mask, c1_and,
                                           c2_preds, c2_mask, c2_and, b_pred);
    }

    k_bm_mma<<<(NN + 127) / 128, 256, SM_GEMM>>>(bitmap, b_bm);

    {
        dim3 grid(8, (NN + 127) / 128);
        k_xg_mma<<<grid, 256, SM_GEMM>>>(b_ih, b_hh);
    }

    k_leaf<<<32768, 256>>>();

    for (int d = 14; d >= 0; d--) {
        int nd = 1 << d;
        int start = NN - (1 << (d + 1)) + 1;
        if (nd >= 128) {
            dim3 grid((nd + 127) / 128, 8);
            k_level_mma<<<grid, 256, SM_GEMM>>>(start, nd);
        } else {
            dim3 grid((nd + 31) / 32, 4);
            k_level<<<grid, 256>>>(start, nd, W_hh);
        }
    }

    k_heads<<<1, 256>>>(W_h2t1, b_h2t1, W_h3t1, b_h3t1, W_o1, b_o1,
                        W_h2t2, b_h2t2, W_h3t2, b_h3t2, W_o2, b_o2,
                        out);
}

// round 7
// speedup vs baseline: 6.7167x; 1.0376x over previous
#include <cuda_runtime.h>
#include <cuda_bf16.h>
#include <math.h>
#include <cstdint>
#include <stdint.h>

#define NN 65535          // number of tree nodes (2^16 - 1)
#define MRPOOL (NN * 8)   // pool GEMM rows
#define BIGF 1e30f
#define STR 72            // smem row stride in bf16 elems (144 B)

// ---------------- scratch (static device globals; no cudaMalloc) -------------
__device__ __nv_bfloat16 g_xh[(size_t)NN * 288];   // features hi
__device__ __nv_bfloat16 g_xl[(size_t)NN * 288];   // features lo
__device__ float g_xg[(size_t)NN * 1024];          // gates pre-activation
__device__ float g_H[(size_t)NN * 256];            // LSTM hidden
__device__ float g_C[(size_t)NN * 256];            // LSTM cell
__device__ int   g_mask_is_byte;

// pre-split weights (bf16 hi/lo)
__device__ __nv_bfloat16 g_Wih_h[1024 * 288], g_Wih_l[1024 * 288];
__device__ __nv_bfloat16 g_Whh_h[1024 * 256], g_Whh_l[1024 * 256];
__device__ __nv_bfloat16 g_Wbm_h[128 * 1000], g_Wbm_l[128 * 1000];
__device__ __nv_bfloat16 g_Wp_h[64 * 64],     g_Wp_l[64 * 64];

__device__ __forceinline__ float sigf(float x) { return 1.0f / (1.0f + expf(-x)); }

__device__ __forceinline__ int read_bool(const void* p, int idx) {
    return g_mask_is_byte ? (int)(((const unsigned char*)p)[idx])
                          : (((const int*)p)[idx] != 0);
}

__device__ __forceinline__ unsigned smem_u32(const void* p) {
    return (unsigned)__cvta_generic_to_shared(p);
}
__device__ __forceinline__ void cpa16(unsigned dst, const void* src, int nbytes) {
    asm volatile("cp.async.cg.shared.global [%0], [%1], 16, %2;\n"
                 :: "r"(dst), "l"(src), "r"(nbytes));
}
#define CPA_COMMIT() asm volatile("cp.async.commit_group;\n")
#define CPA_WAIT0()  asm volatile("cp.async.wait_group 0;\n")

// ---------------- bf16 split helpers -----------------------------------------
__device__ __forceinline__ void split2(float x, float y, uint32_t& h, uint32_t& l) {
    __nv_bfloat16 hx = __float2bfloat16(x), hy = __float2bfloat16(y);
    __nv_bfloat16 lx = __float2bfloat16(x - __bfloat162float(hx));
    __nv_bfloat16 ly = __float2bfloat16(y - __bfloat162float(hy));
    h = ((uint32_t)__bfloat16_as_ushort(hy) << 16) | __bfloat16_as_ushort(hx);
    l = ((uint32_t)__bfloat16_as_ushort(ly) << 16) | __bfloat16_as_ushort(lx);
}

// ---------------- mma.sync m16n8k16 bf16 + ldmatrix --------------------------
__device__ __forceinline__ void mma_bf16(float d[4], const uint32_t a[4], const uint32_t b[2]) {
    asm volatile(
        "mma.sync.aligned.m16n8k16.row.col.f32.bf16.bf16.f32 "
        "{%0,%1,%2,%3}, {%4,%5,%6,%7}, {%8,%9}, {%0,%1,%2,%3};\n"
        : "+f"(d[0]), "+f"(d[1]), "+f"(d[2]), "+f"(d[3])
        : "r"(a[0]), "r"(a[1]), "r"(a[2]), "r"(a[3]), "r"(b[0]), "r"(b[1]));
}

__device__ __forceinline__ void ldsm4(uint32_t r[4], const __nv_bfloat16* p) {
    uint32_t addr = smem_u32(p);
    asm volatile("ldmatrix.sync.aligned.m8n8.x4.shared.b16 {%0,%1,%2,%3}, [%4];"
                 : "=r"(r[0]), "=r"(r[1]), "=r"(r[2]), "=r"(r[3]) : "r"(addr));
}

// One K-chunk (32 fp32 = hi[0:32) + lo[32:64) bf16) for a 32x64 warp tile.
// 3 split passes: Ah*Bh, Ah*Bl, Al*Bh. All fragments via ldmatrix.
__device__ __forceinline__ void mma_chunk(const __nv_bfloat16* As, const __nv_bfloat16* Bs,
                                          int wm, int wn, int lane, float acc[2][8][4]) {
    int lrow = lane & 15, lcol = (lane >> 4) * 8;
#pragma unroll
    for (int pass = 0; pass < 3; pass++) {
        int ka = (pass == 2) ? 32 : 0;
        int kb = (pass == 1) ? 32 : 0;
#pragma unroll
        for (int ks = 0; ks < 2; ks++) {
            int kA = ka + ks * 16 + lcol;
            int kB = kb + ks * 16 + lcol;
            uint32_t af[2][4];
#pragma unroll
            for (int mt = 0; mt < 2; mt++)
                ldsm4(af[mt], As + (wm * 32 + mt * 16 + lrow) * STR + kA);
#pragma unroll
            for (int g = 0; g < 4; g++) {
                uint32_t bf[4];
                ldsm4(bf, Bs + (wn * 64 + g * 16 + lrow) * STR + kB);
                uint32_t b0[2] = { bf[0], bf[2] };
                uint32_t b1[2] = { bf[1], bf[3] };
#pragma unroll
                for (int mt = 0; mt < 2; mt++) {
                    mma_bf16(acc[mt][g * 2], af[mt], b0);
                    mma_bf16(acc[mt][g * 2 + 1], af[mt], b1);
                }
            }
        }
    }
}

// 32x32 warp-tile variant (pool)
__device__ __forceinline__ void mma_chunk32(const __nv_bfloat16* As, const __nv_bfloat16* Bs,
                                            int wm, int wn, int lane, float acc[2][4][4]) {
    int lrow = lane & 15, lcol = (lane >> 4) * 8;
#pragma unroll
    for (int pass = 0; pass < 3; pass++) {
        int ka = (pass == 2) ? 32 : 0;
        int kb = (pass == 1) ? 32 : 0;
#pragma unroll
        for (int ks = 0; ks < 2; ks++) {
            int kA = ka + ks * 16 + lcol;
            int kB = kb + ks * 16 + lcol;
            uint32_t af[2][4];
#pragma unroll
            for (int mt = 0; mt < 2; mt++)
                ldsm4(af[mt], As + (wm * 32 + mt * 16 + lrow) * STR + kA);
#pragma unroll
            for (int g = 0; g < 2; g++) {
                uint32_t bf[4];
                ldsm4(bf, Bs + (wn * 32 + g * 16 + lrow) * STR + kB);
                uint32_t b0[2] = { bf[0], bf[2] };
                uint32_t b1[2] = { bf[1], bf[3] };
#pragma unroll
                for (int mt = 0; mt < 2; mt++) {
                    mma_bf16(acc[mt][g * 2], af[mt], b0);
                    mma_bf16(acc[mt][g * 2 + 1], af[mt], b1);
                }
            }
        }
    }
}

// ---------------- loaders ----------------------------------------------------
template <int SLOTS>
__device__ __forceinline__ void ldg_f32(const float* __restrict__ src, int ld, int rowBase,
                                        int maxRow, int k0, int Ktot, int tid, float4 (*v)[2]) {
#pragma unroll
    for (int s = 0; s < SLOTS; s++) {
        int idx = tid + 256 * s;
        int r = idx >> 2, g = idx & 3;
        int row = rowBase + r, k = k0 + g * 8;
        float4 a = make_float4(0.f, 0.f, 0.f, 0.f), b = a;
        if (row < maxRow && k + 8 <= Ktot) {
            const float* p = src + (size_t)row * ld + k;
            a = *(const float4*)p;
            b = *(const float4*)(p + 4);
        }
        v[s][0] = a; v[s][1] = b;
    }
}

template <int SLOTS>
__device__ __forceinline__ void sts_split(__nv_bfloat16* As, int tid, float4 (*v)[2]) {
#pragma unroll
    for (int s = 0; s < SLOTS; s++) {
        int idx = tid + 256 * s;
        int r = idx >> 2, g = idx & 3;
        uint32_t h0, l0, h1, l1, h2, l2, h3, l3;
        split2(v[s][0].x, v[s][0].y, h0, l0);
        split2(v[s][0].z, v[s][0].w, h1, l1);
        split2(v[s][1].x, v[s][1].y, h2, l2);
        split2(v[s][1].z, v[s][1].w, h3, l3);
        __nv_bfloat16* p = As + r * STR + g * 8;
        *(uint4*)p        = make_uint4(h0, h1, h2, h3);
        *(uint4*)(p + 32) = make_uint4(l0, l1, l2, l3);
    }
}

template <int ROWS>
__device__ __forceinline__ void cpa_bf16(__nv_bfloat16* Bs,
        const __nv_bfloat16* __restrict__ sh, const __nv_bfloat16* __restrict__ sl,
        int ld, int rowBase, int maxRow, int k0, int Ktot, int tid) {
#pragma unroll
    for (int s = 0; s < ROWS / 32; s++) {
        int idx = tid + 256 * s;
        int r = idx >> 3, part = idx & 7;
        int row = rowBase + r;
        int k = k0 + (part & 3) * 8;
        int ok = (row < maxRow && k + 8 <= Ktot) ? 16 : 0;
        int rowc = (row < maxRow) ? row : (maxRow - 1);
        int kc = (k + 8 <= Ktot) ? k : 0;
        const __nv_bfloat16* src = ((part < 4) ? sh : sl) + (size_t)rowc * ld + kc;
        unsigned dst = smem_u32(Bs + r * STR + ((part < 4) ? 0 : 32) + (part & 3) * 8);
        cpa16(dst, src, ok);
    }
}

__device__ __forceinline__ void cpa_Whh(__nv_bfloat16* Bs, int jbase, int k0, int tid) {
#pragma unroll
    for (int s = 0; s < 4; s++) {
        int idx = tid + 256 * s;
        int r = idx >> 3, part = idx & 7;
        int wrow = (r >> 5) * 256 + jbase + (r & 31);
        int k = k0 + (part & 3) * 8;
        const __nv_bfloat16* src = ((part < 4) ? g_Whh_h : g_Whh_l) + (size_t)wrow * 256 + k;
        unsigned dst = smem_u32(Bs + r * STR + ((part < 4) ? 0 : 32) + (part & 3) * 8);
        cpa16(dst, src, 16);
    }
}

__device__ __forceinline__ void ldg_avgH(int start, int nd, int rowBase, int k0, int tid,
                                         float4 (*v)[2]) {
#pragma unroll
    for (int s = 0; s < 2; s++) {
        int idx = tid + 256 * s;
        int r = idx >> 2, g = idx & 3;
        int rr = rowBase + r;
        float4 a = make_float4(0.f, 0.f, 0.f, 0.f), b = a;
        if (rr < nd) {
            int node = start + rr;
            int ci = 2 * node - NN;
            const float* p0 = g_H + (size_t)ci * 256 + k0 + g * 8;
            const float* p1 = g_H + (size_t)(ci - 1) * 256 + k0 + g * 8;
            float4 x0 = *(const float4*)p0, x1 = *(const float4*)(p0 + 4);
            float4 y0 = *(const float4*)p1, y1 = *(const float4*)(p1 + 4);
            a = make_float4(0.5f * (x0.x + y0.x), 0.5f * (x0.y + y0.y),
                            0.5f * (x0.z + y0.z), 0.5f * (x0.w + y0.w));
            b = make_float4(0.5f * (x1.x + y1.x), 0.5f * (x1.y + y1.y),
                            0.5f * (x1.z + y1.z), 0.5f * (x1.w + y1.w));
        }
        v[s][0] = a; v[s][1] = b;
    }
}

// ---------------- small kernels ----------------------------------------------
__global__ void k_detect(const unsigned int* __restrict__ m) {
    __shared__ int found;
    if (threadIdx.x == 0) found = 0;
    __syncthreads();
    unsigned int v = m[threadIdx.x];
    if (v > 1u) found = 1;
    __syncthreads();
    if (threadIdx.x == 0) g_mask_is_byte = found;
}

__global__ void k_wsplit(const float* __restrict__ Wih, const float* __restrict__ Whh,
                         const float* __restrict__ Wbm, const float* __restrict__ Wp) {
    int i = blockIdx.x * 256 + threadIdx.x;
    const int S1 = 1024 * 288, S2 = 1024 * 256, S3 = 128 * 1000, S4 = 64 * 64;
    float w; __nv_bfloat16 h;
    if (i < S1) {
        w = Wih[i]; h = __float2bfloat16(w);
        g_Wih_h[i] = h; g_Wih_l[i] = __float2bfloat16(w - __bfloat162float(h));
    } else if (i < S1 + S2) {
        int j = i - S1; w = Whh[j]; h = __float2bfloat16(w);
        g_Whh_h[j] = h; g_Whh_l[j] = __float2bfloat16(w - __bfloat162float(h));
    } else if (i < S1 + S2 + S3) {
        int j = i - S1 - S2; w = Wbm[j]; h = __float2bfloat16(w);
        g_Wbm_h[j] = h; g_Wbm_l[j] = __float2bfloat16(w - __bfloat162float(h));
    } else if (i < S1 + S2 + S3 + S4) {
        int j = i - S1 - S2 - S3; w = Wp[j]; h = __float2bfloat16(w);
        g_Wp_h[j] = h; g_Wp_l[j] = __float2bfloat16(w - __bfloat162float(h));
    }
}

__global__ void k_op(const float* __restrict__ op_vec,
                     const float* __restrict__ W_op,
                     const float* __restrict__ b_op) {
    __shared__ float Ws[32][33];
    __shared__ float bs[32];
    int tid = threadIdx.x;
    if (tid < 32) bs[tid] = b_op[tid];
    for (int i = tid; i < 1024; i += 256) Ws[i >> 5][i & 31] = W_op[i];
    __syncthreads();
    int node = blockIdx.x * 8 + (tid >> 5);
    int o = tid & 31;
    if (node >= NN) return;
    float vl = op_vec[node * 32 + o];
    float acc = bs[o];
#pragma unroll
    for (int p = 0; p < 32; p++)
        acc += Ws[o][p] * __shfl_sync(0xffffffffu, vl, p);
    __nv_bfloat16 h = __float2bfloat16(acc);
    g_xh[(size_t)node * 288 + o] = h;
    g_xl[(size_t)node * 288 + o] = __float2bfloat16(acc - __bfloat162float(h));
}

// ============ mma GEMM 1: pool (128Mx64N block, warp 32x32, K=64) ============
__global__ __launch_bounds__(256, 2)
void k_pool_mma(const float* __restrict__ preds1, const void* mask1, const void* and1,
                const float* __restrict__ preds2, const void* mask2, const void* and2,
                const float* __restrict__ b_pred) {
    extern __shared__ __nv_bfloat16 sm[];
    __nv_bfloat16* As[2] = { sm, sm + 128 * STR };
    __nv_bfloat16* Bs[2] = { sm + 256 * STR, sm + 256 * STR + 64 * STR };
    float* stage = (float*)sm;   // reused after GEMM: [128][68]

    int tid = threadIdx.x, lane = tid & 31, warp = tid >> 5;
    int wm = warp >> 1, wn = warp & 1;
    int cond = blockIdx.y;
    const float* preds = cond ? preds2 : preds1;
    const void*  maskp = cond ? mask2 : mask1;
    const void*  andp  = cond ? and2  : and1;
    int rowBase = blockIdx.x * 128;

    float acc[2][4][4];
#pragma unroll
    for (int a = 0; a < 2; a++)
#pragma unroll
        for (int b = 0; b < 4; b++)
#pragma unroll
            for (int c = 0; c < 4; c++) acc[a][b][c] = 0.f;

    float4 va[2][2];
    cpa_bf16<64>(Bs[0], g_Wp_h, g_Wp_l, 64, 0, 64, 0, 64, tid);
    cpa_bf16<64>(Bs[1], g_Wp_h, g_Wp_l, 64, 0, 64, 32, 64, tid);
    CPA_COMMIT();
    ldg_f32<2>(preds, 64, rowBase, MRPOOL, 0, 64, tid, va);
    sts_split<2>(As[0], tid, va);
    CPA_WAIT0();
    __syncthreads();

    for (int t = 0; t < 2; t++) {
        bool more = (t == 0);
        if (more) ldg_f32<2>(preds, 64, rowBase, MRPOOL, 32, 64, tid, va);
        mma_chunk32(As[t], Bs[t], wm, wn, lane, acc);
        if (more) sts_split<2>(As[1], tid, va);
        __syncthreads();
    }

#pragma unroll
    for (int mt = 0; mt < 2; mt++) {
#pragma unroll
        for (int nt = 0; nt < 4; nt++) {
            int r = wm * 32 + mt * 16 + (lane >> 2);
            int c = wn * 32 + nt * 8 + (lane & 3) * 2;
            stage[r * 68 + c] = acc[mt][nt][0];
            stage[r * 68 + c + 1] = acc[mt][nt][1];
            stage[(r + 8) * 68 + c] = acc[mt][nt][2];
            stage[(r + 8) * 68 + c + 1] = acc[mt][nt][3];
        }
    }
    __syncthreads();

    int node = blockIdx.x * 16 + (tid >> 4);
    int cg = (tid & 15) * 4;
    if (node < NN) {
        float bb[4];
        *(float4*)bb = *(const float4*)(b_pred + cg);
        int mk[8], anyb = 0;
#pragma unroll
        for (int i = 0; i < 8; i++) { mk[i] = read_bool(maskp, node * 8 + i); anyb |= mk[i]; }
        int ia = read_bool(andp, node);
        int rb = (tid >> 4) * 8;
        float out[4];
#pragma unroll
        for (int j = 0; j < 4; j++) {
            float mn = BIGF, mx = -BIGF;
#pragma unroll
            for (int i = 0; i < 8; i++) {
                float v = stage[(rb + i) * 68 + cg + j] + bb[j];
                if (mk[i]) { mn = fminf(mn, v); mx = fmaxf(mx, v); }
            }
            out[j] = anyb ? (ia ? mn : mx) : 0.0f;
        }
        size_t base = (size_t)node * 288 + 32 + cond * 64 + cg;
        uint32_t h0, l0, h1, l1;
        split2(out[0], out[1], h0, l0);
        split2(out[2], out[3], h1, l1);
        *(uint32_t*)(g_xh + base) = h0;     *(uint32_t*)(g_xh + base + 2) = h1;
        *(uint32_t*)(g_xl + base) = l0;     *(uint32_t*)(g_xl + base + 2) = l1;
    }
}

// ============ mma GEMM 2: bm (128Mx128N block, K=1000) =======================
__global__ __launch_bounds__(256, 2)
void k_bm_mma(const float* __restrict__ bitmap, const float* __restrict__ b_bm) {
    extern __shared__ __nv_bfloat16 sm[];
    __nv_bfloat16* As[2] = { sm, sm + 128 * STR };
    __nv_bfloat16* Bs[2] = { sm + 256 * STR, sm + 384 * STR };
    int tid = threadIdx.x, lane = tid & 31, warp = tid >> 5;
    int wm = warp >> 1, wn = warp & 1;
    int rowBase = blockIdx.x * 128;

    float acc[2][8][4];
#pragma unroll
    for (int a = 0; a < 2; a++)
#pragma unroll
        for (int b = 0; b < 8; b++)
#pragma unroll
            for (int c = 0; c < 4; c++) acc[a][b][c] = 0.f;

    float4 va[2][2];
    cpa_bf16<128>(Bs[0], g_Wbm_h, g_Wbm_l, 1000, 0, 128, 0, 1000, tid);
    CPA_COMMIT();
    ldg_f32<2>(bitmap, 1000, rowBase, NN, 0, 1000, tid, va);
    sts_split<2>(As[0], tid, va);
    CPA_WAIT0();
    __syncthreads();

    const int NC = 32;
    for (int t = 0; t < NC; t++) {
        bool more = (t + 1 < NC);
        if (more) {
            cpa_bf16<128>(Bs[(t + 1) & 1], g_Wbm_h, g_Wbm_l, 1000, 0, 128, (t + 1) * 32, 1000, tid);
            CPA_COMMIT();
            ldg_f32<2>(bitmap, 1000, rowBase, NN, (t + 1) * 32, 1000, tid, va);
        }
        mma_chunk(As[t & 1], Bs[t & 1], wm, wn, lane, acc);
        if (more) {
            sts_split<2>(As[(t + 1) & 1], tid, va);
            CPA_WAIT0();
        }
        __syncthreads();
    }

#pragma unroll
    for (int nt = 0; nt < 8; nt++) {
        int c = wn * 64 + nt * 8 + (lane & 3) * 2;
        float bx = b_bm[c], by = b_bm[c + 1];
#pragma unroll
        for (int mt = 0; mt < 2; mt++) {
            int r0 = rowBase + wm * 32 + mt * 16 + (lane >> 2);
            if (r0 < NN) {
                uint32_t h, l;
                split2(acc[mt][nt][0] + bx, acc[mt][nt][1] + by, h, l);
                *(uint32_t*)(g_xh + (size_t)r0 * 288 + 160 + c) = h;
                *(uint32_t*)(g_xl + (size_t)r0 * 288 + 160 + c) = l;
            }
            if (r0 + 8 < NN) {
                uint32_t h, l;
                split2(acc[mt][nt][2] + bx, acc[mt][nt][3] + by, h, l);
                *(uint32_t*)(g_xh + (size_t)(r0 + 8) * 288 + 160 + c) = h;
                *(uint32_t*)(g_xl + (size_t)(r0 + 8) * 288 + 160 + c) = l;
            }
        }
    }
}

// ============ mma GEMM 3: xg (128Mx128N block, K=288, all cp.async) ==========
__global__ __launch_bounds__(256, 2)
void k_xg_mma(const float* __restrict__ b_ih, const float* __restrict__ b_hh) {
    extern __shared__ __nv_bfloat16 sm[];
    __nv_bfloat16* As[2] = { sm, sm + 128 * STR };
    __nv_bfloat16* Bs[2] = { sm + 256 * STR, sm + 384 * STR };
    int tid = threadIdx.x, lane = tid & 31, warp = tid >> 5;
    int wm = warp >> 1, wn = warp & 1;
    int colBase = blockIdx.x * 128;
    int rowBase = blockIdx.y * 128;

    float acc[2][8][4];
#pragma unroll
    for (int a = 0; a < 2; a++)
#pragma unroll
        for (int b = 0; b < 8; b++)
#pragma unroll
            for (int c = 0; c < 4; c++) acc[a][b][c] = 0.f;

    cpa_bf16<128>(As[0], g_xh, g_xl, 288, rowBase, NN, 0, 288, tid);
    cpa_bf16<128>(Bs[0], g_Wih_h, g_Wih_l, 288, colBase, 1024, 0, 288, tid);
    CPA_COMMIT();
    CPA_WAIT0();
    __syncthreads();

    const int NC = 9;
    for (int t = 0; t < NC; t++) {
        bool more = (t + 1 < NC);
        if (more) {
            cpa_bf16<128>(As[(t + 1) & 1], g_xh, g_xl, 288, rowBase, NN, (t + 1) * 32, 288, tid);
            cpa_bf16<128>(Bs[(t + 1) & 1], g_Wih_h, g_Wih_l, 288, colBase, 1024, (t + 1) * 32, 288, tid);
            CPA_COMMIT();
        }
        mma_chunk(As[t & 1], Bs[t & 1], wm, wn, lane, acc);
        if (more) CPA_WAIT0();
        __syncthreads();
    }

#pragma unroll
    for (int nt = 0; nt < 8; nt++) {
        int c = colBase + wn * 64 + nt * 8 + (lane & 3) * 2;
        float bx = b_ih[c] + b_hh[c], by = b_ih[c + 1] + b_hh[c + 1];
#pragma unroll
        for (int mt = 0; mt < 2; mt++) {
            int r0 = rowBase + wm * 32 + mt * 16 + (lane >> 2);
            if (r0 < NN)
                *(float2*)(g_xg + (size_t)r0 * 1024 + c) =
                    make_float2(acc[mt][nt][0] + bx, acc[mt][nt][1] + by);
            if (r0 + 8 < NN)
                *(float2*)(g_xg + (size_t)(r0 + 8) * 1024 + c) =
                    make_float2(acc[mt][nt][2] + bx, acc[mt][nt][3] + by);
        }
    }
}

// ============ mma level kernel (nd >= 128): fused GEMM + LSTM pointwise ======
__global__ __launch_bounds__(256, 2)
void k_level_mma(int start, int nd) {
    extern __shared__ __nv_bfloat16 sm[];
    __nv_bfloat16* As[2] = { sm, sm + 128 * STR };
    __nv_bfloat16* Bs[2] = { sm + 256 * STR, sm + 384 * STR };
    float* stage = (float*)sm;   // [128][132] after GEMM

    int tid = threadIdx.x, lane = tid & 31, warp = tid >> 5;
    int wm = warp >> 1, wn = warp & 1;
    int rowBase = blockIdx.x * 128;
    int jbase = blockIdx.y * 32;

    float acc[2][8][4];
#pragma unroll
    for (int a = 0; a < 2; a++)
#pragma unroll
        for (int b = 0; b < 8; b++)
#pragma unroll
            for (int c = 0; c < 4; c++) acc[a][b][c] = 0.f;

    float4 va[2][2];
    cpa_Whh(Bs[0], jbase, 0, tid);
    CPA_COMMIT();
    ldg_avgH(start, nd, rowBase, 0, tid, va);
    sts_split<2>(As[0], tid, va);
    CPA_WAIT0();
    __syncthreads();

    const int NC = 8;
    for (int t = 0; t < NC; t++) {
        bool more = (t + 1 < NC);
        if (more) {
            cpa_Whh(Bs[(t + 1) & 1], jbase, (t + 1) * 32, tid);
            CPA_COMMIT();
            ldg_avgH(start, nd, rowBase, (t + 1) * 32, tid, va);
        }
        mma_chunk(As[t & 1], Bs[t & 1], wm, wn, lane, acc);
        if (more) {
            sts_split<2>(As[(t + 1) & 1], tid, va);
            CPA_WAIT0();
        }
        __syncthreads();
    }

#pragma unroll
    for (int mt = 0; mt < 2; mt++) {
#pragma unroll
        for (int nt = 0; nt < 8; nt++) {
            int r = wm * 32 + mt * 16 + (lane >> 2);
            int c = wn * 64 + nt * 8 + (lane & 3) * 2;
            stage[r * 132 + c] = acc[mt][nt][0];
            stage[r * 132 + c + 1] = acc[mt][nt][1];
            stage[(r + 8) * 132 + c] = acc[mt][nt][2];
            stage[(r + 8) * 132 + c + 1] = acc[mt][nt][3];
        }
    }
    __syncthreads();

#pragma unroll
    for (int i = 0; i < 16; i++) {
        int idx = tid + 256 * i;
        int r = idx >> 5, jj = idx & 31;
        int rr = rowBase + r;
        if (rr < nd) {
            int node = start + rr;
            int j = jbase + jj;
            const float* xr = g_xg + (size_t)node * 1024;
            float gi = stage[r * 132 + jj]       + xr[j];
            float gf = stage[r * 132 + 32 + jj]  + xr[256 + j];
            float gg = stage[r * 132 + 64 + jj]  + xr[512 + j];
            float go = stage[r * 132 + 96 + jj]  + xr[768 + j];
            int ci = 2 * node - NN;
            float c0 = 0.5f * (g_C[(size_t)ci * 256 + j] + g_C[(size_t)(ci - 1) * 256 + j]);
            float cn = sigf(gf) * c0 + sigf(gi) * tanhf(gg);
            float hn = sigf(go) * tanhf(cn);
            g_H[(size_t)node * 256 + j] = hn;
            g_C[(size_t)node * 256 + j] = cn;
        }
    }
}

// ---------------- leaves (d = D): c0 = 0 -------------------------------------
__global__ void k_leaf() {
    int n = blockIdx.x;
    int j = threadIdx.x;
    const float* xr = g_xg + (size_t)n * 1024;
    float gi = xr[j];
    float gg = xr[512 + j];
    float go = xr[768 + j];
    float c = sigf(gi) * tanhf(gg);
    float h = sigf(go) * tanhf(c);
    g_H[(size_t)n * 256 + j] = h;
    g_C[(size_t)n * 256 + j] = c;
}

// ---------------- SIMT level kernel for small levels -------------------------
__global__ __launch_bounds__(256)
void k_level(int start, int nd, const float* __restrict__ W_hh) {
    __shared__ float h0s[32][36];
    __shared__ float Ws[256][36];
    int tid = threadIdx.x;
    int jx = tid & 63, ry = tid >> 6;
    int rowBase = blockIdx.x * 32;
    int jbase = blockIdx.y * 64;

    float acc[8][4];
#pragma unroll
    for (int i = 0; i < 8; i++)
#pragma unroll
        for (int g = 0; g < 4; g++) acc[i][g] = 0.0f;

    for (int k0 = 0; k0 < 256; k0 += 32) {
        {
            int r = tid >> 3, c4 = tid & 7;
            float4 v = make_float4(0.f, 0.f, 0.f, 0.f);
            int rr = rowBase + r;
            if (rr < nd) {
                int node = start + rr;
                int ci = 2 * node - NN;
                float4 a = *(const float4*)&g_H[(size_t)ci * 256 + k0 + c4 * 4];
                float4 b = *(const float4*)&g_H[(size_t)(ci - 1) * 256 + k0 + c4 * 4];
                v = make_float4(0.5f * (a.x + b.x), 0.5f * (a.y + b.y),
                                0.5f * (a.z + b.z), 0.5f * (a.w + b.w));
            }
            *(float4*)&h0s[r][c4 * 4] = v;
        }
        {
            int wrow = ry * 256 + jbase + jx;
            const float* src = &W_hh[(size_t)wrow * 256 + k0];
#pragma unroll
            for (int c = 0; c < 8; c++)
                *(float4*)&Ws[tid][c * 4] = *(const float4*)&src[c * 4];
        }
        __syncthreads();
#pragma unroll
        for (int kk4 = 0; kk4 < 8; kk4++) {
            float4 w4[4];
#pragma unroll
            for (int g = 0; g < 4; g++)
                w4[g] = *(const float4*)&Ws[g * 64 + jx][kk4 * 4];
#pragma unroll
            for (int i = 0; i < 8; i++) {
                float4 a4 = *(const float4*)&h0s[ry * 8 + i][kk4 * 4];
#pragma unroll
                for (int g = 0; g < 4; g++)
                    acc[i][g] += a4.x * w4[g].x + a4.y * w4[g].y +
                                 a4.z * w4[g].z + a4.w * w4[g].w;
            }
        }
        __syncthreads();
    }

    int j = jbase + jx;
#pragma unroll
    for (int i = 0; i < 8; i++) {
        int rr = rowBase + ry * 8 + i;
        if (rr < nd) {
            int node = start + rr;
            const float* xr = g_xg + (size_t)node * 1024;
            float gi = acc[i][0] + xr[j];
            float gf = acc[i][1] + xr[256 + j];
            float gg = acc[i][2] + xr[512 + j];
            float go = acc[i][3] + xr[768 + j];
            int ci = 2 * node - NN;
            float c0 = 0.5f * (g_C[(size_t)ci * 256 + j] + g_C[(size_t)(ci - 1) * 256 + j]);
            float cn = sigf(gf) * c0 + sigf(gi) * tanhf(gg);
            float hn = sigf(go) * tanhf(cn);
            g_H[(size_t)node * 256 + j] = hn;
            g_C[(size_t)node * 256 + j] = cn;
        }
    }
}

// ---------------- output heads ----------------------------------------------
__global__ void k_heads(const float* __restrict__ W2a, const float* __restrict__ b2a,
                        const float* __restrict__ W3a, const float* __restrict__ b3a,
                        const float* __restrict__ Woa, const float* __restrict__ boa,
                        const float* __restrict__ W2b, const float* __restrict__ b2b,
                        const float* __restrict__ W3b, const float* __restrict__ b3b,
                        const float* __restrict__ Wob, const float* __restrict__ bob,
                        float* __restrict__ out) {
    __shared__ float hv[256];
    __shared__ float t1[2][128];
    __shared__ float t2[2][128];
    __shared__ float red[256];
    int tid = threadIdx.x;
    hv[tid] = g_H[(size_t)(NN - 1) * 256 + tid];
    __syncthreads();
    int head = tid >> 7, j = tid & 127;
    const float* W2 = head ? W2b : W2a; const float* b2 = head ? b2b : b2a;
    const float* W3 = head ? W3b : W3a; const float* b3 = head ? b3b : b3a;
    const float* Wo = head ? Wob : Woa; const float* bo = head ? bob : boa;

    float t = b2[j];
    for (int k = 0; k < 256; k++) t += W2[j * 256 + k] * hv[k];
    t1[head][j] = fmaxf(t, 0.0f);
    __syncthreads();
    t = b3[j];
    for (int k = 0; k < 128; k++) t += W3[j * 128 + k] * t1[head][k];
    t2[head][j] = fmaxf(t, 0.0f);
    __syncthreads();
    red[tid] = Wo[j] * t2[head][j];
    __syncthreads();
    for (int s = 64; s > 0; s >>= 1) {
        if (j < s) red[tid] += red[tid + s];
        __syncthreads();
    }
    if (j == 0) out[head] = 1.0f / (1.0f + expf(-(red[tid] + bo[0])));
}

// ---------------- launch ------------------------------------------------------
extern "C" void kernel_launch(void* const* d_in, const int* in_sizes, int n_in,
                              void* d_out, int out_size) {
    const float* op_vec   = (const float*)d_in[0];
    const float* c1_preds = (const float*)d_in[1];
    const void*  c1_mask  = d_in[2];
    const void*  c1_and   = d_in[3];
    const float* c2_preds = (const float*)d_in[4];
    const void*  c2_mask  = d_in[5];
    const void*  c2_and   = d_in[6];
    const float* bitmap   = (const float*)d_in[7];
    const float* W_op     = (const float*)d_in[8];
    const float* b_op     = (const float*)d_in[9];
    const float* W_pred   = (const float*)d_in[10];
    const float* b_pred   = (const float*)d_in[11];
    const float* W_bm     = (const float*)d_in[12];
    const float* b_bm     = (const float*)d_in[13];
    const float* W_ih     = (const float*)d_in[14];
    const float* b_ih     = (const float*)d_in[15];
    const float* W_hh     = (const float*)d_in[16];
    const float* b_hh     = (const float*)d_in[17];
    const float* W_h2t1   = (const float*)d_in[18];
    const float* b_h2t1   = (const float*)d_in[19];
    const float* W_h3t1   = (const float*)d_in[20];
    const float* b_h3t1   = (const float*)d_in[21];
    const float* W_o1     = (const float*)d_in[22];
    const float* b_o1     = (const float*)d_in[23];
    const float* W_h2t2   = (const float*)d_in[24];
    const float* b_h2t2   = (const float*)d_in[25];
    const float* W_h3t2   = (const float*)d_in[26];
    const float* b_h3t2   = (const float*)d_in[27];
    const float* W_o2     = (const float*)d_in[28];
    const float* b_o2     = (const float*)d_in[29];
    float* out = (float*)d_out;

    const int SM_GEMM = 4 * 128 * STR * 2;                       // 73728
    const int SM_POOL = (2 * 128 + 2 * 64) * STR * 2;            // 55296
    static int configured = 0;
    if (!configured) {
        cudaFuncSetAttribute(k_pool_mma, cudaFuncAttributeMaxDynamicSharedMemorySize, SM_POOL);
        cudaFuncSetAttribute(k_bm_mma,   cudaFuncAttributeMaxDynamicSharedMemorySize, SM_GEMM);
        cudaFuncSetAttribute(k_xg_mma,   cudaFuncAttributeMaxDynamicSharedMemorySize, SM_GEMM);
        cudaFuncSetAttribute(k_level_mma,cudaFuncAttributeMaxDynamicSharedMemorySize, SM_GEMM);
        configured = 1;
    }

    k_detect<<<1, 256>>>((const unsigned int*)c1_mask);
    k_wsplit<<<(1024 * 288 + 1024 * 256 + 128 * 1000 + 64 * 64 + 255) / 256, 256>>>(
        W_ih, W_hh, W_bm, W_pred);

    k_op<<<(NN + 7) / 8, 256>>>(op_vec, W_op, b_op);

    {
        dim3 grid((MRPOOL + 127) / 128, 2);
        k_pool_mma<<<grid, 256, SM_POOL>>>(c1_preds, c1_mask, c1_and,
                                           c2_preds, c2_mask, c2_and, b_pred);
    }

    k_bm_mma<<<(NN + 127) / 128, 256, SM_GEMM>>>(bitmap, b_bm);

    {
        dim3 grid(8, (NN + 127) / 128);
        k_xg_mma<<<grid, 256, SM_GEMM>>>(b_ih, b_hh);
    }

    k_leaf<<<32768, 256>>>();

    for (int d = 14; d >= 0; d--) {
        int nd = 1 << d;
        int start = NN - (1 << (d + 1)) + 1;
        if (nd >= 128) {
            dim3 grid((nd + 127) / 128, 8);
            k_level_mma<<<grid, 256, SM_GEMM>>>(start, nd);
        } else {
            dim3 grid((nd + 31) / 32, 4);
            k_level<<<grid, 256>>>(start, nd, W_hh);
        }
    }

    k_heads<<<1, 256>>>(W_h2t1, b_h2t1, W_h3t1, b_h3t1, W_o1, b_o1,
                        W_h2t2, b_h2t2, W_h3t2, b_h3t2, W_o2, b_o2,
                        out);
}

// round 8
// speedup vs baseline: 7.4117x; 1.1035x over previous
#include <cuda_runtime.h>
#include <cuda_bf16.h>
#include <math.h>
#include <cstdint>
#include <stdint.h>

#define NN 65535          // number of tree nodes (2^16 - 1)
#define MRPOOL (NN * 8)   // pool GEMM rows
#define BIGF 1e30f
#define STR 72            // smem row stride in bf16 elems (144 B)

// ---------------- scratch (static device globals; no cudaMalloc) -------------
__device__ __nv_bfloat16 g_xh[(size_t)NN * 288];   // features hi
__device__ __nv_bfloat16 g_xl[(size_t)NN * 288];   // features lo
__device__ float g_xg[(size_t)NN * 1024];          // gates pre-activation
__device__ float g_H[(size_t)NN * 256];            // LSTM hidden
__device__ float g_C[(size_t)NN * 256];            // LSTM cell
__device__ int   g_mask_is_byte;

// pre-split weights (bf16 hi/lo)
__device__ __nv_bfloat16 g_Wih_h[1024 * 288], g_Wih_l[1024 * 288];
__device__ __nv_bfloat16 g_Whh_h[1024 * 256], g_Whh_l[1024 * 256];
__device__ __nv_bfloat16 g_Wbm_h[128 * 1000], g_Wbm_l[128 * 1000];
__device__ __nv_bfloat16 g_Wp_h[64 * 64],     g_Wp_l[64 * 64];

__device__ __forceinline__ float sigf(float x) { return 1.0f / (1.0f + expf(-x)); }

__device__ __forceinline__ int read_bool(const void* p, int idx) {
    return g_mask_is_byte ? (int)(((const unsigned char*)p)[idx])
                          : (((const int*)p)[idx] != 0);
}

__device__ __forceinline__ unsigned smem_u32(const void* p) {
    return (unsigned)__cvta_generic_to_shared(p);
}
__device__ __forceinline__ void cpa16(unsigned dst, const void* src, int nbytes) {
    asm volatile("cp.async.cg.shared.global [%0], [%1], 16, %2;\n"
                 :: "r"(dst), "l"(src), "r"(nbytes));
}
#define CPA_COMMIT() asm volatile("cp.async.commit_group;\n")
#define CPA_WAIT0()  asm volatile("cp.async.wait_group 0;\n")

// ---------------- bf16 split helpers -----------------------------------------
__device__ __forceinline__ void split2(float x, float y, uint32_t& h, uint32_t& l) {
    __nv_bfloat16 hx = __float2bfloat16(x), hy = __float2bfloat16(y);
    __nv_bfloat16 lx = __float2bfloat16(x - __bfloat162float(hx));
    __nv_bfloat16 ly = __float2bfloat16(y - __bfloat162float(hy));
    h = ((uint32_t)__bfloat16_as_ushort(hy) << 16) | __bfloat16_as_ushort(hx);
    l = ((uint32_t)__bfloat16_as_ushort(ly) << 16) | __bfloat16_as_ushort(lx);
}

// ---------------- mma.sync m16n8k16 bf16 + ldmatrix --------------------------
__device__ __forceinline__ void mma_bf16(float d[4], const uint32_t a[4], const uint32_t b[2]) {
    asm volatile(
        "mma.sync.aligned.m16n8k16.row.col.f32.bf16.bf16.f32 "
        "{%0,%1,%2,%3}, {%4,%5,%6,%7}, {%8,%9}, {%0,%1,%2,%3};\n"
        : "+f"(d[0]), "+f"(d[1]), "+f"(d[2]), "+f"(d[3])
        : "r"(a[0]), "r"(a[1]), "r"(a[2]), "r"(a[3]), "r"(b[0]), "r"(b[1]));
}

__device__ __forceinline__ void ldsm4(uint32_t r[4], const __nv_bfloat16* p) {
    uint32_t addr = smem_u32(p);
    asm volatile("ldmatrix.sync.aligned.m8n8.x4.shared.b16 {%0,%1,%2,%3}, [%4];"
                 : "=r"(r[0]), "=r"(r[1]), "=r"(r[2]), "=r"(r[3]) : "r"(addr));
}

// One K-chunk (32 fp32 = hi[0:32) + lo[32:64) bf16) for a 32x64 warp tile.
// Fragment-reuse ordering: load Ah, Al, Bh, Bl each once per k-step;
// accumulate AhBh + AhBl + AlBh.
__device__ __forceinline__ void mma_chunk(const __nv_bfloat16* As, const __nv_bfloat16* Bs,
                                          int wm, int wn, int lane, float acc[2][8][4]) {
    int lrow = lane & 15, lcol = (lane >> 4) * 8;
#pragma unroll
    for (int ks = 0; ks < 2; ks++) {
        int kh = ks * 16 + lcol;
        int kl = 32 + ks * 16 + lcol;
        uint32_t ah[2][4], al[2][4];
#pragma unroll
        for (int mt = 0; mt < 2; mt++) {
            ldsm4(ah[mt], As + (wm * 32 + mt * 16 + lrow) * STR + kh);
            ldsm4(al[mt], As + (wm * 32 + mt * 16 + lrow) * STR + kl);
        }
#pragma unroll
        for (int g = 0; g < 4; g++) {
            uint32_t bh[4], bl[4];
            ldsm4(bh, Bs + (wn * 64 + g * 16 + lrow) * STR + kh);
            ldsm4(bl, Bs + (wn * 64 + g * 16 + lrow) * STR + kl);
            uint32_t bh0[2] = { bh[0], bh[2] }, bh1[2] = { bh[1], bh[3] };
            uint32_t bl0[2] = { bl[0], bl[2] }, bl1[2] = { bl[1], bl[3] };
#pragma unroll
            for (int mt = 0; mt < 2; mt++) {
                mma_bf16(acc[mt][g * 2],     ah[mt], bh0);
                mma_bf16(acc[mt][g * 2 + 1], ah[mt], bh1);
                mma_bf16(acc[mt][g * 2],     ah[mt], bl0);
                mma_bf16(acc[mt][g * 2 + 1], ah[mt], bl1);
                mma_bf16(acc[mt][g * 2],     al[mt], bh0);
                mma_bf16(acc[mt][g * 2 + 1], al[mt], bh1);
            }
        }
    }
}

// 32x32 warp-tile variant (pool), same fragment-reuse ordering
__device__ __forceinline__ void mma_chunk32(const __nv_bfloat16* As, const __nv_bfloat16* Bs,
                                            int wm, int wn, int lane, float acc[2][4][4]) {
    int lrow = lane & 15, lcol = (lane >> 4) * 8;
#pragma unroll
    for (int ks = 0; ks < 2; ks++) {
        int kh = ks * 16 + lcol;
        int kl = 32 + ks * 16 + lcol;
        uint32_t ah[2][4], al[2][4];
#pragma unroll
        for (int mt = 0; mt < 2; mt++) {
            ldsm4(ah[mt], As + (wm * 32 + mt * 16 + lrow) * STR + kh);
            ldsm4(al[mt], As + (wm * 32 + mt * 16 + lrow) * STR + kl);
        }
#pragma unroll
        for (int g = 0; g < 2; g++) {
            uint32_t bh[4], bl[4];
            ldsm4(bh, Bs + (wn * 32 + g * 16 + lrow) * STR + kh);
            ldsm4(bl, Bs + (wn * 32 + g * 16 + lrow) * STR + kl);
            uint32_t bh0[2] = { bh[0], bh[2] }, bh1[2] = { bh[1], bh[3] };
            uint32_t bl0[2] = { bl[0], bl[2] }, bl1[2] = { bl[1], bl[3] };
#pragma unroll
            for (int mt = 0; mt < 2; mt++) {
                mma_bf16(acc[mt][g * 2],     ah[mt], bh0);
                mma_bf16(acc[mt][g * 2 + 1], ah[mt], bh1);
                mma_bf16(acc[mt][g * 2],     ah[mt], bl0);
                mma_bf16(acc[mt][g * 2 + 1], ah[mt], bl1);
                mma_bf16(acc[mt][g * 2],     al[mt], bh0);
                mma_bf16(acc[mt][g * 2 + 1], al[mt], bh1);
            }
        }
    }
}

// ---------------- loaders ----------------------------------------------------
template <int SLOTS>
__device__ __forceinline__ void ldg_f32(const float* __restrict__ src, int ld, int rowBase,
                                        int maxRow, int k0, int Ktot, int tid, float4 (*v)[2]) {
#pragma unroll
    for (int s = 0; s < SLOTS; s++) {
        int idx = tid + 256 * s;
        int r = idx >> 2, g = idx & 3;
        int row = rowBase + r, k = k0 + g * 8;
        float4 a = make_float4(0.f, 0.f, 0.f, 0.f), b = a;
        if (row < maxRow && k + 8 <= Ktot) {
            const float* p = src + (size_t)row * ld + k;
            a = *(const float4*)p;
            b = *(const float4*)(p + 4);
        }
        v[s][0] = a; v[s][1] = b;
    }
}

template <int SLOTS>
__device__ __forceinline__ void sts_split(__nv_bfloat16* As, int tid, float4 (*v)[2]) {
#pragma unroll
    for (int s = 0; s < SLOTS; s++) {
        int idx = tid + 256 * s;
        int r = idx >> 2, g = idx & 3;
        uint32_t h0, l0, h1, l1, h2, l2, h3, l3;
        split2(v[s][0].x, v[s][0].y, h0, l0);
        split2(v[s][0].z, v[s][0].w, h1, l1);
        split2(v[s][1].x, v[s][1].y, h2, l2);
        split2(v[s][1].z, v[s][1].w, h3, l3);
        __nv_bfloat16* p = As + r * STR + g * 8;
        *(uint4*)p        = make_uint4(h0, h1, h2, h3);
        *(uint4*)(p + 32) = make_uint4(l0, l1, l2, l3);
    }
}

template <int ROWS>
__device__ __forceinline__ void cpa_bf16(__nv_bfloat16* Bs,
        const __nv_bfloat16* __restrict__ sh, const __nv_bfloat16* __restrict__ sl,
        int ld, int rowBase, int maxRow, int k0, int Ktot, int tid) {
#pragma unroll
    for (int s = 0; s < ROWS / 32; s++) {
        int idx = tid + 256 * s;
        int r = idx >> 3, part = idx & 7;
        int row = rowBase + r;
        int k = k0 + (part & 3) * 8;
        int ok = (row < maxRow && k + 8 <= Ktot) ? 16 : 0;
        int rowc = (row < maxRow) ? row : (maxRow - 1);
        int kc = (k + 8 <= Ktot) ? k : 0;
        const __nv_bfloat16* src = ((part < 4) ? sh : sl) + (size_t)rowc * ld + kc;
        unsigned dst = smem_u32(Bs + r * STR + ((part < 4) ? 0 : 32) + (part & 3) * 8);
        cpa16(dst, src, ok);
    }
}

__device__ __forceinline__ void cpa_Whh(__nv_bfloat16* Bs, int jbase, int k0, int tid) {
#pragma unroll
    for (int s = 0; s < 4; s++) {
        int idx = tid + 256 * s;
        int r = idx >> 3, part = idx & 7;
        int wrow = (r >> 5) * 256 + jbase + (r & 31);
        int k = k0 + (part & 3) * 8;
        const __nv_bfloat16* src = ((part < 4) ? g_Whh_h : g_Whh_l) + (size_t)wrow * 256 + k;
        unsigned dst = smem_u32(Bs + r * STR + ((part < 4) ? 0 : 32) + (part & 3) * 8);
        cpa16(dst, src, 16);
    }
}

__device__ __forceinline__ void ldg_avgH(int start, int nd, int rowBase, int k0, int tid,
                                         float4 (*v)[2]) {
#pragma unroll
    for (int s = 0; s < 2; s++) {
        int idx = tid + 256 * s;
        int r = idx >> 2, g = idx & 3;
        int rr = rowBase + r;
        float4 a = make_float4(0.f, 0.f, 0.f, 0.f), b = a;
        if (rr < nd) {
            int node = start + rr;
            int ci = 2 * node - NN;
            const float* p0 = g_H + (size_t)ci * 256 + k0 + g * 8;
            const float* p1 = g_H + (size_t)(ci - 1) * 256 + k0 + g * 8;
            float4 x0 = *(const float4*)p0, x1 = *(const float4*)(p0 + 4);
            float4 y0 = *(const float4*)p1, y1 = *(const float4*)(p1 + 4);
            a = make_float4(0.5f * (x0.x + y0.x), 0.5f * (x0.y + y0.y),
                            0.5f * (x0.z + y0.z), 0.5f * (x0.w + y0.w));
            b = make_float4(0.5f * (x1.x + y1.x), 0.5f * (x1.y + y1.y),
                            0.5f * (x1.z + y1.z), 0.5f * (x1.w + y1.w));
        }
        v[s][0] = a; v[s][1] = b;
    }
}

// ---------------- small kernels ----------------------------------------------
__global__ void k_detect(const unsigned int* __restrict__ m) {
    __shared__ int found;
    if (threadIdx.x == 0) found = 0;
    __syncthreads();
    unsigned int v = m[threadIdx.x];
    if (v > 1u) found = 1;
    __syncthreads();
    if (threadIdx.x == 0) g_mask_is_byte = found;
}

__global__ void k_wsplit(const float* __restrict__ Wih, const float* __restrict__ Whh,
                         const float* __restrict__ Wbm, const float* __restrict__ Wp) {
    int i = blockIdx.x * 256 + threadIdx.x;
    const int S1 = 1024 * 288, S2 = 1024 * 256, S3 = 128 * 1000, S4 = 64 * 64;
    float w; __nv_bfloat16 h;
    if (i < S1) {
        w = Wih[i]; h = __float2bfloat16(w);
        g_Wih_h[i] = h; g_Wih_l[i] = __float2bfloat16(w - __bfloat162float(h));
    } else if (i < S1 + S2) {
        int j = i - S1; w = Whh[j]; h = __float2bfloat16(w);
        g_Whh_h[j] = h; g_Whh_l[j] = __float2bfloat16(w - __bfloat162float(h));
    } else if (i < S1 + S2 + S3) {
        int j = i - S1 - S2; w = Wbm[j]; h = __float2bfloat16(w);
        g_Wbm_h[j] = h; g_Wbm_l[j] = __float2bfloat16(w - __bfloat162float(h));
    } else if (i < S1 + S2 + S3 + S4) {
        int j = i - S1 - S2 - S3; w = Wp[j]; h = __float2bfloat16(w);
        g_Wp_h[j] = h; g_Wp_l[j] = __float2bfloat16(w - __bfloat162float(h));
    }
}

__global__ void k_op(const float* __restrict__ op_vec,
                     const float* __restrict__ W_op,
                     const float* __restrict__ b_op) {
    __shared__ float Ws[32][33];
    __shared__ float bs[32];
    int tid = threadIdx.x;
    if (tid < 32) bs[tid] = b_op[tid];
    for (int i = tid; i < 1024; i += 256) Ws[i >> 5][i & 31] = W_op[i];
    __syncthreads();
    int node = blockIdx.x * 8 + (tid >> 5);
    int o = tid & 31;
    if (node >= NN) return;
    float vl = op_vec[node * 32 + o];
    float acc = bs[o];
#pragma unroll
    for (int p = 0; p < 32; p++)
        acc += Ws[o][p] * __shfl_sync(0xffffffffu, vl, p);
    __nv_bfloat16 h = __float2bfloat16(acc);
    g_xh[(size_t)node * 288 + o] = h;
    g_xl[(size_t)node * 288 + o] = __float2bfloat16(acc - __bfloat162float(h));
}

// ============ mma GEMM 1: pool (128Mx64N block, warp 32x32, K=64) ============
__global__ __launch_bounds__(256, 3)
void k_pool_mma(const float* __restrict__ preds1, const void* mask1, const void* and1,
                const float* __restrict__ preds2, const void* mask2, const void* and2,
                const float* __restrict__ b_pred) {
    extern __shared__ __nv_bfloat16 sm[];
    __nv_bfloat16* As[2] = { sm, sm + 128 * STR };
    __nv_bfloat16* Bs[2] = { sm + 256 * STR, sm + 256 * STR + 64 * STR };
    float* stage = (float*)sm;   // reused after GEMM: [128][68]

    int tid = threadIdx.x, lane = tid & 31, warp = tid >> 5;
    int wm = warp >> 1, wn = warp & 1;
    int cond = blockIdx.y;
    const float* preds = cond ? preds2 : preds1;
    const void*  maskp = cond ? mask2 : mask1;
    const void*  andp  = cond ? and2  : and1;
    int rowBase = blockIdx.x * 128;

    float acc[2][4][4];
#pragma unroll
    for (int a = 0; a < 2; a++)
#pragma unroll
        for (int b = 0; b < 4; b++)
#pragma unroll
            for (int c = 0; c < 4; c++) acc[a][b][c] = 0.f;

    float4 va[2][2];
    cpa_bf16<64>(Bs[0], g_Wp_h, g_Wp_l, 64, 0, 64, 0, 64, tid);
    cpa_bf16<64>(Bs[1], g_Wp_h, g_Wp_l, 64, 0, 64, 32, 64, tid);
    CPA_COMMIT();
    ldg_f32<2>(preds, 64, rowBase, MRPOOL, 0, 64, tid, va);
    sts_split<2>(As[0], tid, va);
    CPA_WAIT0();
    __syncthreads();

    for (int t = 0; t < 2; t++) {
        bool more = (t == 0);
        if (more) ldg_f32<2>(preds, 64, rowBase, MRPOOL, 32, 64, tid, va);
        mma_chunk32(As[t], Bs[t], wm, wn, lane, acc);
        if (more) sts_split<2>(As[1], tid, va);
        __syncthreads();
    }

#pragma unroll
    for (int mt = 0; mt < 2; mt++) {
#pragma unroll
        for (int nt = 0; nt < 4; nt++) {
            int r = wm * 32 + mt * 16 + (lane >> 2);
            int c = wn * 32 + nt * 8 + (lane & 3) * 2;
            stage[r * 68 + c] = acc[mt][nt][0];
            stage[r * 68 + c + 1] = acc[mt][nt][1];
            stage[(r + 8) * 68 + c] = acc[mt][nt][2];
            stage[(r + 8) * 68 + c + 1] = acc[mt][nt][3];
        }
    }
    __syncthreads();

    int node = blockIdx.x * 16 + (tid >> 4);
    int cg = (tid & 15) * 4;
    if (node < NN) {
        float bb[4];
        *(float4*)bb = *(const float4*)(b_pred + cg);
        int mk[8], anyb = 0;
#pragma unroll
        for (int i = 0; i < 8; i++) { mk[i] = read_bool(maskp, node * 8 + i); anyb |= mk[i]; }
        int ia = read_bool(andp, node);
        int rb = (tid >> 4) * 8;
        float out[4];
#pragma unroll
        for (int j = 0; j < 4; j++) {
            float mn = BIGF, mx = -BIGF;
#pragma unroll
            for (int i = 0; i < 8; i++) {
                float v = stage[(rb + i) * 68 + cg + j] + bb[j];
                if (mk[i]) { mn = fminf(mn, v); mx = fmaxf(mx, v); }
            }
            out[j] = anyb ? (ia ? mn : mx) : 0.0f;
        }
        size_t base = (size_t)node * 288 + 32 + cond * 64 + cg;
        uint32_t h0, l0, h1, l1;
        split2(out[0], out[1], h0, l0);
        split2(out[2], out[3], h1, l1);
        *(uint32_t*)(g_xh + base) = h0;     *(uint32_t*)(g_xh + base + 2) = h1;
        *(uint32_t*)(g_xl + base) = l0;     *(uint32_t*)(g_xl + base + 2) = l1;
    }
}

// ============ mma GEMM 2: bm (128Mx128N block, K=1000) =======================
__global__ __launch_bounds__(256, 2)
void k_bm_mma(const float* __restrict__ bitmap, const float* __restrict__ b_bm) {
    extern __shared__ __nv_bfloat16 sm[];
    __nv_bfloat16* As[2] = { sm, sm + 128 * STR };
    __nv_bfloat16* Bs[2] = { sm + 256 * STR, sm + 384 * STR };
    int tid = threadIdx.x, lane = tid & 31, warp = tid >> 5;
    int wm = warp >> 1, wn = warp & 1;
    int rowBase = blockIdx.x * 128;

    float acc[2][8][4];
#pragma unroll
    for (int a = 0; a < 2; a++)
#pragma unroll
        for (int b = 0; b < 8; b++)
#pragma unroll
            for (int c = 0; c < 4; c++) acc[a][b][c] = 0.f;

    float4 va[2][2];
    cpa_bf16<128>(Bs[0], g_Wbm_h, g_Wbm_l, 1000, 0, 128, 0, 1000, tid);
    CPA_COMMIT();
    ldg_f32<2>(bitmap, 1000, rowBase, NN, 0, 1000, tid, va);
    sts_split<2>(As[0], tid, va);
    CPA_WAIT0();
    __syncthreads();

    const int NC = 32;
    for (int t = 0; t < NC; t++) {
        bool more = (t + 1 < NC);
        if (more) {
            cpa_bf16<128>(Bs[(t + 1) & 1], g_Wbm_h, g_Wbm_l, 1000, 0, 128, (t + 1) * 32, 1000, tid);
            CPA_COMMIT();
            ldg_f32<2>(bitmap, 1000, rowBase, NN, (t + 1) * 32, 1000, tid, va);
        }
        mma_chunk(As[t & 1], Bs[t & 1], wm, wn, lane, acc);
        if (more) {
            sts_split<2>(As[(t + 1) & 1], tid, va);
            CPA_WAIT0();
        }
        __syncthreads();
    }

#pragma unroll
    for (int nt = 0; nt < 8; nt++) {
        int c = wn * 64 + nt * 8 + (lane & 3) * 2;
        float bx = b_bm[c], by = b_bm[c + 1];
#pragma unroll
        for (int mt = 0; mt < 2; mt++) {
            int r0 = rowBase + wm * 32 + mt * 16 + (lane >> 2);
            if (r0 < NN) {
                uint32_t h, l;
                split2(acc[mt][nt][0] + bx, acc[mt][nt][1] + by, h, l);
                *(uint32_t*)(g_xh + (size_t)r0 * 288 + 160 + c) = h;
                *(uint32_t*)(g_xl + (size_t)r0 * 288 + 160 + c) = l;
            }
            if (r0 + 8 < NN) {
                uint32_t h, l;
                split2(acc[mt][nt][2] + bx, acc[mt][nt][3] + by, h, l);
                *(uint32_t*)(g_xh + (size_t)(r0 + 8) * 288 + 160 + c) = h;
                *(uint32_t*)(g_xl + (size_t)(r0 + 8) * 288 + 160 + c) = l;
            }
        }
    }
}

// ============ mma GEMM 3: xg (128Mx128N block, K=288, all cp.async) ==========
__global__ __launch_bounds__(256, 2)
void k_xg_mma(const float* __restrict__ b_ih, const float* __restrict__ b_hh) {
    int colBase = blockIdx.x * 128;
    int rowBase = blockIdx.y * 128;
    // f-gate columns [256,512) are never read for leaf nodes (< 32768)
    if ((colBase == 256 || colBase == 384) && rowBase + 128 <= 32768) return;

    extern __shared__ __nv_bfloat16 sm[];
    __nv_bfloat16* As[2] = { sm, sm + 128 * STR };
    __nv_bfloat16* Bs[2] = { sm + 256 * STR, sm + 384 * STR };
    int tid = threadIdx.x, lane = tid & 31, warp = tid >> 5;
    int wm = warp >> 1, wn = warp & 1;

    float acc[2][8][4];
#pragma unroll
    for (int a = 0; a < 2; a++)
#pragma unroll
        for (int b = 0; b < 8; b++)
#pragma unroll
            for (int c = 0; c < 4; c++) acc[a][b][c] = 0.f;

    cpa_bf16<128>(As[0], g_xh, g_xl, 288, rowBase, NN, 0, 288, tid);
    cpa_bf16<128>(Bs[0], g_Wih_h, g_Wih_l, 288, colBase, 1024, 0, 288, tid);
    CPA_COMMIT();
    CPA_WAIT0();
    __syncthreads();

    const int NC = 9;
    for (int t = 0; t < NC; t++) {
        bool more = (t + 1 < NC);
        if (more) {
            cpa_bf16<128>(As[(t + 1) & 1], g_xh, g_xl, 288, rowBase, NN, (t + 1) * 32, 288, tid);
            cpa_bf16<128>(Bs[(t + 1) & 1], g_Wih_h, g_Wih_l, 288, colBase, 1024, (t + 1) * 32, 288, tid);
            CPA_COMMIT();
        }
        mma_chunk(As[t & 1], Bs[t & 1], wm, wn, lane, acc);
        if (more) CPA_WAIT0();
        __syncthreads();
    }

#pragma unroll
    for (int nt = 0; nt < 8; nt++) {
        int c = colBase + wn * 64 + nt * 8 + (lane & 3) * 2;
        float bx = b_ih[c] + b_hh[c], by = b_ih[c + 1] + b_hh[c + 1];
#pragma unroll
        for (int mt = 0; mt < 2; mt++) {
            int r0 = rowBase + wm * 32 + mt * 16 + (lane >> 2);
            if (r0 < NN)
                *(float2*)(g_xg + (size_t)r0 * 1024 + c) =
                    make_float2(acc[mt][nt][0] + bx, acc[mt][nt][1] + by);
            if (r0 + 8 < NN)
                *(float2*)(g_xg + (size_t)(r0 + 8) * 1024 + c) =
                    make_float2(acc[mt][nt][2] + bx, acc[mt][nt][3] + by);
        }
    }
}

// ============ mma level kernel (nd >= 128): fused GEMM + LSTM pointwise ======
__global__ __launch_bounds__(256, 2)
void k_level_mma(int start, int nd) {
    extern __shared__ __nv_bfloat16 sm[];
    __nv_bfloat16* As[2] = { sm, sm + 128 * STR };
    __nv_bfloat16* Bs[2] = { sm + 256 * STR, sm + 384 * STR };
    float* stage = (float*)sm;   // [128][132] after GEMM

    int tid = threadIdx.x, lane = tid & 31, warp = tid >> 5;
    int wm = warp >> 1, wn = warp & 1;
    int rowBase = blockIdx.x * 128;
    int jbase = blockIdx.y * 32;

    float acc[2][8][4];
#pragma unroll
    for (int a = 0; a < 2; a++)
#pragma unroll
        for (int b = 0; b < 8; b++)
#pragma unroll
            for (int c = 0; c < 4; c++) acc[a][b][c] = 0.f;

    float4 va[2][2];
    cpa_Whh(Bs[0], jbase, 0, tid);
    CPA_COMMIT();
    ldg_avgH(start, nd, rowBase, 0, tid, va);
    sts_split<2>(As[0], tid, va);
    CPA_WAIT0();
    __syncthreads();

    const int NC = 8;
    for (int t = 0; t < NC; t++) {
        bool more = (t + 1 < NC);
        if (more) {
            cpa_Whh(Bs[(t + 1) & 1], jbase, (t + 1) * 32, tid);
            CPA_COMMIT();
            ldg_avgH(start, nd, rowBase, (t + 1) * 32, tid, va);
        }
        mma_chunk(As[t & 1], Bs[t & 1], wm, wn, lane, acc);
        if (more) {
            sts_split<2>(As[(t + 1) & 1], tid, va);
            CPA_WAIT0();
        }
        __syncthreads();
    }

#pragma unroll
    for (int mt = 0; mt < 2; mt++) {
#pragma unroll
        for (int nt = 0; nt < 8; nt++) {
            int r = wm * 32 + mt * 16 + (lane >> 2);
            int c = wn * 64 + nt * 8 + (lane & 3) * 2;
            stage[r * 132 + c] = acc[mt][nt][0];
            stage[r * 132 + c + 1] = acc[mt][nt][1];
            stage[(r + 8) * 132 + c] = acc[mt][nt][2];
            stage[(r + 8) * 132 + c + 1] = acc[mt][nt][3];
        }
    }
    __syncthreads();

#pragma unroll
    for (int i = 0; i < 16; i++) {
        int idx = tid + 256 * i;
        int r = idx >> 5, jj = idx & 31;
        int rr = rowBase + r;
        if (rr < nd) {
            int node = start + rr;
            int j = jbase + jj;
            const float* xr = g_xg + (size_t)node * 1024;
            float gi = stage[r * 132 + jj]       + xr[j];
            float gf = stage[r * 132 + 32 + jj]  + xr[256 + j];
            float gg = stage[r * 132 + 64 + jj]  + xr[512 + j];
            float go = stage[r * 132 + 96 + jj]  + xr[768 + j];
            int ci = 2 * node - NN;
            float c0 = 0.5f * (g_C[(size_t)ci * 256 + j] + g_C[(size_t)(ci - 1) * 256 + j]);
            float cn = sigf(gf) * c0 + sigf(gi) * tanhf(gg);
            float hn = sigf(go) * tanhf(cn);
            g_H[(size_t)node * 256 + j] = hn;
            g_C[(size_t)node * 256 + j] = cn;
        }
    }
}

// ---------------- leaves (d = D): c0 = 0 -------------------------------------
__global__ void k_leaf() {
    int n = blockIdx.x;
    int j = threadIdx.x;
    const float* xr = g_xg + (size_t)n * 1024;
    float gi = xr[j];
    float gg = xr[512 + j];
    float go = xr[768 + j];
    float c = sigf(gi) * tanhf(gg);
    float h = sigf(go) * tanhf(c);
    g_H[(size_t)n * 256 + j] = h;
    g_C[(size_t)n * 256 + j] = c;
}

// ---------------- SIMT level kernel for small levels -------------------------
__global__ __launch_bounds__(256)
void k_level(int start, int nd, const float* __restrict__ W_hh) {
    __shared__ float h0s[32][36];
    __shared__ float Ws[256][36];
    int tid = threadIdx.x;
    int jx = tid & 63, ry = tid >> 6;
    int rowBase = blockIdx.x * 32;
    int jbase = blockIdx.y * 64;

    float acc[8][4];
#pragma unroll
    for (int i = 0; i < 8; i++)
#pragma unroll
        for (int g = 0; g < 4; g++) acc[i][g] = 0.0f;

    for (int k0 = 0; k0 < 256; k0 += 32) {
        {
            int r = tid >> 3, c4 = tid & 7;
            float4 v = make_float4(0.f, 0.f, 0.f, 0.f);
            int rr = rowBase + r;
            if (rr < nd) {
                int node = start + rr;
                int ci = 2 * node - NN;
                float4 a = *(const float4*)&g_H[(size_t)ci * 256 + k0 + c4 * 4];
                float4 b = *(const float4*)&g_H[(size_t)(ci - 1) * 256 + k0 + c4 * 4];
                v = make_float4(0.5f * (a.x + b.x), 0.5f * (a.y + b.y),
                                0.5f * (a.z + b.z), 0.5f * (a.w + b.w));
            }
            *(float4*)&h0s[r][c4 * 4] = v;
        }
        {
            int wrow = ry * 256 + jbase + jx;
            const float* src = &W_hh[(size_t)wrow * 256 + k0];
#pragma unroll
            for (int c = 0; c < 8; c++)
                *(float4*)&Ws[tid][c * 4] = *(const float4*)&src[c * 4];
        }
        __syncthreads();
#pragma unroll
        for (int kk4 = 0; kk4 < 8; kk4++) {
            float4 w4[4];
#pragma unroll
            for (int g = 0; g < 4; g++)
                w4[g] = *(const float4*)&Ws[g * 64 + jx][kk4 * 4];
#pragma unroll
            for (int i = 0; i < 8; i++) {
                float4 a4 = *(const float4*)&h0s[ry * 8 + i][kk4 * 4];
#pragma unroll
                for (int g = 0; g < 4; g++)
                    acc[i][g] += a4.x * w4[g].x + a4.y * w4[g].y +
                                 a4.z * w4[g].z + a4.w * w4[g].w;
            }
        }
        __syncthreads();
    }

    int j = jbase + jx;
#pragma unroll
    for (int i = 0; i < 8; i++) {
        int rr = rowBase + ry * 8 + i;
        if (rr < nd) {
            int node = start + rr;
            const float* xr = g_xg + (size_t)node * 1024;
            float gi = acc[i][0] + xr[j];
            float gf = acc[i][1] + xr[256 + j];
            float gg = acc[i][2] + xr[512 + j];
            float go = acc[i][3] + xr[768 + j];
            int ci = 2 * node - NN;
            float c0 = 0.5f * (g_C[(size_t)ci * 256 + j] + g_C[(size_t)(ci - 1) * 256 + j]);
            float cn = sigf(gf) * c0 + sigf(gi) * tanhf(gg);
            float hn = sigf(go) * tanhf(cn);
            g_H[(size_t)node * 256 + j] = hn;
            g_C[(size_t)node * 256 + j] = cn;
        }
    }
}

// ---------------- output heads ----------------------------------------------
__global__ void k_heads(const float* __restrict__ W2a, const float* __restrict__ b2a,
                        const float* __restrict__ W3a, const float* __restrict__ b3a,
                        const float* __restrict__ Woa, const float* __restrict__ boa,
                        const float* __restrict__ W2b, const float* __restrict__ b2b,
                        const float* __restrict__ W3b, const float* __restrict__ b3b,
                        const float* __restrict__ Wob, const float* __restrict__ bob,
                        float* __restrict__ out) {
    __shared__ float hv[256];
    __shared__ float t1[2][128];
    __shared__ float t2[2][128];
    __shared__ float red[256];
    int tid = threadIdx.x;
    hv[tid] = g_H[(size_t)(NN - 1) * 256 + tid];
    __syncthreads();
    int head = tid >> 7, j = tid & 127;
    const float* W2 = head ? W2b : W2a; const float* b2 = head ? b2b : b2a;
    const float* W3 = head ? W3b : W3a; const float* b3 = head ? b3b : b3a;
    const float* Wo = head ? Wob : Woa; const float* bo = head ? bob : boa;

    float t = b2[j];
    for (int k = 0; k < 256; k++) t += W2[j * 256 + k] * hv[k];
    t1[head][j] = fmaxf(t, 0.0f);
    __syncthreads();
    t = b3[j];
    for (int k = 0; k < 128; k++) t += W3[j * 128 + k] * t1[head][k];
    t2[head][j] = fmaxf(t, 0.0f);
    __syncthreads();
    red[tid] = Wo[j] * t2[head][j];
    __syncthreads();
    for (int s = 64; s > 0; s >>= 1) {
        if (j < s) red[tid] += red[tid + s];
        __syncthreads();
    }
    if (j == 0) out[head] = 1.0f / (1.0f + expf(-(red[tid] + bo[0])));
}

// ---------------- launch ------------------------------------------------------
extern "C" void kernel_launch(void* const* d_in, const int* in_sizes, int n_in,
                              void* d_out, int out_size) {
    const float* op_vec   = (const float*)d_in[0];
    const float* c1_preds = (const float*)d_in[1];
    const void*  c1_mask  = d_in[2];
    const void*  c1_and   = d_in[3];
    const float* c2_preds = (const float*)d_in[4];
    const void*  c2_mask  = d_in[5];
    const void*  c2_and   = d_in[6];
    const float* bitmap   = (const float*)d_in[7];
    const float* W_op     = (const float*)d_in[8];
    const float* b_op     = (const float*)d_in[9];
    const float* W_pred   = (const float*)d_in[10];
    const float* b_pred   = (const float*)d_in[11];
    const float* W_bm     = (const float*)d_in[12];
    const float* b_bm     = (const float*)d_in[13];
    const float* W_ih     = (const float*)d_in[14];
    const float* b_ih     = (const float*)d_in[15];
    const float* W_hh     = (const float*)d_in[16];
    const float* b_hh     = (const float*)d_in[17];
    const float* W_h2t1   = (const float*)d_in[18];
    const float* b_h2t1   = (const float*)d_in[19];
    const float* W_h3t1   = (const float*)d_in[20];
    const float* b_h3t1   = (const float*)d_in[21];
    const float* W_o1     = (const float*)d_in[22];
    const float* b_o1     = (const float*)d_in[23];
    const float* W_h2t2   = (const float*)d_in[24];
    const float* b_h2t2   = (const float*)d_in[25];
    const float* W_h3t2   = (const float*)d_in[26];
    const float* b_h3t2   = (const float*)d_in[27];
    const float* W_o2     = (const float*)d_in[28];
    const float* b_o2     = (const float*)d_in[29];
    float* out = (float*)d_out;

    const int SM_GEMM = 4 * 128 * STR * 2;                       // 73728
    const int SM_POOL = (2 * 128 + 2 * 64) * STR * 2;            // 55296
    static int configured = 0;
    if (!configured) {
        cudaFuncSetAttribute(k_pool_mma, cudaFuncAttributeMaxDynamicSharedMemorySize, SM_POOL);
        cudaFuncSetAttribute(k_bm_mma,   cudaFuncAttributeMaxDynamicSharedMemorySize, SM_GEMM);
        cudaFuncSetAttribute(k_xg_mma,   cudaFuncAttributeMaxDynamicSharedMemorySize, SM_GEMM);
        cudaFuncSetAttribute(k_level_mma,cudaFuncAttributeMaxDynamicSharedMemorySize, SM_GEMM);
        configured = 1;
    }

    k_detect<<<1, 256>>>((const unsigned int*)c1_mask);
    k_wsplit<<<(1024 * 288 + 1024 * 256 + 128 * 1000 + 64 * 64 + 255) / 256, 256>>>(
        W_ih, W_hh, W_bm, W_pred);

    k_op<<<(NN + 7) / 8, 256>>>(op_vec, W_op, b_op);

    {
        dim3 grid((MRPOOL + 127) / 128, 2);
        k_pool_mma<<<grid, 256, SM_POOL>>>(c1_preds, c1_mask, c1_and,
                                           c2_preds, c2_mask, c2_and, b_pred);
    }

    k_bm_mma<<<(NN + 127) / 128, 256, SM_GEMM>>>(bitmap, b_bm);

    {
        dim3 grid(8, (NN + 127) / 128);
        k_xg_mma<<<grid, 256, SM_GEMM>>>(b_ih, b_hh);
    }

    k_leaf<<<32768, 256>>>();

    for (int d = 14; d >= 0; d--) {
        int nd = 1 << d;
        int start = NN - (1 << (d + 1)) + 1;
        if (nd >= 128) {
            dim3 grid((nd + 127) / 128, 8);
            k_level_mma<<<grid, 256, SM_GEMM>>>(start, nd);
        } else {
            dim3 grid((nd + 31) / 32, 4);
            k_level<<<grid, 256>>>(start, nd, W_hh);
        }
    }

    k_heads<<<1, 256>>>(W_h2t1, b_h2t1, W_h3t1, b_h3t1, W_o1, b_o1,
                        W_h2t2, b_h2t2, W_h3t2, b_h3t2, W_o2, b_o2,
                        out);
}

// round 9
// speedup vs baseline: 7.9118x; 1.0675x over previous
#include <cuda_runtime.h>
#include <cuda_bf16.h>
#include <math.h>
#include <cstdint>
#include <stdint.h>

#define NN 65535          // number of tree nodes (2^16 - 1)
#define MRPOOL (NN * 8)   // pool GEMM rows
#define BIGF 1e30f

// Packed tile format: 128 rows x 128 bytes (32 fp32-K as 32 hi bf16 [0:64) +
// 32 lo bf16 [64:128)), SW128-swizzled: byte o -> o ^ ((o>>3)&0x70).
// One chunk tile = 16KB, bulk-copyable global<->shared verbatim.

__device__ __forceinline__ int swz(int o) { return o ^ ((o >> 3) & 0x70); }

// ---------------- scratch (static device globals; no cudaMalloc) -------------
__device__ __align__(1024) unsigned char g_xpk[(size_t)512 * 9 * 16384]; // packed features
__device__ float g_xg[(size_t)NN * 1024];          // gates pre-activation
__device__ float g_H[(size_t)NN * 256];            // LSTM hidden
__device__ float g_C[(size_t)NN * 256];            // LSTM cell
__device__ int   g_mask_is_byte;

// packed weights
__device__ __align__(1024) unsigned char g_Wihpk[72 * 16384];  // 8 colblk x 9 chunks
__device__ __align__(1024) unsigned char g_Whhpk[64 * 16384];  // 8 jblk x 8 chunks
__device__ __align__(1024) unsigned char g_Wbmpk[32 * 16384];  // 32 chunks
__device__ __align__(1024) unsigned char g_Wppk[2 * 8192];     // 2 chunks, 64 rows

__device__ __forceinline__ float sigf(float x) { return 1.0f / (1.0f + expf(-x)); }

__device__ __forceinline__ int read_bool(const void* p, int idx) {
    return g_mask_is_byte ? (int)(((const unsigned char*)p)[idx])
                          : (((const int*)p)[idx] != 0);
}

__device__ __forceinline__ unsigned smem_u32(const void* p) {
    return (unsigned)__cvta_generic_to_shared(p);
}

// ---------------- mbarrier + bulk copy ---------------------------------------
#define MBAR_INIT(a) \
    asm volatile("mbarrier.init.shared.b64 [%0], 1;" :: "r"(a) : "memory")
#define MBAR_EXPECT(a, tx) \
    asm volatile("mbarrier.arrive.expect_tx.shared.b64 _, [%0], %1;" \
                 :: "r"(a), "r"(tx) : "memory")

__device__ __forceinline__ void mbar_wait(uint32_t mbar, uint32_t parity) {
    asm volatile(
        "{\n\t.reg .pred P;\n\t"
        "WL%=:\n\t"
        "mbarrier.try_wait.parity.shared.b64 P, [%0], %1;\n\t"
        "@!P bra WL%=;\n\t}"
        :: "r"(mbar), "r"(parity) : "memory");
}

__device__ __forceinline__ void bulk_g2s(uint32_t dst, const void* src,
                                         uint32_t bytes, uint32_t mbar) {
    asm volatile(
        "cp.async.bulk.shared::cluster.global.mbarrier::complete_tx::bytes "
        "[%0], [%1], %2, [%3];"
        :: "r"(dst), "l"(src), "r"(bytes), "r"(mbar) : "memory");
}

// ---------------- bf16 split helpers -----------------------------------------
__device__ __forceinline__ void split2(float x, float y, uint32_t& h, uint32_t& l) {
    __nv_bfloat16 hx = __float2bfloat16(x), hy = __float2bfloat16(y);
    __nv_bfloat16 lx = __float2bfloat16(x - __bfloat162float(hx));
    __nv_bfloat16 ly = __float2bfloat16(y - __bfloat162float(hy));
    h = ((uint32_t)__bfloat16_as_ushort(hy) << 16) | __bfloat16_as_ushort(hx);
    l = ((uint32_t)__bfloat16_as_ushort(ly) << 16) | __bfloat16_as_ushort(lx);
}

// ---------------- mma.sync m16n8k16 bf16 + ldmatrix --------------------------
__device__ __forceinline__ void mma_bf16(float d[4], const uint32_t a[4], const uint32_t b[2]) {
    asm volatile(
        "mma.sync.aligned.m16n8k16.row.col.f32.bf16.bf16.f32 "
        "{%0,%1,%2,%3}, {%4,%5,%6,%7}, {%8,%9}, {%0,%1,%2,%3};\n"
        : "+f"(d[0]), "+f"(d[1]), "+f"(d[2]), "+f"(d[3])
        : "r"(a[0]), "r"(a[1]), "r"(a[2]), "r"(a[3]), "r"(b[0]), "r"(b[1]));
}

__device__ __forceinline__ void ldsm4(uint32_t r[4], const void* p) {
    uint32_t addr = smem_u32(p);
    asm volatile("ldmatrix.sync.aligned.m8n8.x4.shared.b16 {%0,%1,%2,%3}, [%4];"
                 : "=r"(r[0]), "=r"(r[1]), "=r"(r[2]), "=r"(r[3]) : "r"(addr));
}

// One K-chunk (32 fp32) for a 32x64 warp tile. Packed-swizzled tiles.
__device__ __forceinline__ void mma_chunk(const char* As, const char* Bs,
                                          int wm, int wn, int lane, float acc[2][8][4]) {
    int lrow = lane & 15, lcolb = (lane >> 4) * 16;
#pragma unroll
    for (int ks = 0; ks < 2; ks++) {
        int kb = ks * 32 + lcolb;
        uint32_t ah[2][4], al[2][4];
#pragma unroll
        for (int mt = 0; mt < 2; mt++) {
            int ro = (wm * 32 + mt * 16 + lrow) * 128;
            ldsm4(ah[mt], As + swz(ro + kb));
            ldsm4(al[mt], As + swz(ro + 64 + kb));
        }
#pragma unroll
        for (int g = 0; g < 4; g++) {
            int ro = (wn * 64 + g * 16 + lrow) * 128;
            uint32_t bh[4], bl[4];
            ldsm4(bh, Bs + swz(ro + kb));
            ldsm4(bl, Bs + swz(ro + 64 + kb));
            uint32_t bh0[2] = { bh[0], bh[2] }, bh1[2] = { bh[1], bh[3] };
            uint32_t bl0[2] = { bl[0], bl[2] }, bl1[2] = { bl[1], bl[3] };
#pragma unroll
            for (int mt = 0; mt < 2; mt++) {
                mma_bf16(acc[mt][g * 2],     ah[mt], bh0);
                mma_bf16(acc[mt][g * 2 + 1], ah[mt], bh1);
                mma_bf16(acc[mt][g * 2],     ah[mt], bl0);
                mma_bf16(acc[mt][g * 2 + 1], ah[mt], bl1);
                mma_bf16(acc[mt][g * 2],     al[mt], bh0);
                mma_bf16(acc[mt][g * 2 + 1], al[mt], bh1);
            }
        }
    }
}

// 32x32 warp-tile variant (pool; B tile 64 rows)
__device__ __forceinline__ void mma_chunk32(const char* As, const char* Bs,
                                            int wm, int wn, int lane, float acc[2][4][4]) {
    int lrow = lane & 15, lcolb = (lane >> 4) * 16;
#pragma unroll
    for (int ks = 0; ks < 2; ks++) {
        int kb = ks * 32 + lcolb;
        uint32_t ah[2][4], al[2][4];
#pragma unroll
        for (int mt = 0; mt < 2; mt++) {
            int ro = (wm * 32 + mt * 16 + lrow) * 128;
            ldsm4(ah[mt], As + swz(ro + kb));
            ldsm4(al[mt], As + swz(ro + 64 + kb));
        }
#pragma unroll
        for (int g = 0; g < 2; g++) {
            int ro = (wn * 32 + g * 16 + lrow) * 128;
            uint32_t bh[4], bl[4];
            ldsm4(bh, Bs + swz(ro + kb));
            ldsm4(bl, Bs + swz(ro + 64 + kb));
            uint32_t bh0[2] = { bh[0], bh[2] }, bh1[2] = { bh[1], bh[3] };
            uint32_t bl0[2] = { bl[0], bl[2] }, bl1[2] = { bl[1], bl[3] };
#pragma unroll
            for (int mt = 0; mt < 2; mt++) {
                mma_bf16(acc[mt][g * 2],     ah[mt], bh0);
                mma_bf16(acc[mt][g * 2 + 1], ah[mt], bh1);
                mma_bf16(acc[mt][g * 2],     ah[mt], bl0);
                mma_bf16(acc[mt][g * 2 + 1], ah[mt], bl1);
                mma_bf16(acc[mt][g * 2],     al[mt], bh0);
                mma_bf16(acc[mt][g * 2 + 1], al[mt], bh1);
            }
        }
    }
}

// ---------------- A-side loaders (fp32 sources) -------------------------------
template <int SLOTS>
__device__ __forceinline__ void ldg_f32(const float* __restrict__ src, int ld, int rowBase,
                                        int maxRow, int k0, int Ktot, int tid, float4 (*v)[2]) {
#pragma unroll
    for (int s = 0; s < SLOTS; s++) {
        int idx = tid + 256 * s;
        int r = idx >> 2, g = idx & 3;
        int row = rowBase + r, k = k0 + g * 8;
        float4 a = make_float4(0.f, 0.f, 0.f, 0.f), b = a;
        if (row < maxRow && k + 8 <= Ktot) {
            const float* p = src + (size_t)row * ld + k;
            a = *(const float4*)p;
            b = *(const float4*)(p + 4);
        }
        v[s][0] = a; v[s][1] = b;
    }
}

template <int SLOTS>
__device__ __forceinline__ void sts_split(char* As, int tid, float4 (*v)[2]) {
#pragma unroll
    for (int s = 0; s < SLOTS; s++) {
        int idx = tid + 256 * s;
        int r = idx >> 2, g = idx & 3;
        uint32_t h0, l0, h1, l1, h2, l2, h3, l3;
        split2(v[s][0].x, v[s][0].y, h0, l0);
        split2(v[s][0].z, v[s][0].w, h1, l1);
        split2(v[s][1].x, v[s][1].y, h2, l2);
        split2(v[s][1].z, v[s][1].w, h3, l3);
        *(uint4*)(As + swz(r * 128 + g * 16))      = make_uint4(h0, h1, h2, h3);
        *(uint4*)(As + swz(r * 128 + 64 + g * 16)) = make_uint4(l0, l1, l2, l3);
    }
}

__device__ __forceinline__ void ldg_avgH(int start, int nd, int rowBase, int k0, int tid,
                                         float4 (*v)[2]) {
#pragma unroll
    for (int s = 0; s < 2; s++) {
        int idx = tid + 256 * s;
        int r = idx >> 2, g = idx & 3;
        int rr = rowBase + r;
        float4 a = make_float4(0.f, 0.f, 0.f, 0.f), b = a;
        if (rr < nd) {
            int node = start + rr;
            int ci = 2 * node - NN;
            const float* p0 = g_H + (size_t)ci * 256 + k0 + g * 8;
            const float* p1 = g_H + (size_t)(ci - 1) * 256 + k0 + g * 8;
            float4 x0 = *(const float4*)p0, x1 = *(const float4*)(p0 + 4);
            float4 y0 = *(const float4*)p1, y1 = *(const float4*)(p1 + 4);
            a = make_float4(0.5f * (x0.x + y0.x), 0.5f * (x0.y + y0.y),
                            0.5f * (x0.z + y0.z), 0.5f * (x0.w + y0.w));
            b = make_float4(0.5f * (x1.x + y1.x), 0.5f * (x1.y + y1.y),
                            0.5f * (x1.z + y1.z), 0.5f * (x1.w + y1.w));
        }
        v[s][0] = a; v[s][1] = b;
    }
}

// ---------------- small kernels ----------------------------------------------
__global__ void k_detect(const unsigned int* __restrict__ m) {
    __shared__ int found;
    if (threadIdx.x == 0) found = 0;
    __syncthreads();
    unsigned int v = m[threadIdx.x];
    if (v > 1u) found = 1;
    __syncthreads();
    if (threadIdx.x == 0) g_mask_is_byte = found;
}

__device__ __forceinline__ void pack8(const float* s, unsigned char* dst,
                                      int r, int u, bool zero) {
    uint32_t h[4], l[4];
#pragma unroll
    for (int q = 0; q < 4; q++) {
        float x = zero ? 0.f : s[q * 2];
        float y = zero ? 0.f : s[q * 2 + 1];
        split2(x, y, h[q], l[q]);
    }
    *(uint4*)(dst + swz(r * 128 + u * 16))      = make_uint4(h[0], h[1], h[2], h[3]);
    *(uint4*)(dst + swz(r * 128 + 64 + u * 16)) = make_uint4(l[0], l[1], l[2], l[3]);
}

// pack all weights into tile-contiguous swizzled hi/lo chunks
__global__ void k_wpack(const float* __restrict__ Wih, const float* __restrict__ Whh,
                        const float* __restrict__ Wbm, const float* __restrict__ Wp) {
    int i = blockIdx.x * 256 + threadIdx.x;
    const int N1 = 72 * 512;   // Wih: 72 tiles x 128 rows x 4 units
    const int N2 = 64 * 512;
    const int N3 = 32 * 512;
    const int N4 = 2 * 256;    // Wp: 2 tiles x 64 rows x 4 units
    if (i < N1) {
        int t = i >> 9, rem = i & 511, r = rem >> 2, u = rem & 3;
        int cb = t / 9, ch = t % 9;
        pack8(Wih + (size_t)(cb * 128 + r) * 288 + ch * 32 + u * 8,
              g_Wihpk + (size_t)t * 16384, r, u, false);
    } else if (i < N1 + N2) {
        int j = i - N1;
        int t = j >> 9, rem = j & 511, r = rem >> 2, u = rem & 3;
        int jb = t / 8, ch = t % 8;
        int wrow = (r >> 5) * 256 + jb * 32 + (r & 31);
        pack8(Whh + (size_t)wrow * 256 + ch * 32 + u * 8,
              g_Whhpk + (size_t)t * 16384, r, u, false);
    } else if (i < N1 + N2 + N3) {
        int j = i - N1 - N2;
        int t = j >> 9, rem = j & 511, r = rem >> 2, u = rem & 3;
        int k = t * 32 + u * 8;
        bool zero = (k + 8 > 1000);
        pack8(Wbm + (size_t)r * 1000 + (zero ? 0 : k),
              g_Wbmpk + (size_t)t * 16384, r, u, zero);
    } else if (i < N1 + N2 + N3 + N4) {
        int j = i - N1 - N2 - N3;
        int t = j >> 8, rem = j & 255, r = rem >> 2, u = rem & 3;
        pack8(Wp + (size_t)r * 64 + t * 32 + u * 8,
              g_Wppk + (size_t)t * 8192, r, u, false);
    }
}

__global__ void k_op(const float* __restrict__ op_vec,
                     const float* __restrict__ W_op,
                     const float* __restrict__ b_op) {
    __shared__ float Ws[32][33];
    __shared__ float bs[32];
    int tid = threadIdx.x;
    if (tid < 32) bs[tid] = b_op[tid];
    for (int i = tid; i < 1024; i += 256) Ws[i >> 5][i & 31] = W_op[i];
    __syncthreads();
    int node = blockIdx.x * 8 + (tid >> 5);
    int o = tid & 31;
    if (node >= NN) return;
    float vl = op_vec[node * 32 + o];
    float acc = bs[o];
#pragma unroll
    for (int p = 0; p < 32; p++)
        acc += Ws[o][p] * __shfl_sync(0xffffffffu, vl, p);
    __nv_bfloat16 h = __float2bfloat16(acc);
    __nv_bfloat16 lo = __float2bfloat16(acc - __bfloat162float(h));
    int blk = node >> 7, r = node & 127;
    unsigned char* tb = g_xpk + (size_t)blk * 9 * 16384;   // chunk 0
    *(__nv_bfloat16*)(tb + swz(r * 128 + o * 2)) = h;
    *(__nv_bfloat16*)(tb + swz(r * 128 + 64 + o * 2)) = lo;
}

// ============ GEMM 1: pool (128Mx64N block, warp 32x32, K=64) ================
__global__ __launch_bounds__(256, 3)
void k_pool_mma(const float* __restrict__ preds1, const void* mask1, const void* and1,
                const float* __restrict__ preds2, const void* mask2, const void* and2,
                const float* __restrict__ b_pred) {
    extern __shared__ char sm[];
    char* Abuf[2] = { sm, sm + 16384 };
    char* Bbuf[2] = { sm + 32768, sm + 40960 };
    uint32_t mb = smem_u32(sm + 49152);
    float* stage = (float*)sm;   // [128][68] after GEMM

    int tid = threadIdx.x, lane = tid & 31, warp = tid >> 5;
    int wm = warp >> 1, wn = warp & 1;
    int cond = blockIdx.y;
    const float* preds = cond ? preds2 : preds1;
    const void*  maskp = cond ? mask2 : mask1;
    const void*  andp  = cond ? and2  : and1;
    int rowBase = blockIdx.x * 128;

    if (tid == 0) MBAR_INIT(mb);
    __syncthreads();
    if (tid == 0) {
        MBAR_EXPECT(mb, 16384u);
        bulk_g2s(smem_u32(Bbuf[0]), g_Wppk, 8192u, mb);
        bulk_g2s(smem_u32(Bbuf[1]), g_Wppk + 8192, 8192u, mb);
    }

    float acc[2][4][4];
#pragma unroll
    for (int a = 0; a < 2; a++)
#pragma unroll
        for (int b = 0; b < 4; b++)
#pragma unroll
            for (int c = 0; c < 4; c++) acc[a][b][c] = 0.f;

    float4 va[2][2];
    ldg_f32<2>(preds, 64, rowBase, MRPOOL, 0, 64, tid, va);
    sts_split<2>(Abuf[0], tid, va);
    mbar_wait(mb, 0);
    __syncthreads();

    for (int t = 0; t < 2; t++) {
        bool more = (t == 0);
        if (more) ldg_f32<2>(preds, 64, rowBase, MRPOOL, 32, 64, tid, va);
        mma_chunk32(Abuf[t], Bbuf[t], wm, wn, lane, acc);
        if (more) sts_split<2>(Abuf[1], tid, va);
        __syncthreads();
    }

#pragma unroll
    for (int mt = 0; mt < 2; mt++) {
#pragma unroll
        for (int nt = 0; nt < 4; nt++) {
            int r = wm * 32 + mt * 16 + (lane >> 2);
            int c = wn * 32 + nt * 8 + (lane & 3) * 2;
            stage[r * 68 + c] = acc[mt][nt][0];
            stage[r * 68 + c + 1] = acc[mt][nt][1];
            stage[(r + 8) * 68 + c] = acc[mt][nt][2];
            stage[(r + 8) * 68 + c + 1] = acc[mt][nt][3];
        }
    }
    __syncthreads();

    int node = blockIdx.x * 16 + (tid >> 4);
    int cg = (tid & 15) * 4;
    if (node < NN) {
        float bb[4];
        *(float4*)bb = *(const float4*)(b_pred + cg);
        int mk[8], anyb = 0;
#pragma unroll
        for (int i = 0; i < 8; i++) { mk[i] = read_bool(maskp, node * 8 + i); anyb |= mk[i]; }
        int ia = read_bool(andp, node);
        int rb = (tid >> 4) * 8;
        float out[4];
#pragma unroll
        for (int j = 0; j < 4; j++) {
            float mn = BIGF, mx = -BIGF;
#pragma unroll
            for (int i = 0; i < 8; i++) {
                float v = stage[(rb + i) * 68 + cg + j] + bb[j];
                if (mk[i]) { mn = fminf(mn, v); mx = fmaxf(mx, v); }
            }
            out[j] = anyb ? (ia ? mn : mx) : 0.0f;
        }
        uint32_t h0, l0, h1, l1;
        split2(out[0], out[1], h0, l0);
        split2(out[2], out[3], h1, l1);
        int col0 = 32 + cond * 64 + cg;
        int ch = col0 >> 5, co = col0 & 31;
        int r = node & 127;
        unsigned char* tb = g_xpk + ((size_t)(node >> 7) * 9 + ch) * 16384;
        *(uint2*)(tb + swz(r * 128 + co * 2))      = make_uint2(h0, h1);
        *(uint2*)(tb + swz(r * 128 + 64 + co * 2)) = make_uint2(l0, l1);
    }
}

// ============ GEMM 2: bm (128Mx128N block, K=1000, B bulk) ===================
__global__ __launch_bounds__(256, 2)
void k_bm_mma(const float* __restrict__ bitmap, const float* __restrict__ b_bm) {
    extern __shared__ char sm[];
    char* Abuf[2] = { sm, sm + 16384 };
    char* Bbuf[2] = { sm + 32768, sm + 49152 };
    uint32_t mb = smem_u32(sm + 65536);   // 2 mbars
    int tid = threadIdx.x, lane = tid & 31, warp = tid >> 5;
    int wm = warp >> 1, wn = warp & 1;
    int rowBase = blockIdx.x * 128;

    if (tid == 0) { MBAR_INIT(mb); MBAR_INIT(mb + 8); }
    __syncthreads();
    if (tid == 0) {
        MBAR_EXPECT(mb, 16384u);
        bulk_g2s(smem_u32(Bbuf[0]), g_Wbmpk, 16384u, mb);
        MBAR_EXPECT(mb + 8, 16384u);
        bulk_g2s(smem_u32(Bbuf[1]), g_Wbmpk + 16384, 16384u, mb + 8);
    }

    float acc[2][8][4];
#pragma unroll
    for (int a = 0; a < 2; a++)
#pragma unroll
        for (int b = 0; b < 8; b++)
#pragma unroll
            for (int c = 0; c < 4; c++) acc[a][b][c] = 0.f;

    float4 va[2][2];
    ldg_f32<2>(bitmap, 1000, rowBase, NN, 0, 1000, tid, va);
    sts_split<2>(Abuf[0], tid, va);
    __syncthreads();

    const int NC = 32;
    for (int t = 0; t < NC; t++) {
        bool more = (t + 1 < NC);
        if (more) ldg_f32<2>(bitmap, 1000, rowBase, NN, (t + 1) * 32, 1000, tid, va);
        mbar_wait(mb + 8 * (t & 1), (t >> 1) & 1);
        mma_chunk(Abuf[t & 1], Bbuf[t & 1], wm, wn, lane, acc);
        if (more) sts_split<2>(Abuf[(t + 1) & 1], tid, va);
        __syncthreads();
        if (tid == 0 && t + 2 < NC) {
            int s = t + 2, b = s & 1;
            MBAR_EXPECT(mb + 8 * b, 16384u);
            bulk_g2s(smem_u32(Bbuf[b]), g_Wbmpk + (size_t)s * 16384, 16384u, mb + 8 * b);
        }
    }

#pragma unroll
    for (int nt = 0; nt < 8; nt++) {
        int c = wn * 64 + nt * 8 + (lane & 3) * 2;
        float bx = b_bm[c], by = b_bm[c + 1];
        int ch = (160 + c) >> 5, co = (160 + c) & 31;
#pragma unroll
        for (int mt = 0; mt < 2; mt++) {
            int r0 = rowBase + wm * 32 + mt * 16 + (lane >> 2);
#pragma unroll
            for (int hh = 0; hh < 2; hh++) {
                int row = r0 + hh * 8;
                if (row < NN) {
                    uint32_t h, l;
                    split2(acc[mt][nt][hh * 2] + bx, acc[mt][nt][hh * 2 + 1] + by, h, l);
                    int r = row & 127;
                    unsigned char* tb = g_xpk + ((size_t)(row >> 7) * 9 + ch) * 16384;
                    *(uint32_t*)(tb + swz(r * 128 + co * 2)) = h;
                    *(uint32_t*)(tb + swz(r * 128 + 64 + co * 2)) = l;
                }
            }
        }
    }
}

// ============ GEMM 3: xg (128Mx128N block, K=288, all-bulk 3-stage) ==========
__global__ __launch_bounds__(256, 2)
void k_xg_mma(const float* __restrict__ b_ih, const float* __restrict__ b_hh) {
    int colBase = blockIdx.x * 128;
    int rowBase = blockIdx.y * 128;
    // f-gate columns [256,512) are never read for leaf nodes (< 32768)
    if ((colBase == 256 || colBase == 384) && rowBase + 128 <= 32768) return;

    extern __shared__ char sm[];
    uint32_t mb = smem_u32(sm + 98304);   // 3 mbars
    int tid = threadIdx.x, lane = tid & 31, warp = tid >> 5;
    int wm = warp >> 1, wn = warp & 1;
    int cb = colBase >> 7;
    int rb9 = (rowBase >> 7) * 9;

    if (tid == 0) { MBAR_INIT(mb); MBAR_INIT(mb + 8); MBAR_INIT(mb + 16); }
    __syncthreads();
    const int NC = 9;
    if (tid == 0) {
#pragma unroll
        for (int s = 0; s < 3; s++) {
            char* base = sm + s * 32768;
            MBAR_EXPECT(mb + 8 * s, 32768u);
            bulk_g2s(smem_u32(base), g_xpk + ((size_t)rb9 + s) * 16384, 16384u, mb + 8 * s);
            bulk_g2s(smem_u32(base + 16384), g_Wihpk + ((size_t)cb * 9 + s) * 16384,
                     16384u, mb + 8 * s);
        }
    }

    float acc[2][8][4];
#pragma unroll
    for (int a = 0; a < 2; a++)
#pragma unroll
        for (int b = 0; b < 8; b++)
#pragma unroll
            for (int c = 0; c < 4; c++) acc[a][b][c] = 0.f;

    for (int t = 0; t < NC; t++) {
        int b = t % 3;
        mbar_wait(mb + 8 * b, (uint32_t)((t / 3) & 1));
        mma_chunk(sm + b * 32768, sm + b * 32768 + 16384, wm, wn, lane, acc);
        __syncthreads();
        if (tid == 0 && t + 3 < NC) {
            int s = t + 3;
            char* base = sm + b * 32768;
            MBAR_EXPECT(mb + 8 * b, 32768u);
            bulk_g2s(smem_u32(base), g_xpk + ((size_t)rb9 + s) * 16384, 16384u, mb + 8 * b);
            bulk_g2s(smem_u32(base + 16384), g_Wihpk + ((size_t)cb * 9 + s) * 16384,
                     16384u, mb + 8 * b);
        }
    }

#pragma unroll
    for (int nt = 0; nt < 8; nt++) {
        int c = colBase + wn * 64 + nt * 8 + (lane & 3) * 2;
        float bx = b_ih[c] + b_hh[c], by = b_ih[c + 1] + b_hh[c + 1];
#pragma unroll
        for (int mt = 0; mt < 2; mt++) {
            int r0 = rowBase + wm * 32 + mt * 16 + (lane >> 2);
            if (r0 < NN)
                *(float2*)(g_xg + (size_t)r0 * 1024 + c) =
                    make_float2(acc[mt][nt][0] + bx, acc[mt][nt][1] + by);
            if (r0 + 8 < NN)
                *(float2*)(g_xg + (size_t)(r0 + 8) * 1024 + c) =
                    make_float2(acc[mt][nt][2] + bx, acc[mt][nt][3] + by);
        }
    }
}

// ============ level kernel (nd >= 128): fused GEMM + LSTM pointwise ==========
__global__ __launch_bounds__(256, 2)
void k_level_mma(int start, int nd) {
    extern __shared__ char sm[];
    char* Abuf[2] = { sm, sm + 16384 };
    char* Bbuf[2] = { sm + 32768, sm + 49152 };
    uint32_t mb = smem_u32(sm + 65536);
    float* stage = (float*)sm;   // [128][132] after GEMM

    int tid = threadIdx.x, lane = tid & 31, warp = tid >> 5;
    int wm = warp >> 1, wn = warp & 1;
    int rowBase = blockIdx.x * 128;
    int jb = blockIdx.y;          // j block (32 wide)

    if (tid == 0) { MBAR_INIT(mb); MBAR_INIT(mb + 8); }
    __syncthreads();
    if (tid == 0) {
        MBAR_EXPECT(mb, 16384u);
        bulk_g2s(smem_u32(Bbuf[0]), g_Whhpk + (size_t)(jb * 8) * 16384, 16384u, mb);
        MBAR_EXPECT(mb + 8, 16384u);
        bulk_g2s(smem_u32(Bbuf[1]), g_Whhpk + (size_t)(jb * 8 + 1) * 16384, 16384u, mb + 8);
    }

    float acc[2][8][4];
#pragma unroll
    for (int a = 0; a < 2; a++)
#pragma unroll
        for (int b = 0; b < 8; b++)
#pragma unroll
            for (int c = 0; c < 4; c++) acc[a][b][c] = 0.f;

    float4 va[2][2];
    ldg_avgH(start, nd, rowBase, 0, tid, va);
    sts_split<2>(Abuf[0], tid, va);
    __syncthreads();

    const int NC = 8;
    for (int t = 0; t < NC; t++) {
        bool more = (t + 1 < NC);
        if (more) ldg_avgH(start, nd, rowBase, (t + 1) * 32, tid, va);
        mbar_wait(mb + 8 * (t & 1), (t >> 1) & 1);
        mma_chunk(Abuf[t & 1], Bbuf[t & 1], wm, wn, lane, acc);
        if (more) sts_split<2>(Abuf[(t + 1) & 1], tid, va);
        __syncthreads();
        if (tid == 0 && t + 2 < NC) {
            int s = t + 2, b = s & 1;
            MBAR_EXPECT(mb + 8 * b, 16384u);
            bulk_g2s(smem_u32(Bbuf[b]), g_Whhpk + (size_t)(jb * 8 + s) * 16384,
                     16384u, mb + 8 * b);
        }
    }

#pragma unroll
    for (int mt = 0; mt < 2; mt++) {
#pragma unroll
        for (int nt = 0; nt < 8; nt++) {
            int r = wm * 32 + mt * 16 + (lane >> 2);
            int c = wn * 64 + nt * 8 + (lane & 3) * 2;
            stage[r * 132 + c] = acc[mt][nt][0];
            stage[r * 132 + c + 1] = acc[mt][nt][1];
            stage[(r + 8) * 132 + c] = acc[mt][nt][2];
            stage[(r + 8) * 132 + c + 1] = acc[mt][nt][3];
        }
    }
    __syncthreads();

#pragma unroll
    for (int i = 0; i < 16; i++) {
        int idx = tid + 256 * i;
        int r = idx >> 5, jj = idx & 31;
        int rr = rowBase + r;
        if (rr < nd) {
            int node = start + rr;
            int j = jb * 32 + jj;
            const float* xr = g_xg + (size_t)node * 1024;
            float gi = stage[r * 132 + jj]       + xr[j];
            float gf = stage[r * 132 + 32 + jj]  + xr[256 + j];
            float gg = stage[r * 132 + 64 + jj]  + xr[512 + j];
            float go = stage[r * 132 + 96 + jj]  + xr[768 + j];
            int ci = 2 * node - NN;
            float c0 = 0.5f * (g_C[(size_t)ci * 256 + j] + g_C[(size_t)(ci - 1) * 256 + j]);
            float cn = sigf(gf) * c0 + sigf(gi) * tanhf(gg);
            float hn = sigf(go) * tanhf(cn);
            g_H[(size_t)node * 256 + j] = hn;
            g_C[(size_t)node * 256 + j] = cn;
        }
    }
}

// ---------------- leaves (d = D): c0 = 0 -------------------------------------
__global__ void k_leaf() {
    int n = blockIdx.x;
    int j = threadIdx.x;
    const float* xr = g_xg + (size_t)n * 1024;
    float gi = xr[j];
    float gg = xr[512 + j];
    float go = xr[768 + j];
    float c = sigf(gi) * tanhf(gg);
    float h = sigf(go) * tanhf(c);
    g_H[(size_t)n * 256 + j] = h;
    g_C[(size_t)n * 256 + j] = c;
}

// ---------------- SIMT level kernel for small levels -------------------------
__global__ __launch_bounds__(256)
void k_level(int start, int nd, const float* __restrict__ W_hh) {
    __shared__ float h0s[32][36];
    __shared__ float Ws[256][36];
    int tid = threadIdx.x;
    int jx = tid & 63, ry = tid >> 6;
    int rowBase = blockIdx.x * 32;
    int jbase = blockIdx.y * 64;

    float acc[8][4];
#pragma unroll
    for (int i = 0; i < 8; i++)
#pragma unroll
        for (int g = 0; g < 4; g++) acc[i][g] = 0.0f;

    for (int k0 = 0; k0 < 256; k0 += 32) {
        {
            int r = tid >> 3, c4 = tid & 7;
            float4 v = make_float4(0.f, 0.f, 0.f, 0.f);
            int rr = rowBase + r;
            if (rr < nd) {
                int node = start + rr;
                int ci = 2 * node - NN;
                float4 a = *(const float4*)&g_H[(size_t)ci * 256 + k0 + c4 * 4];
                float4 b = *(const float4*)&g_H[(size_t)(ci - 1) * 256 + k0 + c4 * 4];
                v = make_float4(0.5f * (a.x + b.x), 0.5f * (a.y + b.y),
                                0.5f * (a.z + b.z), 0.5f * (a.w + b.w));
            }
            *(float4*)&h0s[r][c4 * 4] = v;
        }
        {
            int wrow = ry * 256 + jbase + jx;
            const float* src = &W_hh[(size_t)wrow * 256 + k0];
#pragma unroll
            for (int c = 0; c < 8; c++)
                *(float4*)&Ws[tid][c * 4] = *(const float4*)&src[c * 4];
        }
        __syncthreads();
#pragma unroll
        for (int kk4 = 0; kk4 < 8; kk4++) {
            float4 w4[4];
#pragma unroll
            for (int g = 0; g < 4; g++)
                w4[g] = *(const float4*)&Ws[g * 64 + jx][kk4 * 4];
#pragma unroll
            for (int i = 0; i < 8; i++) {
                float4 a4 = *(const float4*)&h0s[ry * 8 + i][kk4 * 4];
#pragma unroll
                for (int g = 0; g < 4; g++)
                    acc[i][g] += a4.x * w4[g].x + a4.y * w4[g].y +
                                 a4.z * w4[g].z + a4.w * w4[g].w;
            }
        }
        __syncthreads();
    }

    int j = jbase + jx;
#pragma unroll
    for (int i = 0; i < 8; i++) {
        int rr = rowBase + ry * 8 + i;
        if (rr < nd) {
            int node = start + rr;
            const float* xr = g_xg + (size_t)node * 1024;
            float gi = acc[i][0] + xr[j];
            float gf = acc[i][1] + xr[256 + j];
            float gg = acc[i][2] + xr[512 + j];
            float go = acc[i][3] + xr[768 + j];
            int ci = 2 * node - NN;
            float c0 = 0.5f * (g_C[(size_t)ci * 256 + j] + g_C[(size_t)(ci - 1) * 256 + j]);
            float cn = sigf(gf) * c0 + sigf(gi) * tanhf(gg);
            float hn = sigf(go) * tanhf(cn);
            g_H[(size_t)node * 256 + j] = hn;
            g_C[(size_t)node * 256 + j] = cn;
        }
    }
}

// ---------------- output heads ----------------------------------------------
__global__ void k_heads(const float* __restrict__ W2a, const float* __restrict__ b2a,
                        const float* __restrict__ W3a, const float* __restrict__ b3a,
                        const float* __restrict__ Woa, const float* __restrict__ boa,
                        const float* __restrict__ W2b, const float* __restrict__ b2b,
                        const float* __restrict__ W3b, const float* __restrict__ b3b,
                        const float* __restrict__ Wob, const float* __restrict__ bob,
                        float* __restrict__ out) {
    __shared__ float hv[256];
    __shared__ float t1[2][128];
    __shared__ float t2[2][128];
    __shared__ float red[256];
    int tid = threadIdx.x;
    hv[tid] = g_H[(size_t)(NN - 1) * 256 + tid];
    __syncthreads();
    int head = tid >> 7, j = tid & 127;
    const float* W2 = head ? W2b : W2a; const float* b2 = head ? b2b : b2a;
    const float* W3 = head ? W3b : W3a; const float* b3 = head ? b3b : b3a;
    const float* Wo = head ? Wob : Woa; const float* bo = head ? bob : boa;

    float t = b2[j];
    for (int k = 0; k < 256; k++) t += W2[j * 256 + k] * hv[k];
    t1[head][j] = fmaxf(t, 0.0f);
    __syncthreads();
    t = b3[j];
    for (int k = 0; k < 128; k++) t += W3[j * 128 + k] * t1[head][k];
    t2[head][j] = fmaxf(t, 0.0f);
    __syncthreads();
    red[tid] = Wo[j] * t2[head][j];
    __syncthreads();
    for (int s = 64; s > 0; s >>= 1) {
        if (j < s) red[tid] += red[tid + s];
        __syncthreads();
    }
    if (j == 0) out[head] = 1.0f / (1.0f + expf(-(red[tid] + bo[0])));
}

// ---------------- launch ------------------------------------------------------
extern "C" void kernel_launch(void* const* d_in, const int* in_sizes, int n_in,
                              void* d_out, int out_size) {
    const float* op_vec   = (const float*)d_in[0];
    const float* c1_preds = (const float*)d_in[1];
    const void*  c1_mask  = d_in[2];
    const void*  c1_and   = d_in[3];
    const float* c2_preds = (const float*)d_in[4];
    const void*  c2_mask  = d_in[5];
    const void*  c2_and   = d_in[6];
    const float* bitmap   = (const float*)d_in[7];
    const float* W_op     = (const float*)d_in[8];
    const float* b_op     = (const float*)d_in[9];
    const float* W_pred   = (const float*)d_in[10];
    const float* b_pred   = (const float*)d_in[11];
    const float* W_bm     = (const float*)d_in[12];
    const float* b_bm     = (const float*)d_in[13];
    const float* W_ih     = (const float*)d_in[14];
    const float* b_ih     = (const float*)d_in[15];
    const float* W_hh     = (const float*)d_in[16];
    const float* b_hh     = (const float*)d_in[17];
    const float* W_h2t1   = (const float*)d_in[18];
    const float* b_h2t1   = (const float*)d_in[19];
    const float* W_h3t1   = (const float*)d_in[20];
    const float* b_h3t1   = (const float*)d_in[21];
    const float* W_o1     = (const float*)d_in[22];
    const float* b_o1     = (const float*)d_in[23];
    const float* W_h2t2   = (const float*)d_in[24];
    const float* b_h2t2   = (const float*)d_in[25];
    const float* W_h3t2   = (const float*)d_in[26];
    const float* b_h3t2   = (const float*)d_in[27];
    const float* W_o2     = (const float*)d_in[28];
    const float* b_o2     = (const float*)d_in[29];
    float* out = (float*)d_out;

    const int SM_PL = 49152 + 64;
    const int SM_BM = 65536 + 64;
    const int SM_XG = 98304 + 64;
    const int SM_LV = 128 * 132 * 4 + 256;   // 67840 (covers 65536+64 too)
    static int configured = 0;
    if (!configured) {
        cudaFuncSetAttribute(k_pool_mma, cudaFuncAttributeMaxDynamicSharedMemorySize, SM_PL);
        cudaFuncSetAttribute(k_bm_mma,   cudaFuncAttributeMaxDynamicSharedMemorySize, SM_BM);
        cudaFuncSetAttribute(k_xg_mma,   cudaFuncAttributeMaxDynamicSharedMemorySize, SM_XG);
        cudaFuncSetAttribute(k_level_mma,cudaFuncAttributeMaxDynamicSharedMemorySize, SM_LV);
        configured = 1;
    }

    k_detect<<<1, 256>>>((const unsigned int*)c1_mask);
    k_wpack<<<(72 * 512 + 64 * 512 + 32 * 512 + 2 * 256 + 255) / 256, 256>>>(
        W_ih, W_hh, W_bm, W_pred);

    k_op<<<(NN + 7) / 8, 256>>>(op_vec, W_op, b_op);

    {
        dim3 grid((MRPOOL + 127) / 128, 2);
        k_pool_mma<<<grid, 256, SM_PL>>>(c1_preds, c1_mask, c1_and,
                                         c2_preds, c2_mask, c2_and, b_pred);
    }

    k_bm_mma<<<(NN + 127) / 128, 256, SM_BM>>>(bitmap, b_bm);

    {
        dim3 grid(8, (NN + 127) / 128);
        k_xg_mma<<<grid, 256, SM_XG>>>(b_ih, b_hh);
    }

    k_leaf<<<32768, 256>>>();

    for (int d = 14; d >= 0; d--) {
        int nd = 1 << d;
        int start = NN - (1 << (d + 1)) + 1;
        if (nd >= 128) {
            dim3 grid((nd + 127) / 128, 8);
            k_level_mma<<<grid, 256, SM_LV>>>(start, nd);
        } else {
            dim3 grid((nd + 31) / 32, 4);
            k_level<<<grid, 256>>>(start, nd, W_hh);
        }
    }

    k_heads<<<1, 256>>>(W_h2t1, b_h2t1, W_h3t1, b_h3t1, W_o1, b_o1,
                        W_h2t2, b_h2t2, W_h3t2, b_h3t2, W_o2, b_o2,
                        out);
}

// round 10
// speedup vs baseline: 8.9072x; 1.1258x over previous
#include <cuda_runtime.h>
#include <cuda_bf16.h>
#include <math.h>
#include <cstdint>
#include <stdint.h>

#define NN 65535          // number of tree nodes (2^16 - 1)
#define MRPOOL (NN * 8)   // pool GEMM rows
#define BIGF 1e30f

// Packed tile format: 128 rows x 128 bytes (32 fp32-K as 32 hi bf16 [0:64) +
// 32 lo bf16 [64:128)), SW128-swizzled: byte o -> o ^ ((o>>3)&0x70).
// One chunk tile = 16KB, bulk-copyable global<->shared verbatim.

__device__ __forceinline__ int swz(int o) { return o ^ ((o >> 3) & 0x70); }

// ---------------- scratch (static device globals; no cudaMalloc) -------------
__device__ __align__(1024) unsigned char g_xpk[(size_t)512 * 9 * 16384]; // packed features
__device__ float g_xg[(size_t)NN * 1024];          // gates pre-activation
__device__ float g_H[(size_t)NN * 256];            // LSTM hidden
__device__ float g_C[(size_t)NN * 256];            // LSTM cell
__device__ int   g_mask_is_byte;

// packed weights
__device__ __align__(1024) unsigned char g_Wihpk[72 * 16384];  // 8 colblk x 9 chunks
__device__ __align__(1024) unsigned char g_Whhpk[64 * 16384];  // 8 jblk x 8 chunks
__device__ __align__(1024) unsigned char g_Wbmpk[32 * 16384];  // 32 chunks
__device__ __align__(1024) unsigned char g_Wppk[2 * 8192];     // 2 chunks, 64 rows

__device__ __forceinline__ float sigf(float x) { return 1.0f / (1.0f + expf(-x)); }

__device__ __forceinline__ int read_bool(const void* p, int idx) {
    return g_mask_is_byte ? (int)(((const unsigned char*)p)[idx])
                          : (((const int*)p)[idx] != 0);
}

__device__ __forceinline__ unsigned smem_u32(const void* p) {
    return (unsigned)__cvta_generic_to_shared(p);
}

// ---------------- mbarrier + bulk copy ---------------------------------------
#define MBAR_INIT(a) \
    asm volatile("mbarrier.init.shared.b64 [%0], 1;" :: "r"(a) : "memory")
#define MBAR_EXPECT(a, tx) \
    asm volatile("mbarrier.arrive.expect_tx.shared.b64 _, [%0], %1;" \
                 :: "r"(a), "r"(tx) : "memory")

__device__ __forceinline__ void mbar_wait(uint32_t mbar, uint32_t parity) {
    asm volatile(
        "{\n\t.reg .pred P;\n\t"
        "WL%=:\n\t"
        "mbarrier.try_wait.parity.shared.b64 P, [%0], %1;\n\t"
        "@!P bra WL%=;\n\t}"
        :: "r"(mbar), "r"(parity) : "memory");
}

__device__ __forceinline__ void bulk_g2s(uint32_t dst, const void* src,
                                         uint32_t bytes, uint32_t mbar) {
    asm volatile(
        "cp.async.bulk.shared::cluster.global.mbarrier::complete_tx::bytes "
        "[%0], [%1], %2, [%3];"
        :: "r"(dst), "l"(src), "r"(bytes), "r"(mbar) : "memory");
}

// ---------------- bf16 split helpers -----------------------------------------
__device__ __forceinline__ void split2(float x, float y, uint32_t& h, uint32_t& l) {
    __nv_bfloat16 hx = __float2bfloat16(x), hy = __float2bfloat16(y);
    __nv_bfloat16 lx = __float2bfloat16(x - __bfloat162float(hx));
    __nv_bfloat16 ly = __float2bfloat16(y - __bfloat162float(hy));
    h = ((uint32_t)__bfloat16_as_ushort(hy) << 16) | __bfloat16_as_ushort(hx);
    l = ((uint32_t)__bfloat16_as_ushort(ly) << 16) | __bfloat16_as_ushort(lx);
}
__device__ __forceinline__ uint32_t pack2h(float x, float y) {
    __nv_bfloat16 hx = __float2bfloat16(x), hy = __float2bfloat16(y);
    return ((uint32_t)__bfloat16_as_ushort(hy) << 16) | __bfloat16_as_ushort(hx);
}

// ---------------- mma.sync m16n8k16 bf16 + ldmatrix --------------------------
__device__ __forceinline__ void mma_bf16(float d[4], const uint32_t a[4], const uint32_t b[2]) {
    asm volatile(
        "mma.sync.aligned.m16n8k16.row.col.f32.bf16.bf16.f32 "
        "{%0,%1,%2,%3}, {%4,%5,%6,%7}, {%8,%9}, {%0,%1,%2,%3};\n"
        : "+f"(d[0]), "+f"(d[1]), "+f"(d[2]), "+f"(d[3])
        : "r"(a[0]), "r"(a[1]), "r"(a[2]), "r"(a[3]), "r"(b[0]), "r"(b[1]));
}

__device__ __forceinline__ void ldsm4(uint32_t r[4], const void* p) {
    uint32_t addr = smem_u32(p);
    asm volatile("ldmatrix.sync.aligned.m8n8.x4.shared.b16 {%0,%1,%2,%3}, [%4];"
                 : "=r"(r[0]), "=r"(r[1]), "=r"(r[2]), "=r"(r[3]) : "r"(addr));
}

// 3-pass K-chunk (Ah*Bh + Ah*Bl + Al*Bh) for a 32x64 warp tile (levels)
__device__ __forceinline__ void mma_chunk(const char* As, const char* Bs,
                                          int wm, int wn, int lane, float acc[2][8][4]) {
    int lrow = lane & 15, lcolb = (lane >> 4) * 16;
#pragma unroll
    for (int ks = 0; ks < 2; ks++) {
        int kb = ks * 32 + lcolb;
        uint32_t ah[2][4], al[2][4];
#pragma unroll
        for (int mt = 0; mt < 2; mt++) {
            int ro = (wm * 32 + mt * 16 + lrow) * 128;
            ldsm4(ah[mt], As + swz(ro + kb));
            ldsm4(al[mt], As + swz(ro + 64 + kb));
        }
#pragma unroll
        for (int g = 0; g < 4; g++) {
            int ro = (wn * 64 + g * 16 + lrow) * 128;
            uint32_t bh[4], bl[4];
            ldsm4(bh, Bs + swz(ro + kb));
            ldsm4(bl, Bs + swz(ro + 64 + kb));
            uint32_t bh0[2] = { bh[0], bh[2] }, bh1[2] = { bh[1], bh[3] };
            uint32_t bl0[2] = { bl[0], bl[2] }, bl1[2] = { bl[1], bl[3] };
#pragma unroll
            for (int mt = 0; mt < 2; mt++) {
                mma_bf16(acc[mt][g * 2],     ah[mt], bh0);
                mma_bf16(acc[mt][g * 2 + 1], ah[mt], bh1);
                mma_bf16(acc[mt][g * 2],     ah[mt], bl0);
                mma_bf16(acc[mt][g * 2 + 1], ah[mt], bl1);
                mma_bf16(acc[mt][g * 2],     al[mt], bh0);
                mma_bf16(acc[mt][g * 2 + 1], al[mt], bh1);
            }
        }
    }
}

// 2-pass K-chunk (Ah*Bh + Ah*Bl; A bf16-rounded) for a 32x64 warp tile
__device__ __forceinline__ void mma_chunk2(const char* As, const char* Bs,
                                           int wm, int wn, int lane, float acc[2][8][4]) {
    int lrow = lane & 15, lcolb = (lane >> 4) * 16;
#pragma unroll
    for (int ks = 0; ks < 2; ks++) {
        int kb = ks * 32 + lcolb;
        uint32_t ah[2][4];
#pragma unroll
        for (int mt = 0; mt < 2; mt++) {
            int ro = (wm * 32 + mt * 16 + lrow) * 128;
            ldsm4(ah[mt], As + swz(ro + kb));
        }
#pragma unroll
        for (int g = 0; g < 4; g++) {
            int ro = (wn * 64 + g * 16 + lrow) * 128;
            uint32_t bh[4], bl[4];
            ldsm4(bh, Bs + swz(ro + kb));
            ldsm4(bl, Bs + swz(ro + 64 + kb));
            uint32_t bh0[2] = { bh[0], bh[2] }, bh1[2] = { bh[1], bh[3] };
            uint32_t bl0[2] = { bl[0], bl[2] }, bl1[2] = { bl[1], bl[3] };
#pragma unroll
            for (int mt = 0; mt < 2; mt++) {
                mma_bf16(acc[mt][g * 2],     ah[mt], bh0);
                mma_bf16(acc[mt][g * 2 + 1], ah[mt], bh1);
                mma_bf16(acc[mt][g * 2],     ah[mt], bl0);
                mma_bf16(acc[mt][g * 2 + 1], ah[mt], bl1);
            }
        }
    }
}

// 2-pass 32x32 warp-tile variant (pool; B tile 64 rows)
__device__ __forceinline__ void mma_chunk32_2(const char* As, const char* Bs,
                                              int wm, int wn, int lane, float acc[2][4][4]) {
    int lrow = lane & 15, lcolb = (lane >> 4) * 16;
#pragma unroll
    for (int ks = 0; ks < 2; ks++) {
        int kb = ks * 32 + lcolb;
        uint32_t ah[2][4];
#pragma unroll
        for (int mt = 0; mt < 2; mt++) {
            int ro = (wm * 32 + mt * 16 + lrow) * 128;
            ldsm4(ah[mt], As + swz(ro + kb));
        }
#pragma unroll
        for (int g = 0; g < 2; g++) {
            int ro = (wn * 32 + g * 16 + lrow) * 128;
            uint32_t bh[4], bl[4];
            ldsm4(bh, Bs + swz(ro + kb));
            ldsm4(bl, Bs + swz(ro + 64 + kb));
            uint32_t bh0[2] = { bh[0], bh[2] }, bh1[2] = { bh[1], bh[3] };
            uint32_t bl0[2] = { bl[0], bl[2] }, bl1[2] = { bl[1], bl[3] };
#pragma unroll
            for (int mt = 0; mt < 2; mt++) {
                mma_bf16(acc[mt][g * 2],     ah[mt], bh0);
                mma_bf16(acc[mt][g * 2 + 1], ah[mt], bh1);
                mma_bf16(acc[mt][g * 2],     ah[mt], bl0);
                mma_bf16(acc[mt][g * 2 + 1], ah[mt], bl1);
            }
        }
    }
}

// ---------------- A-side loaders (fp32 sources) -------------------------------
template <int SLOTS>
__device__ __forceinline__ void ldg_f32(const float* __restrict__ src, int ld, int rowBase,
                                        int maxRow, int k0, int Ktot, int tid, float4 (*v)[2]) {
#pragma unroll
    for (int s = 0; s < SLOTS; s++) {
        int idx = tid + 256 * s;
        int r = idx >> 2, g = idx & 3;
        int row = rowBase + r, k = k0 + g * 8;
        float4 a = make_float4(0.f, 0.f, 0.f, 0.f), b = a;
        if (row < maxRow && k + 8 <= Ktot) {
            const float* p = src + (size_t)row * ld + k;
            a = *(const float4*)p;
            b = *(const float4*)(p + 4);
        }
        v[s][0] = a; v[s][1] = b;
    }
}

// full hi+lo split store (levels A path)
template <int SLOTS>
__device__ __forceinline__ void sts_split(char* As, int tid, float4 (*v)[2]) {
#pragma unroll
    for (int s = 0; s < SLOTS; s++) {
        int idx = tid + 256 * s;
        int r = idx >> 2, g = idx & 3;
        uint32_t h0, l0, h1, l1, h2, l2, h3, l3;
        split2(v[s][0].x, v[s][0].y, h0, l0);
        split2(v[s][0].z, v[s][0].w, h1, l1);
        split2(v[s][1].x, v[s][1].y, h2, l2);
        split2(v[s][1].z, v[s][1].w, h3, l3);
        *(uint4*)(As + swz(r * 128 + g * 16))      = make_uint4(h0, h1, h2, h3);
        *(uint4*)(As + swz(r * 128 + 64 + g * 16)) = make_uint4(l0, l1, l2, l3);
    }
}

// hi-only store (2-pass A operands: pool preds, bm bitmap)
template <int SLOTS>
__device__ __forceinline__ void sts_hi(char* As, int tid, float4 (*v)[2]) {
#pragma unroll
    for (int s = 0; s < SLOTS; s++) {
        int idx = tid + 256 * s;
        int r = idx >> 2, g = idx & 3;
        uint4 h;
        h.x = pack2h(v[s][0].x, v[s][0].y);
        h.y = pack2h(v[s][0].z, v[s][0].w);
        h.z = pack2h(v[s][1].x, v[s][1].y);
        h.w = pack2h(v[s][1].z, v[s][1].w);
        *(uint4*)(As + swz(r * 128 + g * 16)) = h;
    }
}

__device__ __forceinline__ void ldg_avgH(int start, int nd, int rowBase, int k0, int tid,
                                         float4 (*v)[2]) {
#pragma unroll
    for (int s = 0; s < 2; s++) {
        int idx = tid + 256 * s;
        int r = idx >> 2, g = idx & 3;
        int rr = rowBase + r;
        float4 a = make_float4(0.f, 0.f, 0.f, 0.f), b = a;
        if (rr < nd) {
            int node = start + rr;
            int ci = 2 * node - NN;
            const float* p0 = g_H + (size_t)ci * 256 + k0 + g * 8;
            const float* p1 = g_H + (size_t)(ci - 1) * 256 + k0 + g * 8;
            float4 x0 = *(const float4*)p0, x1 = *(const float4*)(p0 + 4);
            float4 y0 = *(const float4*)p1, y1 = *(const float4*)(p1 + 4);
            a = make_float4(0.5f * (x0.x + y0.x), 0.5f * (x0.y + y0.y),
                            0.5f * (x0.z + y0.z), 0.5f * (x0.w + y0.w));
            b = make_float4(0.5f * (x1.x + y1.x), 0.5f * (x1.y + y1.y),
                            0.5f * (x1.z + y1.z), 0.5f * (x1.w + y1.w));
        }
        v[s][0] = a; v[s][1] = b;
    }
}

// ---------------- small kernels ----------------------------------------------
__global__ void k_detect(const unsigned int* __restrict__ m) {
    __shared__ int found;
    if (threadIdx.x == 0) found = 0;
    __syncthreads();
    unsigned int v = m[threadIdx.x];
    if (v > 1u) found = 1;
    __syncthreads();
    if (threadIdx.x == 0) g_mask_is_byte = found;
}

__device__ __forceinline__ void pack8(const float* s, unsigned char* dst,
                                      int r, int u, bool zero) {
    uint32_t h[4], l[4];
#pragma unroll
    for (int q = 0; q < 4; q++) {
        float x = zero ? 0.f : s[q * 2];
        float y = zero ? 0.f : s[q * 2 + 1];
        split2(x, y, h[q], l[q]);
    }
    *(uint4*)(dst + swz(r * 128 + u * 16))      = make_uint4(h[0], h[1], h[2], h[3]);
    *(uint4*)(dst + swz(r * 128 + 64 + u * 16)) = make_uint4(l[0], l[1], l[2], l[3]);
}

// pack all weights into tile-contiguous swizzled hi/lo chunks
__global__ void k_wpack(const float* __restrict__ Wih, const float* __restrict__ Whh,
                        const float* __restrict__ Wbm, const float* __restrict__ Wp) {
    int i = blockIdx.x * 256 + threadIdx.x;
    const int N1 = 72 * 512;
    const int N2 = 64 * 512;
    const int N3 = 32 * 512;
    const int N4 = 2 * 256;
    if (i < N1) {
        int t = i >> 9, rem = i & 511, r = rem >> 2, u = rem & 3;
        int cb = t / 9, ch = t % 9;
        pack8(Wih + (size_t)(cb * 128 + r) * 288 + ch * 32 + u * 8,
              g_Wihpk + (size_t)t * 16384, r, u, false);
    } else if (i < N1 + N2) {
        int j = i - N1;
        int t = j >> 9, rem = j & 511, r = rem >> 2, u = rem & 3;
        int jb = t / 8, ch = t % 8;
        int wrow = (r >> 5) * 256 + jb * 32 + (r & 31);
        pack8(Whh + (size_t)wrow * 256 + ch * 32 + u * 8,
              g_Whhpk + (size_t)t * 16384, r, u, false);
    } else if (i < N1 + N2 + N3) {
        int j = i - N1 - N2;
        int t = j >> 9, rem = j & 511, r = rem >> 2, u = rem & 3;
        int k = t * 32 + u * 8;
        bool zero = (k + 8 > 1000);
        pack8(Wbm + (size_t)r * 1000 + (zero ? 0 : k),
              g_Wbmpk + (size_t)t * 16384, r, u, zero);
    } else if (i < N1 + N2 + N3 + N4) {
        int j = i - N1 - N2 - N3;
        int t = j >> 8, rem = j & 255, r = rem >> 2, u = rem & 3;
        pack8(Wp + (size_t)r * 64 + t * 32 + u * 8,
              g_Wppk + (size_t)t * 8192, r, u, false);
    }
}

__global__ void k_op(const float* __restrict__ op_vec,
                     const float* __restrict__ W_op,
                     const float* __restrict__ b_op) {
    __shared__ float Ws[32][33];
    __shared__ float bs[32];
    int tid = threadIdx.x;
    if (tid < 32) bs[tid] = b_op[tid];
    for (int i = tid; i < 1024; i += 256) Ws[i >> 5][i & 31] = W_op[i];
    __syncthreads();
    int node = blockIdx.x * 8 + (tid >> 5);
    int o = tid & 31;
    if (node >= NN) return;
    float vl = op_vec[node * 32 + o];
    float acc = bs[o];
#pragma unroll
    for (int p = 0; p < 32; p++)
        acc += Ws[o][p] * __shfl_sync(0xffffffffu, vl, p);
    int blk = node >> 7, r = node & 127;
    unsigned char* tb = g_xpk + (size_t)blk * 9 * 16384;   // chunk 0, hi only
    *(__nv_bfloat16*)(tb + swz(r * 128 + o * 2)) = __float2bfloat16(acc);
}

// ============ GEMM 1: pool (128Mx64N block, warp 32x32, K=64, 2-pass) ========
__global__ __launch_bounds__(256, 3)
void k_pool_mma(const float* __restrict__ preds1, const void* mask1, const void* and1,
                const float* __restrict__ preds2, const void* mask2, const void* and2,
                const float* __restrict__ b_pred) {
    extern __shared__ char sm[];
    char* Abuf[2] = { sm, sm + 16384 };
    char* Bbuf[2] = { sm + 32768, sm + 40960 };
    uint32_t mb = smem_u32(sm + 49152);
    float* stage = (float*)sm;   // [128][68] after GEMM

    int tid = threadIdx.x, lane = tid & 31, warp = tid >> 5;
    int wm = warp >> 1, wn = warp & 1;
    int cond = blockIdx.y;
    const float* preds = cond ? preds2 : preds1;
    const void*  maskp = cond ? mask2 : mask1;
    const void*  andp  = cond ? and2  : and1;
    int rowBase = blockIdx.x * 128;

    if (tid == 0) MBAR_INIT(mb);
    __syncthreads();
    if (tid == 0) {
        MBAR_EXPECT(mb, 16384u);
        bulk_g2s(smem_u32(Bbuf[0]), g_Wppk, 8192u, mb);
        bulk_g2s(smem_u32(Bbuf[1]), g_Wppk + 8192, 8192u, mb);
    }

    float acc[2][4][4];
#pragma unroll
    for (int a = 0; a < 2; a++)
#pragma unroll
        for (int b = 0; b < 4; b++)
#pragma unroll
            for (int c = 0; c < 4; c++) acc[a][b][c] = 0.f;

    float4 va[2][2];
    ldg_f32<2>(preds, 64, rowBase, MRPOOL, 0, 64, tid, va);
    sts_hi<2>(Abuf[0], tid, va);
    mbar_wait(mb, 0);
    __syncthreads();

    for (int t = 0; t < 2; t++) {
        bool more = (t == 0);
        if (more) ldg_f32<2>(preds, 64, rowBase, MRPOOL, 32, 64, tid, va);
        mma_chunk32_2(Abuf[t], Bbuf[t], wm, wn, lane, acc);
        if (more) sts_hi<2>(Abuf[1], tid, va);
        __syncthreads();
    }

#pragma unroll
    for (int mt = 0; mt < 2; mt++) {
#pragma unroll
        for (int nt = 0; nt < 4; nt++) {
            int r = wm * 32 + mt * 16 + (lane >> 2);
            int c = wn * 32 + nt * 8 + (lane & 3) * 2;
            stage[r * 68 + c] = acc[mt][nt][0];
            stage[r * 68 + c + 1] = acc[mt][nt][1];
            stage[(r + 8) * 68 + c] = acc[mt][nt][2];
            stage[(r + 8) * 68 + c + 1] = acc[mt][nt][3];
        }
    }
    __syncthreads();

    int node = blockIdx.x * 16 + (tid >> 4);
    int cg = (tid & 15) * 4;
    if (node < NN) {
        float bb[4];
        *(float4*)bb = *(const float4*)(b_pred + cg);
        int mk[8], anyb = 0;
#pragma unroll
        for (int i = 0; i < 8; i++) { mk[i] = read_bool(maskp, node * 8 + i); anyb |= mk[i]; }
        int ia = read_bool(andp, node);
        int rb = (tid >> 4) * 8;
        float out[4];
#pragma unroll
        for (int j = 0; j < 4; j++) {
            float mn = BIGF, mx = -BIGF;
#pragma unroll
            for (int i = 0; i < 8; i++) {
                float v = stage[(rb + i) * 68 + cg + j] + bb[j];
                if (mk[i]) { mn = fminf(mn, v); mx = fmaxf(mx, v); }
            }
            out[j] = anyb ? (ia ? mn : mx) : 0.0f;
        }
        int col0 = 32 + cond * 64 + cg;
        int ch = col0 >> 5, co = col0 & 31;
        int r = node & 127;
        unsigned char* tb = g_xpk + ((size_t)(node >> 7) * 9 + ch) * 16384;
        *(uint2*)(tb + swz(r * 128 + co * 2)) =
            make_uint2(pack2h(out[0], out[1]), pack2h(out[2], out[3]));
    }
}

// ============ GEMM 2: bm (128Mx128N block, K=1000, B bulk, 2-pass) ===========
__global__ __launch_bounds__(256, 2)
void k_bm_mma(const float* __restrict__ bitmap, const float* __restrict__ b_bm) {
    extern __shared__ char sm[];
    char* Abuf[2] = { sm, sm + 16384 };
    char* Bbuf[2] = { sm + 32768, sm + 49152 };
    uint32_t mb = smem_u32(sm + 65536);
    int tid = threadIdx.x, lane = tid & 31, warp = tid >> 5;
    int wm = warp >> 1, wn = warp & 1;
    int rowBase = blockIdx.x * 128;

    if (tid == 0) { MBAR_INIT(mb); MBAR_INIT(mb + 8); }
    __syncthreads();
    if (tid == 0) {
        MBAR_EXPECT(mb, 16384u);
        bulk_g2s(smem_u32(Bbuf[0]), g_Wbmpk, 16384u, mb);
        MBAR_EXPECT(mb + 8, 16384u);
        bulk_g2s(smem_u32(Bbuf[1]), g_Wbmpk + 16384, 16384u, mb + 8);
    }

    float acc[2][8][4];
#pragma unroll
    for (int a = 0; a < 2; a++)
#pragma unroll
        for (int b = 0; b < 8; b++)
#pragma unroll
            for (int c = 0; c < 4; c++) acc[a][b][c] = 0.f;

    float4 va[2][2];
    ldg_f32<2>(bitmap, 1000, rowBase, NN, 0, 1000, tid, va);
    sts_hi<2>(Abuf[0], tid, va);
    __syncthreads();

    const int NC = 32;
    for (int t = 0; t < NC; t++) {
        bool more = (t + 1 < NC);
        if (more) ldg_f32<2>(bitmap, 1000, rowBase, NN, (t + 1) * 32, 1000, tid, va);
        mbar_wait(mb + 8 * (t & 1), (t >> 1) & 1);
        mma_chunk2(Abuf[t & 1], Bbuf[t & 1], wm, wn, lane, acc);
        if (more) sts_hi<2>(Abuf[(t + 1) & 1], tid, va);
        __syncthreads();
        if (tid == 0 && t + 2 < NC) {
            int s = t + 2, b = s & 1;
            MBAR_EXPECT(mb + 8 * b, 16384u);
            bulk_g2s(smem_u32(Bbuf[b]), g_Wbmpk + (size_t)s * 16384, 16384u, mb + 8 * b);
        }
    }

#pragma unroll
    for (int nt = 0; nt < 8; nt++) {
        int c = wn * 64 + nt * 8 + (lane & 3) * 2;
        float bx = b_bm[c], by = b_bm[c + 1];
        int ch = (160 + c) >> 5, co = (160 + c) & 31;
#pragma unroll
        for (int mt = 0; mt < 2; mt++) {
            int r0 = rowBase + wm * 32 + mt * 16 + (lane >> 2);
#pragma unroll
            for (int hh = 0; hh < 2; hh++) {
                int row = r0 + hh * 8;
                if (row < NN) {
                    int r = row & 127;
                    unsigned char* tb = g_xpk + ((size_t)(row >> 7) * 9 + ch) * 16384;
                    *(uint32_t*)(tb + swz(r * 128 + co * 2)) =
                        pack2h(acc[mt][nt][hh * 2] + bx, acc[mt][nt][hh * 2 + 1] + by);
                }
            }
        }
    }
}

// ============ GEMM 3: xg (128Mx128N block, K=288, all-bulk, 2-pass) ==========
__global__ __launch_bounds__(256, 2)
void k_xg_mma(const float* __restrict__ b_ih, const float* __restrict__ b_hh) {
    int colBase = blockIdx.x * 128;
    int rowBase = blockIdx.y * 128;
    // f-gate columns [256,512) are never read for leaf nodes (< 32768)
    if ((colBase == 256 || colBase == 384) && rowBase + 128 <= 32768) return;

    extern __shared__ char sm[];
    uint32_t mb = smem_u32(sm + 98304);
    int tid = threadIdx.x, lane = tid & 31, warp = tid >> 5;
    int wm = warp >> 1, wn = warp & 1;
    int cb = colBase >> 7;
    int rb9 = (rowBase >> 7) * 9;

    if (tid == 0) { MBAR_INIT(mb); MBAR_INIT(mb + 8); MBAR_INIT(mb + 16); }
    __syncthreads();
    const int NC = 9;
    if (tid == 0) {
#pragma unroll
        for (int s = 0; s < 3; s++) {
            char* base = sm + s * 32768;
            MBAR_EXPECT(mb + 8 * s, 32768u);
            bulk_g2s(smem_u32(base), g_xpk + ((size_t)rb9 + s) * 16384, 16384u, mb + 8 * s);
            bulk_g2s(smem_u32(base + 16384), g_Wihpk + ((size_t)cb * 9 + s) * 16384,
                     16384u, mb + 8 * s);
        }
    }

    float acc[2][8][4];
#pragma unroll
    for (int a = 0; a < 2; a++)
#pragma unroll
        for (int b = 0; b < 8; b++)
#pragma unroll
            for (int c = 0; c < 4; c++) acc[a][b][c] = 0.f;

    for (int t = 0; t < NC; t++) {
        int b = t % 3;
        mbar_wait(mb + 8 * b, (uint32_t)((t / 3) & 1));
        mma_chunk2(sm + b * 32768, sm + b * 32768 + 16384, wm, wn, lane, acc);
        __syncthreads();
        if (tid == 0 && t + 3 < NC) {
            int s = t + 3;
            char* base = sm + b * 32768;
            MBAR_EXPECT(mb + 8 * b, 32768u);
            bulk_g2s(smem_u32(base), g_xpk + ((size_t)rb9 + s) * 16384, 16384u, mb + 8 * b);
            bulk_g2s(smem_u32(base + 16384), g_Wihpk + ((size_t)cb * 9 + s) * 16384,
                     16384u, mb + 8 * b);
        }
    }

#pragma unroll
    for (int nt = 0; nt < 8; nt++) {
        int c = colBase + wn * 64 + nt * 8 + (lane & 3) * 2;
        float bx = b_ih[c] + b_hh[c], by = b_ih[c + 1] + b_hh[c + 1];
#pragma unroll
        for (int mt = 0; mt < 2; mt++) {
            int r0 = rowBase + wm * 32 + mt * 16 + (lane >> 2);
            if (r0 < NN)
                *(float2*)(g_xg + (size_t)r0 * 1024 + c) =
                    make_float2(acc[mt][nt][0] + bx, acc[mt][nt][1] + by);
            if (r0 + 8 < NN)
                *(float2*)(g_xg + (size_t)(r0 + 8) * 1024 + c) =
                    make_float2(acc[mt][nt][2] + bx, acc[mt][nt][3] + by);
        }
    }
}

// ============ level kernel (nd >= 128): 3-pass GEMM + LSTM pointwise =========
__global__ __launch_bounds__(256, 2)
void k_level_mma(int start, int nd) {
    extern __shared__ char sm[];
    char* Abuf[2] = { sm, sm + 16384 };
    char* Bbuf[2] = { sm + 32768, sm + 49152 };
    uint32_t mb = smem_u32(sm + 65536);
    float* stage = (float*)sm;   // [128][132] after GEMM

    int tid = threadIdx.x, lane = tid & 31, warp = tid >> 5;
    int wm = warp >> 1, wn = warp & 1;
    int rowBase = blockIdx.x * 128;
    int jb = blockIdx.y;          // j block (32 wide)

    if (tid == 0) { MBAR_INIT(mb); MBAR_INIT(mb + 8); }
    __syncthreads();
    if (tid == 0) {
        MBAR_EXPECT(mb, 16384u);
        bulk_g2s(smem_u32(Bbuf[0]), g_Whhpk + (size_t)(jb * 8) * 16384, 16384u, mb);
        MBAR_EXPECT(mb + 8, 16384u);
        bulk_g2s(smem_u32(Bbuf[1]), g_Whhpk + (size_t)(jb * 8 + 1) * 16384, 16384u, mb + 8);
    }

    float acc[2][8][4];
#pragma unroll
    for (int a = 0; a < 2; a++)
#pragma unroll
        for (int b = 0; b < 8; b++)
#pragma unroll
            for (int c = 0; c < 4; c++) acc[a][b][c] = 0.f;

    float4 va[2][2];
    ldg_avgH(start, nd, rowBase, 0, tid, va);
    sts_split<2>(Abuf[0], tid, va);
    __syncthreads();

    const int NC = 8;
    for (int t = 0; t < NC; t++) {
        bool more = (t + 1 < NC);
        if (more) ldg_avgH(start, nd, rowBase, (t + 1) * 32, tid, va);
        mbar_wait(mb + 8 * (t & 1), (t >> 1) & 1);
        mma_chunk(Abuf[t & 1], Bbuf[t & 1], wm, wn, lane, acc);
        if (more) sts_split<2>(Abuf[(t + 1) & 1], tid, va);
        __syncthreads();
        if (tid == 0 && t + 2 < NC) {
            int s = t + 2, b = s & 1;
            MBAR_EXPECT(mb + 8 * b, 16384u);
            bulk_g2s(smem_u32(Bbuf[b]), g_Whhpk + (size_t)(jb * 8 + s) * 16384,
                     16384u, mb + 8 * b);
        }
    }

#pragma unroll
    for (int mt = 0; mt < 2; mt++) {
#pragma unroll
        for (int nt = 0; nt < 8; nt++) {
            int r = wm * 32 + mt * 16 + (lane >> 2);
            int c = wn * 64 + nt * 8 + (lane & 3) * 2;
            stage[r * 132 + c] = acc[mt][nt][0];
            stage[r * 132 + c + 1] = acc[mt][nt][1];
            stage[(r + 8) * 132 + c] = acc[mt][nt][2];
            stage[(r + 8) * 132 + c + 1] = acc[mt][nt][3];
        }
    }
    __syncthreads();

#pragma unroll
    for (int i = 0; i < 16; i++) {
        int idx = tid + 256 * i;
        int r = idx >> 5, jj = idx & 31;
        int rr = rowBase + r;
        if (rr < nd) {
            int node = start + rr;
            int j = jb * 32 + jj;
            const float* xr = g_xg + (size_t)node * 1024;
            float gi = stage[r * 132 + jj]       + xr[j];
            float gf = stage[r * 132 + 32 + jj]  + xr[256 + j];
            float gg = stage[r * 132 + 64 + jj]  + xr[512 + j];
            float go = stage[r * 132 + 96 + jj]  + xr[768 + j];
            int ci = 2 * node - NN;
            float c0 = 0.5f * (g_C[(size_t)ci * 256 + j] + g_C[(size_t)(ci - 1) * 256 + j]);
            float cn = sigf(gf) * c0 + sigf(gi) * tanhf(gg);
            float hn = sigf(go) * tanhf(cn);
            g_H[(size_t)node * 256 + j] = hn;
            g_C[(size_t)node * 256 + j] = cn;
        }
    }
}

// ---------------- leaves (d = D): c0 = 0 -------------------------------------
__global__ void k_leaf() {
    int n = blockIdx.x;
    int j = threadIdx.x;
    const float* xr = g_xg + (size_t)n * 1024;
    float gi = xr[j];
    float gg = xr[512 + j];
    float go = xr[768 + j];
    float c = sigf(gi) * tanhf(gg);
    float h = sigf(go) * tanhf(c);
    g_H[(size_t)n * 256 + j] = h;
    g_C[(size_t)n * 256 + j] = c;
}

// ---------------- SIMT level kernel for small levels -------------------------
__global__ __launch_bounds__(256)
void k_level(int start, int nd, const float* __restrict__ W_hh) {
    __shared__ float h0s[32][36];
    __shared__ float Ws[256][36];
    int tid = threadIdx.x;
    int jx = tid & 63, ry = tid >> 6;
    int rowBase = blockIdx.x * 32;
    int jbase = blockIdx.y * 64;

    float acc[8][4];
#pragma unroll
    for (int i = 0; i < 8; i++)
#pragma unroll
        for (int g = 0; g < 4; g++) acc[i][g] = 0.0f;

    for (int k0 = 0; k0 < 256; k0 += 32) {
        {
            int r = tid >> 3, c4 = tid & 7;
            float4 v = make_float4(0.f, 0.f, 0.f, 0.f);
            int rr = rowBase + r;
            if (rr < nd) {
                int node = start + rr;
                int ci = 2 * node - NN;
                float4 a = *(const float4*)&g_H[(size_t)ci * 256 + k0 + c4 * 4];
                float4 b = *(const float4*)&g_H[(size_t)(ci - 1) * 256 + k0 + c4 * 4];
                v = make_float4(0.5f * (a.x + b.x), 0.5f * (a.y + b.y),
                                0.5f * (a.z + b.z), 0.5f * (a.w + b.w));
            }
            *(float4*)&h0s[r][c4 * 4] = v;
        }
        {
            int wrow = ry * 256 + jbase + jx;
            const float* src = &W_hh[(size_t)wrow * 256 + k0];
#pragma unroll
            for (int c = 0; c < 8; c++)
                *(float4*)&Ws[tid][c * 4] = *(const float4*)&src[c * 4];
        }
        __syncthreads();
#pragma unroll
        for (int kk4 = 0; kk4 < 8; kk4++) {
            float4 w4[4];
#pragma unroll
            for (int g = 0; g < 4; g++)
                w4[g] = *(const float4*)&Ws[g * 64 + jx][kk4 * 4];
#pragma unroll
            for (int i = 0; i < 8; i++) {
                float4 a4 = *(const float4*)&h0s[ry * 8 + i][kk4 * 4];
#pragma unroll
                for (int g = 0; g < 4; g++)
                    acc[i][g] += a4.x * w4[g].x + a4.y * w4[g].y +
                                 a4.z * w4[g].z + a4.w * w4[g].w;
            }
        }
        __syncthreads();
    }

    int j = jbase + jx;
#pragma unroll
    for (int i = 0; i < 8; i++) {
        int rr = rowBase + ry * 8 + i;
        if (rr < nd) {
            int node = start + rr;
            const float* xr = g_xg + (size_t)node * 1024;
            float gi = acc[i][0] + xr[j];
            float gf = acc[i][1] + xr[256 + j];
            float gg = acc[i][2] + xr[512 + j];
            float go = acc[i][3] + xr[768 + j];
            int ci = 2 * node - NN;
            float c0 = 0.5f * (g_C[(size_t)ci * 256 + j] + g_C[(size_t)(ci - 1) * 256 + j]);
            float cn = sigf(gf) * c0 + sigf(gi) * tanhf(gg);
            float hn = sigf(go) * tanhf(cn);
            g_H[(size_t)node * 256 + j] = hn;
            g_C[(size_t)node * 256 + j] = cn;
        }
    }
}

// ---------------- output heads ----------------------------------------------
__global__ void k_heads(const float* __restrict__ W2a, const float* __restrict__ b2a,
                        const float* __restrict__ W3a, const float* __restrict__ b3a,
                        const float* __restrict__ Woa, const float* __restrict__ boa,
                        const float* __restrict__ W2b, const float* __restrict__ b2b,
                        const float* __restrict__ W3b, const float* __restrict__ b3b,
                        const float* __restrict__ Wob, const float* __restrict__ bob,
                        float* __restrict__ out) {
    __shared__ float hv[256];
    __shared__ float t1[2][128];
    __shared__ float t2[2][128];
    __shared__ float red[256];
    int tid = threadIdx.x;
    hv[tid] = g_H[(size_t)(NN - 1) * 256 + tid];
    __syncthreads();
    int head = tid >> 7, j = tid & 127;
    const float* W2 = head ? W2b : W2a; const float* b2 = head ? b2b : b2a;
    const float* W3 = head ? W3b : W3a; const float* b3 = head ? b3b : b3a;
    const float* Wo = head ? Wob : Woa; const float* bo = head ? bob : boa;

    float t = b2[j];
    for (int k = 0; k < 256; k++) t += W2[j * 256 + k] * hv[k];
    t1[head][j] = fmaxf(t, 0.0f);
    __syncthreads();
    t = b3[j];
    for (int k = 0; k < 128; k++) t += W3[j * 128 + k] * t1[head][k];
    t2[head][j] = fmaxf(t, 0.0f);
    __syncthreads();
    red[tid] = Wo[j] * t2[head][j];
    __syncthreads();
    for (int s = 64; s > 0; s >>= 1) {
        if (j < s) red[tid] += red[tid + s];
        __syncthreads();
    }
    if (j == 0) out[head] = 1.0f / (1.0f + expf(-(red[tid] + bo[0])));
}

// ---------------- launch ------------------------------------------------------
extern "C" void kernel_launch(void* const* d_in, const int* in_sizes, int n_in,
                              void* d_out, int out_size) {
    const float* op_vec   = (const float*)d_in[0];
    const float* c1_preds = (const float*)d_in[1];
    const void*  c1_mask  = d_in[2];
    const void*  c1_and   = d_in[3];
    const float* c2_preds = (const float*)d_in[4];
    const void*  c2_mask  = d_in[5];
    const void*  c2_and   = d_in[6];
    const float* bitmap   = (const float*)d_in[7];
    const float* W_op     = (const float*)d_in[8];
    const float* b_op     = (const float*)d_in[9];
    const float* W_pred   = (const float*)d_in[10];
    const float* b_pred   = (const float*)d_in[11];
    const float* W_bm     = (const float*)d_in[12];
    const float* b_bm     = (const float*)d_in[13];
    const float* W_ih     = (const float*)d_in[14];
    const float* b_ih     = (const float*)d_in[15];
    const float* W_hh     = (const float*)d_in[16];
    const float* b_hh     = (const float*)d_in[17];
    const float* W_h2t1   = (const float*)d_in[18];
    const float* b_h2t1   = (const float*)d_in[19];
    const float* W_h3t1   = (const float*)d_in[20];
    const float* b_h3t1   = (const float*)d_in[21];
    const float* W_o1     = (const float*)d_in[22];
    const float* b_o1     = (const float*)d_in[23];
    const float* W_h2t2   = (const float*)d_in[24];
    const float* b_h2t2   = (const float*)d_in[25];
    const float* W_h3t2   = (const float*)d_in[26];
    const float* b_h3t2   = (const float*)d_in[27];
    const float* W_o2     = (const float*)d_in[28];
    const float* b_o2     = (const float*)d_in[29];
    float* out = (float*)d_out;

    const int SM_PL = 49152 + 64;
    const int SM_BM = 65536 + 64;
    const int SM_XG = 98304 + 64;
    const int SM_LV = 128 * 132 * 4 + 256;
    static int configured = 0;
    if (!configured) {
        cudaFuncSetAttribute(k_pool_mma, cudaFuncAttributeMaxDynamicSharedMemorySize, SM_PL);
        cudaFuncSetAttribute(k_bm_mma,   cudaFuncAttributeMaxDynamicSharedMemorySize, SM_BM);
        cudaFuncSetAttribute(k_xg_mma,   cudaFuncAttributeMaxDynamicSharedMemorySize, SM_XG);
        cudaFuncSetAttribute(k_level_mma,cudaFuncAttributeMaxDynamicSharedMemorySize, SM_LV);
        configured = 1;
    }

    k_detect<<<1, 256>>>((const unsigned int*)c1_mask);
    k_wpack<<<(72 * 512 + 64 * 512 + 32 * 512 + 2 * 256 + 255) / 256, 256>>>(
        W_ih, W_hh, W_bm, W_pred);

    k_op<<<(NN + 7) / 8, 256>>>(op_vec, W_op, b_op);

    {
        dim3 grid((MRPOOL + 127) / 128, 2);
        k_pool_mma<<<grid, 256, SM_PL>>>(c1_preds, c1_mask, c1_and,
                                         c2_preds, c2_mask, c2_and, b_pred);
    }

    k_bm_mma<<<(NN + 127) / 128, 256, SM_BM>>>(bitmap, b_bm);

    {
        dim3 grid(8, (NN + 127) / 128);
        k_xg_mma<<<grid, 256, SM_XG>>>(b_ih, b_hh);
    }

    k_leaf<<<32768, 256>>>();

    for (int d = 14; d >= 0; d--) {
        int nd = 1 << d;
        int start = NN - (1 << (d + 1)) + 1;
        if (nd >= 128) {
            dim3 grid((nd + 127) / 128, 8);
            k_level_mma<<<grid, 256, SM_LV>>>(start, nd);
        } else {
            dim3 grid((nd + 31) / 32, 4);
            k_level<<<grid, 256>>>(start, nd, W_hh);
        }
    }

    k_heads<<<1, 256>>>(W_h2t1, b_h2t1, W_h3t1, b_h3t1, W_o1, b_o1,
                        W_h2t2, b_h2t2, W_h3t2, b_h3t2, W_o2, b_o2,
                        out);
}

// round 11
// speedup vs baseline: 10.5513x; 1.1846x over previous
#include <cuda_runtime.h>
#include <cuda_fp16.h>
#include <math.h>
#include <cstdint>
#include <stdint.h>

#define NN 65535          // number of tree nodes (2^16 - 1)
#define MRPOOL (NN * 8)   // pool GEMM rows
#define BIGF 1e30f

// Packed tile: 128 rows x 64 fp16 K-values (128B/row), SW128-swizzled
// (byte o -> o ^ ((o>>3)&0x70)); 16KB per tile, bulk-copyable verbatim.
__device__ __forceinline__ int swz(int o) { return o ^ ((o >> 3) & 0x70); }

// ---------------- scratch (static device globals; no cudaMalloc) -------------
__device__ __align__(1024) unsigned char g_xpk[(size_t)512 * 5 * 16384]; // packed features (fp16 hi)
__device__ float g_xg[(size_t)NN * 1024];          // gates pre-activation
__device__ float g_H[(size_t)NN * 256];            // LSTM hidden
__device__ float g_C[(size_t)NN * 256];            // LSTM cell
__device__ int   g_mask_is_byte;

// packed weights (fp16 hi only)
__device__ __align__(1024) unsigned char g_Wihpk[40 * 16384];  // 8 colblk x 5 chunks (K=320 pad)
__device__ __align__(1024) unsigned char g_Whhpk[32 * 16384];  // 8 jblk x 4 chunks (K=256)
__device__ __align__(1024) unsigned char g_Wbmpk[16 * 16384];  // 16 chunks (K=1024 pad)
__device__ __align__(1024) unsigned char g_Wppk[8192];         // 64 rows x K=64

__device__ __forceinline__ float sigf(float x) { return 1.0f / (1.0f + expf(-x)); }

__device__ __forceinline__ int read_bool(const void* p, int idx) {
    return g_mask_is_byte ? (int)(((const unsigned char*)p)[idx])
                          : (((const int*)p)[idx] != 0);
}

__device__ __forceinline__ unsigned smem_u32(const void* p) {
    return (unsigned)__cvta_generic_to_shared(p);
}

// ---------------- mbarrier + bulk copy ---------------------------------------
#define MBAR_INIT(a) \
    asm volatile("mbarrier.init.shared.b64 [%0], 1;" :: "r"(a) : "memory")
#define MBAR_EXPECT(a, tx) \
    asm volatile("mbarrier.arrive.expect_tx.shared.b64 _, [%0], %1;" \
                 :: "r"(a), "r"(tx) : "memory")

__device__ __forceinline__ void mbar_wait(uint32_t mbar, uint32_t parity) {
    asm volatile(
        "{\n\t.reg .pred P;\n\t"
        "WL%=:\n\t"
        "mbarrier.try_wait.parity.shared.b64 P, [%0], %1;\n\t"
        "@!P bra WL%=;\n\t}"
        :: "r"(mbar), "r"(parity) : "memory");
}

__device__ __forceinline__ void bulk_g2s(uint32_t dst, const void* src,
                                         uint32_t bytes, uint32_t mbar) {
    asm volatile(
        "cp.async.bulk.shared::cluster.global.mbarrier::complete_tx::bytes "
        "[%0], [%1], %2, [%3];"
        :: "r"(dst), "l"(src), "r"(bytes), "r"(mbar) : "memory");
}

// ---------------- fp16 helpers ------------------------------------------------
__device__ __forceinline__ uint32_t packh2(float x, float y) {
    __half2 h = __floats2half2_rn(x, y);
    return *(uint32_t*)&h;
}
__device__ __forceinline__ void splith2(float x, float y, uint32_t& h, uint32_t& l) {
    __half hx = __float2half_rn(x), hy = __float2half_rn(y);
    __half lx = __float2half_rn(x - __half2float(hx));
    __half ly = __float2half_rn(y - __half2float(hy));
    h = ((uint32_t)__half_as_ushort(hy) << 16) | __half_as_ushort(hx);
    l = ((uint32_t)__half_as_ushort(ly) << 16) | __half_as_ushort(lx);
}

// ---------------- mma.sync m16n8k16 fp16 + ldmatrix --------------------------
__device__ __forceinline__ void mma_f16(float d[4], const uint32_t a[4], const uint32_t b[2]) {
    asm volatile(
        "mma.sync.aligned.m16n8k16.row.col.f32.f16.f16.f32 "
        "{%0,%1,%2,%3}, {%4,%5,%6,%7}, {%8,%9}, {%0,%1,%2,%3};\n"
        : "+f"(d[0]), "+f"(d[1]), "+f"(d[2]), "+f"(d[3])
        : "r"(a[0]), "r"(a[1]), "r"(a[2]), "r"(a[3]), "r"(b[0]), "r"(b[1]));
}

__device__ __forceinline__ void ldsm4(uint32_t r[4], const void* p) {
    uint32_t addr = smem_u32(p);
    asm volatile("ldmatrix.sync.aligned.m8n8.x4.shared.b16 {%0,%1,%2,%3}, [%4];"
                 : "=r"(r[0]), "=r"(r[1]), "=r"(r[2]), "=r"(r[3]) : "r"(addr));
}

// 1-pass K=64 tile, 32x64 warp tile (features: bm, xg)
__device__ __forceinline__ void mma_t64(const char* As, const char* Bs,
                                        int wm, int wn, int lane, float acc[2][8][4]) {
    int lrow = lane & 15, l16 = (lane >> 4) * 16;
#pragma unroll
    for (int ks = 0; ks < 4; ks++) {
        int kb = ks * 32 + l16;
        uint32_t a[2][4];
#pragma unroll
        for (int mt = 0; mt < 2; mt++)
            ldsm4(a[mt], As + swz((wm * 32 + mt * 16 + lrow) * 128 + kb));
#pragma unroll
        for (int g = 0; g < 4; g++) {
            uint32_t b[4];
            ldsm4(b, Bs + swz((wn * 64 + g * 16 + lrow) * 128 + kb));
            uint32_t b0[2] = { b[0], b[2] }, b1[2] = { b[1], b[3] };
#pragma unroll
            for (int mt = 0; mt < 2; mt++) {
                mma_f16(acc[mt][g * 2],     a[mt], b0);
                mma_f16(acc[mt][g * 2 + 1], a[mt], b1);
            }
        }
    }
}

// 1-pass K=64 tile, 32x32 warp tile (pool)
__device__ __forceinline__ void mma_t64_32(const char* As, const char* Bs,
                                           int wm, int wn, int lane, float acc[2][4][4]) {
    int lrow = lane & 15, l16 = (lane >> 4) * 16;
#pragma unroll
    for (int ks = 0; ks < 4; ks++) {
        int kb = ks * 32 + l16;
        uint32_t a[2][4];
#pragma unroll
        for (int mt = 0; mt < 2; mt++)
            ldsm4(a[mt], As + swz((wm * 32 + mt * 16 + lrow) * 128 + kb));
#pragma unroll
        for (int g = 0; g < 2; g++) {
            uint32_t b[4];
            ldsm4(b, Bs + swz((wn * 32 + g * 16 + lrow) * 128 + kb));
            uint32_t b0[2] = { b[0], b[2] }, b1[2] = { b[1], b[3] };
#pragma unroll
            for (int mt = 0; mt < 2; mt++) {
                mma_f16(acc[mt][g * 2],     a[mt], b0);
                mma_f16(acc[mt][g * 2 + 1], a[mt], b1);
            }
        }
    }
}

// 2-pass level chunk: A hi/lo K=32 (hi [0,64), lo [64,128)); B hi K=64 tile,
// byte offset bofs in {0, 64}. acc += Ah*B + Al*B.
__device__ __forceinline__ void mma_lvl(const char* As, const char* Bs, int bofs,
                                        int wm, int wn, int lane, float acc[2][8][4]) {
    int lrow = lane & 15, l16 = (lane >> 4) * 16;
#pragma unroll
    for (int ks = 0; ks < 2; ks++) {
        int ka = ks * 32 + l16;
        int kbb = bofs + ks * 32 + l16;
        uint32_t ah[2][4], al[2][4];
#pragma unroll
        for (int mt = 0; mt < 2; mt++) {
            int ro = (wm * 32 + mt * 16 + lrow) * 128;
            ldsm4(ah[mt], As + swz(ro + ka));
            ldsm4(al[mt], As + swz(ro + 64 + ka));
        }
#pragma unroll
        for (int g = 0; g < 4; g++) {
            uint32_t b[4];
            ldsm4(b, Bs + swz((wn * 64 + g * 16 + lrow) * 128 + kbb));
            uint32_t b0[2] = { b[0], b[2] }, b1[2] = { b[1], b[3] };
#pragma unroll
            for (int mt = 0; mt < 2; mt++) {
                mma_f16(acc[mt][g * 2],     ah[mt], b0);
                mma_f16(acc[mt][g * 2 + 1], ah[mt], b1);
                mma_f16(acc[mt][g * 2],     al[mt], b0);
                mma_f16(acc[mt][g * 2 + 1], al[mt], b1);
            }
        }
    }
}

// ---------------- A-side loaders (fp32 sources) -------------------------------
// K=64 tile loader: 128 rows x 8 units of 8 floats; 4 slots/thread
__device__ __forceinline__ void ldg_f32u(const float* __restrict__ src, int ld, int rowBase,
                                         int maxRow, int k0, int Ktot, int tid, float4 (*v)[2]) {
#pragma unroll
    for (int s = 0; s < 4; s++) {
        int idx = tid + 256 * s;
        int r = idx >> 3, u = idx & 7;
        int row = rowBase + r, k = k0 + u * 8;
        float4 a = make_float4(0.f, 0.f, 0.f, 0.f), b = a;
        if (row < maxRow && k + 8 <= Ktot) {
            const float* p = src + (size_t)row * ld + k;
            a = *(const float4*)p;
            b = *(const float4*)(p + 4);
        }
        v[s][0] = a; v[s][1] = b;
    }
}

__device__ __forceinline__ void sts_h64(char* As, int tid, float4 (*v)[2]) {
#pragma unroll
    for (int s = 0; s < 4; s++) {
        int idx = tid + 256 * s;
        int r = idx >> 3, u = idx & 7;
        uint4 h;
        h.x = packh2(v[s][0].x, v[s][0].y);
        h.y = packh2(v[s][0].z, v[s][0].w);
        h.z = packh2(v[s][1].x, v[s][1].y);
        h.w = packh2(v[s][1].z, v[s][1].w);
        *(uint4*)(As + swz(r * 128 + u * 16)) = h;
    }
}

// level A: K=32 chunk, 2 slots/thread, fp16 split hi/lo
__device__ __forceinline__ void ldg_avgH(int start, int nd, int rowBase, int k0, int tid,
                                         float4 (*v)[2]) {
#pragma unroll
    for (int s = 0; s < 2; s++) {
        int idx = tid + 256 * s;
        int r = idx >> 2, g = idx & 3;
        int rr = rowBase + r;
        float4 a = make_float4(0.f, 0.f, 0.f, 0.f), b = a;
        if (rr < nd) {
            int node = start + rr;
            int ci = 2 * node - NN;
            const float* p0 = g_H + (size_t)ci * 256 + k0 + g * 8;
            const float* p1 = g_H + (size_t)(ci - 1) * 256 + k0 + g * 8;
            float4 x0 = *(const float4*)p0, x1 = *(const float4*)(p0 + 4);
            float4 y0 = *(const float4*)p1, y1 = *(const float4*)(p1 + 4);
            a = make_float4(0.5f * (x0.x + y0.x), 0.5f * (x0.y + y0.y),
                            0.5f * (x0.z + y0.z), 0.5f * (x0.w + y0.w));
            b = make_float4(0.5f * (x1.x + y1.x), 0.5f * (x1.y + y1.y),
                            0.5f * (x1.z + y1.z), 0.5f * (x1.w + y1.w));
        }
        v[s][0] = a; v[s][1] = b;
    }
}

__device__ __forceinline__ void sts_splith(char* As, int tid, float4 (*v)[2]) {
#pragma unroll
    for (int s = 0; s < 2; s++) {
        int idx = tid + 256 * s;
        int r = idx >> 2, g = idx & 3;
        uint32_t h0, l0, h1, l1, h2, l2, h3, l3;
        splith2(v[s][0].x, v[s][0].y, h0, l0);
        splith2(v[s][0].z, v[s][0].w, h1, l1);
        splith2(v[s][1].x, v[s][1].y, h2, l2);
        splith2(v[s][1].z, v[s][1].w, h3, l3);
        *(uint4*)(As + swz(r * 128 + g * 16))      = make_uint4(h0, h1, h2, h3);
        *(uint4*)(As + swz(r * 128 + 64 + g * 16)) = make_uint4(l0, l1, l2, l3);
    }
}

// ---------------- small kernels ----------------------------------------------
__global__ void k_detect(const unsigned int* __restrict__ m) {
    __shared__ int found;
    if (threadIdx.x == 0) found = 0;
    __syncthreads();
    unsigned int v = m[threadIdx.x];
    if (v > 1u) found = 1;
    __syncthreads();
    if (threadIdx.x == 0) g_mask_is_byte = found;
}

__device__ __forceinline__ void pack8h(const float* s, unsigned char* dst,
                                       int r, int u, bool zero) {
    uint4 h;
    h.x = packh2(zero ? 0.f : s[0], zero ? 0.f : s[1]);
    h.y = packh2(zero ? 0.f : s[2], zero ? 0.f : s[3]);
    h.z = packh2(zero ? 0.f : s[4], zero ? 0.f : s[5]);
    h.w = packh2(zero ? 0.f : s[6], zero ? 0.f : s[7]);
    *(uint4*)(dst + swz(r * 128 + u * 16)) = h;
}

__global__ void k_wpack(const float* __restrict__ Wih, const float* __restrict__ Whh,
                        const float* __restrict__ Wbm, const float* __restrict__ Wp) {
    int i = blockIdx.x * 256 + threadIdx.x;
    const int N1 = 40 * 1024;
    const int N2 = 32 * 1024;
    const int N3 = 16 * 1024;
    const int N4 = 512;
    if (i < N1) {
        int t = i >> 10, rem = i & 1023, r = rem >> 3, u = rem & 7;
        int cb = t / 5, ch = t % 5;
        int k = ch * 64 + u * 8;
        bool zero = (k >= 288);
        pack8h(Wih + (size_t)(cb * 128 + r) * 288 + (zero ? 0 : k),
               g_Wihpk + (size_t)t * 16384, r, u, zero);
    } else if (i < N1 + N2) {
        int j = i - N1;
        int t = j >> 10, rem = j & 1023, r = rem >> 3, u = rem & 7;
        int jb = t / 4, ch = t % 4;
        int wrow = (r >> 5) * 256 + jb * 32 + (r & 31);
        pack8h(Whh + (size_t)wrow * 256 + ch * 64 + u * 8,
               g_Whhpk + (size_t)t * 16384, r, u, false);
    } else if (i < N1 + N2 + N3) {
        int j = i - N1 - N2;
        int t = j >> 10, rem = j & 1023, r = rem >> 3, u = rem & 7;
        int k = t * 64 + u * 8;
        bool zero = (k + 8 > 1000);
        pack8h(Wbm + (size_t)r * 1000 + (zero ? 0 : k),
               g_Wbmpk + (size_t)t * 16384, r, u, zero);
    } else if (i < N1 + N2 + N3 + N4) {
        int j = i - N1 - N2 - N3;
        int r = j >> 3, u = j & 7;
        pack8h(Wp + (size_t)r * 64 + u * 8, g_Wppk, r, u, false);
    }
}

__global__ void k_op(const float* __restrict__ op_vec,
                     const float* __restrict__ W_op,
                     const float* __restrict__ b_op) {
    __shared__ float Ws[32][33];
    __shared__ float bs[32];
    int tid = threadIdx.x;
    if (tid < 32) bs[tid] = b_op[tid];
    for (int i = tid; i < 1024; i += 256) Ws[i >> 5][i & 31] = W_op[i];
    __syncthreads();
    int node = blockIdx.x * 8 + (tid >> 5);
    int o = tid & 31;
    if (node >= NN) return;
    float vl = op_vec[node * 32 + o];
    float acc = bs[o];
#pragma unroll
    for (int p = 0; p < 32; p++)
        acc += Ws[o][p] * __shfl_sync(0xffffffffu, vl, p);
    int blk = node >> 7, r = node & 127;
    unsigned char* tb = g_xpk + (size_t)blk * 5 * 16384;   // chunk 0
    *(__half*)(tb + swz(r * 128 + o * 2)) = __float2half_rn(acc);
}

// ============ GEMM 1: pool (128Mx64N, single K=64 tile, 1-pass) ==============
__global__ __launch_bounds__(256, 3)
void k_pool_mma(const float* __restrict__ preds1, const void* mask1, const void* and1,
                const float* __restrict__ preds2, const void* mask2, const void* and2,
                const float* __restrict__ b_pred) {
    extern __shared__ char sm[];
    char* Abuf = sm;                 // 16KB
    char* Bbuf = sm + 16384;         // 8KB
    uint32_t mb = smem_u32(sm + 34816);
    float* stage = (float*)sm;       // [128][68] after GEMM (34816B)

    int tid = threadIdx.x, lane = tid & 31, warp = tid >> 5;
    int wm = warp >> 1, wn = warp & 1;
    int cond = blockIdx.y;
    const float* preds = cond ? preds2 : preds1;
    const void*  maskp = cond ? mask2 : mask1;
    const void*  andp  = cond ? and2  : and1;
    int rowBase = blockIdx.x * 128;

    if (tid == 0) MBAR_INIT(mb);
    __syncthreads();
    if (tid == 0) {
        MBAR_EXPECT(mb, 8192u);
        bulk_g2s(smem_u32(Bbuf), g_Wppk, 8192u, mb);
    }

    float acc[2][4][4];
#pragma unroll
    for (int a = 0; a < 2; a++)
#pragma unroll
        for (int b = 0; b < 4; b++)
#pragma unroll
            for (int c = 0; c < 4; c++) acc[a][b][c] = 0.f;

    float4 va[4][2];
    ldg_f32u(preds, 64, rowBase, MRPOOL, 0, 64, tid, va);
    sts_h64(Abuf, tid, va);
    mbar_wait(mb, 0);
    __syncthreads();

    mma_t64_32(Abuf, Bbuf, wm, wn, lane, acc);
    __syncthreads();

#pragma unroll
    for (int mt = 0; mt < 2; mt++) {
#pragma unroll
        for (int nt = 0; nt < 4; nt++) {
            int r = wm * 32 + mt * 16 + (lane >> 2);
            int c = wn * 32 + nt * 8 + (lane & 3) * 2;
            stage[r * 68 + c] = acc[mt][nt][0];
            stage[r * 68 + c + 1] = acc[mt][nt][1];
            stage[(r + 8) * 68 + c] = acc[mt][nt][2];
            stage[(r + 8) * 68 + c + 1] = acc[mt][nt][3];
        }
    }
    __syncthreads();

    int node = blockIdx.x * 16 + (tid >> 4);
    int cg = (tid & 15) * 4;
    if (node < NN) {
        float bb[4];
        *(float4*)bb = *(const float4*)(b_pred + cg);
        int mk[8], anyb = 0;
#pragma unroll
        for (int i = 0; i < 8; i++) { mk[i] = read_bool(maskp, node * 8 + i); anyb |= mk[i]; }
        int ia = read_bool(andp, node);
        int rb = (tid >> 4) * 8;
        float out[4];
#pragma unroll
        for (int j = 0; j < 4; j++) {
            float mn = BIGF, mx = -BIGF;
#pragma unroll
            for (int i = 0; i < 8; i++) {
                float v = stage[(rb + i) * 68 + cg + j] + bb[j];
                if (mk[i]) { mn = fminf(mn, v); mx = fmaxf(mx, v); }
            }
            out[j] = anyb ? (ia ? mn : mx) : 0.0f;
        }
        int col0 = 32 + cond * 64 + cg;
        int ch = col0 >> 6, co = col0 & 63;
        int r = node & 127;
        unsigned char* tb = g_xpk + ((size_t)(node >> 7) * 5 + ch) * 16384;
        *(uint2*)(tb + swz(r * 128 + co * 2)) =
            make_uint2(packh2(out[0], out[1]), packh2(out[2], out[3]));
    }
}

// ============ GEMM 2: bm (128Mx128N, 16 K=64 chunks, 1-pass) =================
__global__ __launch_bounds__(256, 2)
void k_bm_mma(const float* __restrict__ bitmap, const float* __restrict__ b_bm) {
    extern __shared__ char sm[];
    char* Abuf[2] = { sm, sm + 16384 };
    char* Bbuf[2] = { sm + 32768, sm + 49152 };
    uint32_t mb = smem_u32(sm + 65536);
    int tid = threadIdx.x, lane = tid & 31, warp = tid >> 5;
    int wm = warp >> 1, wn = warp & 1;
    int rowBase = blockIdx.x * 128;

    if (tid == 0) { MBAR_INIT(mb); MBAR_INIT(mb + 8); }
    __syncthreads();
    if (tid == 0) {
        MBAR_EXPECT(mb, 16384u);
        bulk_g2s(smem_u32(Bbuf[0]), g_Wbmpk, 16384u, mb);
        MBAR_EXPECT(mb + 8, 16384u);
        bulk_g2s(smem_u32(Bbuf[1]), g_Wbmpk + 16384, 16384u, mb + 8);
    }

    float acc[2][8][4];
#pragma unroll
    for (int a = 0; a < 2; a++)
#pragma unroll
        for (int b = 0; b < 8; b++)
#pragma unroll
            for (int c = 0; c < 4; c++) acc[a][b][c] = 0.f;

    float4 va[4][2];
    ldg_f32u(bitmap, 1000, rowBase, NN, 0, 1000, tid, va);
    sts_h64(Abuf[0], tid, va);
    __syncthreads();

    const int NC = 16;
    for (int t = 0; t < NC; t++) {
        bool more = (t + 1 < NC);
        if (more) ldg_f32u(bitmap, 1000, rowBase, NN, (t + 1) * 64, 1000, tid, va);
        mbar_wait(mb + 8 * (t & 1), (t >> 1) & 1);
        mma_t64(Abuf[t & 1], Bbuf[t & 1], wm, wn, lane, acc);
        if (more) sts_h64(Abuf[(t + 1) & 1], tid, va);
        __syncthreads();
        if (tid == 0 && t + 2 < NC) {
            int s = t + 2, b = s & 1;
            MBAR_EXPECT(mb + 8 * b, 16384u);
            bulk_g2s(smem_u32(Bbuf[b]), g_Wbmpk + (size_t)s * 16384, 16384u, mb + 8 * b);
        }
    }

#pragma unroll
    for (int nt = 0; nt < 8; nt++) {
        int c = wn * 64 + nt * 8 + (lane & 3) * 2;
        float bx = b_bm[c], by = b_bm[c + 1];
        int ch = (160 + c) >> 6, co = (160 + c) & 63;
#pragma unroll
        for (int mt = 0; mt < 2; mt++) {
            int r0 = rowBase + wm * 32 + mt * 16 + (lane >> 2);
#pragma unroll
            for (int hh = 0; hh < 2; hh++) {
                int row = r0 + hh * 8;
                if (row < NN) {
                    int r = row & 127;
                    unsigned char* tb = g_xpk + ((size_t)(row >> 7) * 5 + ch) * 16384;
                    *(uint32_t*)(tb + swz(r * 128 + co * 2)) =
                        packh2(acc[mt][nt][hh * 2] + bx, acc[mt][nt][hh * 2 + 1] + by);
                }
            }
        }
    }
}

// ============ GEMM 3: xg (128Mx128N, 5 K=64 chunks, all-bulk, 1-pass) ========
__global__ __launch_bounds__(256, 2)
void k_xg_mma(const float* __restrict__ b_ih, const float* __restrict__ b_hh) {
    int colBase = blockIdx.x * 128;
    int rowBase = blockIdx.y * 128;
    // f-gate columns [256,512) are never read for leaf nodes (< 32768)
    if ((colBase == 256 || colBase == 384) && rowBase + 128 <= 32768) return;

    extern __shared__ char sm[];
    uint32_t mb = smem_u32(sm + 98304);
    int tid = threadIdx.x, lane = tid & 31, warp = tid >> 5;
    int wm = warp >> 1, wn = warp & 1;
    int cb = colBase >> 7;
    int rb5 = (rowBase >> 7) * 5;

    if (tid == 0) { MBAR_INIT(mb); MBAR_INIT(mb + 8); MBAR_INIT(mb + 16); }
    __syncthreads();
    const int NC = 5;
    if (tid == 0) {
#pragma unroll
        for (int s = 0; s < 3; s++) {
            char* base = sm + s * 32768;
            MBAR_EXPECT(mb + 8 * s, 32768u);
            bulk_g2s(smem_u32(base), g_xpk + ((size_t)rb5 + s) * 16384, 16384u, mb + 8 * s);
            bulk_g2s(smem_u32(base + 16384), g_Wihpk + ((size_t)cb * 5 + s) * 16384,
                     16384u, mb + 8 * s);
        }
    }

    float acc[2][8][4];
#pragma unroll
    for (int a = 0; a < 2; a++)
#pragma unroll
        for (int b = 0; b < 8; b++)
#pragma unroll
            for (int c = 0; c < 4; c++) acc[a][b][c] = 0.f;

    for (int t = 0; t < NC; t++) {
        int b = t % 3;
        mbar_wait(mb + 8 * b, (uint32_t)((t / 3) & 1));
        mma_t64(sm + b * 32768, sm + b * 32768 + 16384, wm, wn, lane, acc);
        __syncthreads();
        if (tid == 0 && t + 3 < NC) {
            int s = t + 3;
            char* base = sm + b * 32768;
            MBAR_EXPECT(mb + 8 * b, 32768u);
            bulk_g2s(smem_u32(base), g_xpk + ((size_t)rb5 + s) * 16384, 16384u, mb + 8 * b);
            bulk_g2s(smem_u32(base + 16384), g_Wihpk + ((size_t)cb * 5 + s) * 16384,
                     16384u, mb + 8 * b);
        }
    }

#pragma unroll
    for (int nt = 0; nt < 8; nt++) {
        int c = colBase + wn * 64 + nt * 8 + (lane & 3) * 2;
        float bx = b_ih[c] + b_hh[c], by = b_ih[c + 1] + b_hh[c + 1];
#pragma unroll
        for (int mt = 0; mt < 2; mt++) {
            int r0 = rowBase + wm * 32 + mt * 16 + (lane >> 2);
            if (r0 < NN)
                *(float2*)(g_xg + (size_t)r0 * 1024 + c) =
                    make_float2(acc[mt][nt][0] + bx, acc[mt][nt][1] + by);
            if (r0 + 8 < NN)
                *(float2*)(g_xg + (size_t)(r0 + 8) * 1024 + c) =
                    make_float2(acc[mt][nt][2] + bx, acc[mt][nt][3] + by);
        }
    }
}

// ============ level kernel (nd >= 128): 2-pass A-split + LSTM pointwise ======
__global__ __launch_bounds__(256, 2)
void k_level_mma(int start, int nd) {
    extern __shared__ char sm[];
    char* Abuf[2] = { sm, sm + 16384 };
    char* Bbuf[2] = { sm + 32768, sm + 49152 };
    uint32_t mb = smem_u32(sm + 67584);
    float* stage = (float*)sm;   // [128][132] after GEMM (67584B)

    int tid = threadIdx.x, lane = tid & 31, warp = tid >> 5;
    int wm = warp >> 1, wn = warp & 1;
    int rowBase = blockIdx.x * 128;
    int jb = blockIdx.y;          // j block (32 wide)

    if (tid == 0) { MBAR_INIT(mb); MBAR_INIT(mb + 8); }
    __syncthreads();
    if (tid == 0) {
        MBAR_EXPECT(mb, 16384u);
        bulk_g2s(smem_u32(Bbuf[0]), g_Whhpk + (size_t)(jb * 4) * 16384, 16384u, mb);
        MBAR_EXPECT(mb + 8, 16384u);
        bulk_g2s(smem_u32(Bbuf[1]), g_Whhpk + (size_t)(jb * 4 + 1) * 16384, 16384u, mb + 8);
    }

    float acc[2][8][4];
#pragma unroll
    for (int a = 0; a < 2; a++)
#pragma unroll
        for (int b = 0; b < 8; b++)
#pragma unroll
            for (int c = 0; c < 4; c++) acc[a][b][c] = 0.f;

    float4 va[2][2];
    ldg_avgH(start, nd, rowBase, 0, tid, va);
    sts_splith(Abuf[0], tid, va);
    __syncthreads();

    const int NC = 8;   // K=32 chunks; B tile = 2 chunks
    for (int t = 0; t < NC; t++) {
        bool more = (t + 1 < NC);
        if (more) ldg_avgH(start, nd, rowBase, (t + 1) * 32, tid, va);
        int bt = t >> 1;
        if ((t & 1) == 0) mbar_wait(mb + 8 * (bt & 1), (bt >> 1) & 1);
        mma_lvl(Abuf[t & 1], Bbuf[bt & 1], (t & 1) * 64, wm, wn, lane, acc);
        if (more) sts_splith(Abuf[(t + 1) & 1], tid, va);
        __syncthreads();
        if (tid == 0 && (t & 1) == 1 && bt + 2 <= 3) {
            int s = bt + 2, b = s & 1;
            MBAR_EXPECT(mb + 8 * b, 16384u);
            bulk_g2s(smem_u32(Bbuf[b]), g_Whhpk + (size_t)(jb * 4 + s) * 16384,
                     16384u, mb + 8 * b);
        }
    }

#pragma unroll
    for (int mt = 0; mt < 2; mt++) {
#pragma unroll
        for (int nt = 0; nt < 8; nt++) {
            int r = wm * 32 + mt * 16 + (lane >> 2);
            int c = wn * 64 + nt * 8 + (lane & 3) * 2;
            stage[r * 132 + c] = acc[mt][nt][0];
            stage[r * 132 + c + 1] = acc[mt][nt][1];
            stage[(r + 8) * 132 + c] = acc[mt][nt][2];
            stage[(r + 8) * 132 + c + 1] = acc[mt][nt][3];
        }
    }
    __syncthreads();

#pragma unroll
    for (int i = 0; i < 16; i++) {
        int idx = tid + 256 * i;
        int r = idx >> 5, jj = idx & 31;
        int rr = rowBase + r;
        if (rr < nd) {
            int node = start + rr;
            int j = jb * 32 + jj;
            const float* xr = g_xg + (size_t)node * 1024;
            float gi = stage[r * 132 + jj]       + xr[j];
            float gf = stage[r * 132 + 32 + jj]  + xr[256 + j];
            float gg = stage[r * 132 + 64 + jj]  + xr[512 + j];
            float go = stage[r * 132 + 96 + jj]  + xr[768 + j];
            int ci = 2 * node - NN;
            float c0 = 0.5f * (g_C[(size_t)ci * 256 + j] + g_C[(size_t)(ci - 1) * 256 + j]);
            float cn = sigf(gf) * c0 + sigf(gi) * tanhf(gg);
            float hn = sigf(go) * tanhf(cn);
            g_H[(size_t)node * 256 + j] = hn;
            g_C[(size_t)node * 256 + j] = cn;
        }
    }
}

// ---------------- leaves (d = D): c0 = 0 -------------------------------------
__global__ void k_leaf() {
    int n = blockIdx.x;
    int j = threadIdx.x;
    const float* xr = g_xg + (size_t)n * 1024;
    float gi = xr[j];
    float gg = xr[512 + j];
    float go = xr[768 + j];
    float c = sigf(gi) * tanhf(gg);
    float h = sigf(go) * tanhf(c);
    g_H[(size_t)n * 256 + j] = h;
    g_C[(size_t)n * 256 + j] = c;
}

// ---------------- SIMT level kernel for small levels -------------------------
__global__ __launch_bounds__(256)
void k_level(int start, int nd, const float* __restrict__ W_hh) {
    __shared__ float h0s[32][36];
    __shared__ float Ws[256][36];
    int tid = threadIdx.x;
    int jx = tid & 63, ry = tid >> 6;
    int rowBase = blockIdx.x * 32;
    int jbase = blockIdx.y * 64;

    float acc[8][4];
#pragma unroll
    for (int i = 0; i < 8; i++)
#pragma unroll
        for (int g = 0; g < 4; g++) acc[i][g] = 0.0f;

    for (int k0 = 0; k0 < 256; k0 += 32) {
        {
            int r = tid >> 3, c4 = tid & 7;
            float4 v = make_float4(0.f, 0.f, 0.f, 0.f);
            int rr = rowBase + r;
            if (rr < nd) {
                int node = start + rr;
                int ci = 2 * node - NN;
                float4 a = *(const float4*)&g_H[(size_t)ci * 256 + k0 + c4 * 4];
                float4 b = *(const float4*)&g_H[(size_t)(ci - 1) * 256 + k0 + c4 * 4];
                v = make_float4(0.5f * (a.x + b.x), 0.5f * (a.y + b.y),
                                0.5f * (a.z + b.z), 0.5f * (a.w + b.w));
            }
            *(float4*)&h0s[r][c4 * 4] = v;
        }
        {
            int wrow = ry * 256 + jbase + jx;
            const float* src = &W_hh[(size_t)wrow * 256 + k0];
#pragma unroll
            for (int c = 0; c < 8; c++)
                *(float4*)&Ws[tid][c * 4] = *(const float4*)&src[c * 4];
        }
        __syncthreads();
#pragma unroll
        for (int kk4 = 0; kk4 < 8; kk4++) {
            float4 w4[4];
#pragma unroll
            for (int g = 0; g < 4; g++)
                w4[g] = *(const float4*)&Ws[g * 64 + jx][kk4 * 4];
#pragma unroll
            for (int i = 0; i < 8; i++) {
                float4 a4 = *(const float4*)&h0s[ry * 8 + i][kk4 * 4];
#pragma unroll
                for (int g = 0; g < 4; g++)
                    acc[i][g] += a4.x * w4[g].x + a4.y * w4[g].y +
                                 a4.z * w4[g].z + a4.w * w4[g].w;
            }
        }
        __syncthreads();
    }

    int j = jbase + jx;
#pragma unroll
    for (int i = 0; i < 8; i++) {
        int rr = rowBase + ry * 8 + i;
        if (rr < nd) {
            int node = start + rr;
            const float* xr = g_xg + (size_t)node * 1024;
            float gi = acc[i][0] + xr[j];
            float gf = acc[i][1] + xr[256 + j];
            float gg = acc[i][2] + xr[512 + j];
            float go = acc[i][3] + xr[768 + j];
            int ci = 2 * node - NN;
            float c0 = 0.5f * (g_C[(size_t)ci * 256 + j] + g_C[(size_t)(ci - 1) * 256 + j]);
            float cn = sigf(gf) * c0 + sigf(gi) * tanhf(gg);
            float hn = sigf(go) * tanhf(cn);
            g_H[(size_t)node * 256 + j] = hn;
            g_C[(size_t)node * 256 + j] = cn;
        }
    }
}

// ---------------- output heads ----------------------------------------------
__global__ void k_heads(const float* __restrict__ W2a, const float* __restrict__ b2a,
                        const float* __restrict__ W3a, const float* __restrict__ b3a,
                        const float* __restrict__ Woa, const float* __restrict__ boa,
                        const float* __restrict__ W2b, const float* __restrict__ b2b,
                        const float* __restrict__ W3b, const float* __restrict__ b3b,
                        const float* __restrict__ Wob, const float* __restrict__ bob,
                        float* __restrict__ out) {
    __shared__ float hv[256];
    __shared__ float t1[2][128];
    __shared__ float t2[2][128];
    __shared__ float red[256];
    int tid = threadIdx.x;
    hv[tid] = g_H[(size_t)(NN - 1) * 256 + tid];
    __syncthreads();
    int head = tid >> 7, j = tid & 127;
    const float* W2 = head ? W2b : W2a; const float* b2 = head ? b2b : b2a;
    const float* W3 = head ? W3b : W3a; const float* b3 = head ? b3b : b3a;
    const float* Wo = head ? Wob : Woa; const float* bo = head ? bob : boa;

    float t = b2[j];
    for (int k = 0; k < 256; k++) t += W2[j * 256 + k] * hv[k];
    t1[head][j] = fmaxf(t, 0.0f);
    __syncthreads();
    t = b3[j];
    for (int k = 0; k < 128; k++) t += W3[j * 128 + k] * t1[head][k];
    t2[head][j] = fmaxf(t, 0.0f);
    __syncthreads();
    red[tid] = Wo[j] * t2[head][j];
    __syncthreads();
    for (int s = 64; s > 0; s >>= 1) {
        if (j < s) red[tid] += red[tid + s];
        __syncthreads();
    }
    if (j == 0) out[head] = 1.0f / (1.0f + expf(-(red[tid] + bo[0])));
}

// ---------------- launch ------------------------------------------------------
extern "C" void kernel_launch(void* const* d_in, const int* in_sizes, int n_in,
                              void* d_out, int out_size) {
    const float* op_vec   = (const float*)d_in[0];
    const float* c1_preds = (const float*)d_in[1];
    const void*  c1_mask  = d_in[2];
    const void*  c1_and   = d_in[3];
    const float* c2_preds = (const float*)d_in[4];
    const void*  c2_mask  = d_in[5];
    const void*  c2_and   = d_in[6];
    const float* bitmap   = (const float*)d_in[7];
    const float* W_op     = (const float*)d_in[8];
    const float* b_op     = (const float*)d_in[9];
    const float* W_pred   = (const float*)d_in[10];
    const float* b_pred   = (const float*)d_in[11];
    const float* W_bm     = (const float*)d_in[12];
    const float* b_bm     = (const float*)d_in[13];
    const float* W_ih     = (const float*)d_in[14];
    const float* b_ih     = (const float*)d_in[15];
    const float* W_hh     = (const float*)d_in[16];
    const float* b_hh     = (const float*)d_in[17];
    const float* W_h2t1   = (const float*)d_in[18];
    const float* b_h2t1   = (const float*)d_in[19];
    const float* W_h3t1   = (const float*)d_in[20];
    const float* b_h3t1   = (const float*)d_in[21];
    const float* W_o1     = (const float*)d_in[22];
    const float* b_o1     = (const float*)d_in[23];
    const float* W_h2t2   = (const float*)d_in[24];
    const float* b_h2t2   = (const float*)d_in[25];
    const float* W_h3t2   = (const float*)d_in[26];
    const float* b_h3t2   = (const float*)d_in[27];
    const float* W_o2     = (const float*)d_in[28];
    const float* b_o2     = (const float*)d_in[29];
    float* out = (float*)d_out;

    const int SM_PL = 34816 + 64;
    const int SM_BM = 65536 + 64;
    const int SM_XG = 98304 + 64;
    const int SM_LV = 67584 + 64;
    static int configured = 0;
    if (!configured) {
        cudaFuncSetAttribute(k_pool_mma, cudaFuncAttributeMaxDynamicSharedMemorySize, SM_PL);
        cudaFuncSetAttribute(k_bm_mma,   cudaFuncAttributeMaxDynamicSharedMemorySize, SM_BM);
        cudaFuncSetAttribute(k_xg_mma,   cudaFuncAttributeMaxDynamicSharedMemorySize, SM_XG);
        cudaFuncSetAttribute(k_level_mma,cudaFuncAttributeMaxDynamicSharedMemorySize, SM_LV);
        configured = 1;
    }

    k_detect<<<1, 256>>>((const unsigned int*)c1_mask);
    k_wpack<<<(40 * 1024 + 32 * 1024 + 16 * 1024 + 512 + 255) / 256, 256>>>(
        W_ih, W_hh, W_bm, W_pred);

    k_op<<<(NN + 7) / 8, 256>>>(op_vec, W_op, b_op);

    {
        dim3 grid((MRPOOL + 127) / 128, 2);
        k_pool_mma<<<grid, 256, SM_PL>>>(c1_preds, c1_mask, c1_and,
                                         c2_preds, c2_mask, c2_and, b_pred);
    }

    k_bm_mma<<<(NN + 127) / 128, 256, SM_BM>>>(bitmap, b_bm);

    {
        dim3 grid(8, (NN + 127) / 128);
        k_xg_mma<<<grid, 256, SM_XG>>>(b_ih, b_hh);
    }

    k_leaf<<<32768, 256>>>();

    for (int d = 14; d >= 0; d--) {
        int nd = 1 << d;
        int start = NN - (1 << (d + 1)) + 1;
        if (nd >= 128) {
            dim3 grid((nd + 127) / 128, 8);
            k_level_mma<<<grid, 256, SM_LV>>>(start, nd);
        } else {
            dim3 grid((nd + 31) / 32, 4);
            k_level<<<grid, 256>>>(start, nd, W_hh);
        }
    }

    k_heads<<<1, 256>>>(W_h2t1, b_h2t1, W_h3t1, b_h3t1, W_o1, b_o1,
                        W_h2t2, b_h2t2, W_h3t2, b_h3t2, W_o2, b_o2,
                        out);
}

// round 12
// speedup vs baseline: 10.8109x; 1.0246x over previous
#include <cuda_runtime.h>
#include <cuda_fp16.h>
#include <math.h>
#include <cstdint>
#include <stdint.h>

#define NN 65535          // number of tree nodes (2^16 - 1)
#define MRPOOL (NN * 8)   // pool GEMM rows
#define BIGF 1e30f

// Packed tile: 128 rows x 64 fp16 K-values (128B/row), SW128-swizzled
// (byte o -> o ^ ((o>>3)&0x70)); 16KB per tile, bulk-copyable verbatim.
__device__ __forceinline__ int swz(int o) { return o ^ ((o >> 3) & 0x70); }

// ---------------- scratch (static device globals; no cudaMalloc) -------------
__device__ __align__(1024) unsigned char g_xpk[(size_t)512 * 5 * 16384]; // packed features (fp16)
__device__ __half g_xg[(size_t)NN * 1024];         // gates pre-activation (fp16)
__device__ float g_H[(size_t)NN * 256];            // LSTM hidden
__device__ float g_C[(size_t)NN * 256];            // LSTM cell
__device__ int   g_mask_is_byte;

// packed weights (fp16)
__device__ __align__(1024) unsigned char g_Wihpk[40 * 16384];  // 8 colblk x 5 chunks (K=320 pad)
__device__ __align__(1024) unsigned char g_Whhpk[32 * 16384];  // 8 jblk x 4 chunks (K=256)
__device__ __align__(1024) unsigned char g_Wbmpk[16 * 16384];  // 16 chunks (K=1024 pad)
__device__ __align__(1024) unsigned char g_Wppk[8192];         // 64 rows x K=64

__device__ __forceinline__ float sigf(float x) { return 1.0f / (1.0f + expf(-x)); }

__device__ __forceinline__ int read_bool(const void* p, int idx) {
    return g_mask_is_byte ? (int)(((const unsigned char*)p)[idx])
                          : (((const int*)p)[idx] != 0);
}

__device__ __forceinline__ unsigned smem_u32(const void* p) {
    return (unsigned)__cvta_generic_to_shared(p);
}

// ---------------- mbarrier + bulk copy ---------------------------------------
#define MBAR_INIT(a) \
    asm volatile("mbarrier.init.shared.b64 [%0], 1;" :: "r"(a) : "memory")
#define MBAR_EXPECT(a, tx) \
    asm volatile("mbarrier.arrive.expect_tx.shared.b64 _, [%0], %1;" \
                 :: "r"(a), "r"(tx) : "memory")

__device__ __forceinline__ void mbar_wait(uint32_t mbar, uint32_t parity) {
    asm volatile(
        "{\n\t.reg .pred P;\n\t"
        "WL%=:\n\t"
        "mbarrier.try_wait.parity.shared.b64 P, [%0], %1;\n\t"
        "@!P bra WL%=;\n\t}"
        :: "r"(mbar), "r"(parity) : "memory");
}

__device__ __forceinline__ void bulk_g2s(uint32_t dst, const void* src,
                                         uint32_t bytes, uint32_t mbar) {
    asm volatile(
        "cp.async.bulk.shared::cluster.global.mbarrier::complete_tx::bytes "
        "[%0], [%1], %2, [%3];"
        :: "r"(dst), "l"(src), "r"(bytes), "r"(mbar) : "memory");
}

// ---------------- fp16 helpers ------------------------------------------------
__device__ __forceinline__ uint32_t packh2(float x, float y) {
    __half2 h = __floats2half2_rn(x, y);
    return *(uint32_t*)&h;
}
__device__ __forceinline__ void splith2(float x, float y, uint32_t& h, uint32_t& l) {
    __half hx = __float2half_rn(x), hy = __float2half_rn(y);
    __half lx = __float2half_rn(x - __half2float(hx));
    __half ly = __float2half_rn(y - __half2float(hy));
    h = ((uint32_t)__half_as_ushort(hy) << 16) | __half_as_ushort(hx);
    l = ((uint32_t)__half_as_ushort(ly) << 16) | __half_as_ushort(lx);
}

// ---------------- mma.sync m16n8k16 fp16 + ldmatrix --------------------------
__device__ __forceinline__ void mma_f16(float d[4], const uint32_t a[4], const uint32_t b[2]) {
    asm volatile(
        "mma.sync.aligned.m16n8k16.row.col.f32.f16.f16.f32 "
        "{%0,%1,%2,%3}, {%4,%5,%6,%7}, {%8,%9}, {%0,%1,%2,%3};\n"
        : "+f"(d[0]), "+f"(d[1]), "+f"(d[2]), "+f"(d[3])
        : "r"(a[0]), "r"(a[1]), "r"(a[2]), "r"(a[3]), "r"(b[0]), "r"(b[1]));
}

__device__ __forceinline__ void ldsm4(uint32_t r[4], const void* p) {
    uint32_t addr = smem_u32(p);
    asm volatile("ldmatrix.sync.aligned.m8n8.x4.shared.b16 {%0,%1,%2,%3}, [%4];"
                 : "=r"(r[0]), "=r"(r[1]), "=r"(r[2]), "=r"(r[3]) : "r"(addr));
}

// 1-pass K=64 tile, 32x64 warp tile (features: bm, xg)
__device__ __forceinline__ void mma_t64(const char* As, const char* Bs,
                                        int wm, int wn, int lane, float acc[2][8][4]) {
    int lrow = lane & 15, l16 = (lane >> 4) * 16;
#pragma unroll
    for (int ks = 0; ks < 4; ks++) {
        int kb = ks * 32 + l16;
        uint32_t a[2][4];
#pragma unroll
        for (int mt = 0; mt < 2; mt++)
            ldsm4(a[mt], As + swz((wm * 32 + mt * 16 + lrow) * 128 + kb));
#pragma unroll
        for (int g = 0; g < 4; g++) {
            uint32_t b[4];
            ldsm4(b, Bs + swz((wn * 64 + g * 16 + lrow) * 128 + kb));
            uint32_t b0[2] = { b[0], b[2] }, b1[2] = { b[1], b[3] };
#pragma unroll
            for (int mt = 0; mt < 2; mt++) {
                mma_f16(acc[mt][g * 2],     a[mt], b0);
                mma_f16(acc[mt][g * 2 + 1], a[mt], b1);
            }
        }
    }
}

// 1-pass K=64 tile, 32x32 warp tile (pool)
__device__ __forceinline__ void mma_t64_32(const char* As, const char* Bs,
                                           int wm, int wn, int lane, float acc[2][4][4]) {
    int lrow = lane & 15, l16 = (lane >> 4) * 16;
#pragma unroll
    for (int ks = 0; ks < 4; ks++) {
        int kb = ks * 32 + l16;
        uint32_t a[2][4];
#pragma unroll
        for (int mt = 0; mt < 2; mt++)
            ldsm4(a[mt], As + swz((wm * 32 + mt * 16 + lrow) * 128 + kb));
#pragma unroll
        for (int g = 0; g < 2; g++) {
            uint32_t b[4];
            ldsm4(b, Bs + swz((wn * 32 + g * 16 + lrow) * 128 + kb));
            uint32_t b0[2] = { b[0], b[2] }, b1[2] = { b[1], b[3] };
#pragma unroll
            for (int mt = 0; mt < 2; mt++) {
                mma_f16(acc[mt][g * 2],     a[mt], b0);
                mma_f16(acc[mt][g * 2 + 1], a[mt], b1);
            }
        }
    }
}

// 2-pass level chunk: A hi/lo K=32 (hi [0,64), lo [64,128)); B hi K=64 tile,
// byte offset bofs in {0, 64}. acc += Ah*B + Al*B.
__device__ __forceinline__ void mma_lvl(const char* As, const char* Bs, int bofs,
                                        int wm, int wn, int lane, float acc[2][8][4]) {
    int lrow = lane & 15, l16 = (lane >> 4) * 16;
#pragma unroll
    for (int ks = 0; ks < 2; ks++) {
        int ka = ks * 32 + l16;
        int kbb = bofs + ks * 32 + l16;
        uint32_t ah[2][4], al[2][4];
#pragma unroll
        for (int mt = 0; mt < 2; mt++) {
            int ro = (wm * 32 + mt * 16 + lrow) * 128;
            ldsm4(ah[mt], As + swz(ro + ka));
            ldsm4(al[mt], As + swz(ro + 64 + ka));
        }
#pragma unroll
        for (int g = 0; g < 4; g++) {
            uint32_t b[4];
            ldsm4(b, Bs + swz((wn * 64 + g * 16 + lrow) * 128 + kbb));
            uint32_t b0[2] = { b[0], b[2] }, b1[2] = { b[1], b[3] };
#pragma unroll
            for (int mt = 0; mt < 2; mt++) {
                mma_f16(acc[mt][g * 2],     ah[mt], b0);
                mma_f16(acc[mt][g * 2 + 1], ah[mt], b1);
                mma_f16(acc[mt][g * 2],     al[mt], b0);
                mma_f16(acc[mt][g * 2 + 1], al[mt], b1);
            }
        }
    }
}

// ---------------- A-side loaders (fp32 sources) -------------------------------
// K=64 tile loader: 128 rows x 8 units of 8 floats; 4 slots/thread
__device__ __forceinline__ void ldg_f32u(const float* __restrict__ src, int ld, int rowBase,
                                         int maxRow, int k0, int Ktot, int tid, float4 (*v)[2]) {
#pragma unroll
    for (int s = 0; s < 4; s++) {
        int idx = tid + 256 * s;
        int r = idx >> 3, u = idx & 7;
        int row = rowBase + r, k = k0 + u * 8;
        float4 a = make_float4(0.f, 0.f, 0.f, 0.f), b = a;
        if (row < maxRow && k + 8 <= Ktot) {
            const float* p = src + (size_t)row * ld + k;
            a = *(const float4*)p;
            b = *(const float4*)(p + 4);
        }
        v[s][0] = a; v[s][1] = b;
    }
}

__device__ __forceinline__ void sts_h64(char* As, int tid, float4 (*v)[2]) {
#pragma unroll
    for (int s = 0; s < 4; s++) {
        int idx = tid + 256 * s;
        int r = idx >> 3, u = idx & 7;
        uint4 h;
        h.x = packh2(v[s][0].x, v[s][0].y);
        h.y = packh2(v[s][0].z, v[s][0].w);
        h.z = packh2(v[s][1].x, v[s][1].y);
        h.w = packh2(v[s][1].z, v[s][1].w);
        *(uint4*)(As + swz(r * 128 + u * 16)) = h;
    }
}

// level A: K=32 chunk, 2 slots/thread, fp16 split hi/lo
__device__ __forceinline__ void ldg_avgH(int start, int nd, int rowBase, int k0, int tid,
                                         float4 (*v)[2]) {
#pragma unroll
    for (int s = 0; s < 2; s++) {
        int idx = tid + 256 * s;
        int r = idx >> 2, g = idx & 3;
        int rr = rowBase + r;
        float4 a = make_float4(0.f, 0.f, 0.f, 0.f), b = a;
        if (rr < nd) {
            int node = start + rr;
            int ci = 2 * node - NN;
            const float* p0 = g_H + (size_t)ci * 256 + k0 + g * 8;
            const float* p1 = g_H + (size_t)(ci - 1) * 256 + k0 + g * 8;
            float4 x0 = *(const float4*)p0, x1 = *(const float4*)(p0 + 4);
            float4 y0 = *(const float4*)p1, y1 = *(const float4*)(p1 + 4);
            a = make_float4(0.5f * (x0.x + y0.x), 0.5f * (x0.y + y0.y),
                            0.5f * (x0.z + y0.z), 0.5f * (x0.w + y0.w));
            b = make_float4(0.5f * (x1.x + y1.x), 0.5f * (x1.y + y1.y),
                            0.5f * (x1.z + y1.z), 0.5f * (x1.w + y1.w));
        }
        v[s][0] = a; v[s][1] = b;
    }
}

__device__ __forceinline__ void sts_splith(char* As, int tid, float4 (*v)[2]) {
#pragma unroll
    for (int s = 0; s < 2; s++) {
        int idx = tid + 256 * s;
        int r = idx >> 2, g = idx & 3;
        uint32_t h0, l0, h1, l1, h2, l2, h3, l3;
        splith2(v[s][0].x, v[s][0].y, h0, l0);
        splith2(v[s][0].z, v[s][0].w, h1, l1);
        splith2(v[s][1].x, v[s][1].y, h2, l2);
        splith2(v[s][1].z, v[s][1].w, h3, l3);
        *(uint4*)(As + swz(r * 128 + g * 16))      = make_uint4(h0, h1, h2, h3);
        *(uint4*)(As + swz(r * 128 + 64 + g * 16)) = make_uint4(l0, l1, l2, l3);
    }
}

// ---------------- small kernels ----------------------------------------------
__global__ void k_detect(const unsigned int* __restrict__ m) {
    __shared__ int found;
    if (threadIdx.x == 0) found = 0;
    __syncthreads();
    unsigned int v = m[threadIdx.x];
    if (v > 1u) found = 1;
    __syncthreads();
    if (threadIdx.x == 0) g_mask_is_byte = found;
}

__device__ __forceinline__ void pack8h(const float* s, unsigned char* dst,
                                       int r, int u, bool zero) {
    uint4 h;
    h.x = packh2(zero ? 0.f : s[0], zero ? 0.f : s[1]);
    h.y = packh2(zero ? 0.f : s[2], zero ? 0.f : s[3]);
    h.z = packh2(zero ? 0.f : s[4], zero ? 0.f : s[5]);
    h.w = packh2(zero ? 0.f : s[6], zero ? 0.f : s[7]);
    *(uint4*)(dst + swz(r * 128 + u * 16)) = h;
}

__global__ void k_wpack(const float* __restrict__ Wih, const float* __restrict__ Whh,
                        const float* __restrict__ Wbm, const float* __restrict__ Wp) {
    int i = blockIdx.x * 256 + threadIdx.x;
    const int N1 = 40 * 1024;
    const int N2 = 32 * 1024;
    const int N3 = 16 * 1024;
    const int N4 = 512;
    if (i < N1) {
        int t = i >> 10, rem = i & 1023, r = rem >> 3, u = rem & 7;
        int cb = t / 5, ch = t % 5;
        int k = ch * 64 + u * 8;
        bool zero = (k >= 288);
        pack8h(Wih + (size_t)(cb * 128 + r) * 288 + (zero ? 0 : k),
               g_Wihpk + (size_t)t * 16384, r, u, zero);
    } else if (i < N1 + N2) {
        int j = i - N1;
        int t = j >> 10, rem = j & 1023, r = rem >> 3, u = rem & 7;
        int jb = t / 4, ch = t % 4;
        int wrow = (r >> 5) * 256 + jb * 32 + (r & 31);
        pack8h(Whh + (size_t)wrow * 256 + ch * 64 + u * 8,
               g_Whhpk + (size_t)t * 16384, r, u, false);
    } else if (i < N1 + N2 + N3) {
        int j = i - N1 - N2;
        int t = j >> 10, rem = j & 1023, r = rem >> 3, u = rem & 7;
        int k = t * 64 + u * 8;
        bool zero = (k + 8 > 1000);
        pack8h(Wbm + (size_t)r * 1000 + (zero ? 0 : k),
               g_Wbmpk + (size_t)t * 16384, r, u, zero);
    } else if (i < N1 + N2 + N3 + N4) {
        int j = i - N1 - N2 - N3;
        int r = j >> 3, u = j & 7;
        pack8h(Wp + (size_t)r * 64 + u * 8, g_Wppk, r, u, false);
    }
}

__global__ void k_op(const float* __restrict__ op_vec,
                     const float* __restrict__ W_op,
                     const float* __restrict__ b_op) {
    __shared__ float Ws[32][33];
    __shared__ float bs[32];
    int tid = threadIdx.x;
    if (tid < 32) bs[tid] = b_op[tid];
    for (int i = tid; i < 1024; i += 256) Ws[i >> 5][i & 31] = W_op[i];
    __syncthreads();
    int node = blockIdx.x * 8 + (tid >> 5);
    int o = tid & 31;
    if (node >= NN) return;
    float vl = op_vec[node * 32 + o];
    float acc = bs[o];
#pragma unroll
    for (int p = 0; p < 32; p++)
        acc += Ws[o][p] * __shfl_sync(0xffffffffu, vl, p);
    int blk = node >> 7, r = node & 127;
    unsigned char* tb = g_xpk + (size_t)blk * 5 * 16384;   // chunk 0
    *(__half*)(tb + swz(r * 128 + o * 2)) = __float2half_rn(acc);
}

// ============ GEMM 1: pool (128Mx64N, single K=64 tile, 1-pass) ==============
__global__ __launch_bounds__(256, 4)
void k_pool_mma(const float* __restrict__ preds1, const void* mask1, const void* and1,
                const float* __restrict__ preds2, const void* mask2, const void* and2,
                const float* __restrict__ b_pred) {
    extern __shared__ char sm[];
    char* Abuf = sm;                 // 16KB
    char* Bbuf = sm + 16384;         // 8KB
    uint32_t mb = smem_u32(sm + 34816);
    float* stage = (float*)sm;       // [128][68] after GEMM (34816B)

    int tid = threadIdx.x, lane = tid & 31, warp = tid >> 5;
    int wm = warp >> 1, wn = warp & 1;
    int cond = blockIdx.y;
    const float* preds = cond ? preds2 : preds1;
    const void*  maskp = cond ? mask2 : mask1;
    const void*  andp  = cond ? and2  : and1;
    int rowBase = blockIdx.x * 128;

    if (tid == 0) MBAR_INIT(mb);
    __syncthreads();
    if (tid == 0) {
        MBAR_EXPECT(mb, 8192u);
        bulk_g2s(smem_u32(Bbuf), g_Wppk, 8192u, mb);
    }

    float acc[2][4][4];
#pragma unroll
    for (int a = 0; a < 2; a++)
#pragma unroll
        for (int b = 0; b < 4; b++)
#pragma unroll
            for (int c = 0; c < 4; c++) acc[a][b][c] = 0.f;

    float4 va[4][2];
    ldg_f32u(preds, 64, rowBase, MRPOOL, 0, 64, tid, va);
    sts_h64(Abuf, tid, va);
    mbar_wait(mb, 0);
    __syncthreads();

    mma_t64_32(Abuf, Bbuf, wm, wn, lane, acc);
    __syncthreads();

#pragma unroll
    for (int mt = 0; mt < 2; mt++) {
#pragma unroll
        for (int nt = 0; nt < 4; nt++) {
            int r = wm * 32 + mt * 16 + (lane >> 2);
            int c = wn * 32 + nt * 8 + (lane & 3) * 2;
            stage[r * 68 + c] = acc[mt][nt][0];
            stage[r * 68 + c + 1] = acc[mt][nt][1];
            stage[(r + 8) * 68 + c] = acc[mt][nt][2];
            stage[(r + 8) * 68 + c + 1] = acc[mt][nt][3];
        }
    }
    __syncthreads();

    int node = blockIdx.x * 16 + (tid >> 4);
    int cg = (tid & 15) * 4;
    if (node < NN) {
        float bb[4];
        *(float4*)bb = *(const float4*)(b_pred + cg);
        int mk[8], anyb = 0;
#pragma unroll
        for (int i = 0; i < 8; i++) { mk[i] = read_bool(maskp, node * 8 + i); anyb |= mk[i]; }
        int ia = read_bool(andp, node);
        int rb = (tid >> 4) * 8;
        float out[4];
#pragma unroll
        for (int j = 0; j < 4; j++) {
            float mn = BIGF, mx = -BIGF;
#pragma unroll
            for (int i = 0; i < 8; i++) {
                float v = stage[(rb + i) * 68 + cg + j] + bb[j];
                if (mk[i]) { mn = fminf(mn, v); mx = fmaxf(mx, v); }
            }
            out[j] = anyb ? (ia ? mn : mx) : 0.0f;
        }
        int col0 = 32 + cond * 64 + cg;
        int ch = col0 >> 6, co = col0 & 63;
        int r = node & 127;
        unsigned char* tb = g_xpk + ((size_t)(node >> 7) * 5 + ch) * 16384;
        *(uint2*)(tb + swz(r * 128 + co * 2)) =
            make_uint2(packh2(out[0], out[1]), packh2(out[2], out[3]));
    }
}

// ============ GEMM 2: bm (128Mx128N, 16 K=64 chunks, 1-pass) =================
__global__ __launch_bounds__(256, 2)
void k_bm_mma(const float* __restrict__ bitmap, const float* __restrict__ b_bm) {
    extern __shared__ char sm[];
    char* Abuf[2] = { sm, sm + 16384 };
    char* Bbuf[2] = { sm + 32768, sm + 49152 };
    uint32_t mb = smem_u32(sm + 65536);
    int tid = threadIdx.x, lane = tid & 31, warp = tid >> 5;
    int wm = warp >> 1, wn = warp & 1;
    int rowBase = blockIdx.x * 128;

    if (tid == 0) { MBAR_INIT(mb); MBAR_INIT(mb + 8); }
    __syncthreads();
    if (tid == 0) {
        MBAR_EXPECT(mb, 16384u);
        bulk_g2s(smem_u32(Bbuf[0]), g_Wbmpk, 16384u, mb);
        MBAR_EXPECT(mb + 8, 16384u);
        bulk_g2s(smem_u32(Bbuf[1]), g_Wbmpk + 16384, 16384u, mb + 8);
    }

    float acc[2][8][4];
#pragma unroll
    for (int a = 0; a < 2; a++)
#pragma unroll
        for (int b = 0; b < 8; b++)
#pragma unroll
            for (int c = 0; c < 4; c++) acc[a][b][c] = 0.f;

    float4 va[4][2];
    ldg_f32u(bitmap, 1000, rowBase, NN, 0, 1000, tid, va);
    sts_h64(Abuf[0], tid, va);
    __syncthreads();

    const int NC = 16;
    for (int t = 0; t < NC; t++) {
        bool more = (t + 1 < NC);
        if (more) ldg_f32u(bitmap, 1000, rowBase, NN, (t + 1) * 64, 1000, tid, va);
        mbar_wait(mb + 8 * (t & 1), (t >> 1) & 1);
        mma_t64(Abuf[t & 1], Bbuf[t & 1], wm, wn, lane, acc);
        if (more) sts_h64(Abuf[(t + 1) & 1], tid, va);
        __syncthreads();
        if (tid == 0 && t + 2 < NC) {
            int s = t + 2, b = s & 1;
            MBAR_EXPECT(mb + 8 * b, 16384u);
            bulk_g2s(smem_u32(Bbuf[b]), g_Wbmpk + (size_t)s * 16384, 16384u, mb + 8 * b);
        }
    }

#pragma unroll
    for (int nt = 0; nt < 8; nt++) {
        int c = wn * 64 + nt * 8 + (lane & 3) * 2;
        float bx = b_bm[c], by = b_bm[c + 1];
        int ch = (160 + c) >> 6, co = (160 + c) & 63;
#pragma unroll
        for (int mt = 0; mt < 2; mt++) {
            int r0 = rowBase + wm * 32 + mt * 16 + (lane >> 2);
#pragma unroll
            for (int hh = 0; hh < 2; hh++) {
                int row = r0 + hh * 8;
                if (row < NN) {
                    int r = row & 127;
                    unsigned char* tb = g_xpk + ((size_t)(row >> 7) * 5 + ch) * 16384;
                    *(uint32_t*)(tb + swz(r * 128 + co * 2)) =
                        packh2(acc[mt][nt][hh * 2] + bx, acc[mt][nt][hh * 2 + 1] + by);
                }
            }
        }
    }
}

// ============ GEMM 3: xg (128Mx128N, 5 K=64 chunks, all-bulk, 1-pass) ========
__global__ __launch_bounds__(256, 2)
void k_xg_mma(const float* __restrict__ b_ih, const float* __restrict__ b_hh) {
    int colBase = blockIdx.x * 128;
    int rowBase = blockIdx.y * 128;
    // f-gate columns [256,512) are never read for leaf nodes (< 32768)
    if ((colBase == 256 || colBase == 384) && rowBase + 128 <= 32768) return;

    extern __shared__ char sm[];
    uint32_t mb = smem_u32(sm + 98304);
    int tid = threadIdx.x, lane = tid & 31, warp = tid >> 5;
    int wm = warp >> 1, wn = warp & 1;
    int cb = colBase >> 7;
    int rb5 = (rowBase >> 7) * 5;

    if (tid == 0) { MBAR_INIT(mb); MBAR_INIT(mb + 8); MBAR_INIT(mb + 16); }
    __syncthreads();
    const int NC = 5;
    if (tid == 0) {
#pragma unroll
        for (int s = 0; s < 3; s++) {
            char* base = sm + s * 32768;
            MBAR_EXPECT(mb + 8 * s, 32768u);
            bulk_g2s(smem_u32(base), g_xpk + ((size_t)rb5 + s) * 16384, 16384u, mb + 8 * s);
            bulk_g2s(smem_u32(base + 16384), g_Wihpk + ((size_t)cb * 5 + s) * 16384,
                     16384u, mb + 8 * s);
        }
    }

    float acc[2][8][4];
#pragma unroll
    for (int a = 0; a < 2; a++)
#pragma unroll
        for (int b = 0; b < 8; b++)
#pragma unroll
            for (int c = 0; c < 4; c++) acc[a][b][c] = 0.f;

    for (int t = 0; t < NC; t++) {
        int b = t % 3;
        mbar_wait(mb + 8 * b, (uint32_t)((t / 3) & 1));
        mma_t64(sm + b * 32768, sm + b * 32768 + 16384, wm, wn, lane, acc);
        __syncthreads();
        if (tid == 0 && t + 3 < NC) {
            int s = t + 3;
            char* base = sm + b * 32768;
            MBAR_EXPECT(mb + 8 * b, 32768u);
            bulk_g2s(smem_u32(base), g_xpk + ((size_t)rb5 + s) * 16384, 16384u, mb + 8 * b);
            bulk_g2s(smem_u32(base + 16384), g_Wihpk + ((size_t)cb * 5 + s) * 16384,
                     16384u, mb + 8 * b);
        }
    }

#pragma unroll
    for (int nt = 0; nt < 8; nt++) {
        int c = colBase + wn * 64 + nt * 8 + (lane & 3) * 2;
        float bx = b_ih[c] + b_hh[c], by = b_ih[c + 1] + b_hh[c + 1];
#pragma unroll
        for (int mt = 0; mt < 2; mt++) {
            int r0 = rowBase + wm * 32 + mt * 16 + (lane >> 2);
            if (r0 < NN)
                *(uint32_t*)(g_xg + (size_t)r0 * 1024 + c) =
                    packh2(acc[mt][nt][0] + bx, acc[mt][nt][1] + by);
            if (r0 + 8 < NN)
                *(uint32_t*)(g_xg + (size_t)(r0 + 8) * 1024 + c) =
                    packh2(acc[mt][nt][2] + bx, acc[mt][nt][3] + by);
        }
    }
}

// ============ level kernel (nd >= 128): 2-pass A-split + LSTM pointwise ======
__global__ __launch_bounds__(256, 2)
void k_level_mma(int start, int nd) {
    extern __shared__ char sm[];
    char* Abuf[2] = { sm, sm + 16384 };
    char* Bbuf[2] = { sm + 32768, sm + 49152 };
    uint32_t mb = smem_u32(sm + 67584);
    float* stage = (float*)sm;   // [128][132] after GEMM (67584B)

    int tid = threadIdx.x, lane = tid & 31, warp = tid >> 5;
    int wm = warp >> 1, wn = warp & 1;
    int rowBase = blockIdx.x * 128;
    int jb = blockIdx.y;          // j block (32 wide)

    if (tid == 0) { MBAR_INIT(mb); MBAR_INIT(mb + 8); }
    __syncthreads();
    if (tid == 0) {
        MBAR_EXPECT(mb, 16384u);
        bulk_g2s(smem_u32(Bbuf[0]), g_Whhpk + (size_t)(jb * 4) * 16384, 16384u, mb);
        MBAR_EXPECT(mb + 8, 16384u);
        bulk_g2s(smem_u32(Bbuf[1]), g_Whhpk + (size_t)(jb * 4 + 1) * 16384, 16384u, mb + 8);
    }

    float acc[2][8][4];
#pragma unroll
    for (int a = 0; a < 2; a++)
#pragma unroll
        for (int b = 0; b < 8; b++)
#pragma unroll
            for (int c = 0; c < 4; c++) acc[a][b][c] = 0.f;

    float4 va[2][2];
    ldg_avgH(start, nd, rowBase, 0, tid, va);
    sts_splith(Abuf[0], tid, va);
    __syncthreads();

    const int NC = 8;   // K=32 chunks; B tile = 2 chunks
    for (int t = 0; t < NC; t++) {
        bool more = (t + 1 < NC);
        if (more) ldg_avgH(start, nd, rowBase, (t + 1) * 32, tid, va);
        int bt = t >> 1;
        if ((t & 1) == 0) mbar_wait(mb + 8 * (bt & 1), (bt >> 1) & 1);
        mma_lvl(Abuf[t & 1], Bbuf[bt & 1], (t & 1) * 64, wm, wn, lane, acc);
        if (more) sts_splith(Abuf[(t + 1) & 1], tid, va);
        __syncthreads();
        if (tid == 0 && (t & 1) == 1 && bt + 2 <= 3) {
            int s = bt + 2, b = s & 1;
            MBAR_EXPECT(mb + 8 * b, 16384u);
            bulk_g2s(smem_u32(Bbuf[b]), g_Whhpk + (size_t)(jb * 4 + s) * 16384,
                     16384u, mb + 8 * b);
        }
    }

#pragma unroll
    for (int mt = 0; mt < 2; mt++) {
#pragma unroll
        for (int nt = 0; nt < 8; nt++) {
            int r = wm * 32 + mt * 16 + (lane >> 2);
            int c = wn * 64 + nt * 8 + (lane & 3) * 2;
            stage[r * 132 + c] = acc[mt][nt][0];
            stage[r * 132 + c + 1] = acc[mt][nt][1];
            stage[(r + 8) * 132 + c] = acc[mt][nt][2];
            stage[(r + 8) * 132 + c + 1] = acc[mt][nt][3];
        }
    }
    __syncthreads();

#pragma unroll
    for (int i = 0; i < 16; i++) {
        int idx = tid + 256 * i;
        int r = idx >> 5, jj = idx & 31;
        int rr = rowBase + r;
        if (rr < nd) {
            int node = start + rr;
            int j = jb * 32 + jj;
            const __half* xr = g_xg + (size_t)node * 1024;
            float gi = stage[r * 132 + jj]       + __half2float(xr[j]);
            float gf = stage[r * 132 + 32 + jj]  + __half2float(xr[256 + j]);
            float gg = stage[r * 132 + 64 + jj]  + __half2float(xr[512 + j]);
            float go = stage[r * 132 + 96 + jj]  + __half2float(xr[768 + j]);
            int ci = 2 * node - NN;
            float c0 = 0.5f * (g_C[(size_t)ci * 256 + j] + g_C[(size_t)(ci - 1) * 256 + j]);
            float cn = sigf(gf) * c0 + sigf(gi) * tanhf(gg);
            float hn = sigf(go) * tanhf(cn);
            g_H[(size_t)node * 256 + j] = hn;
            g_C[(size_t)node * 256 + j] = cn;
        }
    }
}

// ---------------- leaves (d = D): c0 = 0 -------------------------------------
__global__ void k_leaf() {
    int n = blockIdx.x;
    int j = threadIdx.x;
    const __half* xr = g_xg + (size_t)n * 1024;
    float gi = __half2float(xr[j]);
    float gg = __half2float(xr[512 + j]);
    float go = __half2float(xr[768 + j]);
    float c = sigf(gi) * tanhf(gg);
    float h = sigf(go) * tanhf(c);
    g_H[(size_t)n * 256 + j] = h;
    g_C[(size_t)n * 256 + j] = c;
}

// ---------------- SIMT level kernel for small levels -------------------------
__global__ __launch_bounds__(256)
void k_level(int start, int nd, const float* __restrict__ W_hh) {
    __shared__ float h0s[32][36];
    __shared__ float Ws[256][36];
    int tid = threadIdx.x;
    int jx = tid & 63, ry = tid >> 6;
    int rowBase = blockIdx.x * 32;
    int jbase = blockIdx.y * 64;

    float acc[8][4];
#pragma unroll
    for (int i = 0; i < 8; i++)
#pragma unroll
        for (int g = 0; g < 4; g++) acc[i][g] = 0.0f;

    for (int k0 = 0; k0 < 256; k0 += 32) {
        {
            int r = tid >> 3, c4 = tid & 7;
            float4 v = make_float4(0.f, 0.f, 0.f, 0.f);
            int rr = rowBase + r;
            if (rr < nd) {
                int node = start + rr;
                int ci = 2 * node - NN;
                float4 a = *(const float4*)&g_H[(size_t)ci * 256 + k0 + c4 * 4];
                float4 b = *(const float4*)&g_H[(size_t)(ci - 1) * 256 + k0 + c4 * 4];
                v = make_float4(0.5f * (a.x + b.x), 0.5f * (a.y + b.y),
                                0.5f * (a.z + b.z), 0.5f * (a.w + b.w));
            }
            *(float4*)&h0s[r][c4 * 4] = v;
        }
        {
            int wrow = ry * 256 + jbase + jx;
            const float* src = &W_hh[(size_t)wrow * 256 + k0];
#pragma unroll
            for (int c = 0; c < 8; c++)
                *(float4*)&Ws[tid][c * 4] = *(const float4*)&src[c * 4];
        }
        __syncthreads();
#pragma unroll
        for (int kk4 = 0; kk4 < 8; kk4++) {
            float4 w4[4];
#pragma unroll
            for (int g = 0; g < 4; g++)
                w4[g] = *(const float4*)&Ws[g * 64 + jx][kk4 * 4];
#pragma unroll
            for (int i = 0; i < 8; i++) {
                float4 a4 = *(const float4*)&h0s[ry * 8 + i][kk4 * 4];
#pragma unroll
                for (int g = 0; g < 4; g++)
                    acc[i][g] += a4.x * w4[g].x + a4.y * w4[g].y +
                                 a4.z * w4[g].z + a4.w * w4[g].w;
            }
        }
        __syncthreads();
    }

    int j = jbase + jx;
#pragma unroll
    for (int i = 0; i < 8; i++) {
        int rr = rowBase + ry * 8 + i;
        if (rr < nd) {
            int node = start + rr;
            const __half* xr = g_xg + (size_t)node * 1024;
            float gi = acc[i][0] + __half2float(xr[j]);
            float gf = acc[i][1] + __half2float(xr[256 + j]);
            float gg = acc[i][2] + __half2float(xr[512 + j]);
            float go = acc[i][3] + __half2float(xr[768 + j]);
            int ci = 2 * node - NN;
            float c0 = 0.5f * (g_C[(size_t)ci * 256 + j] + g_C[(size_t)(ci - 1) * 256 + j]);
            float cn = sigf(gf) * c0 + sigf(gi) * tanhf(gg);
            float hn = sigf(go) * tanhf(cn);
            g_H[(size_t)node * 256 + j] = hn;
            g_C[(size_t)node * 256 + j] = cn;
        }
    }
}

// ---------------- output heads ----------------------------------------------
__global__ void k_heads(const float* __restrict__ W2a, const float* __restrict__ b2a,
                        const float* __restrict__ W3a, const float* __restrict__ b3a,
                        const float* __restrict__ Woa, const float* __restrict__ boa,
                        const float* __restrict__ W2b, const float* __restrict__ b2b,
                        const float* __restrict__ W3b, const float* __restrict__ b3b,
                        const float* __restrict__ Wob, const float* __restrict__ bob,
                        float* __restrict__ out) {
    __shared__ float hv[256];
    __shared__ float t1[2][128];
    __shared__ float t2[2][128];
    __shared__ float red[256];
    int tid = threadIdx.x;
    hv[tid] = g_H[(size_t)(NN - 1) * 256 + tid];
    __syncthreads();
    int head = tid >> 7, j = tid & 127;
    const float* W2 = head ? W2b : W2a; const float* b2 = head ? b2b : b2a;
    const float* W3 = head ? W3b : W3a; const float* b3 = head ? b3b : b3a;
    const float* Wo = head ? Wob : Woa; const float* bo = head ? bob : boa;

    float t = b2[j];
    for (int k = 0; k < 256; k++) t += W2[j * 256 + k] * hv[k];
    t1[head][j] = fmaxf(t, 0.0f);
    __syncthreads();
    t = b3[j];
    for (int k = 0; k < 128; k++) t += W3[j * 128 + k] * t1[head][k];
    t2[head][j] = fmaxf(t, 0.0f);
    __syncthreads();
    red[tid] = Wo[j] * t2[head][j];
    __syncthreads();
    for (int s = 64; s > 0; s >>= 1) {
        if (j < s) red[tid] += red[tid + s];
        __syncthreads();
    }
    if (j == 0) out[head] = 1.0f / (1.0f + expf(-(red[tid] + bo[0])));
}

// ---------------- launch ------------------------------------------------------
extern "C" void kernel_launch(void* const* d_in, const int* in_sizes, int n_in,
                              void* d_out, int out_size) {
    const float* op_vec   = (const float*)d_in[0];
    const float* c1_preds = (const float*)d_in[1];
    const void*  c1_mask  = d_in[2];
    const void*  c1_and   = d_in[3];
    const float* c2_preds = (const float*)d_in[4];
    const void*  c2_mask  = d_in[5];
    const void*  c2_and   = d_in[6];
    const float* bitmap   = (const float*)d_in[7];
    const float* W_op     = (const float*)d_in[8];
    const float* b_op     = (const float*)d_in[9];
    const float* W_pred   = (const float*)d_in[10];
    const float* b_pred   = (const float*)d_in[11];
    const float* W_bm     = (const float*)d_in[12];
    const float* b_bm     = (const float*)d_in[13];
    const float* W_ih     = (const float*)d_in[14];
    const float* b_ih     = (const float*)d_in[15];
    const float* W_hh     = (const float*)d_in[16];
    const float* b_hh     = (const float*)d_in[17];
    const float* W_h2t1   = (const float*)d_in[18];
    const float* b_h2t1   = (const float*)d_in[19];
    const float* W_h3t1   = (const float*)d_in[20];
    const float* b_h3t1   = (const float*)d_in[21];
    const float* W_o1     = (const float*)d_in[22];
    const float* b_o1     = (const float*)d_in[23];
    const float* W_h2t2   = (const float*)d_in[24];
    const float* b_h2t2   = (const float*)d_in[25];
    const float* W_h3t2   = (const float*)d_in[26];
    const float* b_h3t2   = (const float*)d_in[27];
    const float* W_o2     = (const float*)d_in[28];
    const float* b_o2     = (const float*)d_in[29];
    float* out = (float*)d_out;

    const int SM_PL = 34816 + 64;
    const int SM_BM = 65536 + 64;
    const int SM_XG = 98304 + 64;
    const int SM_LV = 67584 + 64;
    static int configured = 0;
    if (!configured) {
        cudaFuncSetAttribute(k_pool_mma, cudaFuncAttributeMaxDynamicSharedMemorySize, SM_PL);
        cudaFuncSetAttribute(k_bm_mma,   cudaFuncAttributeMaxDynamicSharedMemorySize, SM_BM);
        cudaFuncSetAttribute(k_xg_mma,   cudaFuncAttributeMaxDynamicSharedMemorySize, SM_XG);
        cudaFuncSetAttribute(k_level_mma,cudaFuncAttributeMaxDynamicSharedMemorySize, SM_LV);
        configured = 1;
    }

    k_detect<<<1, 256>>>((const unsigned int*)c1_mask);
    k_wpack<<<(40 * 1024 + 32 * 1024 + 16 * 1024 + 512 + 255) / 256, 256>>>(
        W_ih, W_hh, W_bm, W_pred);

    k_op<<<(NN + 7) / 8, 256>>>(op_vec, W_op, b_op);

    {
        dim3 grid((MRPOOL + 127) / 128, 2);
        k_pool_mma<<<grid, 256, SM_PL>>>(c1_preds, c1_mask, c1_and,
                                         c2_preds, c2_mask, c2_and, b_pred);
    }

    k_bm_mma<<<(NN + 127) / 128, 256, SM_BM>>>(bitmap, b_bm);

    {
        dim3 grid(8, (NN + 127) / 128);
        k_xg_mma<<<grid, 256, SM_XG>>>(b_ih, b_hh);
    }

    k_leaf<<<32768, 256>>>();

    for (int d = 14; d >= 0; d--) {
        int nd = 1 << d;
        int start = NN - (1 << (d + 1)) + 1;
        if (nd >= 128) {
            dim3 grid((nd + 127) / 128, 8);
            k_level_mma<<<grid, 256, SM_LV>>>(start, nd);
        } else {
            dim3 grid((nd + 31) / 32, 4);
            k_level<<<grid, 256>>>(start, nd, W_hh);
        }
    }

    k_heads<<<1, 256>>>(W_h2t1, b_h2t1, W_h3t1, b_h3t1, W_o1, b_o1,
                        W_h2t2, b_h2t2, W_h3t2, b_h3t2, W_o2, b_o2,
                        out);
}

// round 13
// speedup vs baseline: 12.3614x; 1.1434x over previous
#include <cuda_runtime.h>
#include <cuda_fp16.h>
#include <math.h>
#include <cstdint>
#include <stdint.h>

#define NN 65535          // number of tree nodes (2^16 - 1)
#define MRPOOL (NN * 8)   // pool GEMM rows
#define BIGF 1e30f

// Packed tile: 128 rows x 64 fp16 K-values (128B/row), SW128-swizzled
// (byte o -> o ^ ((o>>3)&0x70)); 16KB per tile, bulk-copyable verbatim.
__device__ __forceinline__ int swz(int o) { return o ^ ((o >> 3) & 0x70); }

// ---------------- scratch (static device globals; no cudaMalloc) -------------
__device__ __align__(1024) unsigned char g_xpk[(size_t)512 * 5 * 16384]; // packed features (fp16)
__device__ __half g_xg[(size_t)NN * 1024];         // gates pre-activation (fp16)
__device__ __half g_H[(size_t)NN * 256];           // LSTM hidden (fp16)
__device__ __half g_C[(size_t)NN * 256];           // LSTM cell (fp16)
__device__ int   g_mask_is_byte;

// packed weights (fp16)
__device__ __align__(1024) unsigned char g_Wihpk[40 * 16384];  // 8 colblk x 5 chunks (K=320 pad)
__device__ __align__(1024) unsigned char g_Whhpk[32 * 16384];  // 8 jblk x 4 chunks (K=256)
__device__ __align__(1024) unsigned char g_Wbmpk[16 * 16384];  // 16 chunks (K=1024 pad)
__device__ __align__(1024) unsigned char g_Wppk[8192];         // 64 rows x K=64

__device__ __forceinline__ float sigf(float x) { return 1.0f / (1.0f + expf(-x)); }

__device__ __forceinline__ int read_bool(const void* p, int idx) {
    return g_mask_is_byte ? (int)(((const unsigned char*)p)[idx])
                          : (((const int*)p)[idx] != 0);
}

__device__ __forceinline__ unsigned smem_u32(const void* p) {
    return (unsigned)__cvta_generic_to_shared(p);
}

// ---------------- mbarrier + bulk copy ---------------------------------------
#define MBAR_INIT(a) \
    asm volatile("mbarrier.init.shared.b64 [%0], 1;" :: "r"(a) : "memory")
#define MBAR_EXPECT(a, tx) \
    asm volatile("mbarrier.arrive.expect_tx.shared.b64 _, [%0], %1;" \
                 :: "r"(a), "r"(tx) : "memory")

__device__ __forceinline__ void mbar_wait(uint32_t mbar, uint32_t parity) {
    asm volatile(
        "{\n\t.reg .pred P;\n\t"
        "WL%=:\n\t"
        "mbarrier.try_wait.parity.shared.b64 P, [%0], %1;\n\t"
        "@!P bra WL%=;\n\t}"
        :: "r"(mbar), "r"(parity) : "memory");
}

__device__ __forceinline__ void bulk_g2s(uint32_t dst, const void* src,
                                         uint32_t bytes, uint32_t mbar) {
    asm volatile(
        "cp.async.bulk.shared::cluster.global.mbarrier::complete_tx::bytes "
        "[%0], [%1], %2, [%3];"
        :: "r"(dst), "l"(src), "r"(bytes), "r"(mbar) : "memory");
}

// ---------------- fp16 helpers ------------------------------------------------
__device__ __forceinline__ uint32_t packh2(float x, float y) {
    __half2 h = __floats2half2_rn(x, y);
    return *(uint32_t*)&h;
}
__device__ __forceinline__ __half2 u2h(uint32_t u) { return *(__half2*)&u; }
__device__ __forceinline__ uint32_t h2u(__half2 h) { return *(uint32_t*)&h; }

// ---------------- mma.sync m16n8k16 fp16 + ldmatrix --------------------------
__device__ __forceinline__ void mma_f16(float d[4], const uint32_t a[4], const uint32_t b[2]) {
    asm volatile(
        "mma.sync.aligned.m16n8k16.row.col.f32.f16.f16.f32 "
        "{%0,%1,%2,%3}, {%4,%5,%6,%7}, {%8,%9}, {%0,%1,%2,%3};\n"
        : "+f"(d[0]), "+f"(d[1]), "+f"(d[2]), "+f"(d[3])
        : "r"(a[0]), "r"(a[1]), "r"(a[2]), "r"(a[3]), "r"(b[0]), "r"(b[1]));
}

__device__ __forceinline__ void ldsm4(uint32_t r[4], const void* p) {
    uint32_t addr = smem_u32(p);
    asm volatile("ldmatrix.sync.aligned.m8n8.x4.shared.b16 {%0,%1,%2,%3}, [%4];"
                 : "=r"(r[0]), "=r"(r[1]), "=r"(r[2]), "=r"(r[3]) : "r"(addr));
}

// 1-pass K=64 tile, 32x64 warp tile (bm, xg, levels)
__device__ __forceinline__ void mma_t64(const char* As, const char* Bs,
                                        int wm, int wn, int lane, float acc[2][8][4]) {
    int lrow = lane & 15, l16 = (lane >> 4) * 16;
#pragma unroll
    for (int ks = 0; ks < 4; ks++) {
        int kb = ks * 32 + l16;
        uint32_t a[2][4];
#pragma unroll
        for (int mt = 0; mt < 2; mt++)
            ldsm4(a[mt], As + swz((wm * 32 + mt * 16 + lrow) * 128 + kb));
#pragma unroll
        for (int g = 0; g < 4; g++) {
            uint32_t b[4];
            ldsm4(b, Bs + swz((wn * 64 + g * 16 + lrow) * 128 + kb));
            uint32_t b0[2] = { b[0], b[2] }, b1[2] = { b[1], b[3] };
#pragma unroll
            for (int mt = 0; mt < 2; mt++) {
                mma_f16(acc[mt][g * 2],     a[mt], b0);
                mma_f16(acc[mt][g * 2 + 1], a[mt], b1);
            }
        }
    }
}

// 1-pass K=64 tile, 32x32 warp tile (pool)
__device__ __forceinline__ void mma_t64_32(const char* As, const char* Bs,
                                           int wm, int wn, int lane, float acc[2][4][4]) {
    int lrow = lane & 15, l16 = (lane >> 4) * 16;
#pragma unroll
    for (int ks = 0; ks < 4; ks++) {
        int kb = ks * 32 + l16;
        uint32_t a[2][4];
#pragma unroll
        for (int mt = 0; mt < 2; mt++)
            ldsm4(a[mt], As + swz((wm * 32 + mt * 16 + lrow) * 128 + kb));
#pragma unroll
        for (int g = 0; g < 2; g++) {
            uint32_t b[4];
            ldsm4(b, Bs + swz((wn * 32 + g * 16 + lrow) * 128 + kb));
            uint32_t b0[2] = { b[0], b[2] }, b1[2] = { b[1], b[3] };
#pragma unroll
            for (int mt = 0; mt < 2; mt++) {
                mma_f16(acc[mt][g * 2],     a[mt], b0);
                mma_f16(acc[mt][g * 2 + 1], a[mt], b1);
            }
        }
    }
}

// ---------------- A-side loaders ----------------------------------------------
// K=64 tile loader: 128 rows x 8 units of 8 floats; 4 slots/thread
__device__ __forceinline__ void ldg_f32u(const float* __restrict__ src, int ld, int rowBase,
                                         int maxRow, int k0, int Ktot, int tid, float4 (*v)[2]) {
#pragma unroll
    for (int s = 0; s < 4; s++) {
        int idx = tid + 256 * s;
        int r = idx >> 3, u = idx & 7;
        int row = rowBase + r, k = k0 + u * 8;
        float4 a = make_float4(0.f, 0.f, 0.f, 0.f), b = a;
        if (row < maxRow && k + 8 <= Ktot) {
            const float* p = src + (size_t)row * ld + k;
            a = *(const float4*)p;
            b = *(const float4*)(p + 4);
        }
        v[s][0] = a; v[s][1] = b;
    }
}

__device__ __forceinline__ void sts_h64(char* As, int tid, float4 (*v)[2]) {
#pragma unroll
    for (int s = 0; s < 4; s++) {
        int idx = tid + 256 * s;
        int r = idx >> 3, u = idx & 7;
        uint4 h;
        h.x = packh2(v[s][0].x, v[s][0].y);
        h.y = packh2(v[s][0].z, v[s][0].w);
        h.z = packh2(v[s][1].x, v[s][1].y);
        h.w = packh2(v[s][1].z, v[s][1].w);
        *(uint4*)(As + swz(r * 128 + u * 16)) = h;
    }
}

// level A: K=64 chunk of averaged child H (fp16 in, fp16 out); 4 slots/thread
__device__ __forceinline__ void ldg_avgH16(int start, int nd, int rowBase, int k0, int tid,
                                           uint4* v) {
    __half2 half2c = __float2half2_rn(0.5f);
#pragma unroll
    for (int s = 0; s < 4; s++) {
        int idx = tid + 256 * s;
        int r = idx >> 3, u = idx & 7;
        int rr = rowBase + r;
        uint4 out = make_uint4(0, 0, 0, 0);
        if (rr < nd) {
            int node = start + rr;
            int ci = 2 * node - NN;
            uint4 A = *(const uint4*)(g_H + (size_t)ci * 256 + k0 + u * 8);
            uint4 B = *(const uint4*)(g_H + (size_t)(ci - 1) * 256 + k0 + u * 8);
            out.x = h2u(__hmul2(__hadd2(u2h(A.x), u2h(B.x)), half2c));
            out.y = h2u(__hmul2(__hadd2(u2h(A.y), u2h(B.y)), half2c));
            out.z = h2u(__hmul2(__hadd2(u2h(A.z), u2h(B.z)), half2c));
            out.w = h2u(__hmul2(__hadd2(u2h(A.w), u2h(B.w)), half2c));
        }
        v[s] = out;
    }
}

__device__ __forceinline__ void sts_u4(char* As, int tid, const uint4* v) {
#pragma unroll
    for (int s = 0; s < 4; s++) {
        int idx = tid + 256 * s;
        int r = idx >> 3, u = idx & 7;
        *(uint4*)(As + swz(r * 128 + u * 16)) = v[s];
    }
}

// ---------------- small kernels ----------------------------------------------
__global__ void k_detect(const unsigned int* __restrict__ m) {
    __shared__ int found;
    if (threadIdx.x == 0) found = 0;
    __syncthreads();
    unsigned int v = m[threadIdx.x];
    if (v > 1u) found = 1;
    __syncthreads();
    if (threadIdx.x == 0) g_mask_is_byte = found;
}

__device__ __forceinline__ void pack8h(const float* s, unsigned char* dst,
                                       int r, int u, bool zero) {
    uint4 h;
    h.x = packh2(zero ? 0.f : s[0], zero ? 0.f : s[1]);
    h.y = packh2(zero ? 0.f : s[2], zero ? 0.f : s[3]);
    h.z = packh2(zero ? 0.f : s[4], zero ? 0.f : s[5]);
    h.w = packh2(zero ? 0.f : s[6], zero ? 0.f : s[7]);
    *(uint4*)(dst + swz(r * 128 + u * 16)) = h;
}

__global__ void k_wpack(const float* __restrict__ Wih, const float* __restrict__ Whh,
                        const float* __restrict__ Wbm, const float* __restrict__ Wp) {
    int i = blockIdx.x * 256 + threadIdx.x;
    const int N1 = 40 * 1024;
    const int N2 = 32 * 1024;
    const int N3 = 16 * 1024;
    const int N4 = 512;
    if (i < N1) {
        int t = i >> 10, rem = i & 1023, r = rem >> 3, u = rem & 7;
        int cb = t / 5, ch = t % 5;
        int k = ch * 64 + u * 8;
        bool zero = (k >= 288);
        pack8h(Wih + (size_t)(cb * 128 + r) * 288 + (zero ? 0 : k),
               g_Wihpk + (size_t)t * 16384, r, u, zero);
    } else if (i < N1 + N2) {
        int j = i - N1;
        int t = j >> 10, rem = j & 1023, r = rem >> 3, u = rem & 7;
        int jb = t / 4, ch = t % 4;
        int wrow = (r >> 5) * 256 + jb * 32 + (r & 31);
        pack8h(Whh + (size_t)wrow * 256 + ch * 64 + u * 8,
               g_Whhpk + (size_t)t * 16384, r, u, false);
    } else if (i < N1 + N2 + N3) {
        int j = i - N1 - N2;
        int t = j >> 10, rem = j & 1023, r = rem >> 3, u = rem & 7;
        int k = t * 64 + u * 8;
        bool zero = (k + 8 > 1000);
        pack8h(Wbm + (size_t)r * 1000 + (zero ? 0 : k),
               g_Wbmpk + (size_t)t * 16384, r, u, zero);
    } else if (i < N1 + N2 + N3 + N4) {
        int j = i - N1 - N2 - N3;
        int r = j >> 3, u = j & 7;
        pack8h(Wp + (size_t)r * 64 + u * 8, g_Wppk, r, u, false);
    }
}

__global__ void k_op(const float* __restrict__ op_vec,
                     const float* __restrict__ W_op,
                     const float* __restrict__ b_op) {
    __shared__ float Ws[32][33];
    __shared__ float bs[32];
    int tid = threadIdx.x;
    if (tid < 32) bs[tid] = b_op[tid];
    for (int i = tid; i < 1024; i += 256) Ws[i >> 5][i & 31] = W_op[i];
    __syncthreads();
    int node = blockIdx.x * 8 + (tid >> 5);
    int o = tid & 31;
    if (node >= NN) return;
    float vl = op_vec[node * 32 + o];
    float acc = bs[o];
#pragma unroll
    for (int p = 0; p < 32; p++)
        acc += Ws[o][p] * __shfl_sync(0xffffffffu, vl, p);
    int blk = node >> 7, r = node & 127;
    unsigned char* tb = g_xpk + (size_t)blk * 5 * 16384;   // chunk 0
    *(__half*)(tb + swz(r * 128 + o * 2)) = __float2half_rn(acc);
}

// ============ GEMM 1: pool (128Mx64N, single K=64 tile, 1-pass) ==============
__global__ __launch_bounds__(256, 4)
void k_pool_mma(const float* __restrict__ preds1, const void* mask1, const void* and1,
                const float* __restrict__ preds2, const void* mask2, const void* and2,
                const float* __restrict__ b_pred) {
    extern __shared__ char sm[];
    char* Abuf = sm;                 // 16KB
    char* Bbuf = sm + 16384;         // 8KB
    uint32_t mb = smem_u32(sm + 34816);
    float* stage = (float*)sm;       // [128][68] after GEMM (34816B)

    int tid = threadIdx.x, lane = tid & 31, warp = tid >> 5;
    int wm = warp >> 1, wn = warp & 1;
    int cond = blockIdx.y;
    const float* preds = cond ? preds2 : preds1;
    const void*  maskp = cond ? mask2 : mask1;
    const void*  andp  = cond ? and2  : and1;
    int rowBase = blockIdx.x * 128;

    if (tid == 0) MBAR_INIT(mb);
    __syncthreads();
    if (tid == 0) {
        MBAR_EXPECT(mb, 8192u);
        bulk_g2s(smem_u32(Bbuf), g_Wppk, 8192u, mb);
    }

    float acc[2][4][4];
#pragma unroll
    for (int a = 0; a < 2; a++)
#pragma unroll
        for (int b = 0; b < 4; b++)
#pragma unroll
            for (int c = 0; c < 4; c++) acc[a][b][c] = 0.f;

    float4 va[4][2];
    ldg_f32u(preds, 64, rowBase, MRPOOL, 0, 64, tid, va);
    sts_h64(Abuf, tid, va);
    mbar_wait(mb, 0);
    __syncthreads();

    mma_t64_32(Abuf, Bbuf, wm, wn, lane, acc);
    __syncthreads();

#pragma unroll
    for (int mt = 0; mt < 2; mt++) {
#pragma unroll
        for (int nt = 0; nt < 4; nt++) {
            int r = wm * 32 + mt * 16 + (lane >> 2);
            int c = wn * 32 + nt * 8 + (lane & 3) * 2;
            stage[r * 68 + c] = acc[mt][nt][0];
            stage[r * 68 + c + 1] = acc[mt][nt][1];
            stage[(r + 8) * 68 + c] = acc[mt][nt][2];
            stage[(r + 8) * 68 + c + 1] = acc[mt][nt][3];
        }
    }
    __syncthreads();

    int node = blockIdx.x * 16 + (tid >> 4);
    int cg = (tid & 15) * 4;
    if (node < NN) {
        float bb[4];
        *(float4*)bb = *(const float4*)(b_pred + cg);
        int mk[8], anyb = 0;
#pragma unroll
        for (int i = 0; i < 8; i++) { mk[i] = read_bool(maskp, node * 8 + i); anyb |= mk[i]; }
        int ia = read_bool(andp, node);
        int rb = (tid >> 4) * 8;
        float out[4];
#pragma unroll
        for (int j = 0; j < 4; j++) {
            float mn = BIGF, mx = -BIGF;
#pragma unroll
            for (int i = 0; i < 8; i++) {
                float v = stage[(rb + i) * 68 + cg + j] + bb[j];
                if (mk[i]) { mn = fminf(mn, v); mx = fmaxf(mx, v); }
            }
            out[j] = anyb ? (ia ? mn : mx) : 0.0f;
        }
        int col0 = 32 + cond * 64 + cg;
        int ch = col0 >> 6, co = col0 & 63;
        int r = node & 127;
        unsigned char* tb = g_xpk + ((size_t)(node >> 7) * 5 + ch) * 16384;
        *(uint2*)(tb + swz(r * 128 + co * 2)) =
            make_uint2(packh2(out[0], out[1]), packh2(out[2], out[3]));
    }
}

// ============ GEMM 2: bm (128Mx128N, 16 K=64 chunks, 1-pass) =================
__global__ __launch_bounds__(256, 2)
void k_bm_mma(const float* __restrict__ bitmap, const float* __restrict__ b_bm) {
    extern __shared__ char sm[];
    char* Abuf[2] = { sm, sm + 16384 };
    char* Bbuf[2] = { sm + 32768, sm + 49152 };
    uint32_t mb = smem_u32(sm + 65536);
    int tid = threadIdx.x, lane = tid & 31, warp = tid >> 5;
    int wm = warp >> 1, wn = warp & 1;
    int rowBase = blockIdx.x * 128;

    if (tid == 0) { MBAR_INIT(mb); MBAR_INIT(mb + 8); }
    __syncthreads();
    if (tid == 0) {
        MBAR_EXPECT(mb, 16384u);
        bulk_g2s(smem_u32(Bbuf[0]), g_Wbmpk, 16384u, mb);
        MBAR_EXPECT(mb + 8, 16384u);
        bulk_g2s(smem_u32(Bbuf[1]), g_Wbmpk + 16384, 16384u, mb + 8);
    }

    float acc[2][8][4];
#pragma unroll
    for (int a = 0; a < 2; a++)
#pragma unroll
        for (int b = 0; b < 8; b++)
#pragma unroll
            for (int c = 0; c < 4; c++) acc[a][b][c] = 0.f;

    float4 va[4][2];
    ldg_f32u(bitmap, 1000, rowBase, NN, 0, 1000, tid, va);
    sts_h64(Abuf[0], tid, va);
    __syncthreads();

    const int NC = 16;
    for (int t = 0; t < NC; t++) {
        bool more = (t + 1 < NC);
        if (more) ldg_f32u(bitmap, 1000, rowBase, NN, (t + 1) * 64, 1000, tid, va);
        mbar_wait(mb + 8 * (t & 1), (t >> 1) & 1);
        mma_t64(Abuf[t & 1], Bbuf[t & 1], wm, wn, lane, acc);
        if (more) sts_h64(Abuf[(t + 1) & 1], tid, va);
        __syncthreads();
        if (tid == 0 && t + 2 < NC) {
            int s = t + 2, b = s & 1;
            MBAR_EXPECT(mb + 8 * b, 16384u);
            bulk_g2s(smem_u32(Bbuf[b]), g_Wbmpk + (size_t)s * 16384, 16384u, mb + 8 * b);
        }
    }

#pragma unroll
    for (int nt = 0; nt < 8; nt++) {
        int c = wn * 64 + nt * 8 + (lane & 3) * 2;
        float bx = b_bm[c], by = b_bm[c + 1];
        int ch = (160 + c) >> 6, co = (160 + c) & 63;
#pragma unroll
        for (int mt = 0; mt < 2; mt++) {
            int r0 = rowBase + wm * 32 + mt * 16 + (lane >> 2);
#pragma unroll
            for (int hh = 0; hh < 2; hh++) {
                int row = r0 + hh * 8;
                if (row < NN) {
                    int r = row & 127;
                    unsigned char* tb = g_xpk + ((size_t)(row >> 7) * 5 + ch) * 16384;
                    *(uint32_t*)(tb + swz(r * 128 + co * 2)) =
                        packh2(acc[mt][nt][hh * 2] + bx, acc[mt][nt][hh * 2 + 1] + by);
                }
            }
        }
    }
}

// ============ GEMM 3: xg (128Mx128N, 5 K=64 chunks, all-bulk, 1-pass) ========
__global__ __launch_bounds__(256, 2)
void k_xg_mma(const float* __restrict__ b_ih, const float* __restrict__ b_hh) {
    int colBase = blockIdx.x * 128;
    int rowBase = blockIdx.y * 128;
    // f-gate columns [256,512) are never read for leaf nodes (< 32768)
    if ((colBase == 256 || colBase == 384) && rowBase + 128 <= 32768) return;

    extern __shared__ char sm[];
    uint32_t mb = smem_u32(sm + 98304);
    int tid = threadIdx.x, lane = tid & 31, warp = tid >> 5;
    int wm = warp >> 1, wn = warp & 1;
    int cb = colBase >> 7;
    int rb5 = (rowBase >> 7) * 5;

    if (tid == 0) { MBAR_INIT(mb); MBAR_INIT(mb + 8); MBAR_INIT(mb + 16); }
    __syncthreads();
    const int NC = 5;
    if (tid == 0) {
#pragma unroll
        for (int s = 0; s < 3; s++) {
            char* base = sm + s * 32768;
            MBAR_EXPECT(mb + 8 * s, 32768u);
            bulk_g2s(smem_u32(base), g_xpk + ((size_t)rb5 + s) * 16384, 16384u, mb + 8 * s);
            bulk_g2s(smem_u32(base + 16384), g_Wihpk + ((size_t)cb * 5 + s) * 16384,
                     16384u, mb + 8 * s);
        }
    }

    float acc[2][8][4];
#pragma unroll
    for (int a = 0; a < 2; a++)
#pragma unroll
        for (int b = 0; b < 8; b++)
#pragma unroll
            for (int c = 0; c < 4; c++) acc[a][b][c] = 0.f;

    for (int t = 0; t < NC; t++) {
        int b = t % 3;
        mbar_wait(mb + 8 * b, (uint32_t)((t / 3) & 1));
        mma_t64(sm + b * 32768, sm + b * 32768 + 16384, wm, wn, lane, acc);
        __syncthreads();
        if (tid == 0 && t + 3 < NC) {
            int s = t + 3;
            char* base = sm + b * 32768;
            MBAR_EXPECT(mb + 8 * b, 32768u);
            bulk_g2s(smem_u32(base), g_xpk + ((size_t)rb5 + s) * 16384, 16384u, mb + 8 * b);
            bulk_g2s(smem_u32(base + 16384), g_Wihpk + ((size_t)cb * 5 + s) * 16384,
                     16384u, mb + 8 * b);
        }
    }

#pragma unroll
    for (int nt = 0; nt < 8; nt++) {
        int c = colBase + wn * 64 + nt * 8 + (lane & 3) * 2;
        float bx = b_ih[c] + b_hh[c], by = b_ih[c + 1] + b_hh[c + 1];
#pragma unroll
        for (int mt = 0; mt < 2; mt++) {
            int r0 = rowBase + wm * 32 + mt * 16 + (lane >> 2);
            if (r0 < NN)
                *(uint32_t*)(g_xg + (size_t)r0 * 1024 + c) =
                    packh2(acc[mt][nt][0] + bx, acc[mt][nt][1] + by);
            if (r0 + 8 < NN)
                *(uint32_t*)(g_xg + (size_t)(r0 + 8) * 1024 + c) =
                    packh2(acc[mt][nt][2] + bx, acc[mt][nt][3] + by);
        }
    }
}

// ============ level kernel (nd >= 128): 1-pass fp16 + LSTM pointwise =========
__global__ __launch_bounds__(256, 2)
void k_level_mma(int start, int nd) {
    extern __shared__ char sm[];
    char* Abuf[2] = { sm, sm + 16384 };
    char* Bbuf[2] = { sm + 32768, sm + 49152 };
    uint32_t mb = smem_u32(sm + 67584);
    float* stage = (float*)sm;   // [128][132] after GEMM (67584B)

    int tid = threadIdx.x, lane = tid & 31, warp = tid >> 5;
    int wm = warp >> 1, wn = warp & 1;
    int rowBase = blockIdx.x * 128;
    int jb = blockIdx.y;          // j block (32 wide)

    if (tid == 0) { MBAR_INIT(mb); MBAR_INIT(mb + 8); }
    __syncthreads();
    if (tid == 0) {
        MBAR_EXPECT(mb, 16384u);
        bulk_g2s(smem_u32(Bbuf[0]), g_Whhpk + (size_t)(jb * 4) * 16384, 16384u, mb);
        MBAR_EXPECT(mb + 8, 16384u);
        bulk_g2s(smem_u32(Bbuf[1]), g_Whhpk + (size_t)(jb * 4 + 1) * 16384, 16384u, mb + 8);
    }

    float acc[2][8][4];
#pragma unroll
    for (int a = 0; a < 2; a++)
#pragma unroll
        for (int b = 0; b < 8; b++)
#pragma unroll
            for (int c = 0; c < 4; c++) acc[a][b][c] = 0.f;

    uint4 va[4];
    ldg_avgH16(start, nd, rowBase, 0, tid, va);
    sts_u4(Abuf[0], tid, va);
    __syncthreads();

    const int NC = 4;   // K=64 chunks
    for (int t = 0; t < NC; t++) {
        bool more = (t + 1 < NC);
        if (more) ldg_avgH16(start, nd, rowBase, (t + 1) * 64, tid, va);
        mbar_wait(mb + 8 * (t & 1), (t >> 1) & 1);
        mma_t64(Abuf[t & 1], Bbuf[t & 1], wm, wn, lane, acc);
        if (more) sts_u4(Abuf[(t + 1) & 1], tid, va);
        __syncthreads();
        if (tid == 0 && t + 2 < NC) {
            int s = t + 2, b = s & 1;
            MBAR_EXPECT(mb + 8 * b, 16384u);
            bulk_g2s(smem_u32(Bbuf[b]), g_Whhpk + (size_t)(jb * 4 + s) * 16384,
                     16384u, mb + 8 * b);
        }
    }

#pragma unroll
    for (int mt = 0; mt < 2; mt++) {
#pragma unroll
        for (int nt = 0; nt < 8; nt++) {
            int r = wm * 32 + mt * 16 + (lane >> 2);
            int c = wn * 64 + nt * 8 + (lane & 3) * 2;
            stage[r * 132 + c] = acc[mt][nt][0];
            stage[r * 132 + c + 1] = acc[mt][nt][1];
            stage[(r + 8) * 132 + c] = acc[mt][nt][2];
            stage[(r + 8) * 132 + c + 1] = acc[mt][nt][3];
        }
    }
    __syncthreads();

#pragma unroll
    for (int i = 0; i < 16; i++) {
        int idx = tid + 256 * i;
        int r = idx >> 5, jj = idx & 31;
        int rr = rowBase + r;
        if (rr < nd) {
            int node = start + rr;
            int j = jb * 32 + jj;
            const __half* xr = g_xg + (size_t)node * 1024;
            float gi = stage[r * 132 + jj]       + __half2float(xr[j]);
            float gf = stage[r * 132 + 32 + jj]  + __half2float(xr[256 + j]);
            float gg = stage[r * 132 + 64 + jj]  + __half2float(xr[512 + j]);
            float go = stage[r * 132 + 96 + jj]  + __half2float(xr[768 + j]);
            int ci = 2 * node - NN;
            float c0 = 0.5f * (__half2float(g_C[(size_t)ci * 256 + j]) +
                               __half2float(g_C[(size_t)(ci - 1) * 256 + j]));
            float cn = sigf(gf) * c0 + sigf(gi) * tanhf(gg);
            float hn = sigf(go) * tanhf(cn);
            g_H[(size_t)node * 256 + j] = __float2half_rn(hn);
            g_C[(size_t)node * 256 + j] = __float2half_rn(cn);
        }
    }
}

// ---------------- leaves (d = D): c0 = 0 -------------------------------------
__global__ void k_leaf() {
    int n = blockIdx.x;
    int j = threadIdx.x;
    const __half* xr = g_xg + (size_t)n * 1024;
    float gi = __half2float(xr[j]);
    float gg = __half2float(xr[512 + j]);
    float go = __half2float(xr[768 + j]);
    float c = sigf(gi) * tanhf(gg);
    float h = sigf(go) * tanhf(c);
    g_H[(size_t)n * 256 + j] = __float2half_rn(h);
    g_C[(size_t)n * 256 + j] = __float2half_rn(c);
}

// ---------------- SIMT level kernel for small levels -------------------------
__global__ __launch_bounds__(256)
void k_level(int start, int nd, const float* __restrict__ W_hh) {
    __shared__ float h0s[32][36];
    __shared__ float Ws[256][36];
    int tid = threadIdx.x;
    int jx = tid & 63, ry = tid >> 6;
    int rowBase = blockIdx.x * 32;
    int jbase = blockIdx.y * 64;

    float acc[8][4];
#pragma unroll
    for (int i = 0; i < 8; i++)
#pragma unroll
        for (int g = 0; g < 4; g++) acc[i][g] = 0.0f;

    for (int k0 = 0; k0 < 256; k0 += 32) {
        {
            int r = tid >> 3, c4 = tid & 7;
            float4 v = make_float4(0.f, 0.f, 0.f, 0.f);
            int rr = rowBase + r;
            if (rr < nd) {
                int node = start + rr;
                int ci = 2 * node - NN;
                const __half2* a2 = (const __half2*)&g_H[(size_t)ci * 256 + k0 + c4 * 4];
                const __half2* b2 = (const __half2*)&g_H[(size_t)(ci - 1) * 256 + k0 + c4 * 4];
                float2 a0 = __half22float2(a2[0]), a1 = __half22float2(a2[1]);
                float2 b0 = __half22float2(b2[0]), b1 = __half22float2(b2[1]);
                v = make_float4(0.5f * (a0.x + b0.x), 0.5f * (a0.y + b0.y),
                                0.5f * (a1.x + b1.x), 0.5f * (a1.y + b1.y));
            }
            *(float4*)&h0s[r][c4 * 4] = v;
        }
        {
            int wrow = ry * 256 + jbase + jx;
            const float* src = &W_hh[(size_t)wrow * 256 + k0];
#pragma unroll
            for (int c = 0; c < 8; c++)
                *(float4*)&Ws[tid][c * 4] = *(const float4*)&src[c * 4];
        }
        __syncthreads();
#pragma unroll
        for (int kk4 = 0; kk4 < 8; kk4++) {
            float4 w4[4];
#pragma unroll
            for (int g = 0; g < 4; g++)
                w4[g] = *(const float4*)&Ws[g * 64 + jx][kk4 * 4];
#pragma unroll
            for (int i = 0; i < 8; i++) {
                float4 a4 = *(const float4*)&h0s[ry * 8 + i][kk4 * 4];
#pragma unroll
                for (int g = 0; g < 4; g++)
                    acc[i][g] += a4.x * w4[g].x + a4.y * w4[g].y +
                                 a4.z * w4[g].z + a4.w * w4[g].w;
            }
        }
        __syncthreads();
    }

    int j = jbase + jx;
#pragma unroll
    for (int i = 0; i < 8; i++) {
        int rr = rowBase + ry * 8 + i;
        if (rr < nd) {
            int node = start + rr;
            const __half* xr = g_xg + (size_t)node * 1024;
            float gi = acc[i][0] + __half2float(xr[j]);
            float gf = acc[i][1] + __half2float(xr[256 + j]);
            float gg = acc[i][2] + __half2float(xr[512 + j]);
            float go = acc[i][3] + __half2float(xr[768 + j]);
            int ci = 2 * node - NN;
            float c0 = 0.5f * (__half2float(g_C[(size_t)ci * 256 + j]) +
                               __half2float(g_C[(size_t)(ci - 1) * 256 + j]));
            float cn = sigf(gf) * c0 + sigf(gi) * tanhf(gg);
            float hn = sigf(go) * tanhf(cn);
            g_H[(size_t)node * 256 + j] = __float2half_rn(hn);
            g_C[(size_t)node * 256 + j] = __float2half_rn(cn);
        }
    }
}

// ---------------- output heads ----------------------------------------------
__global__ void k_heads(const float* __restrict__ W2a, const float* __restrict__ b2a,
                        const float* __restrict__ W3a, const float* __restrict__ b3a,
                        const float* __restrict__ Woa, const float* __restrict__ boa,
                        const float* __restrict__ W2b, const float* __restrict__ b2b,
                        const float* __restrict__ W3b, const float* __restrict__ b3b,
                        const float* __restrict__ Wob, const float* __restrict__ bob,
                        float* __restrict__ out) {
    __shared__ float hv[256];
    __shared__ float t1[2][128];
    __shared__ float t2[2][128];
    __shared__ float red[256];
    int tid = threadIdx.x;
    hv[tid] = __half2float(g_H[(size_t)(NN - 1) * 256 + tid]);
    __syncthreads();
    int head = tid >> 7, j = tid & 127;
    const float* W2 = head ? W2b : W2a; const float* b2 = head ? b2b : b2a;
    const float* W3 = head ? W3b : W3a; const float* b3 = head ? b3b : b3a;
    const float* Wo = head ? Wob : Woa; const float* bo = head ? bob : boa;

    float t = b2[j];
    for (int k = 0; k < 256; k++) t += W2[j * 256 + k] * hv[k];
    t1[head][j] = fmaxf(t, 0.0f);
    __syncthreads();
    t = b3[j];
    for (int k = 0; k < 128; k++) t += W3[j * 128 + k] * t1[head][k];
    t2[head][j] = fmaxf(t, 0.0f);
    __syncthreads();
    red[tid] = Wo[j] * t2[head][j];
    __syncthreads();
    for (int s = 64; s > 0; s >>= 1) {
        if (j < s) red[tid] += red[tid + s];
        __syncthreads();
    }
    if (j == 0) out[head] = 1.0f / (1.0f + expf(-(red[tid] + bo[0])));
}

// ---------------- launch ------------------------------------------------------
extern "C" void kernel_launch(void* const* d_in, const int* in_sizes, int n_in,
                              void* d_out, int out_size) {
    const float* op_vec   = (const float*)d_in[0];
    const float* c1_preds = (const float*)d_in[1];
    const void*  c1_mask  = d_in[2];
    const void*  c1_and   = d_in[3];
    const float* c2_preds = (const float*)d_in[4];
    const void*  c2_mask  = d_in[5];
    const void*  c2_and   = d_in[6];
    const float* bitmap   = (const float*)d_in[7];
    const float* W_op     = (const float*)d_in[8];
    const float* b_op     = (const float*)d_in[9];
    const float* W_pred   = (const float*)d_in[10];
    const float* b_pred   = (const float*)d_in[11];
    const float* W_bm     = (const float*)d_in[12];
    const float* b_bm     = (const float*)d_in[13];
    const float* W_ih     = (const float*)d_in[14];
    const float* b_ih     = (const float*)d_in[15];
    const float* W_hh     = (const float*)d_in[16];
    const float* b_hh     = (const float*)d_in[17];
    const float* W_h2t1   = (const float*)d_in[18];
    const float* b_h2t1   = (const float*)d_in[19];
    const float* W_h3t1   = (const float*)d_in[20];
    const float* b_h3t1   = (const float*)d_in[21];
    const float* W_o1     = (const float*)d_in[22];
    const float* b_o1     = (const float*)d_in[23];
    const float* W_h2t2   = (const float*)d_in[24];
    const float* b_h2t2   = (const float*)d_in[25];
    const float* W_h3t2   = (const float*)d_in[26];
    const float* b_h3t2   = (const float*)d_in[27];
    const float* W_o2     = (const float*)d_in[28];
    const float* b_o2     = (const float*)d_in[29];
    float* out = (float*)d_out;

    const int SM_PL = 34816 + 64;
    const int SM_BM = 65536 + 64;
    const int SM_XG = 98304 + 64;
    const int SM_LV = 67584 + 64;
    static int configured = 0;
    if (!configured) {
        cudaFuncSetAttribute(k_pool_mma, cudaFuncAttributeMaxDynamicSharedMemorySize, SM_PL);
        cudaFuncSetAttribute(k_bm_mma,   cudaFuncAttributeMaxDynamicSharedMemorySize, SM_BM);
        cudaFuncSetAttribute(k_xg_mma,   cudaFuncAttributeMaxDynamicSharedMemorySize, SM_XG);
        cudaFuncSetAttribute(k_level_mma,cudaFuncAttributeMaxDynamicSharedMemorySize, SM_LV);
        configured = 1;
    }

    k_detect<<<1, 256>>>((const unsigned int*)c1_mask);
    k_wpack<<<(40 * 1024 + 32 * 1024 + 16 * 1024 + 512 + 255) / 256, 256>>>(
        W_ih, W_hh, W_bm, W_pred);

    k_op<<<(NN + 7) / 8, 256>>>(op_vec, W_op, b_op);

    {
        dim3 grid((MRPOOL + 127) / 128, 2);
        k_pool_mma<<<grid, 256, SM_PL>>>(c1_preds, c1_mask, c1_and,
                                         c2_preds, c2_mask, c2_and, b_pred);
    }

    k_bm_mma<<<(NN + 127) / 128, 256, SM_BM>>>(bitmap, b_bm);

    {
        dim3 grid(8, (NN + 127) / 128);
        k_xg_mma<<<grid, 256, SM_XG>>>(b_ih, b_hh);
    }

    k_leaf<<<32768, 256>>>();

    for (int d = 14; d >= 0; d--) {
        int nd = 1 << d;
        int start = NN - (1 << (d + 1)) + 1;
        if (nd >= 128) {
            dim3 grid((nd + 127) / 128, 8);
            k_level_mma<<<grid, 256, SM_LV>>>(start, nd);
        } else {
            dim3 grid((nd + 31) / 32, 4);
            k_level<<<grid, 256>>>(start, nd, W_hh);
        }
    }

    k_heads<<<1, 256>>>(W_h2t1, b_h2t1, W_h3t1, b_h3t1, W_o1, b_o1,
                        W_h2t2, b_h2t2, W_h3t2, b_h3t2, W_o2, b_o2,
                        out);
}

// round 15
// speedup vs baseline: 12.6555x; 1.0238x over previous
#include <cuda_runtime.h>
#include <cuda_fp16.h>
#include <math.h>
#include <cstdint>
#include <stdint.h>

#define NN 65535          // number of tree nodes (2^16 - 1)
#define MRPOOL (NN * 8)   // pool GEMM rows
#define BIGF 1e30f

// Packed tile: 128 rows x 64 fp16 K-values (128B/row), SW128-swizzled
// (byte o -> o ^ ((o>>3)&0x70)); 16KB per tile, bulk-copyable verbatim.
__device__ __forceinline__ int swz(int o) { return o ^ ((o >> 3) & 0x70); }

// ---------------- scratch (static device globals; no cudaMalloc) -------------
__device__ __align__(1024) unsigned char g_xpk[(size_t)512 * 5 * 16384]; // packed features (fp16)
__device__ __half g_xg[(size_t)NN * 1024];         // gates pre-activation (fp16)
__device__ __half g_H[(size_t)NN * 256];           // LSTM hidden (fp16)
__device__ __half g_C[(size_t)NN * 256];           // LSTM cell (fp16)
__device__ int   g_mask_is_byte;

// packed weights (fp16)
__device__ __align__(1024) unsigned char g_Wihpk[40 * 16384];  // 8 colblk x 5 chunks (K=320 pad)
__device__ __align__(1024) unsigned char g_Whhpk[32 * 16384];  // 8 jblk x 4 chunks (K=256)
__device__ __align__(1024) unsigned char g_Wbmpk[16 * 16384];  // 16 chunks (K=1024 pad)
__device__ __align__(1024) unsigned char g_Wppk[8192];         // 64 rows x K=64

__device__ __forceinline__ float sigf(float x) { return 1.0f / (1.0f + expf(-x)); }

__device__ __forceinline__ int read_bool(const void* p, int idx) {
    return g_mask_is_byte ? (int)(((const unsigned char*)p)[idx])
                          : (((const int*)p)[idx] != 0);
}

__device__ __forceinline__ unsigned smem_u32(const void* p) {
    return (unsigned)__cvta_generic_to_shared(p);
}

// ---------------- mbarrier + bulk copy ---------------------------------------
#define MBAR_INIT(a) \
    asm volatile("mbarrier.init.shared.b64 [%0], 1;" :: "r"(a) : "memory")
#define MBAR_EXPECT(a, tx) \
    asm volatile("mbarrier.arrive.expect_tx.shared.b64 _, [%0], %1;" \
                 :: "r"(a), "r"(tx) : "memory")

__device__ __forceinline__ void mbar_wait(uint32_t mbar, uint32_t parity) {
    asm volatile(
        "{\n\t.reg .pred P;\n\t"
        "WL%=:\n\t"
        "mbarrier.try_wait.parity.shared.b64 P, [%0], %1;\n\t"
        "@!P bra WL%=;\n\t}"
        :: "r"(mbar), "r"(parity) : "memory");
}

__device__ __forceinline__ void bulk_g2s(uint32_t dst, const void* src,
                                         uint32_t bytes, uint32_t mbar) {
    asm volatile(
        "cp.async.bulk.shared::cluster.global.mbarrier::complete_tx::bytes "
        "[%0], [%1], %2, [%3];"
        :: "r"(dst), "l"(src), "r"(bytes), "r"(mbar) : "memory");
}

// ---------------- fp16 helpers ------------------------------------------------
__device__ __forceinline__ uint32_t packh2(float x, float y) {
    __half2 h = __floats2half2_rn(x, y);
    return *(uint32_t*)&h;
}
__device__ __forceinline__ __half2 u2h(uint32_t u) { return *(__half2*)&u; }
__device__ __forceinline__ uint32_t h2u(__half2 h) { return *(uint32_t*)&h; }

// ---------------- mma.sync m16n8k16 fp16 + ldmatrix --------------------------
__device__ __forceinline__ void mma_f16(float d[4], const uint32_t a[4], const uint32_t b[2]) {
    asm volatile(
        "mma.sync.aligned.m16n8k16.row.col.f32.f16.f16.f32 "
        "{%0,%1,%2,%3}, {%4,%5,%6,%7}, {%8,%9}, {%0,%1,%2,%3};\n"
        : "+f"(d[0]), "+f"(d[1]), "+f"(d[2]), "+f"(d[3])
        : "r"(a[0]), "r"(a[1]), "r"(a[2]), "r"(a[3]), "r"(b[0]), "r"(b[1]));
}

__device__ __forceinline__ void ldsm4(uint32_t r[4], const void* p) {
    uint32_t addr = smem_u32(p);
    asm volatile("ldmatrix.sync.aligned.m8n8.x4.shared.b16 {%0,%1,%2,%3}, [%4];"
                 : "=r"(r[0]), "=r"(r[1]), "=r"(r[2]), "=r"(r[3]) : "r"(addr));
}

// 1-pass K=64 tile, 32x64 warp tile (bm, xg, levels)
__device__ __forceinline__ void mma_t64(const char* As, const char* Bs,
                                        int wm, int wn, int lane, float acc[2][8][4]) {
    int lrow = lane & 15, l16 = (lane >> 4) * 16;
#pragma unroll
    for (int ks = 0; ks < 4; ks++) {
        int kb = ks * 32 + l16;
        uint32_t a[2][4];
#pragma unroll
        for (int mt = 0; mt < 2; mt++)
            ldsm4(a[mt], As + swz((wm * 32 + mt * 16 + lrow) * 128 + kb));
#pragma unroll
        for (int g = 0; g < 4; g++) {
            uint32_t b[4];
            ldsm4(b, Bs + swz((wn * 64 + g * 16 + lrow) * 128 + kb));
            uint32_t b0[2] = { b[0], b[2] }, b1[2] = { b[1], b[3] };
#pragma unroll
            for (int mt = 0; mt < 2; mt++) {
                mma_f16(acc[mt][g * 2],     a[mt], b0);
                mma_f16(acc[mt][g * 2 + 1], a[mt], b1);
            }
        }
    }
}

// 1-pass K=64 tile, 32x32 warp tile (pool)
__device__ __forceinline__ void mma_t64_32(const char* As, const char* Bs,
                                           int wm, int wn, int lane, float acc[2][4][4]) {
    int lrow = lane & 15, l16 = (lane >> 4) * 16;
#pragma unroll
    for (int ks = 0; ks < 4; ks++) {
        int kb = ks * 32 + l16;
        uint32_t a[2][4];
#pragma unroll
        for (int mt = 0; mt < 2; mt++)
            ldsm4(a[mt], As + swz((wm * 32 + mt * 16 + lrow) * 128 + kb));
#pragma unroll
        for (int g = 0; g < 2; g++) {
            uint32_t b[4];
            ldsm4(b, Bs + swz((wn * 32 + g * 16 + lrow) * 128 + kb));
            uint32_t b0[2] = { b[0], b[2] }, b1[2] = { b[1], b[3] };
#pragma unroll
            for (int mt = 0; mt < 2; mt++) {
                mma_f16(acc[mt][g * 2],     a[mt], b0);
                mma_f16(acc[mt][g * 2 + 1], a[mt], b1);
            }
        }
    }
}

// ---------------- A-side loaders ----------------------------------------------
// K=64 tile loader: 128 rows x 8 units of 8 floats; 4 slots/thread
__device__ __forceinline__ void ldg_f32u(const float* __restrict__ src, int ld, int rowBase,
                                         int maxRow, int k0, int Ktot, int tid, float4 (*v)[2]) {
#pragma unroll
    for (int s = 0; s < 4; s++) {
        int idx = tid + 256 * s;
        int r = idx >> 3, u = idx & 7;
        int row = rowBase + r, k = k0 + u * 8;
        float4 a = make_float4(0.f, 0.f, 0.f, 0.f), b = a;
        if (row < maxRow && k + 8 <= Ktot) {
            const float* p = src + (size_t)row * ld + k;
            a = *(const float4*)p;
            b = *(const float4*)(p + 4);
        }
        v[s][0] = a; v[s][1] = b;
    }
}

__device__ __forceinline__ void sts_h64(char* As, int tid, float4 (*v)[2]) {
#pragma unroll
    for (int s = 0; s < 4; s++) {
        int idx = tid + 256 * s;
        int r = idx >> 3, u = idx & 7;
        uint4 h;
        h.x = packh2(v[s][0].x, v[s][0].y);
        h.y = packh2(v[s][0].z, v[s][0].w);
        h.z = packh2(v[s][1].x, v[s][1].y);
        h.w = packh2(v[s][1].z, v[s][1].w);
        *(uint4*)(As + swz(r * 128 + u * 16)) = h;
    }
}

// level A: K=64 chunk of averaged child H (fp16 in, fp16 out); 4 slots/thread
__device__ __forceinline__ void ldg_avgH16(int start, int nd, int rowBase, int k0, int tid,
                                           uint4* v) {
    __half2 half2c = __float2half2_rn(0.5f);
#pragma unroll
    for (int s = 0; s < 4; s++) {
        int idx = tid + 256 * s;
        int r = idx >> 3, u = idx & 7;
        int rr = rowBase + r;
        uint4 out = make_uint4(0, 0, 0, 0);
        if (rr < nd) {
            int node = start + rr;
            int ci = 2 * node - NN;
            uint4 A = *(const uint4*)(g_H + (size_t)ci * 256 + k0 + u * 8);
            uint4 B = *(const uint4*)(g_H + (size_t)(ci - 1) * 256 + k0 + u * 8);
            out.x = h2u(__hmul2(__hadd2(u2h(A.x), u2h(B.x)), half2c));
            out.y = h2u(__hmul2(__hadd2(u2h(A.y), u2h(B.y)), half2c));
            out.z = h2u(__hmul2(__hadd2(u2h(A.z), u2h(B.z)), half2c));
            out.w = h2u(__hmul2(__hadd2(u2h(A.w), u2h(B.w)), half2c));
        }
        v[s] = out;
    }
}

__device__ __forceinline__ void sts_u4(char* As, int tid, const uint4* v) {
#pragma unroll
    for (int s = 0; s < 4; s++) {
        int idx = tid + 256 * s;
        int r = idx >> 3, u = idx & 7;
        *(uint4*)(As + swz(r * 128 + u * 16)) = v[s];
    }
}

// ---------------- small kernels ----------------------------------------------
__global__ void k_detect(const unsigned int* __restrict__ m) {
    __shared__ int found;
    if (threadIdx.x == 0) found = 0;
    __syncthreads();
    unsigned int v = m[threadIdx.x];
    if (v > 1u) found = 1;
    __syncthreads();
    if (threadIdx.x == 0) g_mask_is_byte = found;
}

__device__ __forceinline__ void pack8h(const float* s, unsigned char* dst,
                                       int r, int u, bool zero) {
    uint4 h;
    h.x = packh2(zero ? 0.f : s[0], zero ? 0.f : s[1]);
    h.y = packh2(zero ? 0.f : s[2], zero ? 0.f : s[3]);
    h.z = packh2(zero ? 0.f : s[4], zero ? 0.f : s[5]);
    h.w = packh2(zero ? 0.f : s[6], zero ? 0.f : s[7]);
    *(uint4*)(dst + swz(r * 128 + u * 16)) = h;
}

__global__ void k_wpack(const float* __restrict__ Wih, const float* __restrict__ Whh,
                        const float* __restrict__ Wbm, const float* __restrict__ Wp) {
    int i = blockIdx.x * 256 + threadIdx.x;
    const int N1 = 40 * 1024;
    const int N2 = 32 * 1024;
    const int N3 = 16 * 1024;
    const int N4 = 512;
    if (i < N1) {
        int t = i >> 10, rem = i & 1023, r = rem >> 3, u = rem & 7;
        int cb = t / 5, ch = t % 5;
        int k = ch * 64 + u * 8;
        bool zero = (k >= 288);
        pack8h(Wih + (size_t)(cb * 128 + r) * 288 + (zero ? 0 : k),
               g_Wihpk + (size_t)t * 16384, r, u, zero);
    } else if (i < N1 + N2) {
        int j = i - N1;
        int t = j >> 10, rem = j & 1023, r = rem >> 3, u = rem & 7;
        int jb = t / 4, ch = t % 4;
        int wrow = (r >> 5) * 256 + jb * 32 + (r & 31);
        pack8h(Whh + (size_t)wrow * 256 + ch * 64 + u * 8,
               g_Whhpk + (size_t)t * 16384, r, u, false);
    } else if (i < N1 + N2 + N3) {
        int j = i - N1 - N2;
        int t = j >> 10, rem = j & 1023, r = rem >> 3, u = rem & 7;
        int k = t * 64 + u * 8;
        bool zero = (k + 8 > 1000);
        pack8h(Wbm + (size_t)r * 1000 + (zero ? 0 : k),
               g_Wbmpk + (size_t)t * 16384, r, u, zero);
    } else if (i < N1 + N2 + N3 + N4) {
        int j = i - N1 - N2 - N3;
        int r = j >> 3, u = j & 7;
        pack8h(Wp + (size_t)r * 64 + u * 8, g_Wppk, r, u, false);
    }
}

__global__ void k_op(const float* __restrict__ op_vec,
                     const float* __restrict__ W_op,
                     const float* __restrict__ b_op) {
    __shared__ float Ws[32][33];
    __shared__ float bs[32];
    int tid = threadIdx.x;
    if (tid < 32) bs[tid] = b_op[tid];
    for (int i = tid; i < 1024; i += 256) Ws[i >> 5][i & 31] = W_op[i];
    __syncthreads();
    int node = blockIdx.x * 8 + (tid >> 5);
    int o = tid & 31;
    if (node >= NN) return;
    float vl = op_vec[node * 32 + o];
    float acc = bs[o];
#pragma unroll
    for (int p = 0; p < 32; p++)
        acc += Ws[o][p] * __shfl_sync(0xffffffffu, vl, p);
    int blk = node >> 7, r = node & 127;
    unsigned char* tb = g_xpk + (size_t)blk * 5 * 16384;   // chunk 0
    *(__half*)(tb + swz(r * 128 + o * 2)) = __float2half_rn(acc);
}

// ============ GEMM 1: pool (128Mx64N, single K=64 tile, 1-pass) ==============
__global__ __launch_bounds__(256, 4)
void k_pool_mma(const float* __restrict__ preds1, const void* mask1, const void* and1,
                const float* __restrict__ preds2, const void* mask2, const void* and2,
                const float* __restrict__ b_pred) {
    extern __shared__ char sm[];
    char* Abuf = sm;                 // 16KB
    char* Bbuf = sm + 16384;         // 8KB
    uint32_t mb = smem_u32(sm + 34816);
    float* stage = (float*)sm;       // [128][68] after GEMM (34816B)

    int tid = threadIdx.x, lane = tid & 31, warp = tid >> 5;
    int wm = warp >> 1, wn = warp & 1;
    int cond = blockIdx.y;
    const float* preds = cond ? preds2 : preds1;
    const void*  maskp = cond ? mask2 : mask1;
    const void*  andp  = cond ? and2  : and1;
    int rowBase = blockIdx.x * 128;

    if (tid == 0) MBAR_INIT(mb);
    __syncthreads();
    if (tid == 0) {
        MBAR_EXPECT(mb, 8192u);
        bulk_g2s(smem_u32(Bbuf), g_Wppk, 8192u, mb);
    }

    float acc[2][4][4];
#pragma unroll
    for (int a = 0; a < 2; a++)
#pragma unroll
        for (int b = 0; b < 4; b++)
#pragma unroll
            for (int c = 0; c < 4; c++) acc[a][b][c] = 0.f;

    float4 va[4][2];
    ldg_f32u(preds, 64, rowBase, MRPOOL, 0, 64, tid, va);
    sts_h64(Abuf, tid, va);
    mbar_wait(mb, 0);
    __syncthreads();

    mma_t64_32(Abuf, Bbuf, wm, wn, lane, acc);
    __syncthreads();

#pragma unroll
    for (int mt = 0; mt < 2; mt++) {
#pragma unroll
        for (int nt = 0; nt < 4; nt++) {
            int r = wm * 32 + mt * 16 + (lane >> 2);
            int c = wn * 32 + nt * 8 + (lane & 3) * 2;
            stage[r * 68 + c] = acc[mt][nt][0];
            stage[r * 68 + c + 1] = acc[mt][nt][1];
            stage[(r + 8) * 68 + c] = acc[mt][nt][2];
            stage[(r + 8) * 68 + c + 1] = acc[mt][nt][3];
        }
    }
    __syncthreads();

    int node = blockIdx.x * 16 + (tid >> 4);
    int cg = (tid & 15) * 4;
    if (node < NN) {
        float bb[4];
        *(float4*)bb = *(const float4*)(b_pred + cg);
        int mk[8], anyb = 0;
#pragma unroll
        for (int i = 0; i < 8; i++) { mk[i] = read_bool(maskp, node * 8 + i); anyb |= mk[i]; }
        int ia = read_bool(andp, node);
        int rb = (tid >> 4) * 8;
        float out[4];
#pragma unroll
        for (int j = 0; j < 4; j++) {
            float mn = BIGF, mx = -BIGF;
#pragma unroll
            for (int i = 0; i < 8; i++) {
                float v = stage[(rb + i) * 68 + cg + j] + bb[j];
                if (mk[i]) { mn = fminf(mn, v); mx = fmaxf(mx, v); }
            }
            out[j] = anyb ? (ia ? mn : mx) : 0.0f;
        }
        int col0 = 32 + cond * 64 + cg;
        int ch = col0 >> 6, co = col0 & 63;
        int r = node & 127;
        unsigned char* tb = g_xpk + ((size_t)(node >> 7) * 5 + ch) * 16384;
        *(uint2*)(tb + swz(r * 128 + co * 2)) =
            make_uint2(packh2(out[0], out[1]), packh2(out[2], out[3]));
    }
}

// ============ GEMM 2: bm (128Mx128N, 16 K=64 chunks, 1-pass) =================
__global__ __launch_bounds__(256, 2)
void k_bm_mma(const float* __restrict__ bitmap, const float* __restrict__ b_bm) {
    extern __shared__ char sm[];
    char* Abuf[2] = { sm, sm + 16384 };
    char* Bbuf[2] = { sm + 32768, sm + 49152 };
    uint32_t mb = smem_u32(sm + 65536);
    int tid = threadIdx.x, lane = tid & 31, warp = tid >> 5;
    int wm = warp >> 1, wn = warp & 1;
    int rowBase = blockIdx.x * 128;

    if (tid == 0) { MBAR_INIT(mb); MBAR_INIT(mb + 8); }
    __syncthreads();
    if (tid == 0) {
        MBAR_EXPECT(mb, 16384u);
        bulk_g2s(smem_u32(Bbuf[0]), g_Wbmpk, 16384u, mb);
        MBAR_EXPECT(mb + 8, 16384u);
        bulk_g2s(smem_u32(Bbuf[1]), g_Wbmpk + 16384, 16384u, mb + 8);
    }

    float acc[2][8][4];
#pragma unroll
    for (int a = 0; a < 2; a++)
#pragma unroll
        for (int b = 0; b < 8; b++)
#pragma unroll
            for (int c = 0; c < 4; c++) acc[a][b][c] = 0.f;

    float4 va[4][2];
    ldg_f32u(bitmap, 1000, rowBase, NN, 0, 1000, tid, va);
    sts_h64(Abuf[0], tid, va);
    __syncthreads();

    const int NC = 16;
    for (int t = 0; t < NC; t++) {
        bool more = (t + 1 < NC);
        if (more) ldg_f32u(bitmap, 1000, rowBase, NN, (t + 1) * 64, 1000, tid, va);
        mbar_wait(mb + 8 * (t & 1), (t >> 1) & 1);
        mma_t64(Abuf[t & 1], Bbuf[t & 1], wm, wn, lane, acc);
        if (more) sts_h64(Abuf[(t + 1) & 1], tid, va);
        __syncthreads();
        if (tid == 0 && t + 2 < NC) {
            int s = t + 2, b = s & 1;
            MBAR_EXPECT(mb + 8 * b, 16384u);
            bulk_g2s(smem_u32(Bbuf[b]), g_Wbmpk + (size_t)s * 16384, 16384u, mb + 8 * b);
        }
    }

#pragma unroll
    for (int nt = 0; nt < 8; nt++) {
        int c = wn * 64 + nt * 8 + (lane & 3) * 2;
        float bx = b_bm[c], by = b_bm[c + 1];
        int ch = (160 + c) >> 6, co = (160 + c) & 63;
#pragma unroll
        for (int mt = 0; mt < 2; mt++) {
            int r0 = rowBase + wm * 32 + mt * 16 + (lane >> 2);
#pragma unroll
            for (int hh = 0; hh < 2; hh++) {
                int row = r0 + hh * 8;
                if (row < NN) {
                    int r = row & 127;
                    unsigned char* tb = g_xpk + ((size_t)(row >> 7) * 5 + ch) * 16384;
                    *(uint32_t*)(tb + swz(r * 128 + co * 2)) =
                        packh2(acc[mt][nt][hh * 2] + bx, acc[mt][nt][hh * 2 + 1] + by);
                }
            }
        }
    }
}

// ============ GEMM 3: xg (128Mx128N, 5 K=64 chunks, all-bulk, 1-pass) ========
__global__ __launch_bounds__(256, 2)
void k_xg_mma(const float* __restrict__ b_ih, const float* __restrict__ b_hh) {
    int colBase = blockIdx.x * 128;
    int rowBase = blockIdx.y * 128;
    // f-gate columns [256,512) are never read for leaf nodes (< 32768)
    if ((colBase == 256 || colBase == 384) && rowBase + 128 <= 32768) return;

    extern __shared__ char sm[];
    uint32_t mb = smem_u32(sm + 98304);
    int tid = threadIdx.x, lane = tid & 31, warp = tid >> 5;
    int wm = warp >> 1, wn = warp & 1;
    int cb = colBase >> 7;
    int rb5 = (rowBase >> 7) * 5;

    if (tid == 0) { MBAR_INIT(mb); MBAR_INIT(mb + 8); MBAR_INIT(mb + 16); }
    __syncthreads();
    const int NC = 5;
    if (tid == 0) {
#pragma unroll
        for (int s = 0; s < 3; s++) {
            char* base = sm + s * 32768;
            MBAR_EXPECT(mb + 8 * s, 32768u);
            bulk_g2s(smem_u32(base), g_xpk + ((size_t)rb5 + s) * 16384, 16384u, mb + 8 * s);
            bulk_g2s(smem_u32(base + 16384), g_Wihpk + ((size_t)cb * 5 + s) * 16384,
                     16384u, mb + 8 * s);
        }
    }

    float acc[2][8][4];
#pragma unroll
    for (int a = 0; a < 2; a++)
#pragma unroll
        for (int b = 0; b < 8; b++)
#pragma unroll
            for (int c = 0; c < 4; c++) acc[a][b][c] = 0.f;

    for (int t = 0; t < NC; t++) {
        int b = t % 3;
        mbar_wait(mb + 8 * b, (uint32_t)((t / 3) & 1));
        mma_t64(sm + b * 32768, sm + b * 32768 + 16384, wm, wn, lane, acc);
        __syncthreads();
        if (tid == 0 && t + 3 < NC) {
            int s = t + 3;
            char* base = sm + b * 32768;
            MBAR_EXPECT(mb + 8 * b, 32768u);
            bulk_g2s(smem_u32(base), g_xpk + ((size_t)rb5 + s) * 16384, 16384u, mb + 8 * b);
            bulk_g2s(smem_u32(base + 16384), g_Wihpk + ((size_t)cb * 5 + s) * 16384,
                     16384u, mb + 8 * b);
        }
    }

#pragma unroll
    for (int nt = 0; nt < 8; nt++) {
        int c = colBase + wn * 64 + nt * 8 + (lane & 3) * 2;
        float bx = b_ih[c] + b_hh[c], by = b_ih[c + 1] + b_hh[c + 1];
#pragma unroll
        for (int mt = 0; mt < 2; mt++) {
            int r0 = rowBase + wm * 32 + mt * 16 + (lane >> 2);
            if (r0 < NN)
                *(uint32_t*)(g_xg + (size_t)r0 * 1024 + c) =
                    packh2(acc[mt][nt][0] + bx, acc[mt][nt][1] + by);
            if (r0 + 8 < NN)
                *(uint32_t*)(g_xg + (size_t)(r0 + 8) * 1024 + c) =
                    packh2(acc[mt][nt][2] + bx, acc[mt][nt][3] + by);
        }
    }
}

// ============ level kernel (nd >= 128): 1-pass fp16 + LSTM pointwise =========
__global__ __launch_bounds__(256, 2)
void k_level_mma(int start, int nd) {
    extern __shared__ char sm[];
    char* Abuf[2] = { sm, sm + 16384 };
    char* Bbuf[2] = { sm + 32768, sm + 49152 };
    uint32_t mb = smem_u32(sm + 67584);
    float* stage = (float*)sm;   // [128][132] after GEMM (67584B)

    int tid = threadIdx.x, lane = tid & 31, warp = tid >> 5;
    int wm = warp >> 1, wn = warp & 1;
    int rowBase = blockIdx.x * 128;
    int jb = blockIdx.y;          // j block (32 wide)

    if (tid == 0) { MBAR_INIT(mb); MBAR_INIT(mb + 8); }
    __syncthreads();
    if (tid == 0) {
        MBAR_EXPECT(mb, 16384u);
        bulk_g2s(smem_u32(Bbuf[0]), g_Whhpk + (size_t)(jb * 4) * 16384, 16384u, mb);
        MBAR_EXPECT(mb + 8, 16384u);
        bulk_g2s(smem_u32(Bbuf[1]), g_Whhpk + (size_t)(jb * 4 + 1) * 16384, 16384u, mb + 8);
    }

    float acc[2][8][4];
#pragma unroll
    for (int a = 0; a < 2; a++)
#pragma unroll
        for (int b = 0; b < 8; b++)
#pragma unroll
            for (int c = 0; c < 4; c++) acc[a][b][c] = 0.f;

    uint4 va[4];
    ldg_avgH16(start, nd, rowBase, 0, tid, va);
    sts_u4(Abuf[0], tid, va);
    __syncthreads();

    const int NC = 4;   // K=64 chunks
    for (int t = 0; t < NC; t++) {
        bool more = (t + 1 < NC);
        if (more) ldg_avgH16(start, nd, rowBase, (t + 1) * 64, tid, va);
        mbar_wait(mb + 8 * (t & 1), (t >> 1) & 1);
        mma_t64(Abuf[t & 1], Bbuf[t & 1], wm, wn, lane, acc);
        if (more) sts_u4(Abuf[(t + 1) & 1], tid, va);
        __syncthreads();
        if (tid == 0 && t + 2 < NC) {
            int s = t + 2, b = s & 1;
            MBAR_EXPECT(mb + 8 * b, 16384u);
            bulk_g2s(smem_u32(Bbuf[b]), g_Whhpk + (size_t)(jb * 4 + s) * 16384,
                     16384u, mb + 8 * b);
        }
    }

#pragma unroll
    for (int mt = 0; mt < 2; mt++) {
#pragma unroll
        for (int nt = 0; nt < 8; nt++) {
            int r = wm * 32 + mt * 16 + (lane >> 2);
            int c = wn * 64 + nt * 8 + (lane & 3) * 2;
            stage[r * 132 + c] = acc[mt][nt][0];
            stage[r * 132 + c + 1] = acc[mt][nt][1];
            stage[(r + 8) * 132 + c] = acc[mt][nt][2];
            stage[(r + 8) * 132 + c + 1] = acc[mt][nt][3];
        }
    }
    __syncthreads();

#pragma unroll
    for (int i = 0; i < 16; i++) {
        int idx = tid + 256 * i;
        int r = idx >> 5, jj = idx & 31;
        int rr = rowBase + r;
        if (rr < nd) {
            int node = start + rr;
            int j = jb * 32 + jj;
            const __half* xr = g_xg + (size_t)node * 1024;
            float gi = stage[r * 132 + jj]       + __half2float(xr[j]);
            float gf = stage[r * 132 + 32 + jj]  + __half2float(xr[256 + j]);
            float gg = stage[r * 132 + 64 + jj]  + __half2float(xr[512 + j]);
            float go = stage[r * 132 + 96 + jj]  + __half2float(xr[768 + j]);
            int ci = 2 * node - NN;
            float c0 = 0.5f * (__half2float(g_C[(size_t)ci * 256 + j]) +
                               __half2float(g_C[(size_t)(ci - 1) * 256 + j]));
            float cn = sigf(gf) * c0 + sigf(gi) * tanhf(gg);
            float hn = sigf(go) * tanhf(cn);
            g_H[(size_t)node * 256 + j] = __float2half_rn(hn);
            g_C[(size_t)node * 256 + j] = __float2half_rn(cn);
        }
    }
}

// ---------------- leaves (d = D): c0 = 0 -------------------------------------
__global__ void k_leaf() {
    int n = blockIdx.x;
    int j = threadIdx.x;
    const __half* xr = g_xg + (size_t)n * 1024;
    float gi = __half2float(xr[j]);
    float gg = __half2float(xr[512 + j]);
    float go = __half2float(xr[768 + j]);
    float c = sigf(gi) * tanhf(gg);
    float h = sigf(go) * tanhf(c);
    g_H[(size_t)n * 256 + j] = __float2half_rn(h);
    g_C[(size_t)n * 256 + j] = __float2half_rn(c);
}

// ---------------- SIMT level kernel for small levels -------------------------
__global__ __launch_bounds__(256)
void k_level(int start, int nd, const float* __restrict__ W_hh) {
    __shared__ float h0s[32][36];
    __shared__ float Ws[256][36];
    int tid = threadIdx.x;
    int jx = tid & 63, ry = tid >> 6;
    int rowBase = blockIdx.x * 32;
    int jbase = blockIdx.y * 64;

    float acc[8][4];
#pragma unroll
    for (int i = 0; i < 8; i++)
#pragma unroll
        for (int g = 0; g < 4; g++) acc[i][g] = 0.0f;

    for (int k0 = 0; k0 < 256; k0 += 32) {
        {
            int r = tid >> 3, c4 = tid & 7;
            float4 v = make_float4(0.f, 0.f, 0.f, 0.f);
            int rr = rowBase + r;
            if (rr < nd) {
                int node = start + rr;
                int ci = 2 * node - NN;
                const __half2* a2 = (const __half2*)&g_H[(size_t)ci * 256 + k0 + c4 * 4];
                const __half2* b2 = (const __half2*)&g_H[(size_t)(ci - 1) * 256 + k0 + c4 * 4];
                float2 a0 = __half22float2(a2[0]), a1 = __half22float2(a2[1]);
                float2 b0 = __half22float2(b2[0]), b1 = __half22float2(b2[1]);
                v = make_float4(0.5f * (a0.x + b0.x), 0.5f * (a0.y + b0.y),
                                0.5f * (a1.x + b1.x), 0.5f * (a1.y + b1.y));
            }
            *(float4*)&h0s[r][c4 * 4] = v;
        }
        {
            int wrow = ry * 256 + jbase + jx;
            const float* src = &W_hh[(size_t)wrow * 256 + k0];
#pragma unroll
            for (int c = 0; c < 8; c++)
                *(float4*)&Ws[tid][c * 4] = *(const float4*)&src[c * 4];
        }
        __syncthreads();
#pragma unroll
        for (int kk4 = 0; kk4 < 8; kk4++) {
            float4 w4[4];
#pragma unroll
            for (int g = 0; g < 4; g++)
                w4[g] = *(const float4*)&Ws[g * 64 + jx][kk4 * 4];
#pragma unroll
            for (int i = 0; i < 8; i++) {
                float4 a4 = *(const float4*)&h0s[ry * 8 + i][kk4 * 4];
#pragma unroll
                for (int g = 0; g < 4; g++)
                    acc[i][g] += a4.x * w4[g].x + a4.y * w4[g].y +
                                 a4.z * w4[g].z + a4.w * w4[g].w;
            }
        }
        __syncthreads();
    }

    int j = jbase + jx;
#pragma unroll
    for (int i = 0; i < 8; i++) {
        int rr = rowBase + ry * 8 + i;
        if (rr < nd) {
            int node = start + rr;
            const __half* xr = g_xg + (size_t)node * 1024;
            float gi = acc[i][0] + __half2float(xr[j]);
            float gf = acc[i][1] + __half2float(xr[256 + j]);
            float gg = acc[i][2] + __half2float(xr[512 + j]);
            float go = acc[i][3] + __half2float(xr[768 + j]);
            int ci = 2 * node - NN;
            float c0 = 0.5f * (__half2float(g_C[(size_t)ci * 256 + j]) +
                               __half2float(g_C[(size_t)(ci - 1) * 256 + j]));
            float cn = sigf(gf) * c0 + sigf(gi) * tanhf(gg);
            float hn = sigf(go) * tanhf(cn);
            g_H[(size_t)node * 256 + j] = __float2half_rn(hn);
            g_C[(size_t)node * 256 + j] = __float2half_rn(cn);
        }
    }
}

// ---------------- output heads ----------------------------------------------
__global__ void k_heads(const float* __restrict__ W2a, const float* __restrict__ b2a,
                        const float* __restrict__ W3a, const float* __restrict__ b3a,
                        const float* __restrict__ Woa, const float* __restrict__ boa,
                        const float* __restrict__ W2b, const float* __restrict__ b2b,
                        const float* __restrict__ W3b, const float* __restrict__ b3b,
                        const float* __restrict__ Wob, const float* __restrict__ bob,
                        float* __restrict__ out) {
    __shared__ float hv[256];
    __shared__ float t1[2][128];
    __shared__ float t2[2][128];
    __shared__ float red[256];
    int tid = threadIdx.x;
    hv[tid] = __half2float(g_H[(size_t)(NN - 1) * 256 + tid]);
    __syncthreads();
    int head = tid >> 7, j = tid & 127;
    const float* W2 = head ? W2b : W2a; const float* b2 = head ? b2b : b2a;
    const float* W3 = head ? W3b : W3a; const float* b3 = head ? b3b : b3a;
    const float* Wo = head ? Wob : Woa; const float* bo = head ? bob : boa;

    float t = b2[j];
    for (int k = 0; k < 256; k++) t += W2[j * 256 + k] * hv[k];
    t1[head][j] = fmaxf(t, 0.0f);
    __syncthreads();
    t = b3[j];
    for (int k = 0; k < 128; k++) t += W3[j * 128 + k] * t1[head][k];
    t2[head][j] = fmaxf(t, 0.0f);
    __syncthreads();
    red[tid] = Wo[j] * t2[head][j];
    __syncthreads();
    for (int s = 64; s > 0; s >>= 1) {
        if (j < s) red[tid] += red[tid + s];
        __syncthreads();
    }
    if (j == 0) out[head] = 1.0f / (1.0f + expf(-(red[tid] + bo[0])));
}

// ---------------- launch ------------------------------------------------------
extern "C" void kernel_launch(void* const* d_in, const int* in_sizes, int n_in,
                              void* d_out, int out_size) {
    const float* op_vec   = (const float*)d_in[0];
    const float* c1_preds = (const float*)d_in[1];
    const void*  c1_mask  = d_in[2];
    const void*  c1_and   = d_in[3];
    const float* c2_preds = (const float*)d_in[4];
    const void*  c2_mask  = d_in[5];
    const void*  c2_and   = d_in[6];
    const float* bitmap   = (const float*)d_in[7];
    const float* W_op     = (const float*)d_in[8];
    const float* b_op     = (const float*)d_in[9];
    const float* W_pred   = (const float*)d_in[10];
    const float* b_pred   = (const float*)d_in[11];
    const float* W_bm     = (const float*)d_in[12];
    const float* b_bm     = (const float*)d_in[13];
    const float* W_ih     = (const float*)d_in[14];
    const float* b_ih     = (const float*)d_in[15];
    const float* W_hh     = (const float*)d_in[16];
    const float* b_hh     = (const float*)d_in[17];
    const float* W_h2t1   = (const float*)d_in[18];
    const float* b_h2t1   = (const float*)d_in[19];
    const float* W_h3t1   = (const float*)d_in[20];
    const float* b_h3t1   = (const float*)d_in[21];
    const float* W_o1     = (const float*)d_in[22];
    const float* b_o1     = (const float*)d_in[23];
    const float* W_h2t2   = (const float*)d_in[24];
    const float* b_h2t2   = (const float*)d_in[25];
    const float* W_h3t2   = (const float*)d_in[26];
    const float* b_h3t2   = (const float*)d_in[27];
    const float* W_o2     = (const float*)d_in[28];
    const float* b_o2     = (const float*)d_in[29];
    float* out = (float*)d_out;

    const int SM_PL = 34816 + 64;
    const int SM_BM = 65536 + 64;
    const int SM_XG = 98304 + 64;
    const int SM_LV = 67584 + 64;
    static int configured = 0;
    static cudaStream_t s1, s2;
    static cudaEvent_t evRoot, ev1, ev2;
    if (!configured) {
        cudaFuncSetAttribute(k_pool_mma, cudaFuncAttributeMaxDynamicSharedMemorySize, SM_PL);
        cudaFuncSetAttribute(k_bm_mma,   cudaFuncAttributeMaxDynamicSharedMemorySize, SM_BM);
        cudaFuncSetAttribute(k_xg_mma,   cudaFuncAttributeMaxDynamicSharedMemorySize, SM_XG);
        cudaFuncSetAttribute(k_level_mma,cudaFuncAttributeMaxDynamicSharedMemorySize, SM_LV);
        cudaStreamCreateWithFlags(&s1, cudaStreamNonBlocking);
        cudaStreamCreateWithFlags(&s2, cudaStreamNonBlocking);
        cudaEventCreateWithFlags(&evRoot, cudaEventDisableTiming);
        cudaEventCreateWithFlags(&ev1, cudaEventDisableTiming);
        cudaEventCreateWithFlags(&ev2, cudaEventDisableTiming);
        configured = 1;
    }

    // ---- serial prologue on stream 0: producers of shared packed state ----
    k_detect<<<1, 256>>>((const unsigned int*)c1_mask);
    k_wpack<<<(40 * 1024 + 32 * 1024 + 16 * 1024 + 512 + 255) / 256, 256>>>(
        W_ih, W_hh, W_bm, W_pred);

    // ---- fork: three independent branches (all packed weights ready) ----
    cudaEventRecord(evRoot, 0);
    cudaStreamWaitEvent(s1, evRoot, 0);
    cudaStreamWaitEvent(s2, evRoot, 0);

    // branch 0 (default stream): pool (DRAM-stream bound)
    {
        dim3 grid((MRPOOL + 127) / 128, 2);
        k_pool_mma<<<grid, 256, SM_PL>>>(c1_preds, c1_mask, c1_and,
                                         c2_preds, c2_mask, c2_and, b_pred);
    }

    // branch 1 (s1): bm (tensor bound)
    k_bm_mma<<<(NN + 127) / 128, 256, SM_BM, s1>>>(bitmap, b_bm);

    // branch 2 (s2): op projection (tiny)
    k_op<<<(NN + 7) / 8, 256, 0, s2>>>(op_vec, W_op, b_op);

    // ---- join ----
    cudaEventRecord(ev1, s1);
    cudaEventRecord(ev2, s2);
    cudaStreamWaitEvent(0, ev1, 0);
    cudaStreamWaitEvent(0, ev2, 0);

    {
        dim3 grid(8, (NN + 127) / 128);
        k_xg_mma<<<grid, 256, SM_XG>>>(b_ih, b_hh);
    }

    k_leaf<<<32768, 256>>>();

    for (int d = 14; d >= 0; d--) {
        int nd = 1 << d;
        int start = NN - (1 << (d + 1)) + 1;
        if (nd >= 128) {
            dim3 grid((nd + 127) / 128, 8);
            k_level_mma<<<grid, 256, SM_LV>>>(start, nd);
        } else {
            dim3 grid((nd + 31) / 32, 4);
            k_level<<<grid, 256>>>(start, nd, W_hh);
        }
    }

    k_heads<<<1, 256>>>(W_h2t1, b_h2t1, W_h3t1, b_h3t1, W_o1, b_o1,
                        W_h2t2, b_h2t2, W_h3t2, b_h3t2, W_o2, b_o2,
                        out);
}